// round 2
// baseline (speedup 1.0000x reference)
#include <cuda_runtime.h>
#include <math.h>

#define BB 4
#define TT 1024
#define CC 1024
#define HH 16
#define NN 64
#define MM (BB*TT)   // 4096 rows

// ---------------------------------------------------------------------------
// Scratch (static device memory: allocation-free per harness rules)
// ---------------------------------------------------------------------------
struct Scratch {
    float xx   [MM*CC];
    float xmix [MM*CC];
    float mixin[MM*128];
    float xrg  [MM*CC];
    float xwa  [MM*CC];
    float xk   [MM*CC];
    float xv   [MM*CC];
    float r    [MM*CC];
    float k    [MM*CC];
    float v    [MM*CC];
    float g    [MM*CC];
    float w    [MM*CC];
    float kk   [MM*CC];
    float asig [MM*CC];
    float ma   [MM*CC];
    float mk2  [MM*CC];
    float kf   [MM*CC];
    float dd   [MM*CC];
    float av   [MM*CC];
    float bv   [MM*CC];
    float y    [MM*CC];
    float z    [MM*CC];
    float gate1[MM*128];
    float dec1 [MM*64];
    float aaa1 [MM*16];
    float ma1  [MM*16];
    float kkk1 [MM*16];
    float mk1  [MM*16];
};
__device__ Scratch g_s;

// ---------------------------------------------------------------------------
// Packed f32x2 helpers (Blackwell sm_103a)
// ---------------------------------------------------------------------------
__device__ __forceinline__ unsigned long long dup2(float x) {
    unsigned long long r;
    asm("mov.b64 %0, {%1, %1};" : "=l"(r) : "f"(x));
    return r;
}
__device__ __forceinline__ void fma2(unsigned long long& acc,
                                     unsigned long long a,
                                     unsigned long long b) {
    asm("fma.rn.f32x2 %0, %1, %2, %0;" : "+l"(acc) : "l"(a), "l"(b));
}
__device__ __forceinline__ float2 unpack2(unsigned long long v) {
    float2 f;
    asm("mov.b64 {%0, %1}, %2;" : "=f"(f.x), "=f"(f.y) : "l"(v));
    return f;
}

// ---------------------------------------------------------------------------
// Generic GEMM:  C[M,N] = epilogue( A[M,K] * B )
//   bt=1 : B is (N,K) row-major  -> C = A @ B^T
//   bt=0 : B is (K,N) row-major  -> C = A @ B
// modes: 0: acc                        1: tanh(acc)
//        2: ex + exx*(evec[n]+acc)     3: sigmoid(evec[n]+acc)
//        4: -log1p(exp(-(evec[n]+acc)))-0.5
//        5: ex + acc
// Tiles: BM=128, BN=64, BK=16; 256 thr; each thread 8x4 outputs as 8x2 f32x2
// ---------------------------------------------------------------------------
__global__ void __launch_bounds__(256)
gemm_kernel(const float* __restrict__ A, const float* __restrict__ Bm,
            float* __restrict__ Cm, int M, int N, int K, int lda,
            int bt, int mode,
            const float* __restrict__ ex, const float* __restrict__ exx,
            const float* __restrict__ evec)
{
    __shared__ __align__(16) float As[16][128];
    __shared__ __align__(16) float Bs[16][68];   // 68: keeps 16B alignment per row

    const int tid = threadIdx.x;
    const int tx = tid & 15;        // 16 col-groups of 4
    const int ty = tid >> 4;        // 16 row-groups of 8
    const int n0 = blockIdx.x * 64;
    const int m0 = blockIdx.y * 128;

    unsigned long long acc[8][2];
#pragma unroll
    for (int i = 0; i < 8; i++) { acc[i][0] = 0ull; acc[i][1] = 0ull; }

    for (int kt = 0; kt < K; kt += 16) {
        // --- load A tile (128 rows x 16 k), transposed into As[k][m]
#pragma unroll
        for (int i = 0; i < 2; i++) {
            int f   = tid + 256 * i;     // 0..511
            int row = f >> 2;
            int kq  = f & 3;
            float4 av = *(const float4*)&A[(size_t)(m0 + row) * lda + kt + kq * 4];
            As[kq * 4 + 0][row] = av.x;
            As[kq * 4 + 1][row] = av.y;
            As[kq * 4 + 2][row] = av.z;
            As[kq * 4 + 3][row] = av.w;
        }
        // --- load B tile
        if (bt) {
            int row = tid >> 2;          // 0..63  (n)
            int kq  = tid & 3;
            float4 bvv = make_float4(0.f, 0.f, 0.f, 0.f);
            if (n0 + row < N)
                bvv = *(const float4*)&Bm[(size_t)(n0 + row) * K + kt + kq * 4];
            Bs[kq * 4 + 0][row] = bvv.x;
            Bs[kq * 4 + 1][row] = bvv.y;
            Bs[kq * 4 + 2][row] = bvv.z;
            Bs[kq * 4 + 3][row] = bvv.w;
        } else {
            int krow = tid >> 4;         // 0..15 (k)
            int nq   = tid & 15;         // 0..15 (n/4)
            float4 bvv = make_float4(0.f, 0.f, 0.f, 0.f);
            if (n0 + nq * 4 < N)
                bvv = *(const float4*)&Bm[(size_t)(kt + krow) * N + n0 + nq * 4];
            *(float4*)&Bs[krow][nq * 4] = bvv;
        }
        __syncthreads();

#pragma unroll
        for (int kq = 0; kq < 16; kq++) {
            float4 a0 = *(const float4*)&As[kq][ty * 8];
            float4 a1 = *(const float4*)&As[kq][ty * 8 + 4];
            ulonglong2 bp = *(const ulonglong2*)&Bs[kq][tx * 4];
#define ROWFMA(rI, aval) { unsigned long long dp = dup2(aval); \
            fma2(acc[rI][0], dp, bp.x); fma2(acc[rI][1], dp, bp.y); }
            ROWFMA(0, a0.x) ROWFMA(1, a0.y) ROWFMA(2, a0.z) ROWFMA(3, a0.w)
            ROWFMA(4, a1.x) ROWFMA(5, a1.y) ROWFMA(6, a1.z) ROWFMA(7, a1.w)
#undef ROWFMA
        }
        __syncthreads();
    }

    // --- epilogue
    const int ncol = n0 + tx * 4;
#pragma unroll
    for (int rr = 0; rr < 8; rr++) {
        const int m = m0 + ty * 8 + rr;
        float2 p0 = unpack2(acc[rr][0]);
        float2 p1 = unpack2(acc[rr][1]);
        float vals[4] = { p0.x, p0.y, p1.x, p1.y };
#pragma unroll
        for (int q = 0; q < 4; q++) {
            int nn = ncol + q;
            if (nn < N) {
                float vv = vals[q];
                float res;
                switch (mode) {
                    default:
                    case 0: res = vv; break;
                    case 1: res = tanhf(vv); break;
                    case 2: res = ex[(size_t)m * N + nn]
                                + exx[(size_t)m * N + nn] * (evec[nn] + vv); break;
                    case 3: { float zz = evec[nn] + vv;
                              res = 1.f / (1.f + expf(-zz)); } break;
                    case 4: { float zz = evec[nn] + vv;
                              res = -log1pf(expf(-zz)) - 0.5f; } break;
                    case 5: res = ex[(size_t)m * N + nn] + vv; break;
                }
                Cm[(size_t)m * N + nn] = res;
            }
        }
    }
}

// ---------------------------------------------------------------------------
// ew0: xx = shift(x) - x ;  xmix = x + xx * time_maa_x
// ---------------------------------------------------------------------------
__global__ void __launch_bounds__(256)
ew0_kernel(const float* __restrict__ x, const float* __restrict__ maa_x)
{
    size_t i4  = (size_t)blockIdx.x * 256 + threadIdx.x;  // float4 index
    size_t idx = i4 * 4;
    int c    = (int)(idx & (CC - 1));
    int nrow = (int)(idx >> 10);
    float4 xv = *(const float4*)&x[idx];
    float4 xp = make_float4(0.f, 0.f, 0.f, 0.f);
    if (nrow & (TT - 1))                           // t != 0
        xp = *(const float4*)&x[idx - CC];
    float4 mv = *(const float4*)&maa_x[c];
    float4 d, xm;
    d.x = xp.x - xv.x;  xm.x = xv.x + d.x * mv.x;
    d.y = xp.y - xv.y;  xm.y = xv.y + d.y * mv.y;
    d.z = xp.z - xv.z;  xm.z = xv.z + d.z * mv.z;
    d.w = xp.w - xv.w;  xm.w = xv.w + d.w * mv.w;
    *(float4*)&g_s.xx[idx]   = d;
    *(float4*)&g_s.xmix[idx] = xm;
}

// ---------------------------------------------------------------------------
// combine: kk-normalize per head, k-final, decay dt=exp(w), a/b scan vectors
// One block per row (b,t); 256 threads, 4 channels each; head = 16 lanes.
// ---------------------------------------------------------------------------
__global__ void __launch_bounds__(256)
combine_kernel()
{
    int n   = blockIdx.x;
    int tid = threadIdx.x;
    size_t off = (size_t)n * CC + tid * 4;

    float4 kkv = *(float4*)&g_s.kk[off];
    float ss = kkv.x*kkv.x + kkv.y*kkv.y + kkv.z*kkv.z + kkv.w*kkv.w;
#pragma unroll
    for (int o = 8; o; o >>= 1) ss += __shfl_xor_sync(0xffffffffu, ss, o, 16);
    float inv = 1.f / fmaxf(sqrtf(ss), 1e-12f);

    float4 kq = *(float4*)&g_s.k[off];
    float4 aq = *(float4*)&g_s.asig[off];
    float4 mq = *(float4*)&g_s.ma[off];
    float4 wq = *(float4*)&g_s.w[off];
    float4 mk = *(float4*)&g_s.mk2[off];
    float4 kfv, ddv, avv, bvv;
#define CMB(X) { float fac = mq.X + aq.X * (1.f - mq.X); \
    float ee = expf(fminf(wq.X * mk.X, 0.f)); \
    kfv.X = kq.X * fac * ee; \
    ddv.X = expf(wq.X); \
    float kn = kkv.X * inv; \
    avv.X = -kn; bvv.X = kn * aq.X; }
    CMB(x) CMB(y) CMB(z) CMB(w)
#undef CMB
    *(float4*)&g_s.kf[off] = kfv;
    *(float4*)&g_s.dd[off] = ddv;
    *(float4*)&g_s.av[off] = avv;
    *(float4*)&g_s.bv[off] = bvv;
}

// ---------------------------------------------------------------------------
// WKV-7 scan: one block per (b,h); 64 threads; thread i owns state row S[i][:]
// Prefetch next timestep from GMEM into regs while computing current step.
// ---------------------------------------------------------------------------
__global__ void __launch_bounds__(64)
wkv_kernel()
{
    const int blk = blockIdx.x;
    const int b = blk >> 4;
    const int h = blk & 15;
    const int i = threadIdx.x;

    __shared__ float4 shr[16], shd[16], shk[16], sha[16], shb[16];

    size_t base = ((size_t)b * TT) * CC + h * NN + i;
    float pr = g_s.r [base];
    float pd = g_s.dd[base];
    float pk = g_s.kf[base];
    float pa = g_s.av[base];
    float pb = g_s.bv[base];
    float pv = g_s.v [base];

    float S[64];
#pragma unroll
    for (int j = 0; j < 64; j++) S[j] = 0.f;

    for (int t = 0; t < TT; t++) {
        ((float*)shr)[i] = pr;
        ((float*)shd)[i] = pd;
        ((float*)shk)[i] = pk;
        ((float*)sha)[i] = pa;
        ((float*)shb)[i] = pb;
        const float vi = pv;
        __syncthreads();

        if (t + 1 < TT) {
            size_t nb = base + (size_t)(t + 1) * CC;
            pr = g_s.r [nb];
            pd = g_s.dd[nb];
            pk = g_s.kf[nb];
            pa = g_s.av[nb];
            pb = g_s.bv[nb];
            pv = g_s.v [nb];
        }

        // sa_i = sum_j S[i][j] * a[j]
        float s0 = 0.f, s1 = 0.f, s2 = 0.f, s3 = 0.f;
#pragma unroll
        for (int j = 0; j < 16; j++) {
            float4 a4 = sha[j];
            s0 += S[4*j+0] * a4.x;
            s1 += S[4*j+1] * a4.y;
            s2 += S[4*j+2] * a4.z;
            s3 += S[4*j+3] * a4.w;
        }
        const float sacc = (s0 + s1) + (s2 + s3);

        // S = S*d + sa*b + v*k ;  y_i = sum_j S[i][j]*r[j]
        float y0 = 0.f, y1 = 0.f, y2 = 0.f, y3 = 0.f;
#pragma unroll
        for (int j = 0; j < 16; j++) {
            float4 d4 = shd[j], b4 = shb[j], k4 = shk[j], r4 = shr[j];
            float t0 = fmaf(S[4*j+0], d4.x, fmaf(sacc, b4.x, vi * k4.x));
            float t1 = fmaf(S[4*j+1], d4.y, fmaf(sacc, b4.y, vi * k4.y));
            float t2 = fmaf(S[4*j+2], d4.z, fmaf(sacc, b4.z, vi * k4.z));
            float t3 = fmaf(S[4*j+3], d4.w, fmaf(sacc, b4.w, vi * k4.w));
            S[4*j+0] = t0; S[4*j+1] = t1; S[4*j+2] = t2; S[4*j+3] = t3;
            y0 += t0 * r4.x; y1 += t1 * r4.y; y2 += t2 * r4.z; y3 += t3 * r4.w;
        }
        g_s.y[base + (size_t)t * CC] = (y0 + y1) + (y2 + y3);
        __syncthreads();
    }
}

// ---------------------------------------------------------------------------
// post: GroupNorm(H=16 over N=64) + faaaa bonus + gate multiply -> z
// ---------------------------------------------------------------------------
__global__ void __launch_bounds__(256)
post_kernel(const float* __restrict__ faaaa,
            const float* __restrict__ lnw, const float* __restrict__ lnb)
{
    int n   = blockIdx.x;
    int tid = threadIdx.x;
    int c   = tid * 4;
    size_t off = (size_t)n * CC + c;

    float4 yv = *(float4*)&g_s.y [off];
    float4 rv = *(float4*)&g_s.r [off];
    float4 kv = *(float4*)&g_s.kf[off];
    float4 vv = *(float4*)&g_s.v [off];
    float4 gv = *(float4*)&g_s.g [off];
    float4 fv = *(const float4*)&faaaa[c];

    float s  = yv.x + yv.y + yv.z + yv.w;
    float s2 = yv.x*yv.x + yv.y*yv.y + yv.z*yv.z + yv.w*yv.w;
    float dk = rv.x*kv.x*fv.x + rv.y*kv.y*fv.y + rv.z*kv.z*fv.z + rv.w*kv.w*fv.w;
#pragma unroll
    for (int o = 8; o; o >>= 1) {
        s  += __shfl_xor_sync(0xffffffffu, s,  o, 16);
        s2 += __shfl_xor_sync(0xffffffffu, s2, o, 16);
        dk += __shfl_xor_sync(0xffffffffu, dk, o, 16);
    }
    float mean = s  * (1.f / 64.f);
    float var  = s2 * (1.f / 64.f) - mean * mean;
    float rs   = rsqrtf(var + 64e-5f);

    float4 lw = *(const float4*)&lnw[c];
    float4 lb = *(const float4*)&lnb[c];
    float4 z;
    z.x = (((yv.x - mean) * rs) * lw.x + lb.x + dk * vv.x) * gv.x;
    z.y = (((yv.y - mean) * rs) * lw.y + lb.y + dk * vv.y) * gv.y;
    z.z = (((yv.z - mean) * rs) * lw.z + lb.z + dk * vv.z) * gv.z;
    z.w = (((yv.w - mean) * rs) * lw.w + lb.w + dk * vv.w) * gv.w;
    *(float4*)&g_s.z[off] = z;
}

// ---------------------------------------------------------------------------
// Host orchestration
// ---------------------------------------------------------------------------
static void launch_gemm(const float* A, const float* Bp, float* Cp,
                        int N, int K, int lda, int bt, int mode,
                        const float* ex, const float* exx, const float* evec)
{
    dim3 grid((N + 63) / 64, MM / 128);
    gemm_kernel<<<grid, 256>>>(A, Bp, Cp, MM, N, K, lda, bt, mode, ex, exx, evec);
}

extern "C" void kernel_launch(void* const* d_in, const int* in_sizes, int n_in,
                              void* d_out, int out_size)
{
    const float* x       = (const float*)d_in[0];
    const float* maa_x   = (const float*)d_in[1];
    const float* maa_rg  = (const float*)d_in[2];
    const float* maa_wa  = (const float*)d_in[3];
    const float* maa_k   = (const float*)d_in[4];
    const float* maa_v   = (const float*)d_in[5];
    const float* maa_w1  = (const float*)d_in[6];
    const float* maa_w2  = (const float*)d_in[7];
    const float* tdecay  = (const float*)d_in[8];
    const float* dw1     = (const float*)d_in[9];
    const float* dw2     = (const float*)d_in[10];
    const float* faaaa   = (const float*)d_in[11];
    const float* taaaaa  = (const float*)d_in[12];
    const float* aw1     = (const float*)d_in[13];
    const float* aw2     = (const float*)d_in[14];
    const float* kw1     = (const float*)d_in[15];
    const float* kw2     = (const float*)d_in[16];
    const float* gw1     = (const float*)d_in[17];
    const float* gw2     = (const float*)d_in[18];
    const float* maw1    = (const float*)d_in[19];
    const float* maw2    = (const float*)d_in[20];
    const float* tmisca  = (const float*)d_in[21];
    const float* mkw1    = (const float*)d_in[22];
    const float* mkw2    = (const float*)d_in[23];
    const float* tmisck  = (const float*)d_in[24];
    const float* wr      = (const float*)d_in[25];
    const float* wk      = (const float*)d_in[26];
    const float* wv      = (const float*)d_in[27];
    const float* wo      = (const float*)d_in[28];
    const float* lnw     = (const float*)d_in[29];
    const float* lnb     = (const float*)d_in[30];
    float* out = (float*)d_out;
    (void)in_sizes; (void)n_in; (void)out_size;

    Scratch* S = nullptr;
    cudaGetSymbolAddress((void**)&S, g_s);

    // 1) time-shift + maa_x mix
    ew0_kernel<<<(MM * CC / 4) / 256, 256>>>(x, maa_x);

    // 2) mix_in = tanh(xmix @ maa_w1)                 (4096x128, K=1024)
    launch_gemm(S->xmix, maa_w1, S->mixin, 128, 1024, 1024, 0, 1, 0, 0, 0);

    // 3) xrg/xwa/xk/xv = x + xx*(maa_* + mix_in[:,f] @ maa_w2[f])   (K=32)
    {
        const float* maas[4]  = { maa_rg, maa_wa, maa_k, maa_v };
        float*       xouts[4] = { S->xrg, S->xwa, S->xk, S->xv };
        for (int f = 0; f < 4; f++)
            launch_gemm(S->mixin + f * 32, maa_w2 + (size_t)f * 32 * 1024,
                        xouts[f], 1024, 32, 128, 0, 2, x, S->xx, maas[f]);
    }

    // 4) big projections (A @ B^T)
    launch_gemm(S->xrg, wr, S->r, 1024, 1024, 1024, 1, 0, 0, 0, 0);
    launch_gemm(S->xk,  wk, S->k, 1024, 1024, 1024, 1, 0, 0, 0, 0);
    launch_gemm(S->xv,  wv, S->v, 1024, 1024, 1024, 1, 0, 0, 0, 0);

    // 5) gate
    launch_gemm(S->xrg,   gw1, S->gate1, 128, 1024, 1024, 0, 1, 0, 0, 0);
    launch_gemm(S->gate1, gw2, S->g,    1024,  128,  128, 0, 0, 0, 0, 0);

    // 6) decay:  w = -softplus(-(time_decay + tanh(xwa@dw1)@dw2)) - 0.5
    launch_gemm(S->xwa,  dw1, S->dec1,   64, 1024, 1024, 0, 1, 0, 0, 0);
    launch_gemm(S->dec1, dw2, S->w,    1024,   64,   64, 0, 4, 0, 0, tdecay);

    // 7) LoRA sigmoids + kkk
    launch_gemm(S->xwa,  aw1,  S->aaa1,   16, 1024, 1024, 0, 0, 0, 0, 0);
    launch_gemm(S->aaa1, aw2,  S->asig, 1024,   16,   16, 0, 3, 0, 0, taaaaa);
    launch_gemm(S->xwa,  maw1, S->ma1,    16, 1024, 1024, 0, 0, 0, 0, 0);
    launch_gemm(S->ma1,  maw2, S->ma,   1024,   16,   16, 0, 3, 0, 0, tmisca);
    launch_gemm(S->xk,   kw1,  S->kkk1,   16, 1024, 1024, 0, 1, 0, 0, 0);
    launch_gemm(S->kkk1, kw2,  S->kk,   1024,   16,   16, 0, 5, S->k, 0, 0);
    launch_gemm(S->xk,   mkw1, S->mk1,    16, 1024, 1024, 0, 0, 0, 0, 0);
    launch_gemm(S->mk1,  mkw2, S->mk2,  1024,   16,   16, 0, 3, 0, 0, tmisck);

    // 8) elementwise combine -> kf, dt=exp(w), a=-kk_n, b=kk_n*a_sig
    combine_kernel<<<MM, 256>>>();

    // 9) WKV-7 scan
    wkv_kernel<<<BB * HH, 64>>>();

    // 10) GroupNorm + bonus + gate
    post_kernel<<<MM, 256>>>(faaaa, lnw, lnb);

    // 11) output projection
    launch_gemm(S->z, wo, out, 1024, 1024, 1024, 1, 0, 0, 0, 0);
}

// round 3
// speedup vs baseline: 1.1978x; 1.1978x over previous
#include <cuda_runtime.h>
#include <math.h>

#define BB 4
#define TT 1024
#define CC 1024
#define HH 16
#define NN 64
#define MM (BB*TT)   // 4096 rows

// ---------------------------------------------------------------------------
// Scratch (static device memory)
// ---------------------------------------------------------------------------
struct Scratch {
    float xx   [MM*CC];
    float xmix [MM*CC];
    float mixin[MM*128];
    float xrg  [MM*CC];
    float xwa  [MM*CC];
    float xk   [MM*CC];
    float xv   [MM*CC];
    float r    [MM*CC];
    float k    [MM*CC];
    float v    [MM*CC];
    float g    [MM*CC];
    float w    [MM*CC];
    float kk   [MM*CC];
    float asig [MM*CC];
    float ma   [MM*CC];
    float mk2  [MM*CC];
    float kf   [MM*CC];
    float dd   [MM*CC];
    float av   [MM*CC];
    float bv   [MM*CC];
    float y    [MM*CC];
    float z    [MM*CC];
    float gate1[MM*128];
    float dec1 [MM*64];
    float aaa1 [MM*16];
    float ma1  [MM*16];
    float kkk1 [MM*16];
    float mk1  [MM*16];
};
__device__ Scratch g_s;

// ---------------------------------------------------------------------------
// Packed f32x2 helpers
// ---------------------------------------------------------------------------
__device__ __forceinline__ unsigned long long dup2(float x) {
    unsigned long long r;
    asm("mov.b64 %0, {%1, %1};" : "=l"(r) : "f"(x));
    return r;
}
__device__ __forceinline__ void fma2(unsigned long long& acc,
                                     unsigned long long a,
                                     unsigned long long b) {
    asm("fma.rn.f32x2 %0, %1, %2, %0;" : "+l"(acc) : "l"(a), "l"(b));
}
__device__ __forceinline__ unsigned long long fma2g(unsigned long long a,
                                                    unsigned long long b,
                                                    unsigned long long c) {
    unsigned long long d;
    asm("fma.rn.f32x2 %0, %1, %2, %3;" : "=l"(d) : "l"(a), "l"(b), "l"(c));
    return d;
}
__device__ __forceinline__ unsigned long long mul2(unsigned long long a,
                                                   unsigned long long b) {
    unsigned long long d;
    asm("mul.rn.f32x2 %0, %1, %2;" : "=l"(d) : "l"(a), "l"(b));
    return d;
}
__device__ __forceinline__ float2 unpack2(unsigned long long v) {
    float2 f;
    asm("mov.b64 {%0, %1}, %2;" : "=f"(f.x), "=f"(f.y) : "l"(v));
    return f;
}

// ---------------------------------------------------------------------------
// gemm128: C[M,N] = epi(A[M,K] @ B), N % 128 == 0 (used with N=1024 only)
//   bt=1: B (N,K) row-major -> A@B^T ; bt=0: B (K,N) row-major -> A@B
// modes: 0 plain | 2: ex + exx*(evec[n]+acc) | 3 sigmoid(evec[n]+acc)
//        4: -log1p(exp(-(evec[n]+acc)))-0.5  | 5: ex + acc
// 128x128x16 tiles, 256 thr, 8x8/thread, double-buffered smem.
// ---------------------------------------------------------------------------
__global__ void __launch_bounds__(256, 2)
gemm128(const float* __restrict__ A, const float* __restrict__ Bm,
        float* __restrict__ Cm, int N, int K, int lda, int bt, int mode,
        const float* __restrict__ ex, const float* __restrict__ exx,
        const float* __restrict__ evec)
{
    __shared__ __align__(16) float As[2][16][128];
    __shared__ __align__(16) float Bs[2][16][128];

    const int tid = threadIdx.x;
    const int tx = tid & 15;        // col group (8 cols)
    const int ty = tid >> 4;        // row group (8 rows)
    const int n0 = blockIdx.x * 128;
    const int m0 = blockIdx.y * 128;

    unsigned long long acc[8][4];
#pragma unroll
    for (int i = 0; i < 8; i++)
#pragma unroll
        for (int j = 0; j < 4; j++) acc[i][j] = 0ull;

    // decompositions for loads
    const int arow0 = (tid)       >> 2, akq0 = (tid)       & 3;
    const int arow1 = (tid + 256) >> 2, akq1 = (tid + 256) & 3;
    const int bkrow0 = (tid)       >> 5, bnq0 = (tid)       & 31;
    const int bkrow1 = (tid + 256) >> 5, bnq1 = (tid + 256) & 31;

    // ---- preload tile 0
    {
        float4 a0 = *(const float4*)&A[(size_t)(m0 + arow0) * lda + akq0 * 4];
        float4 a1 = *(const float4*)&A[(size_t)(m0 + arow1) * lda + akq1 * 4];
        As[0][akq0*4+0][arow0] = a0.x; As[0][akq0*4+1][arow0] = a0.y;
        As[0][akq0*4+2][arow0] = a0.z; As[0][akq0*4+3][arow0] = a0.w;
        As[0][akq1*4+0][arow1] = a1.x; As[0][akq1*4+1][arow1] = a1.y;
        As[0][akq1*4+2][arow1] = a1.z; As[0][akq1*4+3][arow1] = a1.w;
        if (bt) {
            float4 b0 = *(const float4*)&Bm[(size_t)(n0 + arow0) * K + akq0 * 4];
            float4 b1 = *(const float4*)&Bm[(size_t)(n0 + arow1) * K + akq1 * 4];
            Bs[0][akq0*4+0][arow0] = b0.x; Bs[0][akq0*4+1][arow0] = b0.y;
            Bs[0][akq0*4+2][arow0] = b0.z; Bs[0][akq0*4+3][arow0] = b0.w;
            Bs[0][akq1*4+0][arow1] = b1.x; Bs[0][akq1*4+1][arow1] = b1.y;
            Bs[0][akq1*4+2][arow1] = b1.z; Bs[0][akq1*4+3][arow1] = b1.w;
        } else {
            *(float4*)&Bs[0][bkrow0][bnq0*4] =
                *(const float4*)&Bm[(size_t)bkrow0 * N + n0 + bnq0 * 4];
            *(float4*)&Bs[0][bkrow1][bnq1*4] =
                *(const float4*)&Bm[(size_t)bkrow1 * N + n0 + bnq1 * 4];
        }
    }
    __syncthreads();

    const int ntiles = K >> 4;
    for (int it = 0; it < ntiles; it++) {
        const int buf = it & 1;
        const bool more = (it + 1 < ntiles);
        float4 pa0, pa1, pb0, pb1;
        if (more) {
            const int kt = (it + 1) << 4;
            pa0 = *(const float4*)&A[(size_t)(m0 + arow0) * lda + kt + akq0 * 4];
            pa1 = *(const float4*)&A[(size_t)(m0 + arow1) * lda + kt + akq1 * 4];
            if (bt) {
                pb0 = *(const float4*)&Bm[(size_t)(n0 + arow0) * K + kt + akq0 * 4];
                pb1 = *(const float4*)&Bm[(size_t)(n0 + arow1) * K + kt + akq1 * 4];
            } else {
                pb0 = *(const float4*)&Bm[(size_t)(kt + bkrow0) * N + n0 + bnq0 * 4];
                pb1 = *(const float4*)&Bm[(size_t)(kt + bkrow1) * N + n0 + bnq1 * 4];
            }
        }

#pragma unroll
        for (int kq = 0; kq < 16; kq++) {
            float4 a0 = *(const float4*)&As[buf][kq][ty * 8];
            float4 a1 = *(const float4*)&As[buf][kq][ty * 8 + 4];
            ulonglong2 bA = *(const ulonglong2*)&Bs[buf][kq][tx * 8];
            ulonglong2 bB = *(const ulonglong2*)&Bs[buf][kq][tx * 8 + 4];
#define RF(rI, aval) { unsigned long long dp = dup2(aval); \
            fma2(acc[rI][0], dp, bA.x); fma2(acc[rI][1], dp, bA.y); \
            fma2(acc[rI][2], dp, bB.x); fma2(acc[rI][3], dp, bB.y); }
            RF(0, a0.x) RF(1, a0.y) RF(2, a0.z) RF(3, a0.w)
            RF(4, a1.x) RF(5, a1.y) RF(6, a1.z) RF(7, a1.w)
#undef RF
        }

        if (more) {
            const int nb = buf ^ 1;
            As[nb][akq0*4+0][arow0] = pa0.x; As[nb][akq0*4+1][arow0] = pa0.y;
            As[nb][akq0*4+2][arow0] = pa0.z; As[nb][akq0*4+3][arow0] = pa0.w;
            As[nb][akq1*4+0][arow1] = pa1.x; As[nb][akq1*4+1][arow1] = pa1.y;
            As[nb][akq1*4+2][arow1] = pa1.z; As[nb][akq1*4+3][arow1] = pa1.w;
            if (bt) {
                Bs[nb][akq0*4+0][arow0] = pb0.x; Bs[nb][akq0*4+1][arow0] = pb0.y;
                Bs[nb][akq0*4+2][arow0] = pb0.z; Bs[nb][akq0*4+3][arow0] = pb0.w;
                Bs[nb][akq1*4+0][arow1] = pb1.x; Bs[nb][akq1*4+1][arow1] = pb1.y;
                Bs[nb][akq1*4+2][arow1] = pb1.z; Bs[nb][akq1*4+3][arow1] = pb1.w;
            } else {
                *(float4*)&Bs[nb][bkrow0][bnq0*4] = pb0;
                *(float4*)&Bs[nb][bkrow1][bnq1*4] = pb1;
            }
        }
        __syncthreads();
    }

    // ---- epilogue
#pragma unroll
    for (int rr = 0; rr < 8; rr++) {
        const int m = m0 + ty * 8 + rr;
        float vals[8];
        { float2 p = unpack2(acc[rr][0]); vals[0] = p.x; vals[1] = p.y; }
        { float2 p = unpack2(acc[rr][1]); vals[2] = p.x; vals[3] = p.y; }
        { float2 p = unpack2(acc[rr][2]); vals[4] = p.x; vals[5] = p.y; }
        { float2 p = unpack2(acc[rr][3]); vals[6] = p.x; vals[7] = p.y; }
#pragma unroll
        for (int q = 0; q < 8; q++) {
            const int nn = n0 + tx * 8 + q;
            float vv = vals[q];
            float res;
            switch (mode) {
                default:
                case 0: res = vv; break;
                case 2: res = ex[(size_t)m * N + nn]
                            + exx[(size_t)m * N + nn] * (evec[nn] + vv); break;
                case 3: { float zz = evec[nn] + vv;
                          res = 1.f / (1.f + expf(-zz)); } break;
                case 4: { float zz = evec[nn] + vv;
                          res = -log1pf(expf(-zz)) - 0.5f; } break;
                case 5: res = ex[(size_t)m * N + nn] + vv; break;
            }
            vals[q] = res;
        }
        float4 o0 = make_float4(vals[0], vals[1], vals[2], vals[3]);
        float4 o1 = make_float4(vals[4], vals[5], vals[6], vals[7]);
        *(float4*)&Cm[(size_t)m * N + n0 + tx * 8]     = o0;
        *(float4*)&Cm[(size_t)m * N + n0 + tx * 8 + 4] = o1;
    }
}

// ---------------------------------------------------------------------------
// gemm32: tall-skinny up-projections. C = epi(A[M,K] @ B[K,N]) (bt=0 only)
// BM=32, BN=64, BK=16, 256 thr, 1x8 per thread. modes: 0 plain, 1 tanh.
// ---------------------------------------------------------------------------
__global__ void __launch_bounds__(256)
gemm32(const float* __restrict__ A, const float* __restrict__ Bm,
       float* __restrict__ Cm, int N, int K, int lda, int mode)
{
    __shared__ __align__(16) float As[16][32];
    __shared__ __align__(16) float Bs[16][64];

    const int tid = threadIdx.x;
    const int tx = tid & 7;         // col group (8 cols)
    const int ty = tid >> 3;        // row (0..31)
    const int n0 = blockIdx.x * 64;
    const int m0 = blockIdx.y * 32;

    unsigned long long acc[4] = {0ull, 0ull, 0ull, 0ull};

    const int arow = tid >> 2, akq = tid & 3;      // tid<128: A loads
    const int bkrow = tid >> 4, bnq = tid & 15;    // B loads

    for (int kt = 0; kt < K; kt += 16) {
        if (tid < 128) {
            float4 a0 = *(const float4*)&A[(size_t)(m0 + arow) * lda + kt + akq * 4];
            As[akq*4+0][arow] = a0.x; As[akq*4+1][arow] = a0.y;
            As[akq*4+2][arow] = a0.z; As[akq*4+3][arow] = a0.w;
        }
        float4 b0 = make_float4(0.f, 0.f, 0.f, 0.f);
        if (n0 + bnq * 4 < N)
            b0 = *(const float4*)&Bm[(size_t)(kt + bkrow) * N + n0 + bnq * 4];
        *(float4*)&Bs[bkrow][bnq*4] = b0;
        __syncthreads();

#pragma unroll
        for (int kq = 0; kq < 16; kq++) {
            unsigned long long dp = dup2(As[kq][ty]);
            ulonglong2 bA = *(const ulonglong2*)&Bs[kq][tx * 8];
            ulonglong2 bB = *(const ulonglong2*)&Bs[kq][tx * 8 + 4];
            fma2(acc[0], dp, bA.x); fma2(acc[1], dp, bA.y);
            fma2(acc[2], dp, bB.x); fma2(acc[3], dp, bB.y);
        }
        __syncthreads();
    }

    const int m = m0 + ty;
    float vals[8];
    { float2 p = unpack2(acc[0]); vals[0] = p.x; vals[1] = p.y; }
    { float2 p = unpack2(acc[1]); vals[2] = p.x; vals[3] = p.y; }
    { float2 p = unpack2(acc[2]); vals[4] = p.x; vals[5] = p.y; }
    { float2 p = unpack2(acc[3]); vals[6] = p.x; vals[7] = p.y; }
#pragma unroll
    for (int q = 0; q < 8; q++) {
        const int nn = n0 + tx * 8 + q;
        if (nn < N) {
            float vv = vals[q];
            Cm[(size_t)m * N + nn] = (mode == 1) ? tanhf(vv) : vv;
        }
    }
}

// ---------------------------------------------------------------------------
// ew0: xx = shift(x) - x ;  xmix = x + xx * time_maa_x
// ---------------------------------------------------------------------------
__global__ void __launch_bounds__(256)
ew0_kernel(const float* __restrict__ x, const float* __restrict__ maa_x)
{
    size_t i4  = (size_t)blockIdx.x * 256 + threadIdx.x;
    size_t idx = i4 * 4;
    int c    = (int)(idx & (CC - 1));
    int nrow = (int)(idx >> 10);
    float4 xv = *(const float4*)&x[idx];
    float4 xp = make_float4(0.f, 0.f, 0.f, 0.f);
    if (nrow & (TT - 1))
        xp = *(const float4*)&x[idx - CC];
    float4 mv = *(const float4*)&maa_x[c];
    float4 d, xm;
    d.x = xp.x - xv.x;  xm.x = xv.x + d.x * mv.x;
    d.y = xp.y - xv.y;  xm.y = xv.y + d.y * mv.y;
    d.z = xp.z - xv.z;  xm.z = xv.z + d.z * mv.z;
    d.w = xp.w - xv.w;  xm.w = xv.w + d.w * mv.w;
    *(float4*)&g_s.xx[idx]   = d;
    *(float4*)&g_s.xmix[idx] = xm;
}

// ---------------------------------------------------------------------------
// combine: kk-normalize per head, k-final, dt=exp(w), a/b scan vectors
// ---------------------------------------------------------------------------
__global__ void __launch_bounds__(256)
combine_kernel()
{
    int n   = blockIdx.x;
    int tid = threadIdx.x;
    size_t off = (size_t)n * CC + tid * 4;

    float4 kkv = *(float4*)&g_s.kk[off];
    float ss = kkv.x*kkv.x + kkv.y*kkv.y + kkv.z*kkv.z + kkv.w*kkv.w;
#pragma unroll
    for (int o = 8; o; o >>= 1) ss += __shfl_xor_sync(0xffffffffu, ss, o, 16);
    float inv = 1.f / fmaxf(sqrtf(ss), 1e-12f);

    float4 kq = *(float4*)&g_s.k[off];
    float4 aq = *(float4*)&g_s.asig[off];
    float4 mq = *(float4*)&g_s.ma[off];
    float4 wq = *(float4*)&g_s.w[off];
    float4 mk = *(float4*)&g_s.mk2[off];
    float4 kfv, ddv, avv, bvv;
#define CMB(X) { float fac = mq.X + aq.X * (1.f - mq.X); \
    float ee = expf(fminf(wq.X * mk.X, 0.f)); \
    kfv.X = kq.X * fac * ee; \
    ddv.X = expf(wq.X); \
    float kn = kkv.X * inv; \
    avv.X = -kn; bvv.X = kn * aq.X; }
    CMB(x) CMB(y) CMB(z) CMB(w)
#undef CMB
    *(float4*)&g_s.kf[off] = kfv;
    *(float4*)&g_s.dd[off] = ddv;
    *(float4*)&g_s.av[off] = avv;
    *(float4*)&g_s.bv[off] = bvv;
}

// ---------------------------------------------------------------------------
// WKV-7 scan: one block per (b,h); 256 threads; thread (i = tid>>2, jq = tid&3)
// owns S[i][16*jq .. 16*jq+15] as 8 packed f32x2. Double-buffered smem vectors,
// 96 loader threads prefetch t+1 while all compute t. One barrier per step.
// ---------------------------------------------------------------------------
__global__ void __launch_bounds__(256)
wkv_kernel()
{
    const int blk = blockIdx.x;
    const int b = blk >> 4;
    const int h = blk & 15;
    const int tid = threadIdx.x;
    const int i  = tid >> 2;
    const int jq = tid & 3;

    __shared__ __align__(16) float sb[2][6][64];   // r,d,k,a,b,v

    const size_t rowbase = ((size_t)b * TT) * CC + h * NN;

    // loader setup (6 arrays x 16 float4)
    const float4* myp = 0;
    int larr = 0, lq = 0;
    if (tid < 96) {
        larr = tid >> 4; lq = tid & 15;
        const float* srcs[6] = { g_s.r, g_s.dd, g_s.kf, g_s.av, g_s.bv, g_s.v };
        myp = (const float4*)(srcs[larr] + rowbase + lq * 4);
    }
    float4 pf;
    if (tid < 96) {
        pf = myp[0];
        ((float4*)sb[0][larr])[lq] = pf;
    }
    __syncthreads();

    unsigned long long S2[8];
#pragma unroll
    for (int u = 0; u < 8; u++) S2[u] = 0ull;

    float* yout = g_s.y + rowbase + i;

    for (int t = 0; t < TT; t++) {
        const int p = t & 1;
        const bool more = (t + 1 < TT);
        if (tid < 96 && more) pf = myp[(size_t)(t + 1) * (CC / 4)];

        const ulonglong2* a2p = (const ulonglong2*)(sb[p][3] + jq * 16);
        const ulonglong2* d2p = (const ulonglong2*)(sb[p][1] + jq * 16);
        const ulonglong2* k2p = (const ulonglong2*)(sb[p][2] + jq * 16);
        const ulonglong2* b2p = (const ulonglong2*)(sb[p][4] + jq * 16);
        const ulonglong2* r2p = (const ulonglong2*)(sb[p][0] + jq * 16);
        const float vi = sb[p][5][i];

        // sa partial: sum over my 16 j's
        unsigned long long acc0 = 0ull, acc1 = 0ull;
#pragma unroll
        for (int u = 0; u < 4; u++) {
            ulonglong2 avp = a2p[u];
            fma2(acc0, S2[2*u],   avp.x);
            fma2(acc1, S2[2*u+1], avp.y);
        }
        float2 f0 = unpack2(acc0), f1 = unpack2(acc1);
        float sa = (f0.x + f0.y) + (f1.x + f1.y);
        sa += __shfl_xor_sync(0xffffffffu, sa, 1, 4);
        sa += __shfl_xor_sync(0xffffffffu, sa, 2, 4);

        const unsigned long long sa2 = dup2(sa);
        const unsigned long long v2  = dup2(vi);

        unsigned long long y0 = 0ull, y1 = 0ull;
#pragma unroll
        for (int u = 0; u < 4; u++) {
            ulonglong2 dvp = d2p[u], kvp = k2p[u], bvp = b2p[u], rvp = r2p[u];
            unsigned long long t0 = fma2g(sa2, bvp.x, mul2(v2, kvp.x));
            t0 = fma2g(S2[2*u], dvp.x, t0);
            S2[2*u] = t0;
            fma2(y0, t0, rvp.x);
            unsigned long long t1 = fma2g(sa2, bvp.y, mul2(v2, kvp.y));
            t1 = fma2g(S2[2*u+1], dvp.y, t1);
            S2[2*u+1] = t1;
            fma2(y1, t1, rvp.y);
        }
        float2 g0 = unpack2(y0), g1 = unpack2(y1);
        float yv = (g0.x + g0.y) + (g1.x + g1.y);
        yv += __shfl_xor_sync(0xffffffffu, yv, 1, 4);
        yv += __shfl_xor_sync(0xffffffffu, yv, 2, 4);
        if (jq == 0) yout[(size_t)t * CC] = yv;

        if (tid < 96 && more) ((float4*)sb[p ^ 1][larr])[lq] = pf;
        __syncthreads();
    }
}

// ---------------------------------------------------------------------------
// post: GroupNorm + faaaa bonus + gate multiply -> z
// ---------------------------------------------------------------------------
__global__ void __launch_bounds__(256)
post_kernel(const float* __restrict__ faaaa,
            const float* __restrict__ lnw, const float* __restrict__ lnb)
{
    int n   = blockIdx.x;
    int tid = threadIdx.x;
    int c   = tid * 4;
    size_t off = (size_t)n * CC + c;

    float4 yv = *(float4*)&g_s.y [off];
    float4 rv = *(float4*)&g_s.r [off];
    float4 kv = *(float4*)&g_s.kf[off];
    float4 vv = *(float4*)&g_s.v [off];
    float4 gv = *(float4*)&g_s.g [off];
    float4 fv = *(const float4*)&faaaa[c];

    float s  = yv.x + yv.y + yv.z + yv.w;
    float s2 = yv.x*yv.x + yv.y*yv.y + yv.z*yv.z + yv.w*yv.w;
    float dk = rv.x*kv.x*fv.x + rv.y*kv.y*fv.y + rv.z*kv.z*fv.z + rv.w*kv.w*fv.w;
#pragma unroll
    for (int o = 8; o; o >>= 1) {
        s  += __shfl_xor_sync(0xffffffffu, s,  o, 16);
        s2 += __shfl_xor_sync(0xffffffffu, s2, o, 16);
        dk += __shfl_xor_sync(0xffffffffu, dk, o, 16);
    }
    float mean = s  * (1.f / 64.f);
    float var  = s2 * (1.f / 64.f) - mean * mean;
    float rs   = rsqrtf(var + 64e-5f);

    float4 lw = *(const float4*)&lnw[c];
    float4 lb = *(const float4*)&lnb[c];
    float4 z;
    z.x = (((yv.x - mean) * rs) * lw.x + lb.x + dk * vv.x) * gv.x;
    z.y = (((yv.y - mean) * rs) * lw.y + lb.y + dk * vv.y) * gv.y;
    z.z = (((yv.z - mean) * rs) * lw.z + lb.z + dk * vv.z) * gv.z;
    z.w = (((yv.w - mean) * rs) * lw.w + lb.w + dk * vv.w) * gv.w;
    *(float4*)&g_s.z[off] = z;
}

// ---------------------------------------------------------------------------
// Host orchestration
// ---------------------------------------------------------------------------
static void g128(const float* A, const float* Bp, float* Cp,
                 int N, int K, int lda, int bt, int mode,
                 const float* ex, const float* exx, const float* evec)
{
    dim3 grid(N / 128, MM / 128);
    gemm128<<<grid, 256>>>(A, Bp, Cp, N, K, lda, bt, mode, ex, exx, evec);
}
static void g32(const float* A, const float* Bp, float* Cp,
                int N, int K, int lda, int mode)
{
    dim3 grid((N + 63) / 64, MM / 32);
    gemm32<<<grid, 256>>>(A, Bp, Cp, N, K, lda, mode);
}

extern "C" void kernel_launch(void* const* d_in, const int* in_sizes, int n_in,
                              void* d_out, int out_size)
{
    const float* x       = (const float*)d_in[0];
    const float* maa_x   = (const float*)d_in[1];
    const float* maa_rg  = (const float*)d_in[2];
    const float* maa_wa  = (const float*)d_in[3];
    const float* maa_k   = (const float*)d_in[4];
    const float* maa_v   = (const float*)d_in[5];
    const float* maa_w1  = (const float*)d_in[6];
    const float* maa_w2  = (const float*)d_in[7];
    const float* tdecay  = (const float*)d_in[8];
    const float* dw1     = (const float*)d_in[9];
    const float* dw2     = (const float*)d_in[10];
    const float* faaaa   = (const float*)d_in[11];
    const float* taaaaa  = (const float*)d_in[12];
    const float* aw1     = (const float*)d_in[13];
    const float* aw2     = (const float*)d_in[14];
    const float* kw1     = (const float*)d_in[15];
    const float* kw2     = (const float*)d_in[16];
    const float* gw1     = (const float*)d_in[17];
    const float* gw2     = (const float*)d_in[18];
    const float* maw1    = (const float*)d_in[19];
    const float* maw2    = (const float*)d_in[20];
    const float* tmisca  = (const float*)d_in[21];
    const float* mkw1    = (const float*)d_in[22];
    const float* mkw2    = (const float*)d_in[23];
    const float* tmisck  = (const float*)d_in[24];
    const float* wr      = (const float*)d_in[25];
    const float* wk      = (const float*)d_in[26];
    const float* wv      = (const float*)d_in[27];
    const float* wo      = (const float*)d_in[28];
    const float* lnw     = (const float*)d_in[29];
    const float* lnb     = (const float*)d_in[30];
    float* out = (float*)d_out;
    (void)in_sizes; (void)n_in; (void)out_size;

    Scratch* S = nullptr;
    cudaGetSymbolAddress((void**)&S, g_s);

    // 1) time-shift + maa_x mix
    ew0_kernel<<<(MM * CC / 4) / 256, 256>>>(x, maa_x);

    // 2) mix_in = tanh(xmix @ maa_w1)
    g32(S->xmix, maa_w1, S->mixin, 128, 1024, 1024, 1);

    // 3) xrg/xwa/xk/xv
    {
        const float* maas[4]  = { maa_rg, maa_wa, maa_k, maa_v };
        float*       xouts[4] = { S->xrg, S->xwa, S->xk, S->xv };
        for (int f = 0; f < 4; f++)
            g128(S->mixin + f * 32, maa_w2 + (size_t)f * 32 * 1024,
                 xouts[f], 1024, 32, 128, 0, 2, x, S->xx, maas[f]);
    }

    // 4) big projections (A @ B^T)
    g128(S->xrg, wr, S->r, 1024, 1024, 1024, 1, 0, 0, 0, 0);
    g128(S->xk,  wk, S->k, 1024, 1024, 1024, 1, 0, 0, 0, 0);
    g128(S->xv,  wv, S->v, 1024, 1024, 1024, 1, 0, 0, 0, 0);

    // 5) gate
    g32(S->xrg, gw1, S->gate1, 128, 1024, 1024, 1);
    g128(S->gate1, gw2, S->g, 1024, 128, 128, 0, 0, 0, 0, 0);

    // 6) decay
    g32(S->xwa, dw1, S->dec1, 64, 1024, 1024, 1);
    g128(S->dec1, dw2, S->w, 1024, 64, 64, 0, 4, 0, 0, tdecay);

    // 7) LoRA sigmoids + kkk
    g32(S->xwa, aw1,  S->aaa1, 16, 1024, 1024, 0);
    g128(S->aaa1, aw2, S->asig, 1024, 16, 16, 0, 3, 0, 0, taaaaa);
    g32(S->xwa, maw1, S->ma1,  16, 1024, 1024, 0);
    g128(S->ma1, maw2, S->ma,  1024, 16, 16, 0, 3, 0, 0, tmisca);
    g32(S->xk,  kw1,  S->kkk1, 16, 1024, 1024, 1);
    g128(S->kkk1, kw2, S->kk,  1024, 16, 16, 0, 5, S->k, 0, 0);
    g32(S->xk,  mkw1, S->mk1,  16, 1024, 1024, 0);
    g128(S->mk1, mkw2, S->mk2, 1024, 16, 16, 0, 3, 0, 0, tmisck);

    // 8) combine
    combine_kernel<<<MM, 256>>>();

    // 9) WKV-7 scan (8 warps per head)
    wkv_kernel<<<BB * HH, 256>>>();

    // 10) GroupNorm + bonus + gate
    post_kernel<<<MM, 256>>>(faaaa, lnw, lnb);

    // 11) output projection
    g128(S->z, wo, out, 1024, 1024, 1024, 1, 0, 0, 0, 0);
}

// round 5
// speedup vs baseline: 1.4494x; 1.2100x over previous
#include <cuda_runtime.h>
#include <cuda_bf16.h>
#include <math.h>
#include <stdint.h>
#include <string.h>

#define BB 4
#define TT 1024
#define CC 1024
#define HH 16
#define NN 64
#define MM (BB*TT)   // 4096 rows

// ---------------------------------------------------------------------------
// Scratch (static device memory)
// ---------------------------------------------------------------------------
struct Scratch {
    float xx   [MM*CC];
    float xmix [MM*CC];
    float mixin[MM*128];
    float xrg  [MM*CC];
    float xwa  [MM*CC];
    float xk   [MM*CC];
    float xv   [MM*CC];
    float r    [MM*CC];
    float k    [MM*CC];
    float v    [MM*CC];
    float g    [MM*CC];
    float w    [MM*CC];
    float kk   [MM*CC];
    float asig [MM*CC];
    float ma   [MM*CC];
    float mk2  [MM*CC];
    float kf   [MM*CC];
    float dd   [MM*CC];
    float av   [MM*CC];
    float bv   [MM*CC];
    float y    [MM*CC];
    float z    [MM*CC];
    float gate1[MM*128];
    float dec1 [MM*64];
    float aaa1 [MM*16];
    float ma1  [MM*16];
    float kkk1 [MM*16];
    float mk1  [MM*16];
    float gw2T [1024*128];   // transposed gate_w2 (N,K)
};
__device__ Scratch g_s;

// ---------------------------------------------------------------------------
// Packed f32x2 helpers
// ---------------------------------------------------------------------------
__device__ __forceinline__ unsigned long long dup2(float x) {
    unsigned long long r;
    asm("mov.b64 %0, {%1, %1};" : "=l"(r) : "f"(x));
    return r;
}
__device__ __forceinline__ void fma2(unsigned long long& acc,
                                     unsigned long long a,
                                     unsigned long long b) {
    asm("fma.rn.f32x2 %0, %1, %2, %0;" : "+l"(acc) : "l"(a), "l"(b));
}
__device__ __forceinline__ unsigned long long fma2g(unsigned long long a,
                                                    unsigned long long b,
                                                    unsigned long long c) {
    unsigned long long d;
    asm("fma.rn.f32x2 %0, %1, %2, %3;" : "=l"(d) : "l"(a), "l"(b), "l"(c));
    return d;
}
__device__ __forceinline__ unsigned long long mul2(unsigned long long a,
                                                   unsigned long long b) {
    unsigned long long d;
    asm("mul.rn.f32x2 %0, %1, %2;" : "=l"(d) : "l"(a), "l"(b));
    return d;
}
__device__ __forceinline__ float2 unpack2(unsigned long long v) {
    float2 f;
    asm("mov.b64 {%0, %1}, %2;" : "=f"(f.x), "=f"(f.y) : "l"(v));
    return f;
}

__device__ __forceinline__ uint32_t smem_u32(const void* p) {
    uint32_t a;
    asm("{ .reg .u64 t; cvta.to.shared.u64 t, %1; cvt.u32.u64 %0, t; }"
        : "=r"(a) : "l"(p));
    return a;
}

// ---------------------------------------------------------------------------
// mma.sync / ldmatrix helpers (baseline PTX, legal at .target sm_103)
// ---------------------------------------------------------------------------
__device__ __forceinline__ void ldsm4(uint32_t* r, uint32_t addr) {
    asm volatile("ldmatrix.sync.aligned.m8n8.x4.shared.b16 {%0,%1,%2,%3}, [%4];"
        : "=r"(r[0]), "=r"(r[1]), "=r"(r[2]), "=r"(r[3]) : "r"(addr));
}
__device__ __forceinline__ void mma_bf16(float* c, const uint32_t* a,
                                         const uint32_t* b) {
    asm volatile("mma.sync.aligned.m16n8k16.row.col.f32.bf16.bf16.f32 "
        "{%0,%1,%2,%3}, {%4,%5,%6,%7}, {%8,%9}, {%0,%1,%2,%3};"
        : "+f"(c[0]), "+f"(c[1]), "+f"(c[2]), "+f"(c[3])
        : "r"(a[0]), "r"(a[1]), "r"(a[2]), "r"(a[3]), "r"(b[0]), "r"(b[1]));
}

// split float4 -> bf16 hi/lo (4 cols) and store 8B each
__device__ __forceinline__ void cvt_store(float4 f, char* hi, char* lo,
                                          uint32_t off) {
    __nv_bfloat162 h01 = __floats2bfloat162_rn(f.x, f.y);
    __nv_bfloat162 h23 = __floats2bfloat162_rn(f.z, f.w);
    float hx = __bfloat162float(h01.x), hy = __bfloat162float(h01.y);
    float hz = __bfloat162float(h23.x), hw = __bfloat162float(h23.y);
    __nv_bfloat162 l01 = __floats2bfloat162_rn(f.x - hx, f.y - hy);
    __nv_bfloat162 l23 = __floats2bfloat162_rn(f.z - hz, f.w - hw);
    uint32_t uh0, uh1, ul0, ul1;
    memcpy(&uh0, &h01, 4); memcpy(&uh1, &h23, 4);
    memcpy(&ul0, &l01, 4); memcpy(&ul1, &l23, 4);
    *(uint2*)(hi + off) = make_uint2(uh0, uh1);
    *(uint2*)(lo + off) = make_uint2(ul0, ul1);
}

// ---------------------------------------------------------------------------
// gemm_mma: C[M,1024] = A[M,K] @ B[1024,K]^T, bf16 hi/lo split, fp32 accum.
// CTA 128x128, k-chunk 32, 8 warps (warp tile 64x32), double-buffered smem.
// smem layout per buffer (stride 80B rows, 128 rows): Ah@0, Al@10240,
// Bh@20480, Bl@30720; buffer stride 40960; total 81920 bytes dynamic.
// ---------------------------------------------------------------------------
#define MMA_SMEM 81920

__global__ void __launch_bounds__(256)
gemm_mma(const float* __restrict__ A, const float* __restrict__ Bw,
         float* __restrict__ Cm, int K)
{
    extern __shared__ __align__(16) char sm[];
    const uint32_t sb = smem_u32(sm);

    const int tid  = threadIdx.x;
    const int lane = tid & 31;
    const int wid  = tid >> 5;
    const int wm   = wid & 1;       // warp m (2)
    const int wn   = wid >> 1;      // warp n (4)
    const int n0 = blockIdx.x * 128;
    const int m0 = blockIdx.y * 128;

    // loader mapping: each thread handles one row-half (16 floats)
    const int row = tid >> 1, half = tid & 1;
    const float* aSrc = A  + (size_t)(m0 + row) * K + half * 16;
    const float* bSrc = Bw + (size_t)(n0 + row) * K + half * 16;
    const uint32_t stOff = (uint32_t)(row * 80 + half * 32);

    // ldmatrix lane offsets
    const uint32_t aLoff = (uint32_t)((lane & 15) * 80 + (lane >> 4) * 16);
    const uint32_t bLoff = (uint32_t)(((lane & 7) + ((lane >> 4) & 1) * 8) * 80
                                      + ((lane >> 3) & 1) * 16);

    float c[4][4][4];
#pragma unroll
    for (int i = 0; i < 4; i++)
#pragma unroll
        for (int j = 0; j < 4; j++)
#pragma unroll
            for (int q = 0; q < 4; q++) c[i][j][q] = 0.f;

    const int chunks = K >> 5;

    // ---- preload chunk 0 into buffer 0
    {
#pragma unroll
        for (int i = 0; i < 4; i++) {
            float4 fa = ((const float4*)aSrc)[i];
            float4 fb = ((const float4*)bSrc)[i];
            cvt_store(fa, sm + 0,     sm + 10240, stOff + i * 8);
            cvt_store(fb, sm + 20480, sm + 30720, stOff + i * 8);
        }
    }
    __syncthreads();

    for (int cidx = 0; cidx < chunks; cidx++) {
        const uint32_t bufOff = (uint32_t)((cidx & 1) * 40960);
        const bool more = (cidx + 1 < chunks);

        // issue global loads for next chunk (regs)
        float4 fa[4], fb[4];
        if (more) {
            const float* ap = aSrc + (cidx + 1) * 32;
            const float* bp = bSrc + (cidx + 1) * 32;
#pragma unroll
            for (int i = 0; i < 4; i++) {
                fa[i] = ((const float4*)ap)[i];
                fb[i] = ((const float4*)bp)[i];
            }
        }

        // ---- MMA phase on current buffer
        const uint32_t aBase = sb + bufOff + (uint32_t)(wm * 64 * 80) + aLoff;
        const uint32_t bBase = sb + bufOff + 20480u + (uint32_t)(wn * 32 * 80) + bLoff;
#pragma unroll
        for (int ks = 0; ks < 2; ks++) {
            uint32_t afh[4][4], afl[4][4];
#pragma unroll
            for (int mi = 0; mi < 4; mi++) {
                ldsm4(afh[mi], aBase + 0u     + (uint32_t)(mi * 1280 + ks * 32));
                ldsm4(afl[mi], aBase + 10240u + (uint32_t)(mi * 1280 + ks * 32));
            }
            uint32_t bfh[2][4], bfl[2][4];
#pragma unroll
            for (int np = 0; np < 2; np++) {
                ldsm4(bfh[np], bBase + 0u     + (uint32_t)(np * 1280 + ks * 32));
                ldsm4(bfl[np], bBase + 10240u + (uint32_t)(np * 1280 + ks * 32));
            }
#pragma unroll
            for (int mi = 0; mi < 4; mi++) {
#pragma unroll
                for (int ni = 0; ni < 4; ni++) {
                    const uint32_t* bh = &bfh[ni >> 1][(ni & 1) * 2];
                    const uint32_t* bl = &bfl[ni >> 1][(ni & 1) * 2];
                    mma_bf16(c[mi][ni], afh[mi], bh);
                    mma_bf16(c[mi][ni], afh[mi], bl);
                    mma_bf16(c[mi][ni], afl[mi], bh);
                }
            }
        }

        // ---- convert + store next chunk
        if (more) {
            char* nb = sm + ((cidx + 1) & 1) * 40960;
#pragma unroll
            for (int i = 0; i < 4; i++) {
                cvt_store(fa[i], nb + 0,     nb + 10240, stOff + i * 8);
                cvt_store(fb[i], nb + 20480, nb + 30720, stOff + i * 8);
            }
        }
        __syncthreads();
    }

    // ---- epilogue: direct STG.64 per fragment pair
    const int erow = m0 + wm * 64 + (lane >> 2);
    const int ecol = n0 + wn * 32 + (lane & 3) * 2;
#pragma unroll
    for (int mi = 0; mi < 4; mi++) {
#pragma unroll
        for (int ni = 0; ni < 4; ni++) {
            size_t base0 = (size_t)(erow + mi * 16)     * 1024 + ecol + ni * 8;
            size_t base1 = (size_t)(erow + mi * 16 + 8) * 1024 + ecol + ni * 8;
            *(float2*)&Cm[base0] = make_float2(c[mi][ni][0], c[mi][ni][1]);
            *(float2*)&Cm[base1] = make_float2(c[mi][ni][2], c[mi][ni][3]);
        }
    }
}

// ---------------------------------------------------------------------------
// transpose 128x1024 -> 1024x128 (for gate_w2)
// ---------------------------------------------------------------------------
__global__ void __launch_bounds__(256)
transpose_kernel(const float* __restrict__ src, float* __restrict__ dst)
{
    __shared__ float tile[32][33];
    int bx = blockIdx.x;
    int by = blockIdx.y;
    int tx = threadIdx.x & 31, ty = threadIdx.x >> 5;
#pragma unroll
    for (int i = 0; i < 4; i++)
        tile[ty + i * 8][tx] = src[(size_t)(by * 32 + ty + i * 8) * 1024 + bx * 32 + tx];
    __syncthreads();
#pragma unroll
    for (int i = 0; i < 4; i++)
        dst[(size_t)(bx * 32 + ty + i * 8) * 128 + by * 32 + tx] = tile[tx][ty + i * 8];
}

// ---------------------------------------------------------------------------
// gemm128 (fp32, for small/medium GEMMs with fused epilogues)
// ---------------------------------------------------------------------------
__global__ void __launch_bounds__(256, 2)
gemm128(const float* __restrict__ A, const float* __restrict__ Bm,
        float* __restrict__ Cm, int N, int K, int lda, int bt, int mode,
        const float* __restrict__ ex, const float* __restrict__ exx,
        const float* __restrict__ evec)
{
    __shared__ __align__(16) float As[2][16][128];
    __shared__ __align__(16) float Bs[2][16][128];

    const int tid = threadIdx.x;
    const int tx = tid & 15;
    const int ty = tid >> 4;
    const int n0 = blockIdx.x * 128;
    const int m0 = blockIdx.y * 128;

    unsigned long long acc[8][4];
#pragma unroll
    for (int i = 0; i < 8; i++)
#pragma unroll
        for (int j = 0; j < 4; j++) acc[i][j] = 0ull;

    const int arow0 = (tid)       >> 2, akq0 = (tid)       & 3;
    const int arow1 = (tid + 256) >> 2, akq1 = (tid + 256) & 3;
    const int bkrow0 = (tid)       >> 5, bnq0 = (tid)       & 31;
    const int bkrow1 = (tid + 256) >> 5, bnq1 = (tid + 256) & 31;

    {
        float4 a0 = *(const float4*)&A[(size_t)(m0 + arow0) * lda + akq0 * 4];
        float4 a1 = *(const float4*)&A[(size_t)(m0 + arow1) * lda + akq1 * 4];
        As[0][akq0*4+0][arow0] = a0.x; As[0][akq0*4+1][arow0] = a0.y;
        As[0][akq0*4+2][arow0] = a0.z; As[0][akq0*4+3][arow0] = a0.w;
        As[0][akq1*4+0][arow1] = a1.x; As[0][akq1*4+1][arow1] = a1.y;
        As[0][akq1*4+2][arow1] = a1.z; As[0][akq1*4+3][arow1] = a1.w;
        if (bt) {
            float4 b0 = *(const float4*)&Bm[(size_t)(n0 + arow0) * K + akq0 * 4];
            float4 b1 = *(const float4*)&Bm[(size_t)(n0 + arow1) * K + akq1 * 4];
            Bs[0][akq0*4+0][arow0] = b0.x; Bs[0][akq0*4+1][arow0] = b0.y;
            Bs[0][akq0*4+2][arow0] = b0.z; Bs[0][akq0*4+3][arow0] = b0.w;
            Bs[0][akq1*4+0][arow1] = b1.x; Bs[0][akq1*4+1][arow1] = b1.y;
            Bs[0][akq1*4+2][arow1] = b1.z; Bs[0][akq1*4+3][arow1] = b1.w;
        } else {
            *(float4*)&Bs[0][bkrow0][bnq0*4] =
                *(const float4*)&Bm[(size_t)bkrow0 * N + n0 + bnq0 * 4];
            *(float4*)&Bs[0][bkrow1][bnq1*4] =
                *(const float4*)&Bm[(size_t)bkrow1 * N + n0 + bnq1 * 4];
        }
    }
    __syncthreads();

    const int ntiles = K >> 4;
    for (int it = 0; it < ntiles; it++) {
        const int buf = it & 1;
        const bool more = (it + 1 < ntiles);
        float4 pa0, pa1, pb0, pb1;
        if (more) {
            const int kt = (it + 1) << 4;
            pa0 = *(const float4*)&A[(size_t)(m0 + arow0) * lda + kt + akq0 * 4];
            pa1 = *(const float4*)&A[(size_t)(m0 + arow1) * lda + kt + akq1 * 4];
            if (bt) {
                pb0 = *(const float4*)&Bm[(size_t)(n0 + arow0) * K + kt + akq0 * 4];
                pb1 = *(const float4*)&Bm[(size_t)(n0 + arow1) * K + kt + akq1 * 4];
            } else {
                pb0 = *(const float4*)&Bm[(size_t)(kt + bkrow0) * N + n0 + bnq0 * 4];
                pb1 = *(const float4*)&Bm[(size_t)(kt + bkrow1) * N + n0 + bnq1 * 4];
            }
        }

#pragma unroll
        for (int kq = 0; kq < 16; kq++) {
            float4 a0 = *(const float4*)&As[buf][kq][ty * 8];
            float4 a1 = *(const float4*)&As[buf][kq][ty * 8 + 4];
            ulonglong2 bA = *(const ulonglong2*)&Bs[buf][kq][tx * 8];
            ulonglong2 bBv = *(const ulonglong2*)&Bs[buf][kq][tx * 8 + 4];
#define RF(rI, aval) { unsigned long long dp = dup2(aval); \
            fma2(acc[rI][0], dp, bA.x); fma2(acc[rI][1], dp, bA.y); \
            fma2(acc[rI][2], dp, bBv.x); fma2(acc[rI][3], dp, bBv.y); }
            RF(0, a0.x) RF(1, a0.y) RF(2, a0.z) RF(3, a0.w)
            RF(4, a1.x) RF(5, a1.y) RF(6, a1.z) RF(7, a1.w)
#undef RF
        }

        if (more) {
            const int nb = buf ^ 1;
            As[nb][akq0*4+0][arow0] = pa0.x; As[nb][akq0*4+1][arow0] = pa0.y;
            As[nb][akq0*4+2][arow0] = pa0.z; As[nb][akq0*4+3][arow0] = pa0.w;
            As[nb][akq1*4+0][arow1] = pa1.x; As[nb][akq1*4+1][arow1] = pa1.y;
            As[nb][akq1*4+2][arow1] = pa1.z; As[nb][akq1*4+3][arow1] = pa1.w;
            if (bt) {
                Bs[nb][akq0*4+0][arow0] = pb0.x; Bs[nb][akq0*4+1][arow0] = pb0.y;
                Bs[nb][akq0*4+2][arow0] = pb0.z; Bs[nb][akq0*4+3][arow0] = pb0.w;
                Bs[nb][akq1*4+0][arow1] = pb1.x; Bs[nb][akq1*4+1][arow1] = pb1.y;
                Bs[nb][akq1*4+2][arow1] = pb1.z; Bs[nb][akq1*4+3][arow1] = pb1.w;
            } else {
                *(float4*)&Bs[nb][bkrow0][bnq0*4] = pb0;
                *(float4*)&Bs[nb][bkrow1][bnq1*4] = pb1;
            }
        }
        __syncthreads();
    }

#pragma unroll
    for (int rr = 0; rr < 8; rr++) {
        const int m = m0 + ty * 8 + rr;
        float vals[8];
        { float2 p = unpack2(acc[rr][0]); vals[0] = p.x; vals[1] = p.y; }
        { float2 p = unpack2(acc[rr][1]); vals[2] = p.x; vals[3] = p.y; }
        { float2 p = unpack2(acc[rr][2]); vals[4] = p.x; vals[5] = p.y; }
        { float2 p = unpack2(acc[rr][3]); vals[6] = p.x; vals[7] = p.y; }
#pragma unroll
        for (int q = 0; q < 8; q++) {
            const int nn = n0 + tx * 8 + q;
            float vv = vals[q];
            float res;
            switch (mode) {
                default:
                case 0: res = vv; break;
                case 2: res = ex[(size_t)m * N + nn]
                            + exx[(size_t)m * N + nn] * (evec[nn] + vv); break;
                case 3: { float zz = evec[nn] + vv;
                          res = 1.f / (1.f + expf(-zz)); } break;
                case 4: { float zz = evec[nn] + vv;
                          res = -log1pf(expf(-zz)) - 0.5f; } break;
                case 5: res = ex[(size_t)m * N + nn] + vv; break;
            }
            vals[q] = res;
        }
        float4 o0 = make_float4(vals[0], vals[1], vals[2], vals[3]);
        float4 o1 = make_float4(vals[4], vals[5], vals[6], vals[7]);
        *(float4*)&Cm[(size_t)m * N + n0 + tx * 8]     = o0;
        *(float4*)&Cm[(size_t)m * N + n0 + tx * 8 + 4] = o1;
    }
}

// ---------------------------------------------------------------------------
// gemm32: tall-skinny up-projections (bt=0). modes: 0 plain, 1 tanh.
// ---------------------------------------------------------------------------
__global__ void __launch_bounds__(256)
gemm32(const float* __restrict__ A, const float* __restrict__ Bm,
       float* __restrict__ Cm, int N, int K, int lda, int mode)
{
    __shared__ __align__(16) float As[16][32];
    __shared__ __align__(16) float Bs[16][64];

    const int tid = threadIdx.x;
    const int tx = tid & 7;
    const int ty = tid >> 3;
    const int n0 = blockIdx.x * 64;
    const int m0 = blockIdx.y * 32;

    unsigned long long acc[4] = {0ull, 0ull, 0ull, 0ull};

    const int arow = tid >> 2, akq = tid & 3;
    const int bkrow = tid >> 4, bnq = tid & 15;

    for (int kt = 0; kt < K; kt += 16) {
        if (tid < 128) {
            float4 a0 = *(const float4*)&A[(size_t)(m0 + arow) * lda + kt + akq * 4];
            As[akq*4+0][arow] = a0.x; As[akq*4+1][arow] = a0.y;
            As[akq*4+2][arow] = a0.z; As[akq*4+3][arow] = a0.w;
        }
        float4 b0 = make_float4(0.f, 0.f, 0.f, 0.f);
        if (n0 + bnq * 4 < N)
            b0 = *(const float4*)&Bm[(size_t)(kt + bkrow) * N + n0 + bnq * 4];
        *(float4*)&Bs[bkrow][bnq*4] = b0;
        __syncthreads();

#pragma unroll
        for (int kq = 0; kq < 16; kq++) {
            unsigned long long dp = dup2(As[kq][ty]);
            ulonglong2 bA = *(const ulonglong2*)&Bs[kq][tx * 8];
            ulonglong2 bBv = *(const ulonglong2*)&Bs[kq][tx * 8 + 4];
            fma2(acc[0], dp, bA.x); fma2(acc[1], dp, bA.y);
            fma2(acc[2], dp, bBv.x); fma2(acc[3], dp, bBv.y);
        }
        __syncthreads();
    }

    const int m = m0 + ty;
    float vals[8];
    { float2 p = unpack2(acc[0]); vals[0] = p.x; vals[1] = p.y; }
    { float2 p = unpack2(acc[1]); vals[2] = p.x; vals[3] = p.y; }
    { float2 p = unpack2(acc[2]); vals[4] = p.x; vals[5] = p.y; }
    { float2 p = unpack2(acc[3]); vals[6] = p.x; vals[7] = p.y; }
#pragma unroll
    for (int q = 0; q < 8; q++) {
        const int nn = n0 + tx * 8 + q;
        if (nn < N) {
            float vv = vals[q];
            Cm[(size_t)m * N + nn] = (mode == 1) ? tanhf(vv) : vv;
        }
    }
}

// ---------------------------------------------------------------------------
// ew0
// ---------------------------------------------------------------------------
__global__ void __launch_bounds__(256)
ew0_kernel(const float* __restrict__ x, const float* __restrict__ maa_x)
{
    size_t i4  = (size_t)blockIdx.x * 256 + threadIdx.x;
    size_t idx = i4 * 4;
    int c    = (int)(idx & (CC - 1));
    int nrow = (int)(idx >> 10);
    float4 xv = *(const float4*)&x[idx];
    float4 xp = make_float4(0.f, 0.f, 0.f, 0.f);
    if (nrow & (TT - 1))
        xp = *(const float4*)&x[idx - CC];
    float4 mv = *(const float4*)&maa_x[c];
    float4 d, xm;
    d.x = xp.x - xv.x;  xm.x = xv.x + d.x * mv.x;
    d.y = xp.y - xv.y;  xm.y = xv.y + d.y * mv.y;
    d.z = xp.z - xv.z;  xm.z = xv.z + d.z * mv.z;
    d.w = xp.w - xv.w;  xm.w = xv.w + d.w * mv.w;
    *(float4*)&g_s.xx[idx]   = d;
    *(float4*)&g_s.xmix[idx] = xm;
}

// ---------------------------------------------------------------------------
// combine
// ---------------------------------------------------------------------------
__global__ void __launch_bounds__(256)
combine_kernel()
{
    int n   = blockIdx.x;
    int tid = threadIdx.x;
    size_t off = (size_t)n * CC + tid * 4;

    float4 kkv = *(float4*)&g_s.kk[off];
    float ss = kkv.x*kkv.x + kkv.y*kkv.y + kkv.z*kkv.z + kkv.w*kkv.w;
#pragma unroll
    for (int o = 8; o; o >>= 1) ss += __shfl_xor_sync(0xffffffffu, ss, o, 16);
    float inv = 1.f / fmaxf(sqrtf(ss), 1e-12f);

    float4 kq = *(float4*)&g_s.k[off];
    float4 aq = *(float4*)&g_s.asig[off];
    float4 mq = *(float4*)&g_s.ma[off];
    float4 wq = *(float4*)&g_s.w[off];
    float4 mk = *(float4*)&g_s.mk2[off];
    float4 kfv, ddv, avv, bvv;
#define CMB(X) { float fac = mq.X + aq.X * (1.f - mq.X); \
    float ee = expf(fminf(wq.X * mk.X, 0.f)); \
    kfv.X = kq.X * fac * ee; \
    ddv.X = expf(wq.X); \
    float kn = kkv.X * inv; \
    avv.X = -kn; bvv.X = kn * aq.X; }
    CMB(x) CMB(y) CMB(z) CMB(w)
#undef CMB
    *(float4*)&g_s.kf[off] = kfv;
    *(float4*)&g_s.dd[off] = ddv;
    *(float4*)&g_s.av[off] = avv;
    *(float4*)&g_s.bv[off] = bvv;
}

// ---------------------------------------------------------------------------
// WKV-7 scan
// ---------------------------------------------------------------------------
__global__ void __launch_bounds__(256)
wkv_kernel()
{
    const int blk = blockIdx.x;
    const int b = blk >> 4;
    const int h = blk & 15;
    const int tid = threadIdx.x;
    const int i  = tid >> 2;
    const int jq = tid & 3;

    __shared__ __align__(16) float sb[2][6][64];

    const size_t rowbase = ((size_t)b * TT) * CC + h * NN;

    const float4* myp = 0;
    int larr = 0, lq = 0;
    if (tid < 96) {
        larr = tid >> 4; lq = tid & 15;
        const float* srcs[6] = { g_s.r, g_s.dd, g_s.kf, g_s.av, g_s.bv, g_s.v };
        myp = (const float4*)(srcs[larr] + rowbase + lq * 4);
    }
    float4 pf;
    if (tid < 96) {
        pf = myp[0];
        ((float4*)sb[0][larr])[lq] = pf;
    }
    __syncthreads();

    unsigned long long S2[8];
#pragma unroll
    for (int u = 0; u < 8; u++) S2[u] = 0ull;

    float* yout = g_s.y + rowbase + i;

    for (int t = 0; t < TT; t++) {
        const int p = t & 1;
        const bool more = (t + 1 < TT);
        if (tid < 96 && more) pf = myp[(size_t)(t + 1) * (CC / 4)];

        const ulonglong2* a2p = (const ulonglong2*)(sb[p][3] + jq * 16);
        const ulonglong2* d2p = (const ulonglong2*)(sb[p][1] + jq * 16);
        const ulonglong2* k2p = (const ulonglong2*)(sb[p][2] + jq * 16);
        const ulonglong2* b2p = (const ulonglong2*)(sb[p][4] + jq * 16);
        const ulonglong2* r2p = (const ulonglong2*)(sb[p][0] + jq * 16);
        const float vi = sb[p][5][i];

        unsigned long long acc0 = 0ull, acc1 = 0ull;
#pragma unroll
        for (int u = 0; u < 4; u++) {
            ulonglong2 avp = a2p[u];
            fma2(acc0, S2[2*u],   avp.x);
            fma2(acc1, S2[2*u+1], avp.y);
        }
        float2 f0 = unpack2(acc0), f1 = unpack2(acc1);
        float sa = (f0.x + f0.y) + (f1.x + f1.y);
        sa += __shfl_xor_sync(0xffffffffu, sa, 1, 4);
        sa += __shfl_xor_sync(0xffffffffu, sa, 2, 4);

        const unsigned long long sa2 = dup2(sa);
        const unsigned long long v2  = dup2(vi);

        unsigned long long y0 = 0ull, y1 = 0ull;
#pragma unroll
        for (int u = 0; u < 4; u++) {
            ulonglong2 dvp = d2p[u], kvp = k2p[u], bvp = b2p[u], rvp = r2p[u];
            unsigned long long t0 = fma2g(sa2, bvp.x, mul2(v2, kvp.x));
            t0 = fma2g(S2[2*u], dvp.x, t0);
            S2[2*u] = t0;
            fma2(y0, t0, rvp.x);
            unsigned long long t1 = fma2g(sa2, bvp.y, mul2(v2, kvp.y));
            t1 = fma2g(S2[2*u+1], dvp.y, t1);
            S2[2*u+1] = t1;
            fma2(y1, t1, rvp.y);
        }
        float2 g0 = unpack2(y0), g1 = unpack2(y1);
        float yv = (g0.x + g0.y) + (g1.x + g1.y);
        yv += __shfl_xor_sync(0xffffffffu, yv, 1, 4);
        yv += __shfl_xor_sync(0xffffffffu, yv, 2, 4);
        if (jq == 0) yout[(size_t)t * CC] = yv;

        if (tid < 96 && more) ((float4*)sb[p ^ 1][larr])[lq] = pf;
        __syncthreads();
    }
}

// ---------------------------------------------------------------------------
// post
// ---------------------------------------------------------------------------
__global__ void __launch_bounds__(256)
post_kernel(const float* __restrict__ faaaa,
            const float* __restrict__ lnw, const float* __restrict__ lnb)
{
    int n   = blockIdx.x;
    int tid = threadIdx.x;
    int c   = tid * 4;
    size_t off = (size_t)n * CC + c;

    float4 yv = *(float4*)&g_s.y [off];
    float4 rv = *(float4*)&g_s.r [off];
    float4 kv = *(float4*)&g_s.kf[off];
    float4 vv = *(float4*)&g_s.v [off];
    float4 gv = *(float4*)&g_s.g [off];
    float4 fv = *(const float4*)&faaaa[c];

    float s  = yv.x + yv.y + yv.z + yv.w;
    float s2 = yv.x*yv.x + yv.y*yv.y + yv.z*yv.z + yv.w*yv.w;
    float dk = rv.x*kv.x*fv.x + rv.y*kv.y*fv.y + rv.z*kv.z*fv.z + rv.w*kv.w*fv.w;
#pragma unroll
    for (int o = 8; o; o >>= 1) {
        s  += __shfl_xor_sync(0xffffffffu, s,  o, 16);
        s2 += __shfl_xor_sync(0xffffffffu, s2, o, 16);
        dk += __shfl_xor_sync(0xffffffffu, dk, o, 16);
    }
    float mean = s  * (1.f / 64.f);
    float var  = s2 * (1.f / 64.f) - mean * mean;
    float rs   = rsqrtf(var + 64e-5f);

    float4 lw = *(const float4*)&lnw[c];
    float4 lb = *(const float4*)&lnb[c];
    float4 z;
    z.x = (((yv.x - mean) * rs) * lw.x + lb.x + dk * vv.x) * gv.x;
    z.y = (((yv.y - mean) * rs) * lw.y + lb.y + dk * vv.y) * gv.y;
    z.z = (((yv.z - mean) * rs) * lw.z + lb.z + dk * vv.z) * gv.z;
    z.w = (((yv.w - mean) * rs) * lw.w + lb.w + dk * vv.w) * gv.w;
    *(float4*)&g_s.z[off] = z;
}

// ---------------------------------------------------------------------------
// Host orchestration
// ---------------------------------------------------------------------------
static void g128(const float* A, const float* Bp, float* Cp,
                 int N, int K, int lda, int bt, int mode,
                 const float* ex, const float* exx, const float* evec)
{
    dim3 grid(N / 128, MM / 128);
    gemm128<<<grid, 256>>>(A, Bp, Cp, N, K, lda, bt, mode, ex, exx, evec);
}
static void g32(const float* A, const float* Bp, float* Cp,
                int N, int K, int lda, int mode)
{
    dim3 grid((N + 63) / 64, MM / 32);
    gemm32<<<grid, 256>>>(A, Bp, Cp, N, K, lda, mode);
}
static void gmma(const float* A, const float* Bw, float* Cp, int K)
{
    dim3 grid(8, MM / 128);
    gemm_mma<<<grid, 256, MMA_SMEM>>>(A, Bw, Cp, K);
}

extern "C" void kernel_launch(void* const* d_in, const int* in_sizes, int n_in,
                              void* d_out, int out_size)
{
    const float* x       = (const float*)d_in[0];
    const float* maa_x   = (const float*)d_in[1];
    const float* maa_rg  = (const float*)d_in[2];
    const float* maa_wa  = (const float*)d_in[3];
    const float* maa_k   = (const float*)d_in[4];
    const float* maa_v   = (const float*)d_in[5];
    const float* maa_w1  = (const float*)d_in[6];
    const float* maa_w2  = (const float*)d_in[7];
    const float* tdecay  = (const float*)d_in[8];
    const float* dw1     = (const float*)d_in[9];
    const float* dw2     = (const float*)d_in[10];
    const float* faaaa   = (const float*)d_in[11];
    const float* taaaaa  = (const float*)d_in[12];
    const float* aw1     = (const float*)d_in[13];
    const float* aw2     = (const float*)d_in[14];
    const float* kw1     = (const float*)d_in[15];
    const float* kw2     = (const float*)d_in[16];
    const float* gw1     = (const float*)d_in[17];
    const float* gw2     = (const float*)d_in[18];
    const float* maw1    = (const float*)d_in[19];
    const float* maw2    = (const float*)d_in[20];
    const float* tmisca  = (const float*)d_in[21];
    const float* mkw1    = (const float*)d_in[22];
    const float* mkw2    = (const float*)d_in[23];
    const float* tmisck  = (const float*)d_in[24];
    const float* wr      = (const float*)d_in[25];
    const float* wk      = (const float*)d_in[26];
    const float* wv      = (const float*)d_in[27];
    const float* wo      = (const float*)d_in[28];
    const float* lnw     = (const float*)d_in[29];
    const float* lnb     = (const float*)d_in[30];
    float* out = (float*)d_out;
    (void)in_sizes; (void)n_in; (void)out_size;

    Scratch* S = nullptr;
    cudaGetSymbolAddress((void**)&S, g_s);
    cudaFuncSetAttribute(gemm_mma, cudaFuncAttributeMaxDynamicSharedMemorySize,
                         MMA_SMEM);

    // 0) transpose gate_w2 (K=128 x N=1024) -> (N,K)
    transpose_kernel<<<dim3(32, 4), 256>>>(gw2, S->gw2T);

    // 1) time-shift + maa_x mix
    ew0_kernel<<<(MM * CC / 4) / 256, 256>>>(x, maa_x);

    // 2) mix_in = tanh(xmix @ maa_w1)
    g32(S->xmix, maa_w1, S->mixin, 128, 1024, 1024, 1);

    // 3) xrg/xwa/xk/xv
    {
        const float* maas[4]  = { maa_rg, maa_wa, maa_k, maa_v };
        float*       xouts[4] = { S->xrg, S->xwa, S->xk, S->xv };
        for (int f = 0; f < 4; f++)
            g128(S->mixin + f * 32, maa_w2 + (size_t)f * 32 * 1024,
                 xouts[f], 1024, 32, 128, 0, 2, x, S->xx, maas[f]);
    }

    // 4) big projections via mma.sync bf16 hi/lo split
    gmma(S->xrg, wr, S->r, 1024);
    gmma(S->xk,  wk, S->k, 1024);
    gmma(S->xv,  wv, S->v, 1024);

    // 5) gate
    g32(S->xrg, gw1, S->gate1, 128, 1024, 1024, 1);
    gmma(S->gate1, S->gw2T, S->g, 128);

    // 6) decay
    g32(S->xwa, dw1, S->dec1, 64, 1024, 1024, 1);
    g128(S->dec1, dw2, S->w, 1024, 64, 64, 0, 4, 0, 0, tdecay);

    // 7) LoRA sigmoids + kkk
    g32(S->xwa, aw1,  S->aaa1, 16, 1024, 1024, 0);
    g128(S->aaa1, aw2, S->asig, 1024, 16, 16, 0, 3, 0, 0, taaaaa);
    g32(S->xwa, maw1, S->ma1,  16, 1024, 1024, 0);
    g128(S->ma1, maw2, S->ma,  1024, 16, 16, 0, 3, 0, 0, tmisca);
    g32(S->xk,  kw1,  S->kkk1, 16, 1024, 1024, 1);
    g128(S->kkk1, kw2, S->kk,  1024, 16, 16, 0, 5, S->k, 0, 0);
    g32(S->xk,  mkw1, S->mk1,  16, 1024, 1024, 0);
    g128(S->mk1, mkw2, S->mk2, 1024, 16, 16, 0, 3, 0, 0, tmisck);

    // 8) combine
    combine_kernel<<<MM, 256>>>();

    // 9) WKV-7 scan
    wkv_kernel<<<BB * HH, 256>>>();

    // 10) GroupNorm + bonus + gate
    post_kernel<<<MM, 256>>>(faaaa, lnw, lnb);

    // 11) output projection via mma.sync
    gmma(S->z, wo, out, 1024);
}

// round 6
// speedup vs baseline: 1.4647x; 1.0106x over previous
#include <cuda_runtime.h>
#include <cuda_bf16.h>
#include <math.h>
#include <stdint.h>
#include <string.h>

#define BB 4
#define TT 1024
#define CC 1024
#define HH 16
#define NN 64
#define MM (BB*TT)   // 4096 rows

typedef __nv_bfloat16 bf16;

// ---------------------------------------------------------------------------
// Scratch (static device memory)
// ---------------------------------------------------------------------------
struct Scratch {
    float xx   [MM*CC];
    float xmix [MM*CC];
    float mixin[MM*128];
    float xrg  [MM*CC];
    float xwa  [MM*CC];
    float xk   [MM*CC];
    float xv   [MM*CC];
    float r    [MM*CC];
    float k    [MM*CC];
    float v    [MM*CC];
    float g    [MM*CC];
    float w    [MM*CC];
    float kk   [MM*CC];
    float asig [MM*CC];
    float ma   [MM*CC];
    float mk2  [MM*CC];
    float kf   [MM*CC];
    float dd   [MM*CC];
    float av   [MM*CC];
    float bv   [MM*CC];
    float y    [MM*CC];
    float gate1[MM*128];
    float dec1 [MM*64];
    float aaa1 [MM*16];
    float ma1  [MM*16];
    float kkk1 [MM*16];
    float mk1  [MM*16];
    // bf16 hi/lo operand arrays
    bf16 xrgh[MM*CC], xrgl[MM*CC];
    bf16 xkh [MM*CC], xkl [MM*CC];
    bf16 xvh [MM*CC], xvl [MM*CC];
    bf16 zh  [MM*CC], zl  [MM*CC];
    bf16 g1h [MM*128], g1l [MM*128];
    bf16 wrh[CC*CC], wrl[CC*CC];
    bf16 wkh[CC*CC], wkl[CC*CC];
    bf16 wvh[CC*CC], wvl[CC*CC];
    bf16 woh[CC*CC], wol[CC*CC];
    bf16 gw2Th[CC*128], gw2Tl[CC*128];
};
__device__ Scratch g_s;

// ---------------------------------------------------------------------------
// Packed f32x2 helpers
// ---------------------------------------------------------------------------
__device__ __forceinline__ unsigned long long dup2(float x) {
    unsigned long long r;
    asm("mov.b64 %0, {%1, %1};" : "=l"(r) : "f"(x));
    return r;
}
__device__ __forceinline__ void fma2(unsigned long long& acc,
                                     unsigned long long a,
                                     unsigned long long b) {
    asm("fma.rn.f32x2 %0, %1, %2, %0;" : "+l"(acc) : "l"(a), "l"(b));
}
__device__ __forceinline__ unsigned long long fma2g(unsigned long long a,
                                                    unsigned long long b,
                                                    unsigned long long c) {
    unsigned long long d;
    asm("fma.rn.f32x2 %0, %1, %2, %3;" : "=l"(d) : "l"(a), "l"(b), "l"(c));
    return d;
}
__device__ __forceinline__ unsigned long long mul2(unsigned long long a,
                                                   unsigned long long b) {
    unsigned long long d;
    asm("mul.rn.f32x2 %0, %1, %2;" : "=l"(d) : "l"(a), "l"(b));
    return d;
}
__device__ __forceinline__ float2 unpack2(unsigned long long v) {
    float2 f;
    asm("mov.b64 {%0, %1}, %2;" : "=f"(f.x), "=f"(f.y) : "l"(v));
    return f;
}
__device__ __forceinline__ uint32_t smem_u32(const void* p) {
    uint32_t a;
    asm("{ .reg .u64 t; cvta.to.shared.u64 t, %1; cvt.u32.u64 %0, t; }"
        : "=r"(a) : "l"(p));
    return a;
}

// hi/lo split of 4 floats -> packed u32 pairs
__device__ __forceinline__ void split4(float4 f, uint2& h, uint2& l) {
    __nv_bfloat162 h01 = __floats2bfloat162_rn(f.x, f.y);
    __nv_bfloat162 h23 = __floats2bfloat162_rn(f.z, f.w);
    float lx = f.x - __bfloat162float(h01.x);
    float ly = f.y - __bfloat162float(h01.y);
    float lz = f.z - __bfloat162float(h23.x);
    float lw = f.w - __bfloat162float(h23.y);
    __nv_bfloat162 l01 = __floats2bfloat162_rn(lx, ly);
    __nv_bfloat162 l23 = __floats2bfloat162_rn(lz, lw);
    memcpy(&h.x, &h01, 4); memcpy(&h.y, &h23, 4);
    memcpy(&l.x, &l01, 4); memcpy(&l.y, &l23, 4);
}

// ---------------------------------------------------------------------------
// mma.sync / ldmatrix helpers
// ---------------------------------------------------------------------------
__device__ __forceinline__ void ldsm4(uint32_t* r, uint32_t addr) {
    asm volatile("ldmatrix.sync.aligned.m8n8.x4.shared.b16 {%0,%1,%2,%3}, [%4];"
        : "=r"(r[0]), "=r"(r[1]), "=r"(r[2]), "=r"(r[3]) : "r"(addr));
}
__device__ __forceinline__ void mma_bf16(float* c, const uint32_t* a,
                                         const uint32_t* b) {
    asm volatile("mma.sync.aligned.m16n8k16.row.col.f32.bf16.bf16.f32 "
        "{%0,%1,%2,%3}, {%4,%5,%6,%7}, {%8,%9}, {%0,%1,%2,%3};"
        : "+f"(c[0]), "+f"(c[1]), "+f"(c[2]), "+f"(c[3])
        : "r"(a[0]), "r"(a[1]), "r"(a[2]), "r"(a[3]), "r"(b[0]), "r"(b[1]));
}

// ---------------------------------------------------------------------------
// gemm_mma2: C[M,1024] = (Ah+Al)[M,K] @ (Bh+Bl)[1024,K]^T, fp32 accum.
// bf16 operands pre-converted in gmem. CTA 128x128, chunk 32, 8 warps,
// double-buffered smem. Tiles 128 rows x 64B (32 bf16), stride 80B.
// Layout/buffer: Ah@0, Al@10240, Bh@20480, Bl@30720; buf stride 40960.
// ---------------------------------------------------------------------------
#define MMA_SMEM 81920

__global__ void __launch_bounds__(256)
gemm_mma2(const bf16* __restrict__ Ah, const bf16* __restrict__ Al,
          const bf16* __restrict__ Bh, const bf16* __restrict__ Bl,
          float* __restrict__ Cm, int K)
{
    extern __shared__ __align__(16) char sm[];
    const uint32_t sb = smem_u32(sm);

    const int tid  = threadIdx.x;
    const int lane = tid & 31;
    const int wid  = tid >> 5;
    const int wm   = wid & 1;
    const int wn   = wid >> 1;
    const int n0 = blockIdx.x * 128;
    const int m0 = blockIdx.y * 128;

    const int row = tid >> 1, half = tid & 1;
    const bf16* pAh = Ah + (size_t)(m0 + row) * K + half * 16;
    const bf16* pAl = Al + (size_t)(m0 + row) * K + half * 16;
    const bf16* pBh = Bh + (size_t)(n0 + row) * K + half * 16;
    const bf16* pBl = Bl + (size_t)(n0 + row) * K + half * 16;
    const uint32_t st = (uint32_t)(row * 80 + half * 32);

    const uint32_t aLoff = (uint32_t)((lane & 15) * 80 + (lane >> 4) * 16);
    const uint32_t bLoff = (uint32_t)(((lane & 7) + ((lane >> 4) & 1) * 8) * 80
                                      + ((lane >> 3) & 1) * 16);

    float c[4][4][4];
#pragma unroll
    for (int i = 0; i < 4; i++)
#pragma unroll
        for (int j = 0; j < 4; j++)
#pragma unroll
            for (int q = 0; q < 4; q++) c[i][j][q] = 0.f;

    const int chunks = K >> 5;

    // preload chunk 0 into buffer 0
    {
        uint4 ah0 = *(const uint4*)pAh, ah1 = *(const uint4*)(pAh + 8);
        uint4 al0 = *(const uint4*)pAl, al1 = *(const uint4*)(pAl + 8);
        uint4 bh0 = *(const uint4*)pBh, bh1 = *(const uint4*)(pBh + 8);
        uint4 bl0 = *(const uint4*)pBl, bl1 = *(const uint4*)(pBl + 8);
        *(uint4*)(sm + 0     + st) = ah0; *(uint4*)(sm + 0     + st + 16) = ah1;
        *(uint4*)(sm + 10240 + st) = al0; *(uint4*)(sm + 10240 + st + 16) = al1;
        *(uint4*)(sm + 20480 + st) = bh0; *(uint4*)(sm + 20480 + st + 16) = bh1;
        *(uint4*)(sm + 30720 + st) = bl0; *(uint4*)(sm + 30720 + st + 16) = bl1;
    }
    __syncthreads();

    for (int cidx = 0; cidx < chunks; cidx++) {
        const uint32_t bufOff = (uint32_t)((cidx & 1) * 40960);
        const bool more = (cidx + 1 < chunks);

        uint4 ah0, ah1, al0, al1, bh0, bh1, bl0, bl1;
        if (more) {
            const int ko = (cidx + 1) * 32;
            ah0 = *(const uint4*)(pAh + ko); ah1 = *(const uint4*)(pAh + ko + 8);
            al0 = *(const uint4*)(pAl + ko); al1 = *(const uint4*)(pAl + ko + 8);
            bh0 = *(const uint4*)(pBh + ko); bh1 = *(const uint4*)(pBh + ko + 8);
            bl0 = *(const uint4*)(pBl + ko); bl1 = *(const uint4*)(pBl + ko + 8);
        }

        const uint32_t aBase = sb + bufOff + (uint32_t)(wm * 64 * 80) + aLoff;
        const uint32_t bBase = sb + bufOff + 20480u + (uint32_t)(wn * 32 * 80) + bLoff;
#pragma unroll
        for (int ks = 0; ks < 2; ks++) {
            uint32_t afh[4][4], afl[4][4];
#pragma unroll
            for (int mi = 0; mi < 4; mi++) {
                ldsm4(afh[mi], aBase + 0u     + (uint32_t)(mi * 1280 + ks * 32));
                ldsm4(afl[mi], aBase + 10240u + (uint32_t)(mi * 1280 + ks * 32));
            }
            uint32_t bfh[2][4], bfl[2][4];
#pragma unroll
            for (int np = 0; np < 2; np++) {
                ldsm4(bfh[np], bBase + 0u     + (uint32_t)(np * 1280 + ks * 32));
                ldsm4(bfl[np], bBase + 10240u + (uint32_t)(np * 1280 + ks * 32));
            }
#pragma unroll
            for (int mi = 0; mi < 4; mi++) {
#pragma unroll
                for (int ni = 0; ni < 4; ni++) {
                    const uint32_t* bh = &bfh[ni >> 1][(ni & 1) * 2];
                    const uint32_t* bl = &bfl[ni >> 1][(ni & 1) * 2];
                    mma_bf16(c[mi][ni], afh[mi], bh);
                    mma_bf16(c[mi][ni], afh[mi], bl);
                    mma_bf16(c[mi][ni], afl[mi], bh);
                }
            }
        }

        if (more) {
            char* nb = sm + ((cidx + 1) & 1) * 40960;
            *(uint4*)(nb + 0     + st) = ah0; *(uint4*)(nb + 0     + st + 16) = ah1;
            *(uint4*)(nb + 10240 + st) = al0; *(uint4*)(nb + 10240 + st + 16) = al1;
            *(uint4*)(nb + 20480 + st) = bh0; *(uint4*)(nb + 20480 + st + 16) = bh1;
            *(uint4*)(nb + 30720 + st) = bl0; *(uint4*)(nb + 30720 + st + 16) = bl1;
        }
        __syncthreads();
    }

    const int erow = m0 + wm * 64 + (lane >> 2);
    const int ecol = n0 + wn * 32 + (lane & 3) * 2;
#pragma unroll
    for (int mi = 0; mi < 4; mi++) {
#pragma unroll
        for (int ni = 0; ni < 4; ni++) {
            size_t base0 = (size_t)(erow + mi * 16)     * 1024 + ecol + ni * 8;
            size_t base1 = (size_t)(erow + mi * 16 + 8) * 1024 + ecol + ni * 8;
            *(float2*)&Cm[base0] = make_float2(c[mi][ni][0], c[mi][ni][1]);
            *(float2*)&Cm[base1] = make_float2(c[mi][ni][2], c[mi][ni][3]);
        }
    }
}

// ---------------------------------------------------------------------------
// conv_bf16: fp32 -> bf16 hi/lo arrays
// ---------------------------------------------------------------------------
__global__ void __launch_bounds__(256)
conv_bf16(const float4* __restrict__ src, uint2* __restrict__ h,
          uint2* __restrict__ l)
{
    int i = blockIdx.x * 256 + threadIdx.x;
    uint2 hh, ll;
    split4(src[i], hh, ll);
    h[i] = hh; l[i] = ll;
}

// ---------------------------------------------------------------------------
// transpose + convert: gw2 (128x1024 fp32) -> gw2T hi/lo (1024x128 bf16)
// ---------------------------------------------------------------------------
__global__ void __launch_bounds__(256)
transconv_kernel(const float* __restrict__ src, bf16* __restrict__ dh,
                 bf16* __restrict__ dl)
{
    __shared__ float tile[32][33];
    int bx = blockIdx.x;   // N/32
    int by = blockIdx.y;   // K/32
    int tx = threadIdx.x & 31, ty = threadIdx.x >> 5;
#pragma unroll
    for (int i = 0; i < 4; i++)
        tile[ty + i * 8][tx] = src[(size_t)(by * 32 + ty + i * 8) * 1024 + bx * 32 + tx];
    __syncthreads();
#pragma unroll
    for (int i = 0; i < 4; i++) {
        float v = tile[tx][ty + i * 8];
        bf16 hv = __float2bfloat16_rn(v);
        bf16 lv = __float2bfloat16_rn(v - __bfloat162float(hv));
        size_t di = (size_t)(bx * 32 + ty + i * 8) * 128 + by * 32 + tx;
        dh[di] = hv; dl[di] = lv;
    }
}

// ---------------------------------------------------------------------------
// fused_mix: for f=0..3 computes out_f = x + xx*(maa_f + mixin[:,f*32:+32]@W2_f)
// one CTA = 128x128 output tile; W2 flat 128x1024. Writes fp32 (all 4) plus
// bf16 hi/lo for f=0 (xrg), f=2 (xk), f=3 (xv).
// smem: As[128k][128m] fp32 @0 (64KB); Bs[128k][128n] @65536 (64KB)
// ---------------------------------------------------------------------------
#define MIX_SMEM 131072

__global__ void __launch_bounds__(256)
fused_mix(const float* __restrict__ x, const float* __restrict__ w2,
          const float* __restrict__ m_rg, const float* __restrict__ m_wa,
          const float* __restrict__ m_k,  const float* __restrict__ m_v)
{
    extern __shared__ __align__(16) char smraw[];
    float* As = (float*)smraw;            // [k][m] flat, stride 128
    float* Bs = (float*)(smraw + 65536);  // [k][n] flat, stride 128

    const int tid = threadIdx.x;
    const int tx = tid & 15;
    const int ty = tid >> 4;
    const int n0 = blockIdx.x * 128;
    const int m0 = blockIdx.y * 128;

    // load mixin tile transposed: As[col][row]
#pragma unroll
    for (int i = 0; i < 16; i++) {
        int u = tid + 256 * i;          // 0..4095
        int rw = u >> 5, c4 = u & 31;
        float4 v = *(const float4*)&g_s.mixin[(size_t)(m0 + rw) * 128 + c4 * 4];
        As[(c4 * 4 + 0) * 128 + rw] = v.x;
        As[(c4 * 4 + 1) * 128 + rw] = v.y;
        As[(c4 * 4 + 2) * 128 + rw] = v.z;
        As[(c4 * 4 + 3) * 128 + rw] = v.w;
    }
    // load W2 tile: Bs[k][n]
#pragma unroll
    for (int i = 0; i < 16; i++) {
        int u = tid + 256 * i;
        int kr = u >> 5, n4 = u & 31;
        *(float4*)&Bs[kr * 128 + n4 * 4] =
            *(const float4*)&w2[(size_t)kr * 1024 + n0 + n4 * 4];
    }
    __syncthreads();

    for (int f = 0; f < 4; f++) {
        unsigned long long acc[8][4];
#pragma unroll
        for (int i = 0; i < 8; i++)
#pragma unroll
            for (int j = 0; j < 4; j++) acc[i][j] = 0ull;

#pragma unroll
        for (int kq2 = 0; kq2 < 32; kq2++) {
            const int kq = f * 32 + kq2;
            float4 a0 = *(const float4*)&As[kq * 128 + ty * 8];
            float4 a1 = *(const float4*)&As[kq * 128 + ty * 8 + 4];
            ulonglong2 bA = *(const ulonglong2*)&Bs[kq * 128 + tx * 8];
            ulonglong2 bB = *(const ulonglong2*)&Bs[kq * 128 + tx * 8 + 4];
#define RF(rI, aval) { unsigned long long dp = dup2(aval); \
            fma2(acc[rI][0], dp, bA.x); fma2(acc[rI][1], dp, bA.y); \
            fma2(acc[rI][2], dp, bB.x); fma2(acc[rI][3], dp, bB.y); }
            RF(0, a0.x) RF(1, a0.y) RF(2, a0.z) RF(3, a0.w)
            RF(4, a1.x) RF(5, a1.y) RF(6, a1.z) RF(7, a1.w)
#undef RF
        }

        float* outf; bf16 *oh, *ol; const float* maa;
        switch (f) {
            case 0: outf = g_s.xrg; oh = g_s.xrgh; ol = g_s.xrgl; maa = m_rg; break;
            case 1: outf = g_s.xwa; oh = 0;        ol = 0;        maa = m_wa; break;
            case 2: outf = g_s.xk;  oh = g_s.xkh;  ol = g_s.xkl;  maa = m_k;  break;
            default:outf = g_s.xv;  oh = g_s.xvh;  ol = g_s.xvl;  maa = m_v;  break;
        }
        const int nc = n0 + tx * 8;
        float4 mv0 = *(const float4*)&maa[nc];
        float4 mv1 = *(const float4*)&maa[nc + 4];
#pragma unroll
        for (int rr = 0; rr < 8; rr++) {
            const int m = m0 + ty * 8 + rr;
            const size_t off = (size_t)m * 1024 + nc;
            float4 xv0 = *(const float4*)&x[off];
            float4 xv1 = *(const float4*)&x[off + 4];
            float4 dx0 = *(const float4*)&g_s.xx[off];
            float4 dx1 = *(const float4*)&g_s.xx[off + 4];
            float vals[8];
            { float2 p = unpack2(acc[rr][0]); vals[0] = p.x; vals[1] = p.y; }
            { float2 p = unpack2(acc[rr][1]); vals[2] = p.x; vals[3] = p.y; }
            { float2 p = unpack2(acc[rr][2]); vals[4] = p.x; vals[5] = p.y; }
            { float2 p = unpack2(acc[rr][3]); vals[6] = p.x; vals[7] = p.y; }
            float4 o0, o1;
            o0.x = xv0.x + dx0.x * (mv0.x + vals[0]);
            o0.y = xv0.y + dx0.y * (mv0.y + vals[1]);
            o0.z = xv0.z + dx0.z * (mv0.z + vals[2]);
            o0.w = xv0.w + dx0.w * (mv0.w + vals[3]);
            o1.x = xv1.x + dx1.x * (mv1.x + vals[4]);
            o1.y = xv1.y + dx1.y * (mv1.y + vals[5]);
            o1.z = xv1.z + dx1.z * (mv1.z + vals[6]);
            o1.w = xv1.w + dx1.w * (mv1.w + vals[7]);
            *(float4*)&outf[off]     = o0;
            *(float4*)&outf[off + 4] = o1;
            if (oh) {
                uint2 h0, l0, h1, l1;
                split4(o0, h0, l0);
                split4(o1, h1, l1);
                *(uint4*)&oh[off] = make_uint4(h0.x, h0.y, h1.x, h1.y);
                *(uint4*)&ol[off] = make_uint4(l0.x, l0.y, l1.x, l1.y);
            }
        }
    }
}

// ---------------------------------------------------------------------------
// gemm128 (fp32, small/medium GEMMs with fused epilogues)
// modes: 0 plain | 3 sigmoid(evec[n]+acc) | 4 -log1p(exp(-(evec[n]+acc)))-0.5
//        5: ex + acc
// ---------------------------------------------------------------------------
__global__ void __launch_bounds__(256, 2)
gemm128(const float* __restrict__ A, const float* __restrict__ Bm,
        float* __restrict__ Cm, int N, int K, int lda, int mode,
        const float* __restrict__ ex, const float* __restrict__ evec)
{
    __shared__ __align__(16) float As[2][16][128];
    __shared__ __align__(16) float Bs[2][16][128];

    const int tid = threadIdx.x;
    const int tx = tid & 15;
    const int ty = tid >> 4;
    const int n0 = blockIdx.x * 128;
    const int m0 = blockIdx.y * 128;

    unsigned long long acc[8][4];
#pragma unroll
    for (int i = 0; i < 8; i++)
#pragma unroll
        for (int j = 0; j < 4; j++) acc[i][j] = 0ull;

    const int arow0 = (tid)       >> 2, akq0 = (tid)       & 3;
    const int arow1 = (tid + 256) >> 2, akq1 = (tid + 256) & 3;
    const int bkrow0 = (tid)       >> 5, bnq0 = (tid)       & 31;
    const int bkrow1 = (tid + 256) >> 5, bnq1 = (tid + 256) & 31;

    {
        float4 a0 = *(const float4*)&A[(size_t)(m0 + arow0) * lda + akq0 * 4];
        float4 a1 = *(const float4*)&A[(size_t)(m0 + arow1) * lda + akq1 * 4];
        As[0][akq0*4+0][arow0] = a0.x; As[0][akq0*4+1][arow0] = a0.y;
        As[0][akq0*4+2][arow0] = a0.z; As[0][akq0*4+3][arow0] = a0.w;
        As[0][akq1*4+0][arow1] = a1.x; As[0][akq1*4+1][arow1] = a1.y;
        As[0][akq1*4+2][arow1] = a1.z; As[0][akq1*4+3][arow1] = a1.w;
        *(float4*)&Bs[0][bkrow0][bnq0*4] =
            *(const float4*)&Bm[(size_t)bkrow0 * N + n0 + bnq0 * 4];
        *(float4*)&Bs[0][bkrow1][bnq1*4] =
            *(const float4*)&Bm[(size_t)bkrow1 * N + n0 + bnq1 * 4];
    }
    __syncthreads();

    const int ntiles = K >> 4;
    for (int it = 0; it < ntiles; it++) {
        const int buf = it & 1;
        const bool more = (it + 1 < ntiles);
        float4 pa0, pa1, pb0, pb1;
        if (more) {
            const int kt = (it + 1) << 4;
            pa0 = *(const float4*)&A[(size_t)(m0 + arow0) * lda + kt + akq0 * 4];
            pa1 = *(const float4*)&A[(size_t)(m0 + arow1) * lda + kt + akq1 * 4];
            pb0 = *(const float4*)&Bm[(size_t)(kt + bkrow0) * N + n0 + bnq0 * 4];
            pb1 = *(const float4*)&Bm[(size_t)(kt + bkrow1) * N + n0 + bnq1 * 4];
        }

#pragma unroll
        for (int kq = 0; kq < 16; kq++) {
            float4 a0 = *(const float4*)&As[buf][kq][ty * 8];
            float4 a1 = *(const float4*)&As[buf][kq][ty * 8 + 4];
            ulonglong2 bA = *(const ulonglong2*)&Bs[buf][kq][tx * 8];
            ulonglong2 bBv = *(const ulonglong2*)&Bs[buf][kq][tx * 8 + 4];
#define RF(rI, aval) { unsigned long long dp = dup2(aval); \
            fma2(acc[rI][0], dp, bA.x); fma2(acc[rI][1], dp, bA.y); \
            fma2(acc[rI][2], dp, bBv.x); fma2(acc[rI][3], dp, bBv.y); }
            RF(0, a0.x) RF(1, a0.y) RF(2, a0.z) RF(3, a0.w)
            RF(4, a1.x) RF(5, a1.y) RF(6, a1.z) RF(7, a1.w)
#undef RF
        }

        if (more) {
            const int nb = buf ^ 1;
            As[nb][akq0*4+0][arow0] = pa0.x; As[nb][akq0*4+1][arow0] = pa0.y;
            As[nb][akq0*4+2][arow0] = pa0.z; As[nb][akq0*4+3][arow0] = pa0.w;
            As[nb][akq1*4+0][arow1] = pa1.x; As[nb][akq1*4+1][arow1] = pa1.y;
            As[nb][akq1*4+2][arow1] = pa1.z; As[nb][akq1*4+3][arow1] = pa1.w;
            *(float4*)&Bs[nb][bkrow0][bnq0*4] = pb0;
            *(float4*)&Bs[nb][bkrow1][bnq1*4] = pb1;
        }
        __syncthreads();
    }

#pragma unroll
    for (int rr = 0; rr < 8; rr++) {
        const int m = m0 + ty * 8 + rr;
        float vals[8];
        { float2 p = unpack2(acc[rr][0]); vals[0] = p.x; vals[1] = p.y; }
        { float2 p = unpack2(acc[rr][1]); vals[2] = p.x; vals[3] = p.y; }
        { float2 p = unpack2(acc[rr][2]); vals[4] = p.x; vals[5] = p.y; }
        { float2 p = unpack2(acc[rr][3]); vals[6] = p.x; vals[7] = p.y; }
#pragma unroll
        for (int q = 0; q < 8; q++) {
            const int nn = n0 + tx * 8 + q;
            float vv = vals[q];
            float res;
            switch (mode) {
                default:
                case 0: res = vv; break;
                case 3: { float zz = evec[nn] + vv;
                          res = 1.f / (1.f + expf(-zz)); } break;
                case 4: { float zz = evec[nn] + vv;
                          res = -log1pf(expf(-zz)) - 0.5f; } break;
                case 5: res = ex[(size_t)m * N + nn] + vv; break;
            }
            vals[q] = res;
        }
        float4 o0 = make_float4(vals[0], vals[1], vals[2], vals[3]);
        float4 o1 = make_float4(vals[4], vals[5], vals[6], vals[7]);
        *(float4*)&Cm[(size_t)m * N + n0 + tx * 8]     = o0;
        *(float4*)&Cm[(size_t)m * N + n0 + tx * 8 + 4] = o1;
    }
}

// ---------------------------------------------------------------------------
// gemm32: tall-skinny up-projections. modes: 0 plain, 1 tanh.
// optional bf16 hi/lo outputs.
// ---------------------------------------------------------------------------
__global__ void __launch_bounds__(256)
gemm32(const float* __restrict__ A, const float* __restrict__ Bm,
       float* __restrict__ Cm, int N, int K, int lda, int mode,
       bf16* __restrict__ oh, bf16* __restrict__ ol)
{
    __shared__ __align__(16) float As[16][32];
    __shared__ __align__(16) float Bs[16][64];

    const int tid = threadIdx.x;
    const int tx = tid & 7;
    const int ty = tid >> 3;
    const int n0 = blockIdx.x * 64;
    const int m0 = blockIdx.y * 32;

    unsigned long long acc[4] = {0ull, 0ull, 0ull, 0ull};

    const int arow = tid >> 2, akq = tid & 3;
    const int bkrow = tid >> 4, bnq = tid & 15;

    for (int kt = 0; kt < K; kt += 16) {
        if (tid < 128) {
            float4 a0 = *(const float4*)&A[(size_t)(m0 + arow) * lda + kt + akq * 4];
            As[akq*4+0][arow] = a0.x; As[akq*4+1][arow] = a0.y;
            As[akq*4+2][arow] = a0.z; As[akq*4+3][arow] = a0.w;
        }
        float4 b0 = make_float4(0.f, 0.f, 0.f, 0.f);
        if (n0 + bnq * 4 < N)
            b0 = *(const float4*)&Bm[(size_t)(kt + bkrow) * N + n0 + bnq * 4];
        *(float4*)&Bs[bkrow][bnq*4] = b0;
        __syncthreads();

#pragma unroll
        for (int kq = 0; kq < 16; kq++) {
            unsigned long long dp = dup2(As[kq][ty]);
            ulonglong2 bA = *(const ulonglong2*)&Bs[kq][tx * 8];
            ulonglong2 bBv = *(const ulonglong2*)&Bs[kq][tx * 8 + 4];
            fma2(acc[0], dp, bA.x); fma2(acc[1], dp, bA.y);
            fma2(acc[2], dp, bBv.x); fma2(acc[3], dp, bBv.y);
        }
        __syncthreads();
    }

    const int m = m0 + ty;
    float vals[8];
    { float2 p = unpack2(acc[0]); vals[0] = p.x; vals[1] = p.y; }
    { float2 p = unpack2(acc[1]); vals[2] = p.x; vals[3] = p.y; }
    { float2 p = unpack2(acc[2]); vals[4] = p.x; vals[5] = p.y; }
    { float2 p = unpack2(acc[3]); vals[6] = p.x; vals[7] = p.y; }
#pragma unroll
    for (int q = 0; q < 8; q++)
        if (mode == 1) vals[q] = tanhf(vals[q]);

    const int nn0 = n0 + tx * 8;
    if (nn0 + 7 < N) {
        *(float4*)&Cm[(size_t)m * N + nn0]     =
            make_float4(vals[0], vals[1], vals[2], vals[3]);
        *(float4*)&Cm[(size_t)m * N + nn0 + 4] =
            make_float4(vals[4], vals[5], vals[6], vals[7]);
        if (oh) {
            float4 o0 = make_float4(vals[0], vals[1], vals[2], vals[3]);
            float4 o1 = make_float4(vals[4], vals[5], vals[6], vals[7]);
            uint2 h0, l0, h1, l1;
            split4(o0, h0, l0); split4(o1, h1, l1);
            *(uint4*)&oh[(size_t)m * N + nn0] = make_uint4(h0.x, h0.y, h1.x, h1.y);
            *(uint4*)&ol[(size_t)m * N + nn0] = make_uint4(l0.x, l0.y, l1.x, l1.y);
        }
    } else {
#pragma unroll
        for (int q = 0; q < 8; q++)
            if (nn0 + q < N) Cm[(size_t)m * N + nn0 + q] = vals[q];
    }
}

// ---------------------------------------------------------------------------
// ew0
// ---------------------------------------------------------------------------
__global__ void __launch_bounds__(256)
ew0_kernel(const float* __restrict__ x, const float* __restrict__ maa_x)
{
    size_t i4  = (size_t)blockIdx.x * 256 + threadIdx.x;
    size_t idx = i4 * 4;
    int c    = (int)(idx & (CC - 1));
    int nrow = (int)(idx >> 10);
    float4 xv = *(const float4*)&x[idx];
    float4 xp = make_float4(0.f, 0.f, 0.f, 0.f);
    if (nrow & (TT - 1))
        xp = *(const float4*)&x[idx - CC];
    float4 mv = *(const float4*)&maa_x[c];
    float4 d, xm;
    d.x = xp.x - xv.x;  xm.x = xv.x + d.x * mv.x;
    d.y = xp.y - xv.y;  xm.y = xv.y + d.y * mv.y;
    d.z = xp.z - xv.z;  xm.z = xv.z + d.z * mv.z;
    d.w = xp.w - xv.w;  xm.w = xv.w + d.w * mv.w;
    *(float4*)&g_s.xx[idx]   = d;
    *(float4*)&g_s.xmix[idx] = xm;
}

// ---------------------------------------------------------------------------
// combine
// ---------------------------------------------------------------------------
__global__ void __launch_bounds__(256)
combine_kernel()
{
    int n   = blockIdx.x;
    int tid = threadIdx.x;
    size_t off = (size_t)n * CC + tid * 4;

    float4 kkv = *(float4*)&g_s.kk[off];
    float ss = kkv.x*kkv.x + kkv.y*kkv.y + kkv.z*kkv.z + kkv.w*kkv.w;
#pragma unroll
    for (int o = 8; o; o >>= 1) ss += __shfl_xor_sync(0xffffffffu, ss, o, 16);
    float inv = 1.f / fmaxf(sqrtf(ss), 1e-12f);

    float4 kq = *(float4*)&g_s.k[off];
    float4 aq = *(float4*)&g_s.asig[off];
    float4 mq = *(float4*)&g_s.ma[off];
    float4 wq = *(float4*)&g_s.w[off];
    float4 mk = *(float4*)&g_s.mk2[off];
    float4 kfv, ddv, avv, bvv;
#define CMB(X) { float fac = mq.X + aq.X * (1.f - mq.X); \
    float ee = expf(fminf(wq.X * mk.X, 0.f)); \
    kfv.X = kq.X * fac * ee; \
    ddv.X = expf(wq.X); \
    float kn = kkv.X * inv; \
    avv.X = -kn; bvv.X = kn * aq.X; }
    CMB(x) CMB(y) CMB(z) CMB(w)
#undef CMB
    *(float4*)&g_s.kf[off] = kfv;
    *(float4*)&g_s.dd[off] = ddv;
    *(float4*)&g_s.av[off] = avv;
    *(float4*)&g_s.bv[off] = bvv;
}

// ---------------------------------------------------------------------------
// WKV-7 scan
// ---------------------------------------------------------------------------
__global__ void __launch_bounds__(256)
wkv_kernel()
{
    const int blk = blockIdx.x;
    const int b = blk >> 4;
    const int h = blk & 15;
    const int tid = threadIdx.x;
    const int i  = tid >> 2;
    const int jq = tid & 3;

    __shared__ __align__(16) float sb[2][6][64];

    const size_t rowbase = ((size_t)b * TT) * CC + h * NN;

    const float4* myp = 0;
    int larr = 0, lq = 0;
    if (tid < 96) {
        larr = tid >> 4; lq = tid & 15;
        const float* srcs[6] = { g_s.r, g_s.dd, g_s.kf, g_s.av, g_s.bv, g_s.v };
        myp = (const float4*)(srcs[larr] + rowbase + lq * 4);
    }
    float4 pf;
    if (tid < 96) {
        pf = myp[0];
        ((float4*)sb[0][larr])[lq] = pf;
    }
    __syncthreads();

    unsigned long long S2[8];
#pragma unroll
    for (int u = 0; u < 8; u++) S2[u] = 0ull;

    float* yout = g_s.y + rowbase + i;

    for (int t = 0; t < TT; t++) {
        const int p = t & 1;
        const bool more = (t + 1 < TT);
        if (tid < 96 && more) pf = myp[(size_t)(t + 1) * (CC / 4)];

        const ulonglong2* a2p = (const ulonglong2*)(sb[p][3] + jq * 16);
        const ulonglong2* d2p = (const ulonglong2*)(sb[p][1] + jq * 16);
        const ulonglong2* k2p = (const ulonglong2*)(sb[p][2] + jq * 16);
        const ulonglong2* b2p = (const ulonglong2*)(sb[p][4] + jq * 16);
        const ulonglong2* r2p = (const ulonglong2*)(sb[p][0] + jq * 16);
        const float vi = sb[p][5][i];

        unsigned long long acc0 = 0ull, acc1 = 0ull;
#pragma unroll
        for (int u = 0; u < 4; u++) {
            ulonglong2 avp = a2p[u];
            fma2(acc0, S2[2*u],   avp.x);
            fma2(acc1, S2[2*u+1], avp.y);
        }
        float2 f0 = unpack2(acc0), f1 = unpack2(acc1);
        float sa = (f0.x + f0.y) + (f1.x + f1.y);
        sa += __shfl_xor_sync(0xffffffffu, sa, 1, 4);
        sa += __shfl_xor_sync(0xffffffffu, sa, 2, 4);

        const unsigned long long sa2 = dup2(sa);
        const unsigned long long v2  = dup2(vi);

        unsigned long long y0 = 0ull, y1 = 0ull;
#pragma unroll
        for (int u = 0; u < 4; u++) {
            ulonglong2 dvp = d2p[u], kvp = k2p[u], bvp = b2p[u], rvp = r2p[u];
            unsigned long long t0 = fma2g(sa2, bvp.x, mul2(v2, kvp.x));
            t0 = fma2g(S2[2*u], dvp.x, t0);
            S2[2*u] = t0;
            fma2(y0, t0, rvp.x);
            unsigned long long t1 = fma2g(sa2, bvp.y, mul2(v2, kvp.y));
            t1 = fma2g(S2[2*u+1], dvp.y, t1);
            S2[2*u+1] = t1;
            fma2(y1, t1, rvp.y);
        }
        float2 g0 = unpack2(y0), g1 = unpack2(y1);
        float yv = (g0.x + g0.y) + (g1.x + g1.y);
        yv += __shfl_xor_sync(0xffffffffu, yv, 1, 4);
        yv += __shfl_xor_sync(0xffffffffu, yv, 2, 4);
        if (jq == 0) yout[(size_t)t * CC] = yv;

        if (tid < 96 && more) ((float4*)sb[p ^ 1][larr])[lq] = pf;
        __syncthreads();
    }
}

// ---------------------------------------------------------------------------
// post: GroupNorm + bonus + gate -> z (bf16 hi/lo)
// ---------------------------------------------------------------------------
__global__ void __launch_bounds__(256)
post_kernel(const float* __restrict__ faaaa,
            const float* __restrict__ lnw, const float* __restrict__ lnb)
{
    int n   = blockIdx.x;
    int tid = threadIdx.x;
    int c   = tid * 4;
    size_t off = (size_t)n * CC + c;

    float4 yv = *(float4*)&g_s.y [off];
    float4 rv = *(float4*)&g_s.r [off];
    float4 kv = *(float4*)&g_s.kf[off];
    float4 vv = *(float4*)&g_s.v [off];
    float4 gv = *(float4*)&g_s.g [off];
    float4 fv = *(const float4*)&faaaa[c];

    float s  = yv.x + yv.y + yv.z + yv.w;
    float s2 = yv.x*yv.x + yv.y*yv.y + yv.z*yv.z + yv.w*yv.w;
    float dk = rv.x*kv.x*fv.x + rv.y*kv.y*fv.y + rv.z*kv.z*fv.z + rv.w*kv.w*fv.w;
#pragma unroll
    for (int o = 8; o; o >>= 1) {
        s  += __shfl_xor_sync(0xffffffffu, s,  o, 16);
        s2 += __shfl_xor_sync(0xffffffffu, s2, o, 16);
        dk += __shfl_xor_sync(0xffffffffu, dk, o, 16);
    }
    float mean = s  * (1.f / 64.f);
    float var  = s2 * (1.f / 64.f) - mean * mean;
    float rs   = rsqrtf(var + 64e-5f);

    float4 lw = *(const float4*)&lnw[c];
    float4 lb = *(const float4*)&lnb[c];
    float4 z;
    z.x = (((yv.x - mean) * rs) * lw.x + lb.x + dk * vv.x) * gv.x;
    z.y = (((yv.y - mean) * rs) * lw.y + lb.y + dk * vv.y) * gv.y;
    z.z = (((yv.z - mean) * rs) * lw.z + lb.z + dk * vv.z) * gv.z;
    z.w = (((yv.w - mean) * rs) * lw.w + lb.w + dk * vv.w) * gv.w;
    uint2 h, l;
    split4(z, h, l);
    *(uint2*)&g_s.zh[off] = h;
    *(uint2*)&g_s.zl[off] = l;
}

// ---------------------------------------------------------------------------
// Host orchestration
// ---------------------------------------------------------------------------
static void g128(const float* A, const float* Bp, float* Cp,
                 int N, int K, int lda, int mode,
                 const float* ex, const float* evec)
{
    dim3 grid(N / 128, MM / 128);
    gemm128<<<grid, 256>>>(A, Bp, Cp, N, K, lda, mode, ex, evec);
}
static void g32(const float* A, const float* Bp, float* Cp,
                int N, int K, int lda, int mode,
                bf16* oh = 0, bf16* ol = 0)
{
    dim3 grid((N + 63) / 64, MM / 32);
    gemm32<<<grid, 256>>>(A, Bp, Cp, N, K, lda, mode, oh, ol);
}
static void gmma(const bf16* Ah, const bf16* Al, const bf16* Bh,
                 const bf16* Bl, float* Cp, int K)
{
    dim3 grid(8, MM / 128);
    gemm_mma2<<<grid, 256, MMA_SMEM>>>(Ah, Al, Bh, Bl, Cp, K);
}
static void convw(const float* src, bf16* h, bf16* l, int elems)
{
    conv_bf16<<<elems / 1024, 256>>>((const float4*)src, (uint2*)h, (uint2*)l);
}

extern "C" void kernel_launch(void* const* d_in, const int* in_sizes, int n_in,
                              void* d_out, int out_size)
{
    const float* x       = (const float*)d_in[0];
    const float* maa_x   = (const float*)d_in[1];
    const float* maa_rg  = (const float*)d_in[2];
    const float* maa_wa  = (const float*)d_in[3];
    const float* maa_k   = (const float*)d_in[4];
    const float* maa_v   = (const float*)d_in[5];
    const float* maa_w1  = (const float*)d_in[6];
    const float* maa_w2  = (const float*)d_in[7];
    const float* tdecay  = (const float*)d_in[8];
    const float* dw1     = (const float*)d_in[9];
    const float* dw2     = (const float*)d_in[10];
    const float* faaaa   = (const float*)d_in[11];
    const float* taaaaa  = (const float*)d_in[12];
    const float* aw1     = (const float*)d_in[13];
    const float* aw2     = (const float*)d_in[14];
    const float* kw1     = (const float*)d_in[15];
    const float* kw2     = (const float*)d_in[16];
    const float* gw1     = (const float*)d_in[17];
    const float* gw2     = (const float*)d_in[18];
    const float* maw1    = (const float*)d_in[19];
    const float* maw2    = (const float*)d_in[20];
    const float* tmisca  = (const float*)d_in[21];
    const float* mkw1    = (const float*)d_in[22];
    const float* mkw2    = (const float*)d_in[23];
    const float* tmisck  = (const float*)d_in[24];
    const float* wr      = (const float*)d_in[25];
    const float* wk      = (const float*)d_in[26];
    const float* wv      = (const float*)d_in[27];
    const float* wo      = (const float*)d_in[28];
    const float* lnw     = (const float*)d_in[29];
    const float* lnb     = (const float*)d_in[30];
    float* out = (float*)d_out;
    (void)in_sizes; (void)n_in; (void)out_size;

    Scratch* S = nullptr;
    cudaGetSymbolAddress((void**)&S, g_s);
    cudaFuncSetAttribute(gemm_mma2, cudaFuncAttributeMaxDynamicSharedMemorySize,
                         MMA_SMEM);
    cudaFuncSetAttribute(fused_mix, cudaFuncAttributeMaxDynamicSharedMemorySize,
                         MIX_SMEM);

    // 1) time-shift + maa_x mix
    ew0_kernel<<<(MM * CC / 4) / 256, 256>>>(x, maa_x);
    // 2) mix_in = tanh(xmix @ maa_w1)
    g32(S->xmix, maa_w1, S->mixin, 128, 1024, 1024, 1);
    // 3) fused xrg/xwa/xk/xv (+ bf16 hi/lo for rg,k,v)
    fused_mix<<<dim3(8, 32), 256, MIX_SMEM>>>(x, maa_w2,
        maa_rg, maa_wa, maa_k, maa_v);
    // 4-5) weight converts
    convw(wr, S->wrh, S->wrl, CC * CC);
    convw(wk, S->wkh, S->wkl, CC * CC);
    // 6) r projection  (sampled by ncu)
    gmma(S->xrgh, S->xrgl, S->wrh, S->wrl, S->r, 1024);
    // 7-9)
    convw(wv, S->wvh, S->wvl, CC * CC);
    gmma(S->xkh, S->xkl, S->wkh, S->wkl, S->k, 1024);
    gmma(S->xvh, S->xvl, S->wvh, S->wvl, S->v, 1024);
    // 10-12) gate
    g32(S->xrg, gw1, S->gate1, 128, 1024, 1024, 1, S->g1h, S->g1l);
    transconv_kernel<<<dim3(32, 4), 256>>>(gw2, S->gw2Th, S->gw2Tl);
    gmma(S->g1h, S->g1l, S->gw2Th, S->gw2Tl, S->g, 128);
    // 13-14) decay
    g32(S->xwa, dw1, S->dec1, 64, 1024, 1024, 1);
    g128(S->dec1, dw2, S->w, 1024, 64, 64, 4, 0, tdecay);
    // 15-22) LoRA paths
    g32(S->xwa, aw1,  S->aaa1, 16, 1024, 1024, 0);
    g128(S->aaa1, aw2, S->asig, 1024, 16, 16, 3, 0, taaaaa);
    g32(S->xwa, maw1, S->ma1,  16, 1024, 1024, 0);
    g128(S->ma1, maw2, S->ma,  1024, 16, 16, 3, 0, tmisca);
    g32(S->xk,  kw1,  S->kkk1, 16, 1024, 1024, 1);
    g128(S->kkk1, kw2, S->kk,  1024, 16, 16, 5, S->k, 0);
    g32(S->xk,  mkw1, S->mk1,  16, 1024, 1024, 0);
    g128(S->mk1, mkw2, S->mk2, 1024, 16, 16, 3, 0, tmisck);
    // 23) combine
    combine_kernel<<<MM, 256>>>();
    // 24) WKV-7 scan
    wkv_kernel<<<BB * HH, 256>>>();
    // 25) GroupNorm + bonus + gate -> z bf16
    post_kernel<<<MM, 256>>>(faaaa, lnw, lnb);
    // 26-27) output projection
    convw(wo, S->woh, S->wol, CC * CC);
    gmma(S->zh, S->zl, S->woh, S->wol, out, 1024);
}

// round 7
// speedup vs baseline: 1.7794x; 1.2148x over previous
#include <cuda_runtime.h>
#include <cuda_bf16.h>
#include <math.h>
#include <stdint.h>
#include <string.h>

#define BB 4
#define TT 1024
#define CC 1024
#define HH 16
#define NN 64
#define MM (BB*TT)   // 4096 rows

typedef __nv_bfloat16 bf16;

// ---------------------------------------------------------------------------
// Scratch (static device memory)
// ---------------------------------------------------------------------------
struct Scratch {
    float xx   [MM*CC];
    float xmix [MM*CC];
    float mixin[MM*128];
    float xrg  [MM*CC];
    float xwa  [MM*CC];
    float xk   [MM*CC];
    float xv   [MM*CC];
    float r    [MM*CC];
    float k    [MM*CC];
    float v    [MM*CC];
    float g    [MM*CC];
    float w    [MM*CC];
    float kk   [MM*CC];
    float asig [MM*CC];
    float ma   [MM*CC];
    float mk2  [MM*CC];
    float kf   [MM*CC];
    float dd   [MM*CC];
    float av   [MM*CC];
    float bv   [MM*CC];
    float y    [MM*CC];
    float gate1[MM*128];
    float lora_wa[MM*96];
    float lora_k [MM*32];
    float bp_wa[1024*96];
    float bp_k [1024*32];
    // bf16 hi/lo operand arrays
    bf16 xrgh[MM*CC], xrgl[MM*CC];
    bf16 xkh [MM*CC], xkl [MM*CC];
    bf16 xvh [MM*CC], xvl [MM*CC];
    bf16 zh  [MM*CC], zl  [MM*CC];
    bf16 g1h [MM*128], g1l [MM*128];
    bf16 wrh[CC*CC], wrl[CC*CC];
    bf16 wkh[CC*CC], wkl[CC*CC];
    bf16 wvh[CC*CC], wvl[CC*CC];
    bf16 woh[CC*CC], wol[CC*CC];
    bf16 gw2Th[CC*128], gw2Tl[CC*128];
};
__device__ Scratch g_s;

// ---------------------------------------------------------------------------
// Packed f32x2 helpers
// ---------------------------------------------------------------------------
__device__ __forceinline__ unsigned long long dup2(float x) {
    unsigned long long r;
    asm("mov.b64 %0, {%1, %1};" : "=l"(r) : "f"(x));
    return r;
}
__device__ __forceinline__ void fma2(unsigned long long& acc,
                                     unsigned long long a,
                                     unsigned long long b) {
    asm("fma.rn.f32x2 %0, %1, %2, %0;" : "+l"(acc) : "l"(a), "l"(b));
}
__device__ __forceinline__ unsigned long long fma2g(unsigned long long a,
                                                    unsigned long long b,
                                                    unsigned long long c) {
    unsigned long long d;
    asm("fma.rn.f32x2 %0, %1, %2, %3;" : "=l"(d) : "l"(a), "l"(b), "l"(c));
    return d;
}
__device__ __forceinline__ unsigned long long mul2(unsigned long long a,
                                                   unsigned long long b) {
    unsigned long long d;
    asm("mul.rn.f32x2 %0, %1, %2;" : "=l"(d) : "l"(a), "l"(b));
    return d;
}
__device__ __forceinline__ float2 unpack2(unsigned long long v) {
    float2 f;
    asm("mov.b64 {%0, %1}, %2;" : "=f"(f.x), "=f"(f.y) : "l"(v));
    return f;
}
__device__ __forceinline__ float hadd4(unsigned long long a,
                                       unsigned long long b) {
    float2 f = unpack2(a), g = unpack2(b);
    return (f.x + f.y) + (g.x + g.y);
}
__device__ __forceinline__ uint32_t smem_u32(const void* p) {
    uint32_t a;
    asm("{ .reg .u64 t; cvta.to.shared.u64 t, %1; cvt.u32.u64 %0, t; }"
        : "=r"(a) : "l"(p));
    return a;
}

// cp.async helpers (sm_80 baseline)
__device__ __forceinline__ void cp_async16(uint32_t saddr, const void* gptr) {
    asm volatile("cp.async.cg.shared.global [%0], [%1], 16;"
        :: "r"(saddr), "l"(gptr) : "memory");
}
#define CP_COMMIT() asm volatile("cp.async.commit_group;" ::: "memory")
#define CP_WAIT2()  asm volatile("cp.async.wait_group 2;" ::: "memory")

// hi/lo split of 4 floats -> packed u32 pairs
__device__ __forceinline__ void split4(float4 f, uint2& h, uint2& l) {
    __nv_bfloat162 h01 = __floats2bfloat162_rn(f.x, f.y);
    __nv_bfloat162 h23 = __floats2bfloat162_rn(f.z, f.w);
    float lx = f.x - __bfloat162float(h01.x);
    float ly = f.y - __bfloat162float(h01.y);
    float lz = f.z - __bfloat162float(h23.x);
    float lw = f.w - __bfloat162float(h23.y);
    __nv_bfloat162 l01 = __floats2bfloat162_rn(lx, ly);
    __nv_bfloat162 l23 = __floats2bfloat162_rn(lz, lw);
    memcpy(&h.x, &h01, 4); memcpy(&h.y, &h23, 4);
    memcpy(&l.x, &l01, 4); memcpy(&l.y, &l23, 4);
}

// ---------------------------------------------------------------------------
// mma.sync / ldmatrix helpers
// ---------------------------------------------------------------------------
__device__ __forceinline__ void ldsm4(uint32_t* r, uint32_t addr) {
    asm volatile("ldmatrix.sync.aligned.m8n8.x4.shared.b16 {%0,%1,%2,%3}, [%4];"
        : "=r"(r[0]), "=r"(r[1]), "=r"(r[2]), "=r"(r[3]) : "r"(addr));
}
__device__ __forceinline__ void mma_bf16(float* c, const uint32_t* a,
                                         const uint32_t* b) {
    asm volatile("mma.sync.aligned.m16n8k16.row.col.f32.bf16.bf16.f32 "
        "{%0,%1,%2,%3}, {%4,%5,%6,%7}, {%8,%9}, {%0,%1,%2,%3};"
        : "+f"(c[0]), "+f"(c[1]), "+f"(c[2]), "+f"(c[3])
        : "r"(a[0]), "r"(a[1]), "r"(a[2]), "r"(a[3]), "r"(b[0]), "r"(b[1]));
}

// ---------------------------------------------------------------------------
// gemm_mma2: C[M,1024] = (Ah+Al)[M,K] @ (Bh+Bl)[1024,K]^T, fp32 accum.
// ---------------------------------------------------------------------------
#define MMA_SMEM 81920

__global__ void __launch_bounds__(256)
gemm_mma2(const bf16* __restrict__ Ah, const bf16* __restrict__ Al,
          const bf16* __restrict__ Bh, const bf16* __restrict__ Bl,
          float* __restrict__ Cm, int K)
{
    extern __shared__ __align__(16) char sm[];
    const uint32_t sb = smem_u32(sm);

    const int tid  = threadIdx.x;
    const int lane = tid & 31;
    const int wid  = tid >> 5;
    const int wm   = wid & 1;
    const int wn   = wid >> 1;
    const int n0 = blockIdx.x * 128;
    const int m0 = blockIdx.y * 128;

    const int row = tid >> 1, half = tid & 1;
    const bf16* pAh = Ah + (size_t)(m0 + row) * K + half * 16;
    const bf16* pAl = Al + (size_t)(m0 + row) * K + half * 16;
    const bf16* pBh = Bh + (size_t)(n0 + row) * K + half * 16;
    const bf16* pBl = Bl + (size_t)(n0 + row) * K + half * 16;
    const uint32_t st = (uint32_t)(row * 80 + half * 32);

    const uint32_t aLoff = (uint32_t)((lane & 15) * 80 + (lane >> 4) * 16);
    const uint32_t bLoff = (uint32_t)(((lane & 7) + ((lane >> 4) & 1) * 8) * 80
                                      + ((lane >> 3) & 1) * 16);

    float c[4][4][4];
#pragma unroll
    for (int i = 0; i < 4; i++)
#pragma unroll
        for (int j = 0; j < 4; j++)
#pragma unroll
            for (int q = 0; q < 4; q++) c[i][j][q] = 0.f;

    const int chunks = K >> 5;

    {
        uint4 ah0 = *(const uint4*)pAh, ah1 = *(const uint4*)(pAh + 8);
        uint4 al0 = *(const uint4*)pAl, al1 = *(const uint4*)(pAl + 8);
        uint4 bh0 = *(const uint4*)pBh, bh1 = *(const uint4*)(pBh + 8);
        uint4 bl0 = *(const uint4*)pBl, bl1 = *(const uint4*)(pBl + 8);
        *(uint4*)(sm + 0     + st) = ah0; *(uint4*)(sm + 0     + st + 16) = ah1;
        *(uint4*)(sm + 10240 + st) = al0; *(uint4*)(sm + 10240 + st + 16) = al1;
        *(uint4*)(sm + 20480 + st) = bh0; *(uint4*)(sm + 20480 + st + 16) = bh1;
        *(uint4*)(sm + 30720 + st) = bl0; *(uint4*)(sm + 30720 + st + 16) = bl1;
    }
    __syncthreads();

    for (int cidx = 0; cidx < chunks; cidx++) {
        const uint32_t bufOff = (uint32_t)((cidx & 1) * 40960);
        const bool more = (cidx + 1 < chunks);

        uint4 ah0, ah1, al0, al1, bh0, bh1, bl0, bl1;
        if (more) {
            const int ko = (cidx + 1) * 32;
            ah0 = *(const uint4*)(pAh + ko); ah1 = *(const uint4*)(pAh + ko + 8);
            al0 = *(const uint4*)(pAl + ko); al1 = *(const uint4*)(pAl + ko + 8);
            bh0 = *(const uint4*)(pBh + ko); bh1 = *(const uint4*)(pBh + ko + 8);
            bl0 = *(const uint4*)(pBl + ko); bl1 = *(const uint4*)(pBl + ko + 8);
        }

        const uint32_t aBase = sb + bufOff + (uint32_t)(wm * 64 * 80) + aLoff;
        const uint32_t bBase = sb + bufOff + 20480u + (uint32_t)(wn * 32 * 80) + bLoff;
#pragma unroll
        for (int ks = 0; ks < 2; ks++) {
            uint32_t afh[4][4], afl[4][4];
#pragma unroll
            for (int mi = 0; mi < 4; mi++) {
                ldsm4(afh[mi], aBase + 0u     + (uint32_t)(mi * 1280 + ks * 32));
                ldsm4(afl[mi], aBase + 10240u + (uint32_t)(mi * 1280 + ks * 32));
            }
            uint32_t bfh[2][4], bfl[2][4];
#pragma unroll
            for (int np = 0; np < 2; np++) {
                ldsm4(bfh[np], bBase + 0u     + (uint32_t)(np * 1280 + ks * 32));
                ldsm4(bfl[np], bBase + 10240u + (uint32_t)(np * 1280 + ks * 32));
            }
#pragma unroll
            for (int mi = 0; mi < 4; mi++) {
#pragma unroll
                for (int ni = 0; ni < 4; ni++) {
                    const uint32_t* bh = &bfh[ni >> 1][(ni & 1) * 2];
                    const uint32_t* bl = &bfl[ni >> 1][(ni & 1) * 2];
                    mma_bf16(c[mi][ni], afh[mi], bh);
                    mma_bf16(c[mi][ni], afh[mi], bl);
                    mma_bf16(c[mi][ni], afl[mi], bh);
                }
            }
        }

        if (more) {
            char* nb = sm + ((cidx + 1) & 1) * 40960;
            *(uint4*)(nb + 0     + st) = ah0; *(uint4*)(nb + 0     + st + 16) = ah1;
            *(uint4*)(nb + 10240 + st) = al0; *(uint4*)(nb + 10240 + st + 16) = al1;
            *(uint4*)(nb + 20480 + st) = bh0; *(uint4*)(nb + 20480 + st + 16) = bh1;
            *(uint4*)(nb + 30720 + st) = bl0; *(uint4*)(nb + 30720 + st + 16) = bl1;
        }
        __syncthreads();
    }

    const int erow = m0 + wm * 64 + (lane >> 2);
    const int ecol = n0 + wn * 32 + (lane & 3) * 2;
#pragma unroll
    for (int mi = 0; mi < 4; mi++) {
#pragma unroll
        for (int ni = 0; ni < 4; ni++) {
            size_t base0 = (size_t)(erow + mi * 16)     * 1024 + ecol + ni * 8;
            size_t base1 = (size_t)(erow + mi * 16 + 8) * 1024 + ecol + ni * 8;
            *(float2*)&Cm[base0] = make_float2(c[mi][ni][0], c[mi][ni][1]);
            *(float2*)&Cm[base1] = make_float2(c[mi][ni][2], c[mi][ni][3]);
        }
    }
}

// ---------------------------------------------------------------------------
// conv_bf16: fp32 -> bf16 hi/lo arrays
// ---------------------------------------------------------------------------
__global__ void __launch_bounds__(256)
conv_bf16(const float4* __restrict__ src, uint2* __restrict__ h,
          uint2* __restrict__ l)
{
    int i = blockIdx.x * 256 + threadIdx.x;
    uint2 hh, ll;
    split4(src[i], hh, ll);
    h[i] = hh; l[i] = ll;
}

// ---------------------------------------------------------------------------
// transpose + convert: gw2 (128x1024 fp32) -> gw2T hi/lo (1024x128 bf16)
// ---------------------------------------------------------------------------
__global__ void __launch_bounds__(256)
transconv_kernel(const float* __restrict__ src, bf16* __restrict__ dh,
                 bf16* __restrict__ dl)
{
    __shared__ float tile[32][33];
    int bx = blockIdx.x;
    int by = blockIdx.y;
    int tx = threadIdx.x & 31, ty = threadIdx.x >> 5;
#pragma unroll
    for (int i = 0; i < 4; i++)
        tile[ty + i * 8][tx] = src[(size_t)(by * 32 + ty + i * 8) * 1024 + bx * 32 + tx];
    __syncthreads();
#pragma unroll
    for (int i = 0; i < 4; i++) {
        float v = tile[tx][ty + i * 8];
        bf16 hv = __float2bfloat16_rn(v);
        bf16 lv = __float2bfloat16_rn(v - __bfloat162float(hv));
        size_t di = (size_t)(bx * 32 + ty + i * 8) * 128 + by * 32 + tx;
        dh[di] = hv; dl[di] = lv;
    }
}

// ---------------------------------------------------------------------------
// packB kernels: pack LoRA up-proj weights into contiguous (K x Npacked)
// ---------------------------------------------------------------------------
__global__ void __launch_bounds__(256)
packB_wa(const float* __restrict__ dw1, const float* __restrict__ aw1,
         const float* __restrict__ maw1)
{
    int idx = blockIdx.x * 256 + threadIdx.x;     // 1024*96
    int r = idx / 96, c = idx - r * 96;
    float v;
    if (c < 64)      v = dw1[r * 64 + c];
    else if (c < 80) v = aw1[r * 16 + (c - 64)];
    else             v = maw1[r * 16 + (c - 80)];
    g_s.bp_wa[idx] = v;
}
__global__ void __launch_bounds__(256)
packB_k(const float* __restrict__ kw1, const float* __restrict__ mkw1)
{
    int idx = blockIdx.x * 256 + threadIdx.x;     // 1024*32
    int r = idx >> 5, c = idx & 31;
    g_s.bp_k[idx] = (c < 16) ? kw1[r * 16 + c] : mkw1[r * 16 + (c - 16)];
}

// ---------------------------------------------------------------------------
// fused_mix
// ---------------------------------------------------------------------------
#define MIX_SMEM 131072

__global__ void __launch_bounds__(256)
fused_mix(const float* __restrict__ x, const float* __restrict__ w2,
          const float* __restrict__ m_rg, const float* __restrict__ m_wa,
          const float* __restrict__ m_k,  const float* __restrict__ m_v)
{
    extern __shared__ __align__(16) char smraw[];
    float* As = (float*)smraw;
    float* Bs = (float*)(smraw + 65536);

    const int tid = threadIdx.x;
    const int tx = tid & 15;
    const int ty = tid >> 4;
    const int n0 = blockIdx.x * 128;
    const int m0 = blockIdx.y * 128;

#pragma unroll
    for (int i = 0; i < 16; i++) {
        int u = tid + 256 * i;
        int rw = u >> 5, c4 = u & 31;
        float4 v = *(const float4*)&g_s.mixin[(size_t)(m0 + rw) * 128 + c4 * 4];
        As[(c4 * 4 + 0) * 128 + rw] = v.x;
        As[(c4 * 4 + 1) * 128 + rw] = v.y;
        As[(c4 * 4 + 2) * 128 + rw] = v.z;
        As[(c4 * 4 + 3) * 128 + rw] = v.w;
    }
#pragma unroll
    for (int i = 0; i < 16; i++) {
        int u = tid + 256 * i;
        int kr = u >> 5, n4 = u & 31;
        *(float4*)&Bs[kr * 128 + n4 * 4] =
            *(const float4*)&w2[(size_t)kr * 1024 + n0 + n4 * 4];
    }
    __syncthreads();

    for (int f = 0; f < 4; f++) {
        unsigned long long acc[8][4];
#pragma unroll
        for (int i = 0; i < 8; i++)
#pragma unroll
            for (int j = 0; j < 4; j++) acc[i][j] = 0ull;

#pragma unroll
        for (int kq2 = 0; kq2 < 32; kq2++) {
            const int kq = f * 32 + kq2;
            float4 a0 = *(const float4*)&As[kq * 128 + ty * 8];
            float4 a1 = *(const float4*)&As[kq * 128 + ty * 8 + 4];
            ulonglong2 bA = *(const ulonglong2*)&Bs[kq * 128 + tx * 8];
            ulonglong2 bB = *(const ulonglong2*)&Bs[kq * 128 + tx * 8 + 4];
#define RF(rI, aval) { unsigned long long dp = dup2(aval); \
            fma2(acc[rI][0], dp, bA.x); fma2(acc[rI][1], dp, bA.y); \
            fma2(acc[rI][2], dp, bB.x); fma2(acc[rI][3], dp, bB.y); }
            RF(0, a0.x) RF(1, a0.y) RF(2, a0.z) RF(3, a0.w)
            RF(4, a1.x) RF(5, a1.y) RF(6, a1.z) RF(7, a1.w)
#undef RF
        }

        float* outf; bf16 *oh, *ol; const float* maa;
        switch (f) {
            case 0: outf = g_s.xrg; oh = g_s.xrgh; ol = g_s.xrgl; maa = m_rg; break;
            case 1: outf = g_s.xwa; oh = 0;        ol = 0;        maa = m_wa; break;
            case 2: outf = g_s.xk;  oh = g_s.xkh;  ol = g_s.xkl;  maa = m_k;  break;
            default:outf = g_s.xv;  oh = g_s.xvh;  ol = g_s.xvl;  maa = m_v;  break;
        }
        const int nc = n0 + tx * 8;
        float4 mv0 = *(const float4*)&maa[nc];
        float4 mv1 = *(const float4*)&maa[nc + 4];
#pragma unroll
        for (int rr = 0; rr < 8; rr++) {
            const int m = m0 + ty * 8 + rr;
            const size_t off = (size_t)m * 1024 + nc;
            float4 xv0 = *(const float4*)&x[off];
            float4 xv1 = *(const float4*)&x[off + 4];
            float4 dx0 = *(const float4*)&g_s.xx[off];
            float4 dx1 = *(const float4*)&g_s.xx[off + 4];
            float vals[8];
            { float2 p = unpack2(acc[rr][0]); vals[0] = p.x; vals[1] = p.y; }
            { float2 p = unpack2(acc[rr][1]); vals[2] = p.x; vals[3] = p.y; }
            { float2 p = unpack2(acc[rr][2]); vals[4] = p.x; vals[5] = p.y; }
            { float2 p = unpack2(acc[rr][3]); vals[6] = p.x; vals[7] = p.y; }
            float4 o0, o1;
            o0.x = xv0.x + dx0.x * (mv0.x + vals[0]);
            o0.y = xv0.y + dx0.y * (mv0.y + vals[1]);
            o0.z = xv0.z + dx0.z * (mv0.z + vals[2]);
            o0.w = xv0.w + dx0.w * (mv0.w + vals[3]);
            o1.x = xv1.x + dx1.x * (mv1.x + vals[4]);
            o1.y = xv1.y + dx1.y * (mv1.y + vals[5]);
            o1.z = xv1.z + dx1.z * (mv1.z + vals[6]);
            o1.w = xv1.w + dx1.w * (mv1.w + vals[7]);
            *(float4*)&outf[off]     = o0;
            *(float4*)&outf[off + 4] = o1;
            if (oh) {
                uint2 h0, l0, h1, l1;
                split4(o0, h0, l0);
                split4(o1, h1, l1);
                *(uint4*)&oh[off] = make_uint4(h0.x, h0.y, h1.x, h1.y);
                *(uint4*)&ol[off] = make_uint4(l0.x, l0.y, l1.x, l1.y);
            }
        }
    }
}

// ---------------------------------------------------------------------------
// gemm128 (fp32, small-K GEMMs with fused epilogues)
// modes: 0 plain | 3 sigmoid(evec[n]+acc) | 4 -log1p(exp(-(evec[n]+acc)))-0.5
//        5: ex + acc
// ---------------------------------------------------------------------------
__global__ void __launch_bounds__(256, 2)
gemm128(const float* __restrict__ A, const float* __restrict__ Bm,
        float* __restrict__ Cm, int N, int K, int lda, int mode,
        const float* __restrict__ ex, const float* __restrict__ evec)
{
    __shared__ __align__(16) float As[2][16][128];
    __shared__ __align__(16) float Bs[2][16][128];

    const int tid = threadIdx.x;
    const int tx = tid & 15;
    const int ty = tid >> 4;
    const int n0 = blockIdx.x * 128;
    const int m0 = blockIdx.y * 128;

    unsigned long long acc[8][4];
#pragma unroll
    for (int i = 0; i < 8; i++)
#pragma unroll
        for (int j = 0; j < 4; j++) acc[i][j] = 0ull;

    const int arow0 = (tid)       >> 2, akq0 = (tid)       & 3;
    const int arow1 = (tid + 256) >> 2, akq1 = (tid + 256) & 3;
    const int bkrow0 = (tid)       >> 5, bnq0 = (tid)       & 31;
    const int bkrow1 = (tid + 256) >> 5, bnq1 = (tid + 256) & 31;

    {
        float4 a0 = *(const float4*)&A[(size_t)(m0 + arow0) * lda + akq0 * 4];
        float4 a1 = *(const float4*)&A[(size_t)(m0 + arow1) * lda + akq1 * 4];
        As[0][akq0*4+0][arow0] = a0.x; As[0][akq0*4+1][arow0] = a0.y;
        As[0][akq0*4+2][arow0] = a0.z; As[0][akq0*4+3][arow0] = a0.w;
        As[0][akq1*4+0][arow1] = a1.x; As[0][akq1*4+1][arow1] = a1.y;
        As[0][akq1*4+2][arow1] = a1.z; As[0][akq1*4+3][arow1] = a1.w;
        *(float4*)&Bs[0][bkrow0][bnq0*4] =
            *(const float4*)&Bm[(size_t)bkrow0 * N + n0 + bnq0 * 4];
        *(float4*)&Bs[0][bkrow1][bnq1*4] =
            *(const float4*)&Bm[(size_t)bkrow1 * N + n0 + bnq1 * 4];
    }
    __syncthreads();

    const int ntiles = K >> 4;
    for (int it = 0; it < ntiles; it++) {
        const int buf = it & 1;
        const bool more = (it + 1 < ntiles);
        float4 pa0, pa1, pb0, pb1;
        if (more) {
            const int kt = (it + 1) << 4;
            pa0 = *(const float4*)&A[(size_t)(m0 + arow0) * lda + kt + akq0 * 4];
            pa1 = *(const float4*)&A[(size_t)(m0 + arow1) * lda + kt + akq1 * 4];
            pb0 = *(const float4*)&Bm[(size_t)(kt + bkrow0) * N + n0 + bnq0 * 4];
            pb1 = *(const float4*)&Bm[(size_t)(kt + bkrow1) * N + n0 + bnq1 * 4];
        }

#pragma unroll
        for (int kq = 0; kq < 16; kq++) {
            float4 a0 = *(const float4*)&As[buf][kq][ty * 8];
            float4 a1 = *(const float4*)&As[buf][kq][ty * 8 + 4];
            ulonglong2 bA = *(const ulonglong2*)&Bs[buf][kq][tx * 8];
            ulonglong2 bBv = *(const ulonglong2*)&Bs[buf][kq][tx * 8 + 4];
#define RF(rI, aval) { unsigned long long dp = dup2(aval); \
            fma2(acc[rI][0], dp, bA.x); fma2(acc[rI][1], dp, bA.y); \
            fma2(acc[rI][2], dp, bBv.x); fma2(acc[rI][3], dp, bBv.y); }
            RF(0, a0.x) RF(1, a0.y) RF(2, a0.z) RF(3, a0.w)
            RF(4, a1.x) RF(5, a1.y) RF(6, a1.z) RF(7, a1.w)
#undef RF
        }

        if (more) {
            const int nb = buf ^ 1;
            As[nb][akq0*4+0][arow0] = pa0.x; As[nb][akq0*4+1][arow0] = pa0.y;
            As[nb][akq0*4+2][arow0] = pa0.z; As[nb][akq0*4+3][arow0] = pa0.w;
            As[nb][akq1*4+0][arow1] = pa1.x; As[nb][akq1*4+1][arow1] = pa1.y;
            As[nb][akq1*4+2][arow1] = pa1.z; As[nb][akq1*4+3][arow1] = pa1.w;
            *(float4*)&Bs[nb][bkrow0][bnq0*4] = pb0;
            *(float4*)&Bs[nb][bkrow1][bnq1*4] = pb1;
        }
        __syncthreads();
    }

#pragma unroll
    for (int rr = 0; rr < 8; rr++) {
        const int m = m0 + ty * 8 + rr;
        float vals[8];
        { float2 p = unpack2(acc[rr][0]); vals[0] = p.x; vals[1] = p.y; }
        { float2 p = unpack2(acc[rr][1]); vals[2] = p.x; vals[3] = p.y; }
        { float2 p = unpack2(acc[rr][2]); vals[4] = p.x; vals[5] = p.y; }
        { float2 p = unpack2(acc[rr][3]); vals[6] = p.x; vals[7] = p.y; }
#pragma unroll
        for (int q = 0; q < 8; q++) {
            const int nn = n0 + tx * 8 + q;
            float vv = vals[q];
            float res;
            switch (mode) {
                default:
                case 0: res = vv; break;
                case 3: { float zz = evec[nn] + vv;
                          res = 1.f / (1.f + expf(-zz)); } break;
                case 4: { float zz = evec[nn] + vv;
                          res = -log1pf(expf(-zz)) - 0.5f; } break;
                case 5: res = ex[(size_t)m * N + nn] + vv; break;
            }
            vals[q] = res;
        }
        float4 o0 = make_float4(vals[0], vals[1], vals[2], vals[3]);
        float4 o1 = make_float4(vals[4], vals[5], vals[6], vals[7]);
        *(float4*)&Cm[(size_t)m * N + n0 + tx * 8]     = o0;
        *(float4*)&Cm[(size_t)m * N + n0 + tx * 8 + 4] = o1;
    }
}

// ---------------------------------------------------------------------------
// gemm32: tall-skinny up-projections. tanh applied to cols < tanhN.
// optional bf16 hi/lo outputs.
// ---------------------------------------------------------------------------
__global__ void __launch_bounds__(256)
gemm32(const float* __restrict__ A, const float* __restrict__ Bm,
       float* __restrict__ Cm, int N, int K, int lda, int tanhN,
       bf16* __restrict__ oh, bf16* __restrict__ ol)
{
    __shared__ __align__(16) float As[16][32];
    __shared__ __align__(16) float Bs[16][64];

    const int tid = threadIdx.x;
    const int tx = tid & 7;
    const int ty = tid >> 3;
    const int n0 = blockIdx.x * 64;
    const int m0 = blockIdx.y * 32;

    unsigned long long acc[4] = {0ull, 0ull, 0ull, 0ull};

    const int arow = tid >> 2, akq = tid & 3;
    const int bkrow = tid >> 4, bnq = tid & 15;

    for (int kt = 0; kt < K; kt += 16) {
        if (tid < 128) {
            float4 a0 = *(const float4*)&A[(size_t)(m0 + arow) * lda + kt + akq * 4];
            As[akq*4+0][arow] = a0.x; As[akq*4+1][arow] = a0.y;
            As[akq*4+2][arow] = a0.z; As[akq*4+3][arow] = a0.w;
        }
        float4 b0 = make_float4(0.f, 0.f, 0.f, 0.f);
        if (n0 + bnq * 4 < N)
            b0 = *(const float4*)&Bm[(size_t)(kt + bkrow) * N + n0 + bnq * 4];
        *(float4*)&Bs[bkrow][bnq*4] = b0;
        __syncthreads();

#pragma unroll
        for (int kq = 0; kq < 16; kq++) {
            unsigned long long dp = dup2(As[kq][ty]);
            ulonglong2 bA = *(const ulonglong2*)&Bs[kq][tx * 8];
            ulonglong2 bBv = *(const ulonglong2*)&Bs[kq][tx * 8 + 4];
            fma2(acc[0], dp, bA.x); fma2(acc[1], dp, bA.y);
            fma2(acc[2], dp, bBv.x); fma2(acc[3], dp, bBv.y);
        }
        __syncthreads();
    }

    const int m = m0 + ty;
    float vals[8];
    { float2 p = unpack2(acc[0]); vals[0] = p.x; vals[1] = p.y; }
    { float2 p = unpack2(acc[1]); vals[2] = p.x; vals[3] = p.y; }
    { float2 p = unpack2(acc[2]); vals[4] = p.x; vals[5] = p.y; }
    { float2 p = unpack2(acc[3]); vals[6] = p.x; vals[7] = p.y; }
    const int nn0 = n0 + tx * 8;
#pragma unroll
    for (int q = 0; q < 8; q++)
        if (nn0 + q < tanhN) vals[q] = tanhf(vals[q]);

    if (nn0 + 7 < N) {
        float4 o0 = make_float4(vals[0], vals[1], vals[2], vals[3]);
        float4 o1 = make_float4(vals[4], vals[5], vals[6], vals[7]);
        *(float4*)&Cm[(size_t)m * N + nn0]     = o0;
        *(float4*)&Cm[(size_t)m * N + nn0 + 4] = o1;
        if (oh) {
            uint2 h0, l0, h1, l1;
            split4(o0, h0, l0); split4(o1, h1, l1);
            *(uint4*)&oh[(size_t)m * N + nn0] = make_uint4(h0.x, h0.y, h1.x, h1.y);
            *(uint4*)&ol[(size_t)m * N + nn0] = make_uint4(l0.x, l0.y, l1.x, l1.y);
        }
    } else {
#pragma unroll
        for (int q = 0; q < 8; q++)
            if (nn0 + q < N) Cm[(size_t)m * N + nn0 + q] = vals[q];
    }
}

// ---------------------------------------------------------------------------
// ew0
// ---------------------------------------------------------------------------
__global__ void __launch_bounds__(256)
ew0_kernel(const float* __restrict__ x, const float* __restrict__ maa_x)
{
    size_t i4  = (size_t)blockIdx.x * 256 + threadIdx.x;
    size_t idx = i4 * 4;
    int c    = (int)(idx & (CC - 1));
    int nrow = (int)(idx >> 10);
    float4 xv = *(const float4*)&x[idx];
    float4 xp = make_float4(0.f, 0.f, 0.f, 0.f);
    if (nrow & (TT - 1))
        xp = *(const float4*)&x[idx - CC];
    float4 mv = *(const float4*)&maa_x[c];
    float4 d, xm;
    d.x = xp.x - xv.x;  xm.x = xv.x + d.x * mv.x;
    d.y = xp.y - xv.y;  xm.y = xv.y + d.y * mv.y;
    d.z = xp.z - xv.z;  xm.z = xv.z + d.z * mv.z;
    d.w = xp.w - xv.w;  xm.w = xv.w + d.w * mv.w;
    *(float4*)&g_s.xx[idx]   = d;
    *(float4*)&g_s.xmix[idx] = xm;
}

// ---------------------------------------------------------------------------
// combine
// ---------------------------------------------------------------------------
__global__ void __launch_bounds__(256)
combine_kernel()
{
    int n   = blockIdx.x;
    int tid = threadIdx.x;
    size_t off = (size_t)n * CC + tid * 4;

    float4 kkv = *(float4*)&g_s.kk[off];
    float ss = kkv.x*kkv.x + kkv.y*kkv.y + kkv.z*kkv.z + kkv.w*kkv.w;
#pragma unroll
    for (int o = 8; o; o >>= 1) ss += __shfl_xor_sync(0xffffffffu, ss, o, 16);
    float inv = 1.f / fmaxf(sqrtf(ss), 1e-12f);

    float4 kq = *(float4*)&g_s.k[off];
    float4 aq = *(float4*)&g_s.asig[off];
    float4 mq = *(float4*)&g_s.ma[off];
    float4 wq = *(float4*)&g_s.w[off];
    float4 mk = *(float4*)&g_s.mk2[off];
    float4 kfv, ddv, avv, bvv;
#define CMB(X) { float fac = mq.X + aq.X * (1.f - mq.X); \
    float ee = expf(fminf(wq.X * mk.X, 0.f)); \
    kfv.X = kq.X * fac * ee; \
    ddv.X = expf(wq.X); \
    float kn = kkv.X * inv; \
    avv.X = -kn; bvv.X = kn * aq.X; }
    CMB(x) CMB(y) CMB(z) CMB(w)
#undef CMB
    *(float4*)&g_s.kf[off] = kfv;
    *(float4*)&g_s.dd[off] = ddv;
    *(float4*)&g_s.av[off] = avv;
    *(float4*)&g_s.bv[off] = bvv;
}

// ---------------------------------------------------------------------------
// WKV-7 scan: cp.async 3-deep pipeline, y = S(d∘r) + sa(b·r) + v(k·r)
// ---------------------------------------------------------------------------
__global__ void __launch_bounds__(256)
wkv_kernel()
{
    const int blk = blockIdx.x;
    const int b = blk >> 4;
    const int h = blk & 15;
    const int tid = threadIdx.x;
    const int i  = tid >> 2;
    const int jq = tid & 3;

    __shared__ __align__(16) float sb[4][6][64];
    const size_t rowbase = ((size_t)b * TT) * CC + h * NN;

    const float* gsrc = 0;
    uint32_t sdst[4];
    if (tid < 96) {
        int larr = tid >> 4, lq = tid & 15;
        const float* srcs[6] = { g_s.r, g_s.dd, g_s.kf, g_s.av, g_s.bv, g_s.v };
        gsrc = srcs[larr] + rowbase + lq * 4;
#pragma unroll
        for (int q = 0; q < 4; q++) sdst[q] = smem_u32(&sb[q][larr][lq * 4]);
    }

    // prologue: prefetch t = 0,1,2
#pragma unroll
    for (int pre = 0; pre < 3; pre++) {
        if (tid < 96) cp_async16(sdst[pre], gsrc + (size_t)pre * CC);
        CP_COMMIT();
    }

    unsigned long long S2[8];
#pragma unroll
    for (int u = 0; u < 8; u++) S2[u] = 0ull;

    float* yout = g_s.y + rowbase + i;

    for (int t = 0; t < TT; t++) {
        CP_WAIT2();
        __syncthreads();
        const int p = t & 3;

        const ulonglong2* r2p = (const ulonglong2*)(sb[p][0] + jq * 16);
        const ulonglong2* d2p = (const ulonglong2*)(sb[p][1] + jq * 16);
        const ulonglong2* k2p = (const ulonglong2*)(sb[p][2] + jq * 16);
        const ulonglong2* a2p = (const ulonglong2*)(sb[p][3] + jq * 16);
        const ulonglong2* b2p = (const ulonglong2*)(sb[p][4] + jq * 16);
        const float vi = sb[p][5][i];

        ulonglong2 Rv[4], Dv[4], Kv[4], Av[4], Bv[4];
#pragma unroll
        for (int u = 0; u < 4; u++) {
            Rv[u] = r2p[u]; Dv[u] = d2p[u]; Kv[u] = k2p[u];
            Av[u] = a2p[u]; Bv[u] = b2p[u];
        }

        // issue prefetch for t+3 early
        if (tid < 96 && t + 3 < TT)
            cp_async16(sdst[(t + 3) & 3], gsrc + (size_t)(t + 3) * CC);
        CP_COMMIT();

        unsigned long long sa0 = 0ull, sa1 = 0ull, pp0 = 0ull, pp1 = 0ull;
        unsigned long long br0 = 0ull, br1 = 0ull, kr0 = 0ull, kr1 = 0ull;
#pragma unroll
        for (int u = 0; u < 4; u++) {
            unsigned long long drx = mul2(Dv[u].x, Rv[u].x);
            unsigned long long dry = mul2(Dv[u].y, Rv[u].y);
            fma2(sa0, S2[2*u],   Av[u].x);
            fma2(sa1, S2[2*u+1], Av[u].y);
            fma2(pp0, S2[2*u],   drx);
            fma2(pp1, S2[2*u+1], dry);
            fma2(br0, Bv[u].x, Rv[u].x);
            fma2(br1, Bv[u].y, Rv[u].y);
            fma2(kr0, Kv[u].x, Rv[u].x);
            fma2(kr1, Kv[u].y, Rv[u].y);
        }
        float sa = hadd4(sa0, sa1);
        float pp = hadd4(pp0, pp1);
        float br = hadd4(br0, br1);
        float kr = hadd4(kr0, kr1);
        sa += __shfl_xor_sync(0xffffffffu, sa, 1, 4);
        pp += __shfl_xor_sync(0xffffffffu, pp, 1, 4);
        br += __shfl_xor_sync(0xffffffffu, br, 1, 4);
        kr += __shfl_xor_sync(0xffffffffu, kr, 1, 4);
        sa += __shfl_xor_sync(0xffffffffu, sa, 2, 4);
        pp += __shfl_xor_sync(0xffffffffu, pp, 2, 4);
        br += __shfl_xor_sync(0xffffffffu, br, 2, 4);
        kr += __shfl_xor_sync(0xffffffffu, kr, 2, 4);

        if (jq == 0) yout[(size_t)t * CC] = pp + sa * br + vi * kr;

        const unsigned long long sa2 = dup2(sa);
        const unsigned long long v2  = dup2(vi);
#pragma unroll
        for (int u = 0; u < 4; u++) {
            S2[2*u]   = fma2g(S2[2*u],   Dv[u].x,
                              fma2g(sa2, Bv[u].x, mul2(v2, Kv[u].x)));
            S2[2*u+1] = fma2g(S2[2*u+1], Dv[u].y,
                              fma2g(sa2, Bv[u].y, mul2(v2, Kv[u].y)));
        }
    }
}

// ---------------------------------------------------------------------------
// post: GroupNorm + bonus + gate -> z (bf16 hi/lo)
// ---------------------------------------------------------------------------
__global__ void __launch_bounds__(256)
post_kernel(const float* __restrict__ faaaa,
            const float* __restrict__ lnw, const float* __restrict__ lnb)
{
    int n   = blockIdx.x;
    int tid = threadIdx.x;
    int c   = tid * 4;
    size_t off = (size_t)n * CC + c;

    float4 yv = *(float4*)&g_s.y [off];
    float4 rv = *(float4*)&g_s.r [off];
    float4 kv = *(float4*)&g_s.kf[off];
    float4 vv = *(float4*)&g_s.v [off];
    float4 gv = *(float4*)&g_s.g [off];
    float4 fv = *(const float4*)&faaaa[c];

    float s  = yv.x + yv.y + yv.z + yv.w;
    float s2 = yv.x*yv.x + yv.y*yv.y + yv.z*yv.z + yv.w*yv.w;
    float dk = rv.x*kv.x*fv.x + rv.y*kv.y*fv.y + rv.z*kv.z*fv.z + rv.w*kv.w*fv.w;
#pragma unroll
    for (int o = 8; o; o >>= 1) {
        s  += __shfl_xor_sync(0xffffffffu, s,  o, 16);
        s2 += __shfl_xor_sync(0xffffffffu, s2, o, 16);
        dk += __shfl_xor_sync(0xffffffffu, dk, o, 16);
    }
    float mean = s  * (1.f / 64.f);
    float var  = s2 * (1.f / 64.f) - mean * mean;
    float rs   = rsqrtf(var + 64e-5f);

    float4 lw = *(const float4*)&lnw[c];
    float4 lb = *(const float4*)&lnb[c];
    float4 z;
    z.x = (((yv.x - mean) * rs) * lw.x + lb.x + dk * vv.x) * gv.x;
    z.y = (((yv.y - mean) * rs) * lw.y + lb.y + dk * vv.y) * gv.y;
    z.z = (((yv.z - mean) * rs) * lw.z + lb.z + dk * vv.z) * gv.z;
    z.w = (((yv.w - mean) * rs) * lw.w + lb.w + dk * vv.w) * gv.w;
    uint2 h, l;
    split4(z, h, l);
    *(uint2*)&g_s.zh[off] = h;
    *(uint2*)&g_s.zl[off] = l;
}

// ---------------------------------------------------------------------------
// Host orchestration
// ---------------------------------------------------------------------------
static void g128(const float* A, const float* Bp, float* Cp,
                 int N, int K, int lda, int mode,
                 const float* ex, const float* evec)
{
    dim3 grid(N / 128, MM / 128);
    gemm128<<<grid, 256>>>(A, Bp, Cp, N, K, lda, mode, ex, evec);
}
static void g32(const float* A, const float* Bp, float* Cp,
                int N, int K, int lda, int tanhN,
                bf16* oh = 0, bf16* ol = 0)
{
    dim3 grid((N + 63) / 64, MM / 32);
    gemm32<<<grid, 256>>>(A, Bp, Cp, N, K, lda, tanhN, oh, ol);
}
static void gmma(const bf16* Ah, const bf16* Al, const bf16* Bh,
                 const bf16* Bl, float* Cp, int K)
{
    dim3 grid(8, MM / 128);
    gemm_mma2<<<grid, 256, MMA_SMEM>>>(Ah, Al, Bh, Bl, Cp, K);
}
static void convw(const float* src, bf16* h, bf16* l, int elems)
{
    conv_bf16<<<elems / 1024, 256>>>((const float4*)src, (uint2*)h, (uint2*)l);
}

extern "C" void kernel_launch(void* const* d_in, const int* in_sizes, int n_in,
                              void* d_out, int out_size)
{
    const float* x       = (const float*)d_in[0];
    const float* maa_x   = (const float*)d_in[1];
    const float* maa_rg  = (const float*)d_in[2];
    const float* maa_wa  = (const float*)d_in[3];
    const float* maa_k   = (const float*)d_in[4];
    const float* maa_v   = (const float*)d_in[5];
    const float* maa_w1  = (const float*)d_in[6];
    const float* maa_w2  = (const float*)d_in[7];
    const float* tdecay  = (const float*)d_in[8];
    const float* dw1     = (const float*)d_in[9];
    const float* dw2     = (const float*)d_in[10];
    const float* faaaa   = (const float*)d_in[11];
    const float* taaaaa  = (const float*)d_in[12];
    const float* aw1     = (const float*)d_in[13];
    const float* aw2     = (const float*)d_in[14];
    const float* kw1     = (const float*)d_in[15];
    const float* kw2     = (const float*)d_in[16];
    const float* gw1     = (const float*)d_in[17];
    const float* gw2     = (const float*)d_in[18];
    const float* maw1    = (const float*)d_in[19];
    const float* maw2    = (const float*)d_in[20];
    const float* tmisca  = (const float*)d_in[21];
    const float* mkw1    = (const float*)d_in[22];
    const float* mkw2    = (const float*)d_in[23];
    const float* tmisck  = (const float*)d_in[24];
    const float* wr      = (const float*)d_in[25];
    const float* wk      = (const float*)d_in[26];
    const float* wv      = (const float*)d_in[27];
    const float* wo      = (const float*)d_in[28];
    const float* lnw     = (const float*)d_in[29];
    const float* lnb     = (const float*)d_in[30];
    float* out = (float*)d_out;
    (void)in_sizes; (void)n_in; (void)out_size;

    Scratch* S = nullptr;
    cudaGetSymbolAddress((void**)&S, g_s);
    cudaFuncSetAttribute(gemm_mma2, cudaFuncAttributeMaxDynamicSharedMemorySize,
                         MMA_SMEM);
    cudaFuncSetAttribute(fused_mix, cudaFuncAttributeMaxDynamicSharedMemorySize,
                         MIX_SMEM);

    // 1-2) weight converts for r,k (positions sample window)
    convw(wr, S->wrh, S->wrl, CC * CC);
    convw(wk, S->wkh, S->wkl, CC * CC);
    // 3) time-shift + maa_x mix
    ew0_kernel<<<(MM * CC / 4) / 256, 256>>>(x, maa_x);
    // 4) mix_in = tanh(xmix @ maa_w1)
    g32(S->xmix, maa_w1, S->mixin, 128, 1024, 1024, 128);
    // 5) fused xrg/xwa/xk/xv (+ bf16 hi/lo)
    fused_mix<<<dim3(8, 32), 256, MIX_SMEM>>>(x, maa_w2,
        maa_rg, maa_wa, maa_k, maa_v);
    // 6) r projection  <- ncu sample target
    gmma(S->xrgh, S->xrgl, S->wrh, S->wrl, S->r, 1024);
    // 7-9)
    convw(wv, S->wvh, S->wvl, CC * CC);
    gmma(S->xkh, S->xkl, S->wkh, S->wkl, S->k, 1024);
    gmma(S->xvh, S->xvl, S->wvh, S->wvl, S->v, 1024);
    // 10-12) gate
    g32(S->xrg, gw1, S->gate1, 128, 1024, 1024, 128, S->g1h, S->g1l);
    transconv_kernel<<<dim3(32, 4), 256>>>(gw2, S->gw2Th, S->gw2Tl);
    gmma(S->g1h, S->g1l, S->gw2Th, S->gw2Tl, S->g, 128);
    // 13-17) xwa LoRA group (decay + aaa + ma)
    packB_wa<<<(1024 * 96) / 256, 256>>>(dw1, aw1, maw1);
    g32(S->xwa, S->bp_wa, S->lora_wa, 96, 1024, 1024, 64);
    g128(S->lora_wa,      dw2,  S->w,    1024, 64, 96, 4, 0, tdecay);
    g128(S->lora_wa + 64, aw2,  S->asig, 1024, 16, 96, 3, 0, taaaaa);
    g128(S->lora_wa + 80, maw2, S->ma,   1024, 16, 96, 3, 0, tmisca);
    // 18-21) xk LoRA group (kkk + mk)
    packB_k<<<(1024 * 32) / 256, 256>>>(kw1, mkw1);
    g32(S->xk, S->bp_k, S->lora_k, 32, 1024, 1024, 16);
    g128(S->lora_k,      kw2,  S->kk,  1024, 16, 32, 5, S->k, 0);
    g128(S->lora_k + 16, mkw2, S->mk2, 1024, 16, 32, 3, 0, tmisck);
    // 22) combine
    combine_kernel<<<MM, 256>>>();
    // 23) WKV-7 scan
    wkv_kernel<<<BB * HH, 256>>>();
    // 24) GroupNorm + bonus + gate -> z bf16
    post_kernel<<<MM, 256>>>(faaaa, lnw, lnb);
    // 25-26) output projection
    convw(wo, S->woh, S->wol, CC * CC);
    gmma(S->zh, S->zl, S->woh, S->wol, out, 1024);
}

// round 8
// speedup vs baseline: 2.3195x; 1.3035x over previous
#include <cuda_runtime.h>
#include <cuda_bf16.h>
#include <math.h>
#include <stdint.h>
#include <string.h>

#define BB 4
#define TT 1024
#define CC 1024
#define HH 16
#define NN 64
#define MM (BB*TT)   // 4096 rows

typedef __nv_bfloat16 bf16;

// ---------------------------------------------------------------------------
// Scratch (static device memory)
// ---------------------------------------------------------------------------
struct Scratch {
    float xx   [MM*CC];
    float mixin[MM*128];
    float r    [MM*CC];
    float k    [MM*CC];
    float v    [MM*CC];
    float g    [MM*CC];
    float w    [MM*CC];
    float kk   [MM*CC];
    float asig [MM*CC];
    float ma   [MM*CC];
    float mk2  [MM*CC];
    float kf   [MM*CC];
    float dd   [MM*CC];
    float av   [MM*CC];
    float bv   [MM*CC];
    float y    [MM*CC];
    float gate1[MM*128];
    float lora_wa[MM*128];
    float lora_k [MM*32];
    // bf16 hi/lo activation arrays
    bf16 xmixh[MM*CC], xmixl[MM*CC];
    bf16 xrgh[MM*CC], xrgl[MM*CC];
    bf16 xwah[MM*CC], xwal[MM*CC];
    bf16 xkh [MM*CC], xkl [MM*CC];
    bf16 xvh [MM*CC], xvl [MM*CC];
    bf16 zh  [MM*CC], zl  [MM*CC];
    bf16 g1h [MM*128], g1l [MM*128];
    // bf16 hi/lo weights
    bf16 wrh[CC*CC], wrl[CC*CC];
    bf16 wkh[CC*CC], wkl[CC*CC];
    bf16 wvh[CC*CC], wvl[CC*CC];
    bf16 woh[CC*CC], wol[CC*CC];
    bf16 gw2Th[CC*128], gw2Tl[CC*128];
    bf16 mw1Th[128*1024], mw1Tl[128*1024];
    bf16 gw1Th[128*1024], gw1Tl[128*1024];
    bf16 waTh [128*1024], waTl [128*1024];
    bf16 kTh  [32*1024],  kTl  [32*1024];
};
__device__ Scratch g_s;

// ---------------------------------------------------------------------------
// Packed f32x2 helpers
// ---------------------------------------------------------------------------
__device__ __forceinline__ unsigned long long dup2(float x) {
    unsigned long long r;
    asm("mov.b64 %0, {%1, %1};" : "=l"(r) : "f"(x));
    return r;
}
__device__ __forceinline__ void fma2(unsigned long long& acc,
                                     unsigned long long a,
                                     unsigned long long b) {
    asm("fma.rn.f32x2 %0, %1, %2, %0;" : "+l"(acc) : "l"(a), "l"(b));
}
__device__ __forceinline__ unsigned long long fma2g(unsigned long long a,
                                                    unsigned long long b,
                                                    unsigned long long c) {
    unsigned long long d;
    asm("fma.rn.f32x2 %0, %1, %2, %3;" : "=l"(d) : "l"(a), "l"(b), "l"(c));
    return d;
}
__device__ __forceinline__ unsigned long long mul2(unsigned long long a,
                                                   unsigned long long b) {
    unsigned long long d;
    asm("mul.rn.f32x2 %0, %1, %2;" : "=l"(d) : "l"(a), "l"(b));
    return d;
}
__device__ __forceinline__ float2 unpack2(unsigned long long v) {
    float2 f;
    asm("mov.b64 {%0, %1}, %2;" : "=f"(f.x), "=f"(f.y) : "l"(v));
    return f;
}
__device__ __forceinline__ float hadd4(unsigned long long a,
                                       unsigned long long b) {
    float2 f = unpack2(a), g = unpack2(b);
    return (f.x + f.y) + (g.x + g.y);
}
__device__ __forceinline__ uint32_t smem_u32(const void* p) {
    uint32_t a;
    asm("{ .reg .u64 t; cvta.to.shared.u64 t, %1; cvt.u32.u64 %0, t; }"
        : "=r"(a) : "l"(p));
    return a;
}

// cp.async helpers
__device__ __forceinline__ void cp_async16(uint32_t saddr, const void* gptr) {
    asm volatile("cp.async.cg.shared.global [%0], [%1], 16;"
        :: "r"(saddr), "l"(gptr) : "memory");
}
#define CP_COMMIT() asm volatile("cp.async.commit_group;" ::: "memory")
#define CP_WAIT2()  asm volatile("cp.async.wait_group 2;" ::: "memory")

// hi/lo splits
__device__ __forceinline__ void split4(float4 f, uint2& h, uint2& l) {
    __nv_bfloat162 h01 = __floats2bfloat162_rn(f.x, f.y);
    __nv_bfloat162 h23 = __floats2bfloat162_rn(f.z, f.w);
    float lx = f.x - __bfloat162float(h01.x);
    float ly = f.y - __bfloat162float(h01.y);
    float lz = f.z - __bfloat162float(h23.x);
    float lw = f.w - __bfloat162float(h23.y);
    __nv_bfloat162 l01 = __floats2bfloat162_rn(lx, ly);
    __nv_bfloat162 l23 = __floats2bfloat162_rn(lz, lw);
    memcpy(&h.x, &h01, 4); memcpy(&h.y, &h23, 4);
    memcpy(&l.x, &l01, 4); memcpy(&l.y, &l23, 4);
}
__device__ __forceinline__ void split2(float a, float b,
                                       uint32_t& h, uint32_t& l) {
    __nv_bfloat162 hh = __floats2bfloat162_rn(a, b);
    float la = a - __bfloat162float(hh.x);
    float lb = b - __bfloat162float(hh.y);
    __nv_bfloat162 ll = __floats2bfloat162_rn(la, lb);
    memcpy(&h, &hh, 4); memcpy(&l, &ll, 4);
}

// ---------------------------------------------------------------------------
// mma.sync / ldmatrix helpers
// ---------------------------------------------------------------------------
__device__ __forceinline__ void ldsm4(uint32_t* r, uint32_t addr) {
    asm volatile("ldmatrix.sync.aligned.m8n8.x4.shared.b16 {%0,%1,%2,%3}, [%4];"
        : "=r"(r[0]), "=r"(r[1]), "=r"(r[2]), "=r"(r[3]) : "r"(addr));
}
__device__ __forceinline__ void ldsm2(uint32_t* r, uint32_t addr) {
    asm volatile("ldmatrix.sync.aligned.m8n8.x2.shared.b16 {%0,%1}, [%2];"
        : "=r"(r[0]), "=r"(r[1]) : "r"(addr));
}
__device__ __forceinline__ void mma_bf16(float* c, const uint32_t* a,
                                         const uint32_t* b) {
    asm volatile("mma.sync.aligned.m16n8k16.row.col.f32.bf16.bf16.f32 "
        "{%0,%1,%2,%3}, {%4,%5,%6,%7}, {%8,%9}, {%0,%1,%2,%3};"
        : "+f"(c[0]), "+f"(c[1]), "+f"(c[2]), "+f"(c[3])
        : "r"(a[0]), "r"(a[1]), "r"(a[2]), "r"(a[3]), "r"(b[0]), "r"(b[1]));
}

// ---------------------------------------------------------------------------
// gemm_mma2: C[M,1024] = (Ah+Al)[M,K] @ (Bh+Bl)[1024,K]^T, fp32 accum.
// ---------------------------------------------------------------------------
#define MMA_SMEM 81920

__global__ void __launch_bounds__(256)
gemm_mma2(const bf16* __restrict__ Ah, const bf16* __restrict__ Al,
          const bf16* __restrict__ Bh, const bf16* __restrict__ Bl,
          float* __restrict__ Cm, int K)
{
    extern __shared__ __align__(16) char sm[];
    const uint32_t sb = smem_u32(sm);

    const int tid  = threadIdx.x;
    const int lane = tid & 31;
    const int wid  = tid >> 5;
    const int wm   = wid & 1;
    const int wn   = wid >> 1;
    const int n0 = blockIdx.x * 128;
    const int m0 = blockIdx.y * 128;

    const int row = tid >> 1, half = tid & 1;
    const bf16* pAh = Ah + (size_t)(m0 + row) * K + half * 16;
    const bf16* pAl = Al + (size_t)(m0 + row) * K + half * 16;
    const bf16* pBh = Bh + (size_t)(n0 + row) * K + half * 16;
    const bf16* pBl = Bl + (size_t)(n0 + row) * K + half * 16;
    const uint32_t st = (uint32_t)(row * 80 + half * 32);

    const uint32_t aLoff = (uint32_t)((lane & 15) * 80 + (lane >> 4) * 16);
    const uint32_t bLoff = (uint32_t)(((lane & 7) + ((lane >> 4) & 1) * 8) * 80
                                      + ((lane >> 3) & 1) * 16);

    float c[4][4][4];
#pragma unroll
    for (int i = 0; i < 4; i++)
#pragma unroll
        for (int j = 0; j < 4; j++)
#pragma unroll
            for (int q = 0; q < 4; q++) c[i][j][q] = 0.f;

    const int chunks = K >> 5;

    {
        uint4 ah0 = *(const uint4*)pAh, ah1 = *(const uint4*)(pAh + 8);
        uint4 al0 = *(const uint4*)pAl, al1 = *(const uint4*)(pAl + 8);
        uint4 bh0 = *(const uint4*)pBh, bh1 = *(const uint4*)(pBh + 8);
        uint4 bl0 = *(const uint4*)pBl, bl1 = *(const uint4*)(pBl + 8);
        *(uint4*)(sm + 0     + st) = ah0; *(uint4*)(sm + 0     + st + 16) = ah1;
        *(uint4*)(sm + 10240 + st) = al0; *(uint4*)(sm + 10240 + st + 16) = al1;
        *(uint4*)(sm + 20480 + st) = bh0; *(uint4*)(sm + 20480 + st + 16) = bh1;
        *(uint4*)(sm + 30720 + st) = bl0; *(uint4*)(sm + 30720 + st + 16) = bl1;
    }
    __syncthreads();

    for (int cidx = 0; cidx < chunks; cidx++) {
        const uint32_t bufOff = (uint32_t)((cidx & 1) * 40960);
        const bool more = (cidx + 1 < chunks);

        uint4 ah0, ah1, al0, al1, bh0, bh1, bl0, bl1;
        if (more) {
            const int ko = (cidx + 1) * 32;
            ah0 = *(const uint4*)(pAh + ko); ah1 = *(const uint4*)(pAh + ko + 8);
            al0 = *(const uint4*)(pAl + ko); al1 = *(const uint4*)(pAl + ko + 8);
            bh0 = *(const uint4*)(pBh + ko); bh1 = *(const uint4*)(pBh + ko + 8);
            bl0 = *(const uint4*)(pBl + ko); bl1 = *(const uint4*)(pBl + ko + 8);
        }

        const uint32_t aBase = sb + bufOff + (uint32_t)(wm * 64 * 80) + aLoff;
        const uint32_t bBase = sb + bufOff + 20480u + (uint32_t)(wn * 32 * 80) + bLoff;
#pragma unroll
        for (int ks = 0; ks < 2; ks++) {
            uint32_t afh[4][4], afl[4][4];
#pragma unroll
            for (int mi = 0; mi < 4; mi++) {
                ldsm4(afh[mi], aBase + 0u     + (uint32_t)(mi * 1280 + ks * 32));
                ldsm4(afl[mi], aBase + 10240u + (uint32_t)(mi * 1280 + ks * 32));
            }
            uint32_t bfh[2][4], bfl[2][4];
#pragma unroll
            for (int np = 0; np < 2; np++) {
                ldsm4(bfh[np], bBase + 0u     + (uint32_t)(np * 1280 + ks * 32));
                ldsm4(bfl[np], bBase + 10240u + (uint32_t)(np * 1280 + ks * 32));
            }
#pragma unroll
            for (int mi = 0; mi < 4; mi++) {
#pragma unroll
                for (int ni = 0; ni < 4; ni++) {
                    const uint32_t* bh = &bfh[ni >> 1][(ni & 1) * 2];
                    const uint32_t* bl = &bfl[ni >> 1][(ni & 1) * 2];
                    mma_bf16(c[mi][ni], afh[mi], bh);
                    mma_bf16(c[mi][ni], afh[mi], bl);
                    mma_bf16(c[mi][ni], afl[mi], bh);
                }
            }
        }

        if (more) {
            char* nb = sm + ((cidx + 1) & 1) * 40960;
            *(uint4*)(nb + 0     + st) = ah0; *(uint4*)(nb + 0     + st + 16) = ah1;
            *(uint4*)(nb + 10240 + st) = al0; *(uint4*)(nb + 10240 + st + 16) = al1;
            *(uint4*)(nb + 20480 + st) = bh0; *(uint4*)(nb + 20480 + st + 16) = bh1;
            *(uint4*)(nb + 30720 + st) = bl0; *(uint4*)(nb + 30720 + st + 16) = bl1;
        }
        __syncthreads();
    }

    const int erow = m0 + wm * 64 + (lane >> 2);
    const int ecol = n0 + wn * 32 + (lane & 3) * 2;
#pragma unroll
    for (int mi = 0; mi < 4; mi++) {
#pragma unroll
        for (int ni = 0; ni < 4; ni++) {
            size_t base0 = (size_t)(erow + mi * 16)     * 1024 + ecol + ni * 8;
            size_t base1 = (size_t)(erow + mi * 16 + 8) * 1024 + ecol + ni * 8;
            *(float2*)&Cm[base0] = make_float2(c[mi][ni][0], c[mi][ni][1]);
            *(float2*)&Cm[base1] = make_float2(c[mi][ni][2], c[mi][ni][3]);
        }
    }
}

// ---------------------------------------------------------------------------
// gemm_up<BN>: C[4096,BN] = (Ah+Al)[4096,1024] @ (Bh+Bl)[BN,1024]^T
// CTA 64xBN, 8 warps (warp 32 x BN/4), K-chunks 32, double-buffered.
// Epilogue: tanh on cols < tanhN; optional bf16 hi/lo outputs.
// smem/buffer: Ah@0(5120) Al@5120 Bh@10240(BN*80) Bl@10240+BN*80.
// ---------------------------------------------------------------------------
template<int BN>
__global__ void __launch_bounds__(256)
gemm_up(const bf16* __restrict__ Ah, const bf16* __restrict__ Al,
        const bf16* __restrict__ Bh, const bf16* __restrict__ Bl,
        float* __restrict__ Cm, int tanhN,
        bf16* __restrict__ oh, bf16* __restrict__ ol)
{
    constexpr int NI = BN / 32;               // 4 (BN=128) or 1 (BN=32)
    constexpr int B_BYTES = BN * 80;
    constexpr int OFF_AL = 5120;
    constexpr int OFF_BH = 10240;
    constexpr int OFF_BL = 10240 + B_BYTES;
    constexpr int BUF = 10240 + 2 * B_BYTES;
    constexpr int BITER = (BN * 4 + 255) / 256;

    extern __shared__ __align__(16) char sm[];
    const uint32_t sb = smem_u32(sm);

    const int tid  = threadIdx.x;
    const int lane = tid & 31;
    const int wid  = tid >> 5;
    const int wm   = wid & 1;
    const int wn   = wid >> 1;
    const int m0 = blockIdx.x * 64;

    const int arow = tid >> 2, aq = tid & 3;
    const bf16* pAh = Ah + (size_t)(m0 + arow) * 1024 + aq * 8;
    const bf16* pAl = Al + (size_t)(m0 + arow) * 1024 + aq * 8;
    const uint32_t stA = (uint32_t)(arow * 80 + aq * 16);

    const uint32_t aLoff = (uint32_t)((lane & 15) * 80 + (lane >> 4) * 16);
    const uint32_t bLoff = (uint32_t)(((lane & 7) + ((lane >> 4) & 1) * 8) * 80
                                      + ((lane >> 3) & 1) * 16);
    const uint32_t bLoff2 = (uint32_t)((lane & 7) * 80 + ((lane >> 3) & 1) * 16);

    float c[2][NI][4];
#pragma unroll
    for (int i = 0; i < 2; i++)
#pragma unroll
        for (int j = 0; j < NI; j++)
#pragma unroll
            for (int q = 0; q < 4; q++) c[i][j][q] = 0.f;

    // preload chunk 0
    {
        *(uint4*)(sm + stA)          = *(const uint4*)pAh;
        *(uint4*)(sm + OFF_AL + stA) = *(const uint4*)pAl;
#pragma unroll
        for (int it = 0; it < BITER; it++) {
            int u = tid + it * 256;
            if (u < BN * 4) {
                int brow = u >> 2, bq = u & 3;
                uint32_t stB = (uint32_t)(brow * 80 + bq * 16);
                *(uint4*)(sm + OFF_BH + stB) =
                    *(const uint4*)(Bh + (size_t)brow * 1024 + bq * 8);
                *(uint4*)(sm + OFF_BL + stB) =
                    *(const uint4*)(Bl + (size_t)brow * 1024 + bq * 8);
            }
        }
    }
    __syncthreads();

    for (int cidx = 0; cidx < 32; cidx++) {
        const uint32_t bufOff = (uint32_t)((cidx & 1) * BUF);
        const bool more = (cidx + 1 < 32);

        uint4 rah, ral, rbh[BITER], rbl[BITER];
        if (more) {
            const int ko = (cidx + 1) * 32;
            rah = *(const uint4*)(pAh + ko);
            ral = *(const uint4*)(pAl + ko);
#pragma unroll
            for (int it = 0; it < BITER; it++) {
                int u = tid + it * 256;
                if (u < BN * 4) {
                    int brow = u >> 2, bq = u & 3;
                    rbh[it] = *(const uint4*)(Bh + (size_t)brow * 1024 + ko + bq * 8);
                    rbl[it] = *(const uint4*)(Bl + (size_t)brow * 1024 + ko + bq * 8);
                }
            }
        }

        const uint32_t aBase = sb + bufOff + (uint32_t)(wm * 32 * 80) + aLoff;
#pragma unroll
        for (int ks = 0; ks < 2; ks++) {
            uint32_t afh[2][4], afl[2][4];
#pragma unroll
            for (int mi = 0; mi < 2; mi++) {
                ldsm4(afh[mi], aBase + (uint32_t)(mi * 1280 + ks * 32));
                ldsm4(afl[mi], aBase + OFF_AL + (uint32_t)(mi * 1280 + ks * 32));
            }
            if (BN == 128) {
                uint32_t bfh[2][4], bfl[2][4];
                const uint32_t bBase = sb + bufOff + OFF_BH
                                     + (uint32_t)(wn * 32 * 80) + bLoff;
#pragma unroll
                for (int np = 0; np < 2; np++) {
                    ldsm4(bfh[np], bBase + (uint32_t)(np * 1280 + ks * 32));
                    ldsm4(bfl[np], bBase + (uint32_t)(B_BYTES + np * 1280 + ks * 32));
                }
#pragma unroll
                for (int mi = 0; mi < 2; mi++) {
#pragma unroll
                    for (int ni = 0; ni < NI; ni++) {
                        const uint32_t* bhp = &bfh[ni >> 1][(ni & 1) * 2];
                        const uint32_t* blp = &bfl[ni >> 1][(ni & 1) * 2];
                        mma_bf16(c[mi][ni], afh[mi], bhp);
                        mma_bf16(c[mi][ni], afh[mi], blp);
                        mma_bf16(c[mi][ni], afl[mi], bhp);
                    }
                }
            } else {
                uint32_t bfh2[2], bfl2[2];
                const uint32_t bBase = sb + bufOff + OFF_BH
                                     + (uint32_t)(wn * 8 * 80) + bLoff2
                                     + (uint32_t)(ks * 32);
                ldsm2(bfh2, bBase);
                ldsm2(bfl2, bBase + (uint32_t)B_BYTES);
#pragma unroll
                for (int mi = 0; mi < 2; mi++) {
                    mma_bf16(c[mi][0], afh[mi], bfh2);
                    mma_bf16(c[mi][0], afh[mi], bfl2);
                    mma_bf16(c[mi][0], afl[mi], bfh2);
                }
            }
        }

        if (more) {
            char* nb = sm + ((cidx + 1) & 1) * BUF;
            *(uint4*)(nb + stA)          = rah;
            *(uint4*)(nb + OFF_AL + stA) = ral;
#pragma unroll
            for (int it = 0; it < BITER; it++) {
                int u = tid + it * 256;
                if (u < BN * 4) {
                    int brow = u >> 2, bq = u & 3;
                    uint32_t stB = (uint32_t)(brow * 80 + bq * 16);
                    *(uint4*)(nb + OFF_BH + stB) = rbh[it];
                    *(uint4*)(nb + OFF_BL + stB) = rbl[it];
                }
            }
        }
        __syncthreads();
    }

    // epilogue
#pragma unroll
    for (int mi = 0; mi < 2; mi++) {
#pragma unroll
        for (int ni = 0; ni < NI; ni++) {
            const int r0  = m0 + wm * 32 + mi * 16 + (lane >> 2);
            const int col = wn * 8 * NI + ni * 8 + (lane & 3) * 2;
            float v0 = c[mi][ni][0], v1 = c[mi][ni][1];
            float v2 = c[mi][ni][2], v3 = c[mi][ni][3];
            if (col < tanhN) {
                v0 = tanhf(v0); v1 = tanhf(v1);
                v2 = tanhf(v2); v3 = tanhf(v3);
            }
            *(float2*)&Cm[(size_t)r0 * BN + col]       = make_float2(v0, v1);
            *(float2*)&Cm[(size_t)(r0 + 8) * BN + col] = make_float2(v2, v3);
            if (oh) {
                uint32_t h0, l0, h1, l1;
                split2(v0, v1, h0, l0);
                split2(v2, v3, h1, l1);
                *(uint32_t*)&oh[(size_t)r0 * BN + col]       = h0;
                *(uint32_t*)&ol[(size_t)r0 * BN + col]       = l0;
                *(uint32_t*)&oh[(size_t)(r0 + 8) * BN + col] = h1;
                *(uint32_t*)&ol[(size_t)(r0 + 8) * BN + col] = l1;
            }
        }
    }
}

// ---------------------------------------------------------------------------
// conv_bf16: fp32 -> bf16 hi/lo arrays
// ---------------------------------------------------------------------------
__global__ void __launch_bounds__(256)
conv_bf16(const float4* __restrict__ src, uint2* __restrict__ h,
          uint2* __restrict__ l)
{
    int i = blockIdx.x * 256 + threadIdx.x;
    uint2 hh, ll;
    split4(src[i], hh, ll);
    h[i] = hh; l[i] = ll;
}

// ---------------------------------------------------------------------------
// transpose + convert: gw2 (128x1024 fp32) -> gw2T hi/lo (1024x128 bf16)
// ---------------------------------------------------------------------------
__global__ void __launch_bounds__(256)
transconv_kernel(const float* __restrict__ src, bf16* __restrict__ dh,
                 bf16* __restrict__ dl)
{
    __shared__ float tile[32][33];
    int bx = blockIdx.x;
    int by = blockIdx.y;
    int tx = threadIdx.x & 31, ty = threadIdx.x >> 5;
#pragma unroll
    for (int i = 0; i < 4; i++)
        tile[ty + i * 8][tx] = src[(size_t)(by * 32 + ty + i * 8) * 1024 + bx * 32 + tx];
    __syncthreads();
#pragma unroll
    for (int i = 0; i < 4; i++) {
        float v = tile[tx][ty + i * 8];
        bf16 hv = __float2bfloat16_rn(v);
        bf16 lv = __float2bfloat16_rn(v - __bfloat162float(hv));
        size_t di = (size_t)(bx * 32 + ty + i * 8) * 128 + by * 32 + tx;
        dh[di] = hv; dl[di] = lv;
    }
}

// ---------------------------------------------------------------------------
// packT kernels: w1 matrices (1024 x N) -> transposed bf16 hi/lo (N x 1024)
// ---------------------------------------------------------------------------
__global__ void __launch_bounds__(256)
packT_w1(const float* __restrict__ src, bf16* __restrict__ dh,
         bf16* __restrict__ dl)
{
    int idx = blockIdx.x * 256 + threadIdx.x;   // 128*1024
    int cth = idx >> 10, r = idx & 1023;
    float v = src[(size_t)r * 128 + cth];
    bf16 hv = __float2bfloat16_rn(v);
    bf16 lv = __float2bfloat16_rn(v - __bfloat162float(hv));
    dh[idx] = hv; dl[idx] = lv;
}
__global__ void __launch_bounds__(256)
packT_wa(const float* __restrict__ dw1, const float* __restrict__ aw1,
         const float* __restrict__ maw1)
{
    int idx = blockIdx.x * 256 + threadIdx.x;   // 128*1024
    int cth = idx >> 10, r = idx & 1023;
    float v = 0.f;
    if (cth < 64)      v = dw1[r * 64 + cth];
    else if (cth < 80) v = aw1[r * 16 + (cth - 64)];
    else if (cth < 96) v = maw1[r * 16 + (cth - 80)];
    bf16 hv = __float2bfloat16_rn(v);
    bf16 lv = __float2bfloat16_rn(v - __bfloat162float(hv));
    g_s.waTh[idx] = hv; g_s.waTl[idx] = lv;
}
__global__ void __launch_bounds__(256)
packT_k(const float* __restrict__ kw1, const float* __restrict__ mkw1)
{
    int idx = blockIdx.x * 256 + threadIdx.x;   // 32*1024
    int cth = idx >> 10, r = idx & 1023;
    float v = (cth < 16) ? kw1[r * 16 + cth] : mkw1[r * 16 + (cth - 16)];
    bf16 hv = __float2bfloat16_rn(v);
    bf16 lv = __float2bfloat16_rn(v - __bfloat162float(hv));
    g_s.kTh[idx] = hv; g_s.kTl[idx] = lv;
}

// ---------------------------------------------------------------------------
// fused_mix: for f=0..3 out_f = x + xx*(maa_f + mixin[:,f*32:+32]@W2_f)
// writes bf16 hi/lo only (xrg, xwa, xk, xv).
// ---------------------------------------------------------------------------
#define MIX_SMEM 131072

__global__ void __launch_bounds__(256)
fused_mix(const float* __restrict__ x, const float* __restrict__ w2,
          const float* __restrict__ m_rg, const float* __restrict__ m_wa,
          const float* __restrict__ m_k,  const float* __restrict__ m_v)
{
    extern __shared__ __align__(16) char smraw[];
    float* As = (float*)smraw;
    float* Bs = (float*)(smraw + 65536);

    const int tid = threadIdx.x;
    const int tx = tid & 15;
    const int ty = tid >> 4;
    const int n0 = blockIdx.x * 128;
    const int m0 = blockIdx.y * 128;

#pragma unroll
    for (int i = 0; i < 16; i++) {
        int u = tid + 256 * i;
        int rw = u >> 5, c4 = u & 31;
        float4 v = *(const float4*)&g_s.mixin[(size_t)(m0 + rw) * 128 + c4 * 4];
        As[(c4 * 4 + 0) * 128 + rw] = v.x;
        As[(c4 * 4 + 1) * 128 + rw] = v.y;
        As[(c4 * 4 + 2) * 128 + rw] = v.z;
        As[(c4 * 4 + 3) * 128 + rw] = v.w;
    }
#pragma unroll
    for (int i = 0; i < 16; i++) {
        int u = tid + 256 * i;
        int kr = u >> 5, n4 = u & 31;
        *(float4*)&Bs[kr * 128 + n4 * 4] =
            *(const float4*)&w2[(size_t)kr * 1024 + n0 + n4 * 4];
    }
    __syncthreads();

    for (int f = 0; f < 4; f++) {
        unsigned long long acc[8][4];
#pragma unroll
        for (int i = 0; i < 8; i++)
#pragma unroll
            for (int j = 0; j < 4; j++) acc[i][j] = 0ull;

#pragma unroll
        for (int kq2 = 0; kq2 < 32; kq2++) {
            const int kq = f * 32 + kq2;
            float4 a0 = *(const float4*)&As[kq * 128 + ty * 8];
            float4 a1 = *(const float4*)&As[kq * 128 + ty * 8 + 4];
            ulonglong2 bA = *(const ulonglong2*)&Bs[kq * 128 + tx * 8];
            ulonglong2 bB = *(const ulonglong2*)&Bs[kq * 128 + tx * 8 + 4];
#define RF(rI, aval) { unsigned long long dp = dup2(aval); \
            fma2(acc[rI][0], dp, bA.x); fma2(acc[rI][1], dp, bA.y); \
            fma2(acc[rI][2], dp, bB.x); fma2(acc[rI][3], dp, bB.y); }
            RF(0, a0.x) RF(1, a0.y) RF(2, a0.z) RF(3, a0.w)
            RF(4, a1.x) RF(5, a1.y) RF(6, a1.z) RF(7, a1.w)
#undef RF
        }

        bf16 *oh, *ol; const float* maa;
        switch (f) {
            case 0: oh = g_s.xrgh; ol = g_s.xrgl; maa = m_rg; break;
            case 1: oh = g_s.xwah; ol = g_s.xwal; maa = m_wa; break;
            case 2: oh = g_s.xkh;  ol = g_s.xkl;  maa = m_k;  break;
            default:oh = g_s.xvh;  ol = g_s.xvl;  maa = m_v;  break;
        }
        const int nc = n0 + tx * 8;
        float4 mv0 = *(const float4*)&maa[nc];
        float4 mv1 = *(const float4*)&maa[nc + 4];
#pragma unroll
        for (int rr = 0; rr < 8; rr++) {
            const int m = m0 + ty * 8 + rr;
            const size_t off = (size_t)m * 1024 + nc;
            float4 xv0 = *(const float4*)&x[off];
            float4 xv1 = *(const float4*)&x[off + 4];
            float4 dx0 = *(const float4*)&g_s.xx[off];
            float4 dx1 = *(const float4*)&g_s.xx[off + 4];
            float vals[8];
            { float2 p = unpack2(acc[rr][0]); vals[0] = p.x; vals[1] = p.y; }
            { float2 p = unpack2(acc[rr][1]); vals[2] = p.x; vals[3] = p.y; }
            { float2 p = unpack2(acc[rr][2]); vals[4] = p.x; vals[5] = p.y; }
            { float2 p = unpack2(acc[rr][3]); vals[6] = p.x; vals[7] = p.y; }
            float4 o0, o1;
            o0.x = xv0.x + dx0.x * (mv0.x + vals[0]);
            o0.y = xv0.y + dx0.y * (mv0.y + vals[1]);
            o0.z = xv0.z + dx0.z * (mv0.z + vals[2]);
            o0.w = xv0.w + dx0.w * (mv0.w + vals[3]);
            o1.x = xv1.x + dx1.x * (mv1.x + vals[4]);
            o1.y = xv1.y + dx1.y * (mv1.y + vals[5]);
            o1.z = xv1.z + dx1.z * (mv1.z + vals[6]);
            o1.w = xv1.w + dx1.w * (mv1.w + vals[7]);
            uint2 h0, l0, h1, l1;
            split4(o0, h0, l0);
            split4(o1, h1, l1);
            *(uint4*)&oh[off] = make_uint4(h0.x, h0.y, h1.x, h1.y);
            *(uint4*)&ol[off] = make_uint4(l0.x, l0.y, l1.x, l1.y);
        }
    }
}

// ---------------------------------------------------------------------------
// gemm128 (fp32, small-K GEMMs with fused epilogues)
// modes: 0 plain | 3 sigmoid(evec[n]+acc) | 4 -log1p(exp(-(evec[n]+acc)))-0.5
//        5: ex + acc
// ---------------------------------------------------------------------------
__global__ void __launch_bounds__(256, 2)
gemm128(const float* __restrict__ A, const float* __restrict__ Bm,
        float* __restrict__ Cm, int N, int K, int lda, int mode,
        const float* __restrict__ ex, const float* __restrict__ evec)
{
    __shared__ __align__(16) float As[2][16][128];
    __shared__ __align__(16) float Bs[2][16][128];

    const int tid = threadIdx.x;
    const int tx = tid & 15;
    const int ty = tid >> 4;
    const int n0 = blockIdx.x * 128;
    const int m0 = blockIdx.y * 128;

    unsigned long long acc[8][4];
#pragma unroll
    for (int i = 0; i < 8; i++)
#pragma unroll
        for (int j = 0; j < 4; j++) acc[i][j] = 0ull;

    const int arow0 = (tid)       >> 2, akq0 = (tid)       & 3;
    const int arow1 = (tid + 256) >> 2, akq1 = (tid + 256) & 3;
    const int bkrow0 = (tid)       >> 5, bnq0 = (tid)       & 31;
    const int bkrow1 = (tid + 256) >> 5, bnq1 = (tid + 256) & 31;

    {
        float4 a0 = *(const float4*)&A[(size_t)(m0 + arow0) * lda + akq0 * 4];
        float4 a1 = *(const float4*)&A[(size_t)(m0 + arow1) * lda + akq1 * 4];
        As[0][akq0*4+0][arow0] = a0.x; As[0][akq0*4+1][arow0] = a0.y;
        As[0][akq0*4+2][arow0] = a0.z; As[0][akq0*4+3][arow0] = a0.w;
        As[0][akq1*4+0][arow1] = a1.x; As[0][akq1*4+1][arow1] = a1.y;
        As[0][akq1*4+2][arow1] = a1.z; As[0][akq1*4+3][arow1] = a1.w;
        *(float4*)&Bs[0][bkrow0][bnq0*4] =
            *(const float4*)&Bm[(size_t)bkrow0 * N + n0 + bnq0 * 4];
        *(float4*)&Bs[0][bkrow1][bnq1*4] =
            *(const float4*)&Bm[(size_t)bkrow1 * N + n0 + bnq1 * 4];
    }
    __syncthreads();

    const int ntiles = K >> 4;
    for (int it = 0; it < ntiles; it++) {
        const int buf = it & 1;
        const bool more = (it + 1 < ntiles);
        float4 pa0, pa1, pb0, pb1;
        if (more) {
            const int kt = (it + 1) << 4;
            pa0 = *(const float4*)&A[(size_t)(m0 + arow0) * lda + kt + akq0 * 4];
            pa1 = *(const float4*)&A[(size_t)(m0 + arow1) * lda + kt + akq1 * 4];
            pb0 = *(const float4*)&Bm[(size_t)(kt + bkrow0) * N + n0 + bnq0 * 4];
            pb1 = *(const float4*)&Bm[(size_t)(kt + bkrow1) * N + n0 + bnq1 * 4];
        }

#pragma unroll
        for (int kq = 0; kq < 16; kq++) {
            float4 a0 = *(const float4*)&As[buf][kq][ty * 8];
            float4 a1 = *(const float4*)&As[buf][kq][ty * 8 + 4];
            ulonglong2 bA = *(const ulonglong2*)&Bs[buf][kq][tx * 8];
            ulonglong2 bBv = *(const ulonglong2*)&Bs[buf][kq][tx * 8 + 4];
#define RF(rI, aval) { unsigned long long dp = dup2(aval); \
            fma2(acc[rI][0], dp, bA.x); fma2(acc[rI][1], dp, bA.y); \
            fma2(acc[rI][2], dp, bBv.x); fma2(acc[rI][3], dp, bBv.y); }
            RF(0, a0.x) RF(1, a0.y) RF(2, a0.z) RF(3, a0.w)
            RF(4, a1.x) RF(5, a1.y) RF(6, a1.z) RF(7, a1.w)
#undef RF
        }

        if (more) {
            const int nb = buf ^ 1;
            As[nb][akq0*4+0][arow0] = pa0.x; As[nb][akq0*4+1][arow0] = pa0.y;
            As[nb][akq0*4+2][arow0] = pa0.z; As[nb][akq0*4+3][arow0] = pa0.w;
            As[nb][akq1*4+0][arow1] = pa1.x; As[nb][akq1*4+1][arow1] = pa1.y;
            As[nb][akq1*4+2][arow1] = pa1.z; As[nb][akq1*4+3][arow1] = pa1.w;
            *(float4*)&Bs[nb][bkrow0][bnq0*4] = pb0;
            *(float4*)&Bs[nb][bkrow1][bnq1*4] = pb1;
        }
        __syncthreads();
    }

#pragma unroll
    for (int rr = 0; rr < 8; rr++) {
        const int m = m0 + ty * 8 + rr;
        float vals[8];
        { float2 p = unpack2(acc[rr][0]); vals[0] = p.x; vals[1] = p.y; }
        { float2 p = unpack2(acc[rr][1]); vals[2] = p.x; vals[3] = p.y; }
        { float2 p = unpack2(acc[rr][2]); vals[4] = p.x; vals[5] = p.y; }
        { float2 p = unpack2(acc[rr][3]); vals[6] = p.x; vals[7] = p.y; }
#pragma unroll
        for (int q = 0; q < 8; q++) {
            const int nn = n0 + tx * 8 + q;
            float vv = vals[q];
            float res;
            switch (mode) {
                default:
                case 0: res = vv; break;
                case 3: { float zz = evec[nn] + vv;
                          res = 1.f / (1.f + expf(-zz)); } break;
                case 4: { float zz = evec[nn] + vv;
                          res = -log1pf(expf(-zz)) - 0.5f; } break;
                case 5: res = ex[(size_t)m * N + nn] + vv; break;
            }
            vals[q] = res;
        }
        float4 o0 = make_float4(vals[0], vals[1], vals[2], vals[3]);
        float4 o1 = make_float4(vals[4], vals[5], vals[6], vals[7]);
        *(float4*)&Cm[(size_t)m * N + n0 + tx * 8]     = o0;
        *(float4*)&Cm[(size_t)m * N + n0 + tx * 8 + 4] = o1;
    }
}

// ---------------------------------------------------------------------------
// ew0: xx = shift(x)-x; xmix bf16 hi/lo = x + xx*maa_x
// ---------------------------------------------------------------------------
__global__ void __launch_bounds__(256)
ew0_kernel(const float* __restrict__ x, const float* __restrict__ maa_x)
{
    size_t i4  = (size_t)blockIdx.x * 256 + threadIdx.x;
    size_t idx = i4 * 4;
    int c    = (int)(idx & (CC - 1));
    int nrow = (int)(idx >> 10);
    float4 xv = *(const float4*)&x[idx];
    float4 xp = make_float4(0.f, 0.f, 0.f, 0.f);
    if (nrow & (TT - 1))
        xp = *(const float4*)&x[idx - CC];
    float4 mv = *(const float4*)&maa_x[c];
    float4 d, xm;
    d.x = xp.x - xv.x;  xm.x = xv.x + d.x * mv.x;
    d.y = xp.y - xv.y;  xm.y = xv.y + d.y * mv.y;
    d.z = xp.z - xv.z;  xm.z = xv.z + d.z * mv.z;
    d.w = xp.w - xv.w;  xm.w = xv.w + d.w * mv.w;
    *(float4*)&g_s.xx[idx] = d;
    uint2 h, l;
    split4(xm, h, l);
    *(uint2*)&g_s.xmixh[idx] = h;
    *(uint2*)&g_s.xmixl[idx] = l;
}

// ---------------------------------------------------------------------------
// combine
// ---------------------------------------------------------------------------
__global__ void __launch_bounds__(256)
combine_kernel()
{
    int n   = blockIdx.x;
    int tid = threadIdx.x;
    size_t off = (size_t)n * CC + tid * 4;

    float4 kkv = *(float4*)&g_s.kk[off];
    float ss = kkv.x*kkv.x + kkv.y*kkv.y + kkv.z*kkv.z + kkv.w*kkv.w;
#pragma unroll
    for (int o = 8; o; o >>= 1) ss += __shfl_xor_sync(0xffffffffu, ss, o, 16);
    float inv = 1.f / fmaxf(sqrtf(ss), 1e-12f);

    float4 kq = *(float4*)&g_s.k[off];
    float4 aq = *(float4*)&g_s.asig[off];
    float4 mq = *(float4*)&g_s.ma[off];
    float4 wq = *(float4*)&g_s.w[off];
    float4 mk = *(float4*)&g_s.mk2[off];
    float4 kfv, ddv, avv, bvv;
#define CMB(X) { float fac = mq.X + aq.X * (1.f - mq.X); \
    float ee = expf(fminf(wq.X * mk.X, 0.f)); \
    kfv.X = kq.X * fac * ee; \
    ddv.X = expf(wq.X); \
    float kn = kkv.X * inv; \
    avv.X = -kn; bvv.X = kn * aq.X; }
    CMB(x) CMB(y) CMB(z) CMB(w)
#undef CMB
    *(float4*)&g_s.kf[off] = kfv;
    *(float4*)&g_s.dd[off] = ddv;
    *(float4*)&g_s.av[off] = avv;
    *(float4*)&g_s.bv[off] = bvv;
}

// ---------------------------------------------------------------------------
// WKV-7 scan: cp.async 3-deep pipeline
// ---------------------------------------------------------------------------
__global__ void __launch_bounds__(256)
wkv_kernel()
{
    const int blk = blockIdx.x;
    const int b = blk >> 4;
    const int h = blk & 15;
    const int tid = threadIdx.x;
    const int i  = tid >> 2;
    const int jq = tid & 3;

    __shared__ __align__(16) float sb[4][6][64];
    const size_t rowbase = ((size_t)b * TT) * CC + h * NN;

    const float* gsrc = 0;
    uint32_t sdst[4];
    if (tid < 96) {
        int larr = tid >> 4, lq = tid & 15;
        const float* srcs[6] = { g_s.r, g_s.dd, g_s.kf, g_s.av, g_s.bv, g_s.v };
        gsrc = srcs[larr] + rowbase + lq * 4;
#pragma unroll
        for (int q = 0; q < 4; q++) sdst[q] = smem_u32(&sb[q][larr][lq * 4]);
    }

#pragma unroll
    for (int pre = 0; pre < 3; pre++) {
        if (tid < 96) cp_async16(sdst[pre], gsrc + (size_t)pre * CC);
        CP_COMMIT();
    }

    unsigned long long S2[8];
#pragma unroll
    for (int u = 0; u < 8; u++) S2[u] = 0ull;

    float* yout = g_s.y + rowbase + i;

    for (int t = 0; t < TT; t++) {
        CP_WAIT2();
        __syncthreads();
        const int p = t & 3;

        const ulonglong2* r2p = (const ulonglong2*)(sb[p][0] + jq * 16);
        const ulonglong2* d2p = (const ulonglong2*)(sb[p][1] + jq * 16);
        const ulonglong2* k2p = (const ulonglong2*)(sb[p][2] + jq * 16);
        const ulonglong2* a2p = (const ulonglong2*)(sb[p][3] + jq * 16);
        const ulonglong2* b2p = (const ulonglong2*)(sb[p][4] + jq * 16);
        const float vi = sb[p][5][i];

        ulonglong2 Rv[4], Dv[4], Kv[4], Av[4], Bv[4];
#pragma unroll
        for (int u = 0; u < 4; u++) {
            Rv[u] = r2p[u]; Dv[u] = d2p[u]; Kv[u] = k2p[u];
            Av[u] = a2p[u]; Bv[u] = b2p[u];
        }

        if (tid < 96 && t + 3 < TT)
            cp_async16(sdst[(t + 3) & 3], gsrc + (size_t)(t + 3) * CC);
        CP_COMMIT();

        unsigned long long sa0 = 0ull, sa1 = 0ull, pp0 = 0ull, pp1 = 0ull;
        unsigned long long br0 = 0ull, br1 = 0ull, kr0 = 0ull, kr1 = 0ull;
#pragma unroll
        for (int u = 0; u < 4; u++) {
            unsigned long long drx = mul2(Dv[u].x, Rv[u].x);
            unsigned long long dry = mul2(Dv[u].y, Rv[u].y);
            fma2(sa0, S2[2*u],   Av[u].x);
            fma2(sa1, S2[2*u+1], Av[u].y);
            fma2(pp0, S2[2*u],   drx);
            fma2(pp1, S2[2*u+1], dry);
            fma2(br0, Bv[u].x, Rv[u].x);
            fma2(br1, Bv[u].y, Rv[u].y);
            fma2(kr0, Kv[u].x, Rv[u].x);
            fma2(kr1, Kv[u].y, Rv[u].y);
        }
        float sa = hadd4(sa0, sa1);
        float pp = hadd4(pp0, pp1);
        float br = hadd4(br0, br1);
        float kr = hadd4(kr0, kr1);
        sa += __shfl_xor_sync(0xffffffffu, sa, 1, 4);
        pp += __shfl_xor_sync(0xffffffffu, pp, 1, 4);
        br += __shfl_xor_sync(0xffffffffu, br, 1, 4);
        kr += __shfl_xor_sync(0xffffffffu, kr, 1, 4);
        sa += __shfl_xor_sync(0xffffffffu, sa, 2, 4);
        pp += __shfl_xor_sync(0xffffffffu, pp, 2, 4);
        br += __shfl_xor_sync(0xffffffffu, br, 2, 4);
        kr += __shfl_xor_sync(0xffffffffu, kr, 2, 4);

        if (jq == 0) yout[(size_t)t * CC] = pp + sa * br + vi * kr;

        const unsigned long long sa2 = dup2(sa);
        const unsigned long long v2  = dup2(vi);
#pragma unroll
        for (int u = 0; u < 4; u++) {
            S2[2*u]   = fma2g(S2[2*u],   Dv[u].x,
                              fma2g(sa2, Bv[u].x, mul2(v2, Kv[u].x)));
            S2[2*u+1] = fma2g(S2[2*u+1], Dv[u].y,
                              fma2g(sa2, Bv[u].y, mul2(v2, Kv[u].y)));
        }
    }
}

// ---------------------------------------------------------------------------
// post: GroupNorm + bonus + gate -> z (bf16 hi/lo)
// ---------------------------------------------------------------------------
__global__ void __launch_bounds__(256)
post_kernel(const float* __restrict__ faaaa,
            const float* __restrict__ lnw, const float* __restrict__ lnb)
{
    int n   = blockIdx.x;
    int tid = threadIdx.x;
    int c   = tid * 4;
    size_t off = (size_t)n * CC + c;

    float4 yv = *(float4*)&g_s.y [off];
    float4 rv = *(float4*)&g_s.r [off];
    float4 kv = *(float4*)&g_s.kf[off];
    float4 vv = *(float4*)&g_s.v [off];
    float4 gv = *(float4*)&g_s.g [off];
    float4 fv = *(const float4*)&faaaa[c];

    float s  = yv.x + yv.y + yv.z + yv.w;
    float s2 = yv.x*yv.x + yv.y*yv.y + yv.z*yv.z + yv.w*yv.w;
    float dk = rv.x*kv.x*fv.x + rv.y*kv.y*fv.y + rv.z*kv.z*fv.z + rv.w*kv.w*fv.w;
#pragma unroll
    for (int o = 8; o; o >>= 1) {
        s  += __shfl_xor_sync(0xffffffffu, s,  o, 16);
        s2 += __shfl_xor_sync(0xffffffffu, s2, o, 16);
        dk += __shfl_xor_sync(0xffffffffu, dk, o, 16);
    }
    float mean = s  * (1.f / 64.f);
    float var  = s2 * (1.f / 64.f) - mean * mean;
    float rs   = rsqrtf(var + 64e-5f);

    float4 lw = *(const float4*)&lnw[c];
    float4 lb = *(const float4*)&lnb[c];
    float4 z;
    z.x = (((yv.x - mean) * rs) * lw.x + lb.x + dk * vv.x) * gv.x;
    z.y = (((yv.y - mean) * rs) * lw.y + lb.y + dk * vv.y) * gv.y;
    z.z = (((yv.z - mean) * rs) * lw.z + lb.z + dk * vv.z) * gv.z;
    z.w = (((yv.w - mean) * rs) * lw.w + lb.w + dk * vv.w) * gv.w;
    uint2 h, l;
    split4(z, h, l);
    *(uint2*)&g_s.zh[off] = h;
    *(uint2*)&g_s.zl[off] = l;
}

// ---------------------------------------------------------------------------
// Host orchestration
// ---------------------------------------------------------------------------
static void g128(const float* A, const float* Bp, float* Cp,
                 int N, int K, int lda, int mode,
                 const float* ex, const float* evec)
{
    dim3 grid(N / 128, MM / 128);
    gemm128<<<grid, 256>>>(A, Bp, Cp, N, K, lda, mode, ex, evec);
}
static void gmma(const bf16* Ah, const bf16* Al, const bf16* Bh,
                 const bf16* Bl, float* Cp, int K)
{
    dim3 grid(8, MM / 128);
    gemm_mma2<<<grid, 256, MMA_SMEM>>>(Ah, Al, Bh, Bl, Cp, K);
}
static void convw(const float* src, bf16* h, bf16* l, int elems)
{
    conv_bf16<<<elems / 1024, 256>>>((const float4*)src, (uint2*)h, (uint2*)l);
}

#define UP128_SMEM 61440
#define UP32_SMEM  30720

extern "C" void kernel_launch(void* const* d_in, const int* in_sizes, int n_in,
                              void* d_out, int out_size)
{
    const float* x       = (const float*)d_in[0];
    const float* maa_x   = (const float*)d_in[1];
    const float* maa_rg  = (const float*)d_in[2];
    const float* maa_wa  = (const float*)d_in[3];
    const float* maa_k   = (const float*)d_in[4];
    const float* maa_v   = (const float*)d_in[5];
    const float* maa_w1  = (const float*)d_in[6];
    const float* maa_w2  = (const float*)d_in[7];
    const float* tdecay  = (const float*)d_in[8];
    const float* dw1     = (const float*)d_in[9];
    const float* dw2     = (const float*)d_in[10];
    const float* faaaa   = (const float*)d_in[11];
    const float* taaaaa  = (const float*)d_in[12];
    const float* aw1     = (const float*)d_in[13];
    const float* aw2     = (const float*)d_in[14];
    const float* kw1     = (const float*)d_in[15];
    const float* kw2     = (const float*)d_in[16];
    const float* gw1     = (const float*)d_in[17];
    const float* gw2     = (const float*)d_in[18];
    const float* maw1    = (const float*)d_in[19];
    const float* maw2    = (const float*)d_in[20];
    const float* tmisca  = (const float*)d_in[21];
    const float* mkw1    = (const float*)d_in[22];
    const float* mkw2    = (const float*)d_in[23];
    const float* tmisck  = (const float*)d_in[24];
    const float* wr      = (const float*)d_in[25];
    const float* wk      = (const float*)d_in[26];
    const float* wv      = (const float*)d_in[27];
    const float* wo      = (const float*)d_in[28];
    const float* lnw     = (const float*)d_in[29];
    const float* lnb     = (const float*)d_in[30];
    float* out = (float*)d_out;
    (void)in_sizes; (void)n_in; (void)out_size;

    Scratch* S = nullptr;
    cudaGetSymbolAddress((void**)&S, g_s);
    cudaFuncSetAttribute(gemm_mma2, cudaFuncAttributeMaxDynamicSharedMemorySize,
                         MMA_SMEM);
    cudaFuncSetAttribute(fused_mix, cudaFuncAttributeMaxDynamicSharedMemorySize,
                         MIX_SMEM);
    cudaFuncSetAttribute(gemm_up<128>,
                         cudaFuncAttributeMaxDynamicSharedMemorySize, UP128_SMEM);
    cudaFuncSetAttribute(gemm_up<32>,
                         cudaFuncAttributeMaxDynamicSharedMemorySize, UP32_SMEM);

    // 1-5: setup so launch #6 is gmma(r) for ncu sampling
    convw(wr, S->wrh, S->wrl, CC * CC);                                  // 1
    ew0_kernel<<<(MM * CC / 4) / 256, 256>>>(x, maa_x);                  // 2
    packT_w1<<<512, 256>>>(maa_w1, S->mw1Th, S->mw1Tl);                  // 3
    gemm_up<128><<<64, 256, UP128_SMEM>>>(S->xmixh, S->xmixl,            // 4
        S->mw1Th, S->mw1Tl, S->mixin, 128, 0, 0);
    fused_mix<<<dim3(8, 32), 256, MIX_SMEM>>>(x, maa_w2,                 // 5
        maa_rg, maa_wa, maa_k, maa_v);
    gmma(S->xrgh, S->xrgl, S->wrh, S->wrl, S->r, 1024);                  // 6
    convw(wk, S->wkh, S->wkl, CC * CC);                                  // 7
    gmma(S->xkh, S->xkl, S->wkh, S->wkl, S->k, 1024);                    // 8
    convw(wv, S->wvh, S->wvl, CC * CC);                                  // 9
    gmma(S->xvh, S->xvl, S->wvh, S->wvl, S->v, 1024);                    // 10

    // gate
    packT_w1<<<512, 256>>>(gw1, S->gw1Th, S->gw1Tl);
    gemm_up<128><<<64, 256, UP128_SMEM>>>(S->xrgh, S->xrgl,
        S->gw1Th, S->gw1Tl, S->gate1, 128, S->g1h, S->g1l);
    transconv_kernel<<<dim3(32, 4), 256>>>(gw2, S->gw2Th, S->gw2Tl);
    gmma(S->g1h, S->g1l, S->gw2Th, S->gw2Tl, S->g, 128);

    // xwa LoRA group (decay + aaa + ma), packed N=96 -> padded 128
    packT_wa<<<512, 256>>>(dw1, aw1, maw1);
    gemm_up<128><<<64, 256, UP128_SMEM>>>(S->xwah, S->xwal,
        S->waTh, S->waTl, S->lora_wa, 64, 0, 0);
    g128(S->lora_wa,      dw2,  S->w,    1024, 64, 128, 4, 0, tdecay);
    g128(S->lora_wa + 64, aw2,  S->asig, 1024, 16, 128, 3, 0, taaaaa);
    g128(S->lora_wa + 80, maw2, S->ma,   1024, 16, 128, 3, 0, tmisca);

    // xk LoRA group (kkk + mk), packed N=32
    packT_k<<<128, 256>>>(kw1, mkw1);
    gemm_up<32><<<64, 256, UP32_SMEM>>>(S->xkh, S->xkl,
        S->kTh, S->kTl, S->lora_k, 16, 0, 0);
    g128(S->lora_k,      kw2,  S->kk,  1024, 16, 32, 5, S->k, 0);
    g128(S->lora_k + 16, mkw2, S->mk2, 1024, 16, 32, 3, 0, tmisck);

    // combine + scan + post + output
    combine_kernel<<<MM, 256>>>();
    wkv_kernel<<<BB * HH, 256>>>();
    post_kernel<<<MM, 256>>>(faaaa, lnw, lnb);
    convw(wo, S->woh, S->wol, CC * CC);
    gmma(S->zh, S->zl, S->woh, S->wol, out, 1024);
}

// round 9
// speedup vs baseline: 2.3702x; 1.0219x over previous
#include <cuda_runtime.h>
#include <cuda_bf16.h>
#include <math.h>
#include <stdint.h>
#include <string.h>

#define BB 4
#define TT 1024
#define CC 1024
#define HH 16
#define NN 64
#define MM (BB*TT)   // 4096 rows

typedef __nv_bfloat16 bf16;

// ---------------------------------------------------------------------------
// Scratch (static device memory)
// ---------------------------------------------------------------------------
struct Scratch {
    float xx   [MM*CC];
    float mixin[MM*128];
    float r    [MM*CC];
    float k    [MM*CC];
    float v    [MM*CC];
    float g    [MM*CC];
    float w    [MM*CC];
    float kk   [MM*CC];
    float asig [MM*CC];
    float ma   [MM*CC];
    float mk2  [MM*CC];
    float kf   [MM*CC];
    float dd   [MM*CC];
    float av   [MM*CC];
    float bv   [MM*CC];
    float y    [MM*CC];
    // bf16 hi/lo activations
    bf16 xmixh[MM*CC], xmixl[MM*CC];
    bf16 xrgh[MM*CC], xrgl[MM*CC];
    bf16 xwah[MM*CC], xwal[MM*CC];
    bf16 xkh [MM*CC], xkl [MM*CC];
    bf16 xvh [MM*CC], xvl [MM*CC];
    bf16 zh  [MM*CC], zl  [MM*CC];
    bf16 g1h [MM*128], g1l [MM*128];
    bf16 loraAh[MM*160], loraAl[MM*160];
    // bf16 hi/lo weights
    bf16 wrh[CC*CC], wrl[CC*CC];
    bf16 wkh[CC*CC], wkl[CC*CC];
    bf16 wvh[CC*CC], wvl[CC*CC];
    bf16 woh[CC*CC], wol[CC*CC];
    bf16 gw2Th[CC*128], gw2Tl[CC*128];
    bf16 mw1Th[128*1024], mw1Tl[128*1024];
    bf16 gw1Th[128*1024], gw1Tl[128*1024];
    bf16 waTh [128*1024], waTl [128*1024];
    bf16 kTh  [32*1024],  kTl  [32*1024];
    bf16 bigBh[5120*160], bigBl[5120*160];
};
__device__ Scratch g_s;

// ---------------------------------------------------------------------------
// Packed f32x2 helpers
// ---------------------------------------------------------------------------
__device__ __forceinline__ unsigned long long dup2(float x) {
    unsigned long long r;
    asm("mov.b64 %0, {%1, %1};" : "=l"(r) : "f"(x));
    return r;
}
__device__ __forceinline__ void fma2(unsigned long long& acc,
                                     unsigned long long a,
                                     unsigned long long b) {
    asm("fma.rn.f32x2 %0, %1, %2, %0;" : "+l"(acc) : "l"(a), "l"(b));
}
__device__ __forceinline__ unsigned long long fma2g(unsigned long long a,
                                                    unsigned long long b,
                                                    unsigned long long c) {
    unsigned long long d;
    asm("fma.rn.f32x2 %0, %1, %2, %3;" : "=l"(d) : "l"(a), "l"(b), "l"(c));
    return d;
}
__device__ __forceinline__ unsigned long long mul2(unsigned long long a,
                                                   unsigned long long b) {
    unsigned long long d;
    asm("mul.rn.f32x2 %0, %1, %2;" : "=l"(d) : "l"(a), "l"(b));
    return d;
}
__device__ __forceinline__ float2 unpack2(unsigned long long v) {
    float2 f;
    asm("mov.b64 {%0, %1}, %2;" : "=f"(f.x), "=f"(f.y) : "l"(v));
    return f;
}
__device__ __forceinline__ float hadd4(unsigned long long a,
                                       unsigned long long b) {
    float2 f = unpack2(a), g = unpack2(b);
    return (f.x + f.y) + (g.x + g.y);
}
__device__ __forceinline__ uint32_t smem_u32(const void* p) {
    uint32_t a;
    asm("{ .reg .u64 t; cvta.to.shared.u64 t, %1; cvt.u32.u64 %0, t; }"
        : "=r"(a) : "l"(p));
    return a;
}

// cp.async helpers
__device__ __forceinline__ void cp_async16(uint32_t saddr, const void* gptr) {
    asm volatile("cp.async.cg.shared.global [%0], [%1], 16;"
        :: "r"(saddr), "l"(gptr) : "memory");
}
#define CP_COMMIT() asm volatile("cp.async.commit_group;" ::: "memory")
#define CP_WAIT0()  asm volatile("cp.async.wait_group 0;" ::: "memory")
#define CP_WAIT2()  asm volatile("cp.async.wait_group 2;" ::: "memory")

// hi/lo splits
__device__ __forceinline__ void split4(float4 f, uint2& h, uint2& l) {
    __nv_bfloat162 h01 = __floats2bfloat162_rn(f.x, f.y);
    __nv_bfloat162 h23 = __floats2bfloat162_rn(f.z, f.w);
    float lx = f.x - __bfloat162float(h01.x);
    float ly = f.y - __bfloat162float(h01.y);
    float lz = f.z - __bfloat162float(h23.x);
    float lw = f.w - __bfloat162float(h23.y);
    __nv_bfloat162 l01 = __floats2bfloat162_rn(lx, ly);
    __nv_bfloat162 l23 = __floats2bfloat162_rn(lz, lw);
    memcpy(&h.x, &h01, 4); memcpy(&h.y, &h23, 4);
    memcpy(&l.x, &l01, 4); memcpy(&l.y, &l23, 4);
}
__device__ __forceinline__ void split2(float a, float b,
                                       uint32_t& h, uint32_t& l) {
    __nv_bfloat162 hh = __floats2bfloat162_rn(a, b);
    float la = a - __bfloat162float(hh.x);
    float lb = b - __bfloat162float(hh.y);
    __nv_bfloat162 ll = __floats2bfloat162_rn(la, lb);
    memcpy(&h, &hh, 4); memcpy(&l, &ll, 4);
}

// ---------------------------------------------------------------------------
// mma.sync / ldmatrix helpers
// ---------------------------------------------------------------------------
__device__ __forceinline__ void ldsm4(uint32_t* r, uint32_t addr) {
    asm volatile("ldmatrix.sync.aligned.m8n8.x4.shared.b16 {%0,%1,%2,%3}, [%4];"
        : "=r"(r[0]), "=r"(r[1]), "=r"(r[2]), "=r"(r[3]) : "r"(addr));
}
__device__ __forceinline__ void ldsm2(uint32_t* r, uint32_t addr) {
    asm volatile("ldmatrix.sync.aligned.m8n8.x2.shared.b16 {%0,%1}, [%2];"
        : "=r"(r[0]), "=r"(r[1]) : "r"(addr));
}
__device__ __forceinline__ void mma_bf16(float* c, const uint32_t* a,
                                         const uint32_t* b) {
    asm volatile("mma.sync.aligned.m16n8k16.row.col.f32.bf16.bf16.f32 "
        "{%0,%1,%2,%3}, {%4,%5,%6,%7}, {%8,%9}, {%0,%1,%2,%3};"
        : "+f"(c[0]), "+f"(c[1]), "+f"(c[2]), "+f"(c[3])
        : "r"(a[0]), "r"(a[1]), "r"(a[2]), "r"(a[3]), "r"(b[0]), "r"(b[1]));
}

// ---------------------------------------------------------------------------
// gemm_mma2: C[M,1024] = (Ah+Al)[M,K] @ (Bh+Bl)[1024,K]^T, fp32 accum.
// cp.async double-buffered, CTA 128x128, chunk 32.
// ---------------------------------------------------------------------------
#define MMA_SMEM 81920

__global__ void __launch_bounds__(256)
gemm_mma2(const bf16* __restrict__ Ah, const bf16* __restrict__ Al,
          const bf16* __restrict__ Bh, const bf16* __restrict__ Bl,
          float* __restrict__ Cm, int K)
{
    extern __shared__ __align__(16) char sm[];
    const uint32_t sb = smem_u32(sm);

    const int tid  = threadIdx.x;
    const int lane = tid & 31;
    const int wid  = tid >> 5;
    const int wm   = wid & 1;
    const int wn   = wid >> 1;
    const int n0 = blockIdx.x * 128;
    const int m0 = blockIdx.y * 128;

    const int row = tid >> 1, half = tid & 1;
    const bf16* pAh = Ah + (size_t)(m0 + row) * K + half * 16;
    const bf16* pAl = Al + (size_t)(m0 + row) * K + half * 16;
    const bf16* pBh = Bh + (size_t)(n0 + row) * K + half * 16;
    const bf16* pBl = Bl + (size_t)(n0 + row) * K + half * 16;
    const uint32_t st = (uint32_t)(row * 80 + half * 32);

    const uint32_t aLoff = (uint32_t)((lane & 15) * 80 + (lane >> 4) * 16);
    const uint32_t bLoff = (uint32_t)(((lane & 7) + ((lane >> 4) & 1) * 8) * 80
                                      + ((lane >> 3) & 1) * 16);

    float c[4][4][4];
#pragma unroll
    for (int i = 0; i < 4; i++)
#pragma unroll
        for (int j = 0; j < 4; j++)
#pragma unroll
            for (int q = 0; q < 4; q++) c[i][j][q] = 0.f;

    const int chunks = K >> 5;

    // prologue: async-load chunk 0 into buffer 0
    {
        uint32_t d = sb + st;
        cp_async16(d,             pAh); cp_async16(d + 16,         pAh + 8);
        cp_async16(d + 10240,     pAl); cp_async16(d + 10240 + 16, pAl + 8);
        cp_async16(d + 20480,     pBh); cp_async16(d + 20480 + 16, pBh + 8);
        cp_async16(d + 30720,     pBl); cp_async16(d + 30720 + 16, pBl + 8);
        CP_COMMIT();
        CP_WAIT0();
    }
    __syncthreads();

    for (int cidx = 0; cidx < chunks; cidx++) {
        const uint32_t bufOff = (uint32_t)((cidx & 1) * 40960);
        const bool more = (cidx + 1 < chunks);

        if (more) {
            const int ko = (cidx + 1) * 32;
            uint32_t d = sb + (uint32_t)(((cidx + 1) & 1) * 40960) + st;
            cp_async16(d,             pAh + ko); cp_async16(d + 16,         pAh + ko + 8);
            cp_async16(d + 10240,     pAl + ko); cp_async16(d + 10240 + 16, pAl + ko + 8);
            cp_async16(d + 20480,     pBh + ko); cp_async16(d + 20480 + 16, pBh + ko + 8);
            cp_async16(d + 30720,     pBl + ko); cp_async16(d + 30720 + 16, pBl + ko + 8);
            CP_COMMIT();
        }

        const uint32_t aBase = sb + bufOff + (uint32_t)(wm * 64 * 80) + aLoff;
        const uint32_t bBase = sb + bufOff + 20480u + (uint32_t)(wn * 32 * 80) + bLoff;
#pragma unroll
        for (int ks = 0; ks < 2; ks++) {
            uint32_t afh[4][4], afl[4][4];
#pragma unroll
            for (int mi = 0; mi < 4; mi++) {
                ldsm4(afh[mi], aBase + 0u     + (uint32_t)(mi * 1280 + ks * 32));
                ldsm4(afl[mi], aBase + 10240u + (uint32_t)(mi * 1280 + ks * 32));
            }
            uint32_t bfh[2][4], bfl[2][4];
#pragma unroll
            for (int np = 0; np < 2; np++) {
                ldsm4(bfh[np], bBase + 0u     + (uint32_t)(np * 1280 + ks * 32));
                ldsm4(bfl[np], bBase + 10240u + (uint32_t)(np * 1280 + ks * 32));
            }
#pragma unroll
            for (int mi = 0; mi < 4; mi++) {
#pragma unroll
                for (int ni = 0; ni < 4; ni++) {
                    const uint32_t* bh = &bfh[ni >> 1][(ni & 1) * 2];
                    const uint32_t* bl = &bfl[ni >> 1][(ni & 1) * 2];
                    mma_bf16(c[mi][ni], afh[mi], bh);
                    mma_bf16(c[mi][ni], afh[mi], bl);
                    mma_bf16(c[mi][ni], afl[mi], bh);
                }
            }
        }

        if (more) CP_WAIT0();
        __syncthreads();
    }

    const int erow = m0 + wm * 64 + (lane >> 2);
    const int ecol = n0 + wn * 32 + (lane & 3) * 2;
#pragma unroll
    for (int mi = 0; mi < 4; mi++) {
#pragma unroll
        for (int ni = 0; ni < 4; ni++) {
            size_t base0 = (size_t)(erow + mi * 16)     * 1024 + ecol + ni * 8;
            size_t base1 = (size_t)(erow + mi * 16 + 8) * 1024 + ecol + ni * 8;
            *(float2*)&Cm[base0] = make_float2(c[mi][ni][0], c[mi][ni][1]);
            *(float2*)&Cm[base1] = make_float2(c[mi][ni][2], c[mi][ni][3]);
        }
    }
}

// ---------------------------------------------------------------------------
// gemm_down: fused LoRA down-projections as one block-diagonal GEMM.
// C[4096, 5120] = (loraAh+loraAl)[4096,160] @ (bigBh+bigBl)[5120,160]^T
// column block b = n/1024 selects output + epilogue:
//   0: w    = -log1p(exp(-(tdecay+acc)))-0.5
//   1: asig = sigmoid(taaaaa+acc)
//   2: ma   = sigmoid(tmisca+acc)
//   3: kk   = k + acc
//   4: mk2  = sigmoid(tmisck+acc)
// ---------------------------------------------------------------------------
__global__ void __launch_bounds__(256)
gemm_down(const float* __restrict__ tdecay, const float* __restrict__ taaaaa,
          const float* __restrict__ tmisca, const float* __restrict__ tmisck)
{
    extern __shared__ __align__(16) char sm[];
    const uint32_t sb = smem_u32(sm);

    const int tid  = threadIdx.x;
    const int lane = tid & 31;
    const int wid  = tid >> 5;
    const int wm   = wid & 1;
    const int wn   = wid >> 1;
    const int n0 = blockIdx.x * 128;
    const int m0 = blockIdx.y * 128;

    const int row = tid >> 1, half = tid & 1;
    const bf16* pAh = g_s.loraAh + (size_t)(m0 + row) * 160 + half * 16;
    const bf16* pAl = g_s.loraAl + (size_t)(m0 + row) * 160 + half * 16;
    const bf16* pBh = g_s.bigBh  + (size_t)(n0 + row) * 160 + half * 16;
    const bf16* pBl = g_s.bigBl  + (size_t)(n0 + row) * 160 + half * 16;
    const uint32_t st = (uint32_t)(row * 80 + half * 32);

    const uint32_t aLoff = (uint32_t)((lane & 15) * 80 + (lane >> 4) * 16);
    const uint32_t bLoff = (uint32_t)(((lane & 7) + ((lane >> 4) & 1) * 8) * 80
                                      + ((lane >> 3) & 1) * 16);

    float c[4][4][4];
#pragma unroll
    for (int i = 0; i < 4; i++)
#pragma unroll
        for (int j = 0; j < 4; j++)
#pragma unroll
            for (int q = 0; q < 4; q++) c[i][j][q] = 0.f;

    {
        uint32_t d = sb + st;
        cp_async16(d,             pAh); cp_async16(d + 16,         pAh + 8);
        cp_async16(d + 10240,     pAl); cp_async16(d + 10240 + 16, pAl + 8);
        cp_async16(d + 20480,     pBh); cp_async16(d + 20480 + 16, pBh + 8);
        cp_async16(d + 30720,     pBl); cp_async16(d + 30720 + 16, pBl + 8);
        CP_COMMIT();
        CP_WAIT0();
    }
    __syncthreads();

    for (int cidx = 0; cidx < 5; cidx++) {
        const uint32_t bufOff = (uint32_t)((cidx & 1) * 40960);
        const bool more = (cidx + 1 < 5);

        if (more) {
            const int ko = (cidx + 1) * 32;
            uint32_t d = sb + (uint32_t)(((cidx + 1) & 1) * 40960) + st;
            cp_async16(d,             pAh + ko); cp_async16(d + 16,         pAh + ko + 8);
            cp_async16(d + 10240,     pAl + ko); cp_async16(d + 10240 + 16, pAl + ko + 8);
            cp_async16(d + 20480,     pBh + ko); cp_async16(d + 20480 + 16, pBh + ko + 8);
            cp_async16(d + 30720,     pBl + ko); cp_async16(d + 30720 + 16, pBl + ko + 8);
            CP_COMMIT();
        }

        const uint32_t aBase = sb + bufOff + (uint32_t)(wm * 64 * 80) + aLoff;
        const uint32_t bBase = sb + bufOff + 20480u + (uint32_t)(wn * 32 * 80) + bLoff;
#pragma unroll
        for (int ks = 0; ks < 2; ks++) {
            uint32_t afh[4][4], afl[4][4];
#pragma unroll
            for (int mi = 0; mi < 4; mi++) {
                ldsm4(afh[mi], aBase + 0u     + (uint32_t)(mi * 1280 + ks * 32));
                ldsm4(afl[mi], aBase + 10240u + (uint32_t)(mi * 1280 + ks * 32));
            }
            uint32_t bfh[2][4], bfl[2][4];
#pragma unroll
            for (int np = 0; np < 2; np++) {
                ldsm4(bfh[np], bBase + 0u     + (uint32_t)(np * 1280 + ks * 32));
                ldsm4(bfl[np], bBase + 10240u + (uint32_t)(np * 1280 + ks * 32));
            }
#pragma unroll
            for (int mi = 0; mi < 4; mi++) {
#pragma unroll
                for (int ni = 0; ni < 4; ni++) {
                    const uint32_t* bh = &bfh[ni >> 1][(ni & 1) * 2];
                    const uint32_t* bl = &bfl[ni >> 1][(ni & 1) * 2];
                    mma_bf16(c[mi][ni], afh[mi], bh);
                    mma_bf16(c[mi][ni], afh[mi], bl);
                    mma_bf16(c[mi][ni], afl[mi], bh);
                }
            }
        }

        if (more) CP_WAIT0();
        __syncthreads();
    }

    // epilogue: block select
    const int blk = n0 >> 10;
    float* outp; const float* ev; int mode;
    switch (blk) {
        case 0:  outp = g_s.w;    ev = tdecay; mode = 4; break;
        case 1:  outp = g_s.asig; ev = taaaaa; mode = 3; break;
        case 2:  outp = g_s.ma;   ev = tmisca; mode = 3; break;
        case 3:  outp = g_s.kk;   ev = 0;      mode = 5; break;
        default: outp = g_s.mk2;  ev = tmisck; mode = 3; break;
    }
    const int erow = m0 + wm * 64 + (lane >> 2);
    const int ecol = (n0 & 1023) + wn * 32 + (lane & 3) * 2;
#pragma unroll
    for (int mi = 0; mi < 4; mi++) {
#pragma unroll
        for (int ni = 0; ni < 4; ni++) {
            const int col = ecol + ni * 8;
            const int r0 = erow + mi * 16, r1 = r0 + 8;
            float v0 = c[mi][ni][0], v1 = c[mi][ni][1];
            float v2 = c[mi][ni][2], v3 = c[mi][ni][3];
            if (mode == 4) {
                float e0 = ev[col], e1 = ev[col + 1];
                v0 = -log1pf(expf(-(e0 + v0))) - 0.5f;
                v1 = -log1pf(expf(-(e1 + v1))) - 0.5f;
                v2 = -log1pf(expf(-(e0 + v2))) - 0.5f;
                v3 = -log1pf(expf(-(e1 + v3))) - 0.5f;
            } else if (mode == 3) {
                float e0 = ev[col], e1 = ev[col + 1];
                v0 = 1.f / (1.f + expf(-(e0 + v0)));
                v1 = 1.f / (1.f + expf(-(e1 + v1)));
                v2 = 1.f / (1.f + expf(-(e0 + v2)));
                v3 = 1.f / (1.f + expf(-(e1 + v3)));
            } else {
                float2 k0 = *(const float2*)&g_s.k[(size_t)r0 * 1024 + col];
                float2 k1 = *(const float2*)&g_s.k[(size_t)r1 * 1024 + col];
                v0 += k0.x; v1 += k0.y; v2 += k1.x; v3 += k1.y;
            }
            *(float2*)&outp[(size_t)r0 * 1024 + col] = make_float2(v0, v1);
            *(float2*)&outp[(size_t)r1 * 1024 + col] = make_float2(v2, v3);
        }
    }
}

// ---------------------------------------------------------------------------
// gemm_up<BN>: C[4096,BN] = (Ah+Al)[4096,1024] @ (Bh+Bl)[BN,1024]^T
// CTA 32xBN (grid 128), 8 warps, cp.async double-buffered, chunk 32.
// Epilogue: tanh on local cols < tanhN; fp32 out (stride BN) if Cm != 0;
// bf16 hi/lo out at [row*ostride + ocol + col] if oh != 0.
// ---------------------------------------------------------------------------
template<int BN>
__global__ void __launch_bounds__(256)
gemm_up(const bf16* __restrict__ Ah, const bf16* __restrict__ Al,
        const bf16* __restrict__ Bh, const bf16* __restrict__ Bl,
        float* __restrict__ Cm, int tanhN,
        bf16* __restrict__ oh, bf16* __restrict__ ol,
        int ostride, int ocol)
{
    constexpr int NI = BN / 32;               // 4 or 1
    constexpr int B_BYTES = BN * 80;
    constexpr int OFF_AL = 2560;
    constexpr int OFF_BH = 5120;
    constexpr int BUF = 5120 + 2 * B_BYTES;
    constexpr int BITER = (BN * 4 + 255) / 256;

    extern __shared__ __align__(16) char sm[];
    const uint32_t sb = smem_u32(sm);

    const int tid  = threadIdx.x;
    const int lane = tid & 31;
    const int wid  = tid >> 5;
    const int wm   = wid & 1;
    const int wn   = wid >> 1;
    const int m0 = blockIdx.x * 32;

    const int arow = (tid & 127) >> 2, aq = tid & 3;
    const bf16* pAh = Ah + (size_t)(m0 + arow) * 1024 + aq * 8;
    const bf16* pAl = Al + (size_t)(m0 + arow) * 1024 + aq * 8;
    const uint32_t stA = (uint32_t)(arow * 80 + aq * 16);

    const uint32_t aLoff = (uint32_t)((lane & 15) * 80 + (lane >> 4) * 16);
    const uint32_t bLoff = (uint32_t)(((lane & 7) + ((lane >> 4) & 1) * 8) * 80
                                      + ((lane >> 3) & 1) * 16);
    const uint32_t bLoff2 = (uint32_t)((lane & 7) * 80 + ((lane >> 3) & 1) * 16);

    float c[NI][4];
#pragma unroll
    for (int j = 0; j < NI; j++)
#pragma unroll
        for (int q = 0; q < 4; q++) c[j][q] = 0.f;

    // prologue
    {
        uint32_t d = sb;
        if (tid < 128) {
            cp_async16(d + stA, pAh);
            cp_async16(d + OFF_AL + stA, pAl);
        }
#pragma unroll
        for (int it = 0; it < BITER; it++) {
            int u = tid + it * 256;
            if (u < BN * 4) {
                int brow = u >> 2, bq = u & 3;
                uint32_t stB = (uint32_t)(brow * 80 + bq * 16);
                cp_async16(d + OFF_BH + stB,
                           Bh + (size_t)brow * 1024 + bq * 8);
                cp_async16(d + OFF_BH + B_BYTES + stB,
                           Bl + (size_t)brow * 1024 + bq * 8);
            }
        }
        CP_COMMIT();
        CP_WAIT0();
    }
    __syncthreads();

    for (int cidx = 0; cidx < 32; cidx++) {
        const uint32_t bufOff = (uint32_t)((cidx & 1) * BUF);
        const bool more = (cidx + 1 < 32);

        if (more) {
            const int ko = (cidx + 1) * 32;
            uint32_t d = sb + (uint32_t)(((cidx + 1) & 1) * BUF);
            if (tid < 128) {
                cp_async16(d + stA, pAh + ko);
                cp_async16(d + OFF_AL + stA, pAl + ko);
            }
#pragma unroll
            for (int it = 0; it < BITER; it++) {
                int u = tid + it * 256;
                if (u < BN * 4) {
                    int brow = u >> 2, bq = u & 3;
                    uint32_t stB = (uint32_t)(brow * 80 + bq * 16);
                    cp_async16(d + OFF_BH + stB,
                               Bh + (size_t)brow * 1024 + ko + bq * 8);
                    cp_async16(d + OFF_BH + B_BYTES + stB,
                               Bl + (size_t)brow * 1024 + ko + bq * 8);
                }
            }
            CP_COMMIT();
        }

        const uint32_t aBase = sb + bufOff + (uint32_t)(wm * 16 * 80) + aLoff;
#pragma unroll
        for (int ks = 0; ks < 2; ks++) {
            uint32_t afh[4], afl[4];
            ldsm4(afh, aBase + (uint32_t)(ks * 32));
            ldsm4(afl, aBase + OFF_AL + (uint32_t)(ks * 32));
            if (BN == 128) {
                uint32_t bfh[2][4], bfl[2][4];
                const uint32_t bBase = sb + bufOff + OFF_BH
                                     + (uint32_t)(wn * 32 * 80) + bLoff;
#pragma unroll
                for (int np = 0; np < 2; np++) {
                    ldsm4(bfh[np], bBase + (uint32_t)(np * 1280 + ks * 32));
                    ldsm4(bfl[np], bBase + (uint32_t)(B_BYTES + np * 1280 + ks * 32));
                }
#pragma unroll
                for (int ni = 0; ni < NI; ni++) {
                    const uint32_t* bhp = &bfh[ni >> 1][(ni & 1) * 2];
                    const uint32_t* blp = &bfl[ni >> 1][(ni & 1) * 2];
                    mma_bf16(c[ni], afh, bhp);
                    mma_bf16(c[ni], afh, blp);
                    mma_bf16(c[ni], afl, bhp);
                }
            } else {
                uint32_t bfh2[2], bfl2[2];
                const uint32_t bBase = sb + bufOff + OFF_BH
                                     + (uint32_t)(wn * 8 * 80) + bLoff2
                                     + (uint32_t)(ks * 32);
                ldsm2(bfh2, bBase);
                ldsm2(bfl2, bBase + (uint32_t)B_BYTES);
                mma_bf16(c[0], afh, bfh2);
                mma_bf16(c[0], afh, bfl2);
                mma_bf16(c[0], afl, bfh2);
            }
        }

        if (more) CP_WAIT0();
        __syncthreads();
    }

    // epilogue
    const int r0 = m0 + wm * 16 + (lane >> 2);
    const int r1 = r0 + 8;
#pragma unroll
    for (int ni = 0; ni < NI; ni++) {
        const int col = wn * 8 * NI + ni * 8 + (lane & 3) * 2;
        float v0 = c[ni][0], v1 = c[ni][1];
        float v2 = c[ni][2], v3 = c[ni][3];
        if (col < tanhN) {
            v0 = tanhf(v0); v1 = tanhf(v1);
            v2 = tanhf(v2); v3 = tanhf(v3);
        }
        if (Cm) {
            *(float2*)&Cm[(size_t)r0 * BN + col] = make_float2(v0, v1);
            *(float2*)&Cm[(size_t)r1 * BN + col] = make_float2(v2, v3);
        }
        if (oh) {
            uint32_t h0, l0, h1, l1;
            split2(v0, v1, h0, l0);
            split2(v2, v3, h1, l1);
            *(uint32_t*)&oh[(size_t)r0 * ostride + ocol + col] = h0;
            *(uint32_t*)&ol[(size_t)r0 * ostride + ocol + col] = l0;
            *(uint32_t*)&oh[(size_t)r1 * ostride + ocol + col] = h1;
            *(uint32_t*)&ol[(size_t)r1 * ostride + ocol + col] = l1;
        }
    }
}

// ---------------------------------------------------------------------------
// conv_bf16: fp32 -> bf16 hi/lo arrays
// ---------------------------------------------------------------------------
__global__ void __launch_bounds__(256)
conv_bf16(const float4* __restrict__ src, uint2* __restrict__ h,
          uint2* __restrict__ l)
{
    int i = blockIdx.x * 256 + threadIdx.x;
    uint2 hh, ll;
    split4(src[i], hh, ll);
    h[i] = hh; l[i] = ll;
}

// ---------------------------------------------------------------------------
// transpose + convert: gw2 (128x1024 fp32) -> gw2T hi/lo (1024x128 bf16)
// ---------------------------------------------------------------------------
__global__ void __launch_bounds__(256)
transconv_kernel(const float* __restrict__ src, bf16* __restrict__ dh,
                 bf16* __restrict__ dl)
{
    __shared__ float tile[32][33];
    int bx = blockIdx.x;
    int by = blockIdx.y;
    int tx = threadIdx.x & 31, ty = threadIdx.x >> 5;
#pragma unroll
    for (int i = 0; i < 4; i++)
        tile[ty + i * 8][tx] = src[(size_t)(by * 32 + ty + i * 8) * 1024 + bx * 32 + tx];
    __syncthreads();
#pragma unroll
    for (int i = 0; i < 4; i++) {
        float v = tile[tx][ty + i * 8];
        bf16 hv = __float2bfloat16_rn(v);
        bf16 lv = __float2bfloat16_rn(v - __bfloat162float(hv));
        size_t di = (size_t)(bx * 32 + ty + i * 8) * 128 + by * 32 + tx;
        dh[di] = hv; dl[di] = lv;
    }
}

// ---------------------------------------------------------------------------
// packT kernels: w1 matrices (1024 x N) -> transposed bf16 hi/lo (N x 1024)
// ---------------------------------------------------------------------------
__global__ void __launch_bounds__(256)
packT_w1(const float* __restrict__ src, bf16* __restrict__ dh,
         bf16* __restrict__ dl)
{
    int idx = blockIdx.x * 256 + threadIdx.x;   // 128*1024
    int cth = idx >> 10, r = idx & 1023;
    float v = src[(size_t)r * 128 + cth];
    bf16 hv = __float2bfloat16_rn(v);
    bf16 lv = __float2bfloat16_rn(v - __bfloat162float(hv));
    dh[idx] = hv; dl[idx] = lv;
}
__global__ void __launch_bounds__(256)
packT_wa(const float* __restrict__ dw1, const float* __restrict__ aw1,
         const float* __restrict__ maw1)
{
    int idx = blockIdx.x * 256 + threadIdx.x;   // 128*1024
    int cth = idx >> 10, r = idx & 1023;
    float v = 0.f;
    if (cth < 64)      v = dw1[r * 64 + cth];
    else if (cth < 80) v = aw1[r * 16 + (cth - 64)];
    else if (cth < 96) v = maw1[r * 16 + (cth - 80)];
    bf16 hv = __float2bfloat16_rn(v);
    bf16 lv = __float2bfloat16_rn(v - __bfloat162float(hv));
    g_s.waTh[idx] = hv; g_s.waTl[idx] = lv;
}
__global__ void __launch_bounds__(256)
packT_k(const float* __restrict__ kw1, const float* __restrict__ mkw1)
{
    int idx = blockIdx.x * 256 + threadIdx.x;   // 32*1024
    int cth = idx >> 10, r = idx & 1023;
    float v = (cth < 16) ? kw1[r * 16 + cth] : mkw1[r * 16 + (cth - 16)];
    bf16 hv = __float2bfloat16_rn(v);
    bf16 lv = __float2bfloat16_rn(v - __bfloat162float(hv));
    g_s.kTh[idx] = hv; g_s.kTl[idx] = lv;
}

// ---------------------------------------------------------------------------
// pack_bigB: block-diagonal down-proj weight (5120 x 160) bf16 hi/lo
// ---------------------------------------------------------------------------
__global__ void __launch_bounds__(256)
pack_bigB(const float* __restrict__ dw2, const float* __restrict__ aw2,
          const float* __restrict__ maw2, const float* __restrict__ kw2,
          const float* __restrict__ mkw2)
{
    int idx = blockIdx.x * 256 + threadIdx.x;    // 5120*160
    int n = idx / 160, kq = idx - (idx / 160) * 160;
    int blk = n >> 10, nloc = n & 1023;
    float v = 0.f;
    switch (blk) {
        case 0: if (kq < 64)               v = dw2 [(size_t)kq * 1024 + nloc]; break;
        case 1: if (kq >= 64 && kq < 80)   v = aw2 [(size_t)(kq - 64) * 1024 + nloc]; break;
        case 2: if (kq >= 80 && kq < 96)   v = maw2[(size_t)(kq - 80) * 1024 + nloc]; break;
        case 3: if (kq >= 128 && kq < 144) v = kw2 [(size_t)(kq - 128) * 1024 + nloc]; break;
        default:if (kq >= 144)             v = mkw2[(size_t)(kq - 144) * 1024 + nloc]; break;
    }
    bf16 hv = __float2bfloat16_rn(v);
    bf16 lv = __float2bfloat16_rn(v - __bfloat162float(hv));
    g_s.bigBh[idx] = hv; g_s.bigBl[idx] = lv;
}

// ---------------------------------------------------------------------------
// fused_mix
// ---------------------------------------------------------------------------
#define MIX_SMEM 131072

__global__ void __launch_bounds__(256)
fused_mix(const float* __restrict__ x, const float* __restrict__ w2,
          const float* __restrict__ m_rg, const float* __restrict__ m_wa,
          const float* __restrict__ m_k,  const float* __restrict__ m_v)
{
    extern __shared__ __align__(16) char smraw[];
    float* As = (float*)smraw;
    float* Bs = (float*)(smraw + 65536);

    const int tid = threadIdx.x;
    const int tx = tid & 15;
    const int ty = tid >> 4;
    const int n0 = blockIdx.x * 128;
    const int m0 = blockIdx.y * 128;

#pragma unroll
    for (int i = 0; i < 16; i++) {
        int u = tid + 256 * i;
        int rw = u >> 5, c4 = u & 31;
        float4 v = *(const float4*)&g_s.mixin[(size_t)(m0 + rw) * 128 + c4 * 4];
        As[(c4 * 4 + 0) * 128 + rw] = v.x;
        As[(c4 * 4 + 1) * 128 + rw] = v.y;
        As[(c4 * 4 + 2) * 128 + rw] = v.z;
        As[(c4 * 4 + 3) * 128 + rw] = v.w;
    }
#pragma unroll
    for (int i = 0; i < 16; i++) {
        int u = tid + 256 * i;
        int kr = u >> 5, n4 = u & 31;
        *(float4*)&Bs[kr * 128 + n4 * 4] =
            *(const float4*)&w2[(size_t)kr * 1024 + n0 + n4 * 4];
    }
    __syncthreads();

    for (int f = 0; f < 4; f++) {
        unsigned long long acc[8][4];
#pragma unroll
        for (int i = 0; i < 8; i++)
#pragma unroll
            for (int j = 0; j < 4; j++) acc[i][j] = 0ull;

#pragma unroll
        for (int kq2 = 0; kq2 < 32; kq2++) {
            const int kq = f * 32 + kq2;
            float4 a0 = *(const float4*)&As[kq * 128 + ty * 8];
            float4 a1 = *(const float4*)&As[kq * 128 + ty * 8 + 4];
            ulonglong2 bA = *(const ulonglong2*)&Bs[kq * 128 + tx * 8];
            ulonglong2 bB = *(const ulonglong2*)&Bs[kq * 128 + tx * 8 + 4];
#define RF(rI, aval) { unsigned long long dp = dup2(aval); \
            fma2(acc[rI][0], dp, bA.x); fma2(acc[rI][1], dp, bA.y); \
            fma2(acc[rI][2], dp, bB.x); fma2(acc[rI][3], dp, bB.y); }
            RF(0, a0.x) RF(1, a0.y) RF(2, a0.z) RF(3, a0.w)
            RF(4, a1.x) RF(5, a1.y) RF(6, a1.z) RF(7, a1.w)
#undef RF
        }

        bf16 *oh, *ol; const float* maa;
        switch (f) {
            case 0: oh = g_s.xrgh; ol = g_s.xrgl; maa = m_rg; break;
            case 1: oh = g_s.xwah; ol = g_s.xwal; maa = m_wa; break;
            case 2: oh = g_s.xkh;  ol = g_s.xkl;  maa = m_k;  break;
            default:oh = g_s.xvh;  ol = g_s.xvl;  maa = m_v;  break;
        }
        const int nc = n0 + tx * 8;
        float4 mv0 = *(const float4*)&maa[nc];
        float4 mv1 = *(const float4*)&maa[nc + 4];
#pragma unroll
        for (int rr = 0; rr < 8; rr++) {
            const int m = m0 + ty * 8 + rr;
            const size_t off = (size_t)m * 1024 + nc;
            float4 xv0 = *(const float4*)&x[off];
            float4 xv1 = *(const float4*)&x[off + 4];
            float4 dx0 = *(const float4*)&g_s.xx[off];
            float4 dx1 = *(const float4*)&g_s.xx[off + 4];
            float vals[8];
            { float2 p = unpack2(acc[rr][0]); vals[0] = p.x; vals[1] = p.y; }
            { float2 p = unpack2(acc[rr][1]); vals[2] = p.x; vals[3] = p.y; }
            { float2 p = unpack2(acc[rr][2]); vals[4] = p.x; vals[5] = p.y; }
            { float2 p = unpack2(acc[rr][3]); vals[6] = p.x; vals[7] = p.y; }
            float4 o0, o1;
            o0.x = xv0.x + dx0.x * (mv0.x + vals[0]);
            o0.y = xv0.y + dx0.y * (mv0.y + vals[1]);
            o0.z = xv0.z + dx0.z * (mv0.z + vals[2]);
            o0.w = xv0.w + dx0.w * (mv0.w + vals[3]);
            o1.x = xv1.x + dx1.x * (mv1.x + vals[4]);
            o1.y = xv1.y + dx1.y * (mv1.y + vals[5]);
            o1.z = xv1.z + dx1.z * (mv1.z + vals[6]);
            o1.w = xv1.w + dx1.w * (mv1.w + vals[7]);
            uint2 h0, l0, h1, l1;
            split4(o0, h0, l0);
            split4(o1, h1, l1);
            *(uint4*)&oh[off] = make_uint4(h0.x, h0.y, h1.x, h1.y);
            *(uint4*)&ol[off] = make_uint4(l0.x, l0.y, l1.x, l1.y);
        }
    }
}

// ---------------------------------------------------------------------------
// ew0: xx = shift(x)-x; xmix bf16 hi/lo = x + xx*maa_x
// ---------------------------------------------------------------------------
__global__ void __launch_bounds__(256)
ew0_kernel(const float* __restrict__ x, const float* __restrict__ maa_x)
{
    size_t i4  = (size_t)blockIdx.x * 256 + threadIdx.x;
    size_t idx = i4 * 4;
    int c    = (int)(idx & (CC - 1));
    int nrow = (int)(idx >> 10);
    float4 xv = *(const float4*)&x[idx];
    float4 xp = make_float4(0.f, 0.f, 0.f, 0.f);
    if (nrow & (TT - 1))
        xp = *(const float4*)&x[idx - CC];
    float4 mv = *(const float4*)&maa_x[c];
    float4 d, xm;
    d.x = xp.x - xv.x;  xm.x = xv.x + d.x * mv.x;
    d.y = xp.y - xv.y;  xm.y = xv.y + d.y * mv.y;
    d.z = xp.z - xv.z;  xm.z = xv.z + d.z * mv.z;
    d.w = xp.w - xv.w;  xm.w = xv.w + d.w * mv.w;
    *(float4*)&g_s.xx[idx] = d;
    uint2 h, l;
    split4(xm, h, l);
    *(uint2*)&g_s.xmixh[idx] = h;
    *(uint2*)&g_s.xmixl[idx] = l;
}

// ---------------------------------------------------------------------------
// combine
// ---------------------------------------------------------------------------
__global__ void __launch_bounds__(256)
combine_kernel()
{
    int n   = blockIdx.x;
    int tid = threadIdx.x;
    size_t off = (size_t)n * CC + tid * 4;

    float4 kkv = *(float4*)&g_s.kk[off];
    float ss = kkv.x*kkv.x + kkv.y*kkv.y + kkv.z*kkv.z + kkv.w*kkv.w;
#pragma unroll
    for (int o = 8; o; o >>= 1) ss += __shfl_xor_sync(0xffffffffu, ss, o, 16);
    float inv = 1.f / fmaxf(sqrtf(ss), 1e-12f);

    float4 kq = *(float4*)&g_s.k[off];
    float4 aq = *(float4*)&g_s.asig[off];
    float4 mq = *(float4*)&g_s.ma[off];
    float4 wq = *(float4*)&g_s.w[off];
    float4 mk = *(float4*)&g_s.mk2[off];
    float4 kfv, ddv, avv, bvv;
#define CMB(X) { float fac = mq.X + aq.X * (1.f - mq.X); \
    float ee = expf(fminf(wq.X * mk.X, 0.f)); \
    kfv.X = kq.X * fac * ee; \
    ddv.X = expf(wq.X); \
    float kn = kkv.X * inv; \
    avv.X = -kn; bvv.X = kn * aq.X; }
    CMB(x) CMB(y) CMB(z) CMB(w)
#undef CMB
    *(float4*)&g_s.kf[off] = kfv;
    *(float4*)&g_s.dd[off] = ddv;
    *(float4*)&g_s.av[off] = avv;
    *(float4*)&g_s.bv[off] = bvv;
}

// ---------------------------------------------------------------------------
// WKV-7 scan: cp.async 3-deep pipeline
// ---------------------------------------------------------------------------
__global__ void __launch_bounds__(256)
wkv_kernel()
{
    const int blk = blockIdx.x;
    const int b = blk >> 4;
    const int h = blk & 15;
    const int tid = threadIdx.x;
    const int i  = tid >> 2;
    const int jq = tid & 3;

    __shared__ __align__(16) float sb[4][6][64];
    const size_t rowbase = ((size_t)b * TT) * CC + h * NN;

    const float* gsrc = 0;
    uint32_t sdst[4];
    if (tid < 96) {
        int larr = tid >> 4, lq = tid & 15;
        const float* srcs[6] = { g_s.r, g_s.dd, g_s.kf, g_s.av, g_s.bv, g_s.v };
        gsrc = srcs[larr] + rowbase + lq * 4;
#pragma unroll
        for (int q = 0; q < 4; q++) sdst[q] = smem_u32(&sb[q][larr][lq * 4]);
    }

#pragma unroll
    for (int pre = 0; pre < 3; pre++) {
        if (tid < 96) cp_async16(sdst[pre], gsrc + (size_t)pre * CC);
        CP_COMMIT();
    }

    unsigned long long S2[8];
#pragma unroll
    for (int u = 0; u < 8; u++) S2[u] = 0ull;

    float* yout = g_s.y + rowbase + i;

    for (int t = 0; t < TT; t++) {
        CP_WAIT2();
        __syncthreads();
        const int p = t & 3;

        const ulonglong2* r2p = (const ulonglong2*)(sb[p][0] + jq * 16);
        const ulonglong2* d2p = (const ulonglong2*)(sb[p][1] + jq * 16);
        const ulonglong2* k2p = (const ulonglong2*)(sb[p][2] + jq * 16);
        const ulonglong2* a2p = (const ulonglong2*)(sb[p][3] + jq * 16);
        const ulonglong2* b2p = (const ulonglong2*)(sb[p][4] + jq * 16);
        const float vi = sb[p][5][i];

        ulonglong2 Rv[4], Dv[4], Kv[4], Av[4], Bv[4];
#pragma unroll
        for (int u = 0; u < 4; u++) {
            Rv[u] = r2p[u]; Dv[u] = d2p[u]; Kv[u] = k2p[u];
            Av[u] = a2p[u]; Bv[u] = b2p[u];
        }

        if (tid < 96 && t + 3 < TT)
            cp_async16(sdst[(t + 3) & 3], gsrc + (size_t)(t + 3) * CC);
        CP_COMMIT();

        unsigned long long sa0 = 0ull, sa1 = 0ull, pp0 = 0ull, pp1 = 0ull;
        unsigned long long br0 = 0ull, br1 = 0ull, kr0 = 0ull, kr1 = 0ull;
#pragma unroll
        for (int u = 0; u < 4; u++) {
            unsigned long long drx = mul2(Dv[u].x, Rv[u].x);
            unsigned long long dry = mul2(Dv[u].y, Rv[u].y);
            fma2(sa0, S2[2*u],   Av[u].x);
            fma2(sa1, S2[2*u+1], Av[u].y);
            fma2(pp0, S2[2*u],   drx);
            fma2(pp1, S2[2*u+1], dry);
            fma2(br0, Bv[u].x, Rv[u].x);
            fma2(br1, Bv[u].y, Rv[u].y);
            fma2(kr0, Kv[u].x, Rv[u].x);
            fma2(kr1, Kv[u].y, Rv[u].y);
        }
        float sa = hadd4(sa0, sa1);
        float pp = hadd4(pp0, pp1);
        float br = hadd4(br0, br1);
        float kr = hadd4(kr0, kr1);
        sa += __shfl_xor_sync(0xffffffffu, sa, 1, 4);
        pp += __shfl_xor_sync(0xffffffffu, pp, 1, 4);
        br += __shfl_xor_sync(0xffffffffu, br, 1, 4);
        kr += __shfl_xor_sync(0xffffffffu, kr, 1, 4);
        sa += __shfl_xor_sync(0xffffffffu, sa, 2, 4);
        pp += __shfl_xor_sync(0xffffffffu, pp, 2, 4);
        br += __shfl_xor_sync(0xffffffffu, br, 2, 4);
        kr += __shfl_xor_sync(0xffffffffu, kr, 2, 4);

        if (jq == 0) yout[(size_t)t * CC] = pp + sa * br + vi * kr;

        const unsigned long long sa2 = dup2(sa);
        const unsigned long long v2  = dup2(vi);
#pragma unroll
        for (int u = 0; u < 4; u++) {
            S2[2*u]   = fma2g(S2[2*u],   Dv[u].x,
                              fma2g(sa2, Bv[u].x, mul2(v2, Kv[u].x)));
            S2[2*u+1] = fma2g(S2[2*u+1], Dv[u].y,
                              fma2g(sa2, Bv[u].y, mul2(v2, Kv[u].y)));
        }
    }
}

// ---------------------------------------------------------------------------
// post: GroupNorm + bonus + gate -> z (bf16 hi/lo)
// ---------------------------------------------------------------------------
__global__ void __launch_bounds__(256)
post_kernel(const float* __restrict__ faaaa,
            const float* __restrict__ lnw, const float* __restrict__ lnb)
{
    int n   = blockIdx.x;
    int tid = threadIdx.x;
    int c   = tid * 4;
    size_t off = (size_t)n * CC + c;

    float4 yv = *(float4*)&g_s.y [off];
    float4 rv = *(float4*)&g_s.r [off];
    float4 kv = *(float4*)&g_s.kf[off];
    float4 vv = *(float4*)&g_s.v [off];
    float4 gv = *(float4*)&g_s.g [off];
    float4 fv = *(const float4*)&faaaa[c];

    float s  = yv.x + yv.y + yv.z + yv.w;
    float s2 = yv.x*yv.x + yv.y*yv.y + yv.z*yv.z + yv.w*yv.w;
    float dk = rv.x*kv.x*fv.x + rv.y*kv.y*fv.y + rv.z*kv.z*fv.z + rv.w*kv.w*fv.w;
#pragma unroll
    for (int o = 8; o; o >>= 1) {
        s  += __shfl_xor_sync(0xffffffffu, s,  o, 16);
        s2 += __shfl_xor_sync(0xffffffffu, s2, o, 16);
        dk += __shfl_xor_sync(0xffffffffu, dk, o, 16);
    }
    float mean = s  * (1.f / 64.f);
    float var  = s2 * (1.f / 64.f) - mean * mean;
    float rs   = rsqrtf(var + 64e-5f);

    float4 lw = *(const float4*)&lnw[c];
    float4 lb = *(const float4*)&lnb[c];
    float4 z;
    z.x = (((yv.x - mean) * rs) * lw.x + lb.x + dk * vv.x) * gv.x;
    z.y = (((yv.y - mean) * rs) * lw.y + lb.y + dk * vv.y) * gv.y;
    z.z = (((yv.z - mean) * rs) * lw.z + lb.z + dk * vv.z) * gv.z;
    z.w = (((yv.w - mean) * rs) * lw.w + lb.w + dk * vv.w) * gv.w;
    uint2 h, l;
    split4(z, h, l);
    *(uint2*)&g_s.zh[off] = h;
    *(uint2*)&g_s.zl[off] = l;
}

// ---------------------------------------------------------------------------
// Host orchestration
// ---------------------------------------------------------------------------
static void gmma(const bf16* Ah, const bf16* Al, const bf16* Bh,
                 const bf16* Bl, float* Cp, int K)
{
    dim3 grid(8, MM / 128);
    gemm_mma2<<<grid, 256, MMA_SMEM>>>(Ah, Al, Bh, Bl, Cp, K);
}
static void convw(const float* src, bf16* h, bf16* l, int elems)
{
    conv_bf16<<<elems / 1024, 256>>>((const float4*)src, (uint2*)h, (uint2*)l);
}

#define UP128_SMEM 51200
#define UP32_SMEM  20480

extern "C" void kernel_launch(void* const* d_in, const int* in_sizes, int n_in,
                              void* d_out, int out_size)
{
    const float* x       = (const float*)d_in[0];
    const float* maa_x   = (const float*)d_in[1];
    const float* maa_rg  = (const float*)d_in[2];
    const float* maa_wa  = (const float*)d_in[3];
    const float* maa_k   = (const float*)d_in[4];
    const float* maa_v   = (const float*)d_in[5];
    const float* maa_w1  = (const float*)d_in[6];
    const float* maa_w2  = (const float*)d_in[7];
    const float* tdecay  = (const float*)d_in[8];
    const float* dw1     = (const float*)d_in[9];
    const float* dw2     = (const float*)d_in[10];
    const float* faaaa   = (const float*)d_in[11];
    const float* taaaaa  = (const float*)d_in[12];
    const float* aw1     = (const float*)d_in[13];
    const float* aw2     = (const float*)d_in[14];
    const float* kw1     = (const float*)d_in[15];
    const float* kw2     = (const float*)d_in[16];
    const float* gw1     = (const float*)d_in[17];
    const float* gw2     = (const float*)d_in[18];
    const float* maw1    = (const float*)d_in[19];
    const float* maw2    = (const float*)d_in[20];
    const float* tmisca  = (const float*)d_in[21];
    const float* mkw1    = (const float*)d_in[22];
    const float* mkw2    = (const float*)d_in[23];
    const float* tmisck  = (const float*)d_in[24];
    const float* wr      = (const float*)d_in[25];
    const float* wk      = (const float*)d_in[26];
    const float* wv      = (const float*)d_in[27];
    const float* wo      = (const float*)d_in[28];
    const float* lnw     = (const float*)d_in[29];
    const float* lnb     = (const float*)d_in[30];
    float* out = (float*)d_out;
    (void)in_sizes; (void)n_in; (void)out_size;

    Scratch* S = nullptr;
    cudaGetSymbolAddress((void**)&S, g_s);
    cudaFuncSetAttribute(gemm_mma2, cudaFuncAttributeMaxDynamicSharedMemorySize,
                         MMA_SMEM);
    cudaFuncSetAttribute(gemm_down, cudaFuncAttributeMaxDynamicSharedMemorySize,
                         MMA_SMEM);
    cudaFuncSetAttribute(fused_mix, cudaFuncAttributeMaxDynamicSharedMemorySize,
                         MIX_SMEM);
    cudaFuncSetAttribute(gemm_up<128>,
                         cudaFuncAttributeMaxDynamicSharedMemorySize, UP128_SMEM);
    cudaFuncSetAttribute(gemm_up<32>,
                         cudaFuncAttributeMaxDynamicSharedMemorySize, UP32_SMEM);

    // 1-5: setup so launch #6 is gmma(r) for ncu sampling
    convw(wr, S->wrh, S->wrl, CC * CC);                                  // 1
    ew0_kernel<<<(MM * CC / 4) / 256, 256>>>(x, maa_x);                  // 2
    packT_w1<<<512, 256>>>(maa_w1, S->mw1Th, S->mw1Tl);                  // 3
    gemm_up<128><<<128, 256, UP128_SMEM>>>(S->xmixh, S->xmixl,           // 4
        S->mw1Th, S->mw1Tl, S->mixin, 128, 0, 0, 128, 0);
    fused_mix<<<dim3(8, 32), 256, MIX_SMEM>>>(x, maa_w2,                 // 5
        maa_rg, maa_wa, maa_k, maa_v);
    gmma(S->xrgh, S->xrgl, S->wrh, S->wrl, S->r, 1024);                  // 6
    convw(wk, S->wkh, S->wkl, CC * CC);                                  // 7
    gmma(S->xkh, S->xkl, S->wkh, S->wkl, S->k, 1024);                    // 8
    convw(wv, S->wvh, S->wvl, CC * CC);                                  // 9
    gmma(S->xvh, S->xvl, S->wvh, S->wvl, S->v, 1024);                    // 10

    // gate
    packT_w1<<<512, 256>>>(gw1, S->gw1Th, S->gw1Tl);
    gemm_up<128><<<128, 256, UP128_SMEM>>>(S->xrgh, S->xrgl,
        S->gw1Th, S->gw1Tl, 0, 128, S->g1h, S->g1l, 128, 0);
    transconv_kernel<<<dim3(32, 4), 256>>>(gw2, S->gw2Th, S->gw2Tl);
    gmma(S->g1h, S->g1l, S->gw2Th, S->gw2Tl, S->g, 128);

    // LoRA up-projections into loraA (stride 160)
    packT_wa<<<512, 256>>>(dw1, aw1, maw1);
    gemm_up<128><<<128, 256, UP128_SMEM>>>(S->xwah, S->xwal,
        S->waTh, S->waTl, 0, 64, S->loraAh, S->loraAl, 160, 0);
    packT_k<<<128, 256>>>(kw1, mkw1);
    gemm_up<32><<<128, 256, UP32_SMEM>>>(S->xkh, S->xkl,
        S->kTh, S->kTl, 0, 16, S->loraAh, S->loraAl, 160, 128);

    // fused block-diagonal down-projection -> w, asig, ma, kk, mk2
    pack_bigB<<<(5120 * 160) / 256, 256>>>(dw2, aw2, maw2, kw2, mkw2);
    gemm_down<<<dim3(40, 32), 256, MMA_SMEM>>>(tdecay, taaaaa, tmisca, tmisck);

    // combine + scan + post + output
    combine_kernel<<<MM, 256>>>();
    wkv_kernel<<<BB * HH, 256>>>();
    post_kernel<<<MM, 256>>>(faaaa, lnw, lnb);
    convw(wo, S->woh, S->wol, CC * CC);
    gmma(S->zh, S->zl, S->woh, S->wol, out, 1024);
}

// round 10
// speedup vs baseline: 2.3823x; 1.0051x over previous
#include <cuda_runtime.h>
#include <cuda_bf16.h>
#include <math.h>
#include <stdint.h>
#include <string.h>

#define BB 4
#define TT 1024
#define CC 1024
#define HH 16
#define NN 64
#define MM (BB*TT)   // 4096 rows

typedef __nv_bfloat16 bf16;

// ---------------------------------------------------------------------------
// Scratch (static device memory)
// ---------------------------------------------------------------------------
struct Scratch {
    float xx   [MM*CC];
    float mixin[MM*128];
    float r    [MM*CC];
    float k    [MM*CC];
    float v    [MM*CC];
    float g    [MM*CC];
    float w    [MM*CC];
    float kk   [MM*CC];
    float asig [MM*CC];
    float ma   [MM*CC];
    float mk2  [MM*CC];
    float kf   [MM*CC];
    float dd   [MM*CC];
    float av   [MM*CC];
    float bv   [MM*CC];
    float y    [MM*CC];
    // bf16 hi/lo activations
    bf16 xmixh[MM*CC], xmixl[MM*CC];
    bf16 xrgh[MM*CC], xrgl[MM*CC];
    bf16 xwah[MM*CC], xwal[MM*CC];
    bf16 xkh [MM*CC], xkl [MM*CC];
    bf16 xvh [MM*CC], xvl [MM*CC];
    bf16 zh  [MM*CC], zl  [MM*CC];
    bf16 g1h [MM*128], g1l [MM*128];
    bf16 loraAh[MM*160], loraAl[MM*160];
    // bf16 hi/lo weights
    bf16 wrh[CC*CC], wrl[CC*CC];
    bf16 wkh[CC*CC], wkl[CC*CC];
    bf16 wvh[CC*CC], wvl[CC*CC];
    bf16 woh[CC*CC], wol[CC*CC];
    bf16 gw2Th[CC*128], gw2Tl[CC*128];
    bf16 mw1Th[128*1024], mw1Tl[128*1024];
    bf16 gw1Th[128*1024], gw1Tl[128*1024];
    bf16 waTh [128*1024], waTl [128*1024];
    bf16 kTh  [32*1024],  kTl  [32*1024];
    bf16 bigBh[5120*160], bigBl[5120*160];
};
__device__ Scratch g_s;

// ---------------------------------------------------------------------------
// Packed f32x2 helpers
// ---------------------------------------------------------------------------
__device__ __forceinline__ unsigned long long dup2(float x) {
    unsigned long long r;
    asm("mov.b64 %0, {%1, %1};" : "=l"(r) : "f"(x));
    return r;
}
__device__ __forceinline__ void fma2(unsigned long long& acc,
                                     unsigned long long a,
                                     unsigned long long b) {
    asm("fma.rn.f32x2 %0, %1, %2, %0;" : "+l"(acc) : "l"(a), "l"(b));
}
__device__ __forceinline__ unsigned long long fma2g(unsigned long long a,
                                                    unsigned long long b,
                                                    unsigned long long c) {
    unsigned long long d;
    asm("fma.rn.f32x2 %0, %1, %2, %3;" : "=l"(d) : "l"(a), "l"(b), "l"(c));
    return d;
}
__device__ __forceinline__ unsigned long long mul2(unsigned long long a,
                                                   unsigned long long b) {
    unsigned long long d;
    asm("mul.rn.f32x2 %0, %1, %2;" : "=l"(d) : "l"(a), "l"(b));
    return d;
}
__device__ __forceinline__ float2 unpack2(unsigned long long v) {
    float2 f;
    asm("mov.b64 {%0, %1}, %2;" : "=f"(f.x), "=f"(f.y) : "l"(v));
    return f;
}
__device__ __forceinline__ float hadd4(unsigned long long a,
                                       unsigned long long b) {
    float2 f = unpack2(a), g = unpack2(b);
    return (f.x + f.y) + (g.x + g.y);
}
__device__ __forceinline__ uint32_t smem_u32(const void* p) {
    uint32_t a;
    asm("{ .reg .u64 t; cvta.to.shared.u64 t, %1; cvt.u32.u64 %0, t; }"
        : "=r"(a) : "l"(p));
    return a;
}

// cp.async helpers
__device__ __forceinline__ void cp_async16(uint32_t saddr, const void* gptr) {
    asm volatile("cp.async.cg.shared.global [%0], [%1], 16;"
        :: "r"(saddr), "l"(gptr) : "memory");
}
#define CP_COMMIT() asm volatile("cp.async.commit_group;" ::: "memory")
#define CP_WAIT0()  asm volatile("cp.async.wait_group 0;" ::: "memory")
#define CP_WAIT2()  asm volatile("cp.async.wait_group 2;" ::: "memory")

// hi/lo splits
__device__ __forceinline__ void split4(float4 f, uint2& h, uint2& l) {
    __nv_bfloat162 h01 = __floats2bfloat162_rn(f.x, f.y);
    __nv_bfloat162 h23 = __floats2bfloat162_rn(f.z, f.w);
    float lx = f.x - __bfloat162float(h01.x);
    float ly = f.y - __bfloat162float(h01.y);
    float lz = f.z - __bfloat162float(h23.x);
    float lw = f.w - __bfloat162float(h23.y);
    __nv_bfloat162 l01 = __floats2bfloat162_rn(lx, ly);
    __nv_bfloat162 l23 = __floats2bfloat162_rn(lz, lw);
    memcpy(&h.x, &h01, 4); memcpy(&h.y, &h23, 4);
    memcpy(&l.x, &l01, 4); memcpy(&l.y, &l23, 4);
}
__device__ __forceinline__ void split2(float a, float b,
                                       uint32_t& h, uint32_t& l) {
    __nv_bfloat162 hh = __floats2bfloat162_rn(a, b);
    float la = a - __bfloat162float(hh.x);
    float lb = b - __bfloat162float(hh.y);
    __nv_bfloat162 ll = __floats2bfloat162_rn(la, lb);
    memcpy(&h, &hh, 4); memcpy(&l, &ll, 4);
}

// ---------------------------------------------------------------------------
// mma.sync / ldmatrix helpers
// ---------------------------------------------------------------------------
__device__ __forceinline__ void ldsm4(uint32_t* r, uint32_t addr) {
    asm volatile("ldmatrix.sync.aligned.m8n8.x4.shared.b16 {%0,%1,%2,%3}, [%4];"
        : "=r"(r[0]), "=r"(r[1]), "=r"(r[2]), "=r"(r[3]) : "r"(addr));
}
__device__ __forceinline__ void ldsm2(uint32_t* r, uint32_t addr) {
    asm volatile("ldmatrix.sync.aligned.m8n8.x2.shared.b16 {%0,%1}, [%2];"
        : "=r"(r[0]), "=r"(r[1]) : "r"(addr));
}
__device__ __forceinline__ void mma_bf16(float* c, const uint32_t* a,
                                         const uint32_t* b) {
    asm volatile("mma.sync.aligned.m16n8k16.row.col.f32.bf16.bf16.f32 "
        "{%0,%1,%2,%3}, {%4,%5,%6,%7}, {%8,%9}, {%0,%1,%2,%3};"
        : "+f"(c[0]), "+f"(c[1]), "+f"(c[2]), "+f"(c[3])
        : "r"(a[0]), "r"(a[1]), "r"(a[2]), "r"(a[3]), "r"(b[0]), "r"(b[1]));
}

// ---------------------------------------------------------------------------
// gemm_mma2: C[M,1024] = (Ah+Al)[M,K] @ (Bh+Bl)[1024,K]^T, fp32 accum.
// cp.async double-buffered, CTA 128x128, chunk 32. Forced 2 CTAs/SM.
// ---------------------------------------------------------------------------
#define MMA_SMEM 81920

__global__ void __launch_bounds__(256, 2)
gemm_mma2(const bf16* __restrict__ Ah, const bf16* __restrict__ Al,
          const bf16* __restrict__ Bh, const bf16* __restrict__ Bl,
          float* __restrict__ Cm, int K)
{
    extern __shared__ __align__(16) char sm[];
    const uint32_t sb = smem_u32(sm);

    const int tid  = threadIdx.x;
    const int lane = tid & 31;
    const int wid  = tid >> 5;
    const int wm   = wid & 1;
    const int wn   = wid >> 1;
    const int n0 = blockIdx.x * 128;
    const int m0 = blockIdx.y * 128;

    const int row = tid >> 1, half = tid & 1;
    const bf16* pAh = Ah + (size_t)(m0 + row) * K + half * 16;
    const bf16* pAl = Al + (size_t)(m0 + row) * K + half * 16;
    const bf16* pBh = Bh + (size_t)(n0 + row) * K + half * 16;
    const bf16* pBl = Bl + (size_t)(n0 + row) * K + half * 16;
    const uint32_t st = (uint32_t)(row * 80 + half * 32);

    const uint32_t aLoff = (uint32_t)((lane & 15) * 80 + (lane >> 4) * 16);
    const uint32_t bLoff = (uint32_t)(((lane & 7) + ((lane >> 4) & 1) * 8) * 80
                                      + ((lane >> 3) & 1) * 16);

    float c[4][4][4];
#pragma unroll
    for (int i = 0; i < 4; i++)
#pragma unroll
        for (int j = 0; j < 4; j++)
#pragma unroll
            for (int q = 0; q < 4; q++) c[i][j][q] = 0.f;

    const int chunks = K >> 5;

    {
        uint32_t d = sb + st;
        cp_async16(d,             pAh); cp_async16(d + 16,         pAh + 8);
        cp_async16(d + 10240,     pAl); cp_async16(d + 10240 + 16, pAl + 8);
        cp_async16(d + 20480,     pBh); cp_async16(d + 20480 + 16, pBh + 8);
        cp_async16(d + 30720,     pBl); cp_async16(d + 30720 + 16, pBl + 8);
        CP_COMMIT();
        CP_WAIT0();
    }
    __syncthreads();

    for (int cidx = 0; cidx < chunks; cidx++) {
        const uint32_t bufOff = (uint32_t)((cidx & 1) * 40960);
        const bool more = (cidx + 1 < chunks);

        if (more) {
            const int ko = (cidx + 1) * 32;
            uint32_t d = sb + (uint32_t)(((cidx + 1) & 1) * 40960) + st;
            cp_async16(d,             pAh + ko); cp_async16(d + 16,         pAh + ko + 8);
            cp_async16(d + 10240,     pAl + ko); cp_async16(d + 10240 + 16, pAl + ko + 8);
            cp_async16(d + 20480,     pBh + ko); cp_async16(d + 20480 + 16, pBh + ko + 8);
            cp_async16(d + 30720,     pBl + ko); cp_async16(d + 30720 + 16, pBl + ko + 8);
            CP_COMMIT();
        }

        const uint32_t aBase = sb + bufOff + (uint32_t)(wm * 64 * 80) + aLoff;
        const uint32_t bBase = sb + bufOff + 20480u + (uint32_t)(wn * 32 * 80) + bLoff;
#pragma unroll
        for (int ks = 0; ks < 2; ks++) {
            uint32_t afh[4][4], afl[4][4];
#pragma unroll
            for (int mi = 0; mi < 4; mi++) {
                ldsm4(afh[mi], aBase + 0u     + (uint32_t)(mi * 1280 + ks * 32));
                ldsm4(afl[mi], aBase + 10240u + (uint32_t)(mi * 1280 + ks * 32));
            }
            uint32_t bfh[2][4], bfl[2][4];
#pragma unroll
            for (int np = 0; np < 2; np++) {
                ldsm4(bfh[np], bBase + 0u     + (uint32_t)(np * 1280 + ks * 32));
                ldsm4(bfl[np], bBase + 10240u + (uint32_t)(np * 1280 + ks * 32));
            }
#pragma unroll
            for (int mi = 0; mi < 4; mi++) {
#pragma unroll
                for (int ni = 0; ni < 4; ni++) {
                    const uint32_t* bh = &bfh[ni >> 1][(ni & 1) * 2];
                    const uint32_t* bl = &bfl[ni >> 1][(ni & 1) * 2];
                    mma_bf16(c[mi][ni], afh[mi], bh);
                    mma_bf16(c[mi][ni], afh[mi], bl);
                    mma_bf16(c[mi][ni], afl[mi], bh);
                }
            }
        }

        if (more) CP_WAIT0();
        __syncthreads();
    }

    const int erow = m0 + wm * 64 + (lane >> 2);
    const int ecol = n0 + wn * 32 + (lane & 3) * 2;
#pragma unroll
    for (int mi = 0; mi < 4; mi++) {
#pragma unroll
        for (int ni = 0; ni < 4; ni++) {
            size_t base0 = (size_t)(erow + mi * 16)     * 1024 + ecol + ni * 8;
            size_t base1 = (size_t)(erow + mi * 16 + 8) * 1024 + ecol + ni * 8;
            *(float2*)&Cm[base0] = make_float2(c[mi][ni][0], c[mi][ni][1]);
            *(float2*)&Cm[base1] = make_float2(c[mi][ni][2], c[mi][ni][3]);
        }
    }
}

// ---------------------------------------------------------------------------
// gemm_down: fused LoRA down-projections (block-diagonal). Forced 2 CTAs/SM.
// C[4096, 5120] = loraA[4096,160] @ bigB[5120,160]^T, per-block epilogues.
// ---------------------------------------------------------------------------
__global__ void __launch_bounds__(256, 2)
gemm_down(const float* __restrict__ tdecay, const float* __restrict__ taaaaa,
          const float* __restrict__ tmisca, const float* __restrict__ tmisck)
{
    extern __shared__ __align__(16) char sm[];
    const uint32_t sb = smem_u32(sm);

    const int tid  = threadIdx.x;
    const int lane = tid & 31;
    const int wid  = tid >> 5;
    const int wm   = wid & 1;
    const int wn   = wid >> 1;
    const int n0 = blockIdx.x * 128;
    const int m0 = blockIdx.y * 128;

    const int row = tid >> 1, half = tid & 1;
    const bf16* pAh = g_s.loraAh + (size_t)(m0 + row) * 160 + half * 16;
    const bf16* pAl = g_s.loraAl + (size_t)(m0 + row) * 160 + half * 16;
    const bf16* pBh = g_s.bigBh  + (size_t)(n0 + row) * 160 + half * 16;
    const bf16* pBl = g_s.bigBl  + (size_t)(n0 + row) * 160 + half * 16;
    const uint32_t st = (uint32_t)(row * 80 + half * 32);

    const uint32_t aLoff = (uint32_t)((lane & 15) * 80 + (lane >> 4) * 16);
    const uint32_t bLoff = (uint32_t)(((lane & 7) + ((lane >> 4) & 1) * 8) * 80
                                      + ((lane >> 3) & 1) * 16);

    float c[4][4][4];
#pragma unroll
    for (int i = 0; i < 4; i++)
#pragma unroll
        for (int j = 0; j < 4; j++)
#pragma unroll
            for (int q = 0; q < 4; q++) c[i][j][q] = 0.f;

    {
        uint32_t d = sb + st;
        cp_async16(d,             pAh); cp_async16(d + 16,         pAh + 8);
        cp_async16(d + 10240,     pAl); cp_async16(d + 10240 + 16, pAl + 8);
        cp_async16(d + 20480,     pBh); cp_async16(d + 20480 + 16, pBh + 8);
        cp_async16(d + 30720,     pBl); cp_async16(d + 30720 + 16, pBl + 8);
        CP_COMMIT();
        CP_WAIT0();
    }
    __syncthreads();

    for (int cidx = 0; cidx < 5; cidx++) {
        const uint32_t bufOff = (uint32_t)((cidx & 1) * 40960);
        const bool more = (cidx + 1 < 5);

        if (more) {
            const int ko = (cidx + 1) * 32;
            uint32_t d = sb + (uint32_t)(((cidx + 1) & 1) * 40960) + st;
            cp_async16(d,             pAh + ko); cp_async16(d + 16,         pAh + ko + 8);
            cp_async16(d + 10240,     pAl + ko); cp_async16(d + 10240 + 16, pAl + ko + 8);
            cp_async16(d + 20480,     pBh + ko); cp_async16(d + 20480 + 16, pBh + ko + 8);
            cp_async16(d + 30720,     pBl + ko); cp_async16(d + 30720 + 16, pBl + ko + 8);
            CP_COMMIT();
        }

        const uint32_t aBase = sb + bufOff + (uint32_t)(wm * 64 * 80) + aLoff;
        const uint32_t bBase = sb + bufOff + 20480u + (uint32_t)(wn * 32 * 80) + bLoff;
#pragma unroll
        for (int ks = 0; ks < 2; ks++) {
            uint32_t afh[4][4], afl[4][4];
#pragma unroll
            for (int mi = 0; mi < 4; mi++) {
                ldsm4(afh[mi], aBase + 0u     + (uint32_t)(mi * 1280 + ks * 32));
                ldsm4(afl[mi], aBase + 10240u + (uint32_t)(mi * 1280 + ks * 32));
            }
            uint32_t bfh[2][4], bfl[2][4];
#pragma unroll
            for (int np = 0; np < 2; np++) {
                ldsm4(bfh[np], bBase + 0u     + (uint32_t)(np * 1280 + ks * 32));
                ldsm4(bfl[np], bBase + 10240u + (uint32_t)(np * 1280 + ks * 32));
            }
#pragma unroll
            for (int mi = 0; mi < 4; mi++) {
#pragma unroll
                for (int ni = 0; ni < 4; ni++) {
                    const uint32_t* bh = &bfh[ni >> 1][(ni & 1) * 2];
                    const uint32_t* bl = &bfl[ni >> 1][(ni & 1) * 2];
                    mma_bf16(c[mi][ni], afh[mi], bh);
                    mma_bf16(c[mi][ni], afh[mi], bl);
                    mma_bf16(c[mi][ni], afl[mi], bh);
                }
            }
        }

        if (more) CP_WAIT0();
        __syncthreads();
    }

    const int blk = n0 >> 10;
    float* outp; const float* ev; int mode;
    switch (blk) {
        case 0:  outp = g_s.w;    ev = tdecay; mode = 4; break;
        case 1:  outp = g_s.asig; ev = taaaaa; mode = 3; break;
        case 2:  outp = g_s.ma;   ev = tmisca; mode = 3; break;
        case 3:  outp = g_s.kk;   ev = 0;      mode = 5; break;
        default: outp = g_s.mk2;  ev = tmisck; mode = 3; break;
    }
    const int erow = m0 + wm * 64 + (lane >> 2);
    const int ecol = (n0 & 1023) + wn * 32 + (lane & 3) * 2;
#pragma unroll
    for (int mi = 0; mi < 4; mi++) {
#pragma unroll
        for (int ni = 0; ni < 4; ni++) {
            const int col = ecol + ni * 8;
            const int r0 = erow + mi * 16, r1 = r0 + 8;
            float v0 = c[mi][ni][0], v1 = c[mi][ni][1];
            float v2 = c[mi][ni][2], v3 = c[mi][ni][3];
            if (mode == 4) {
                float e0 = ev[col], e1 = ev[col + 1];
                v0 = -log1pf(expf(-(e0 + v0))) - 0.5f;
                v1 = -log1pf(expf(-(e1 + v1))) - 0.5f;
                v2 = -log1pf(expf(-(e0 + v2))) - 0.5f;
                v3 = -log1pf(expf(-(e1 + v3))) - 0.5f;
            } else if (mode == 3) {
                float e0 = ev[col], e1 = ev[col + 1];
                v0 = 1.f / (1.f + expf(-(e0 + v0)));
                v1 = 1.f / (1.f + expf(-(e1 + v1)));
                v2 = 1.f / (1.f + expf(-(e0 + v2)));
                v3 = 1.f / (1.f + expf(-(e1 + v3)));
            } else {
                float2 k0 = *(const float2*)&g_s.k[(size_t)r0 * 1024 + col];
                float2 k1 = *(const float2*)&g_s.k[(size_t)r1 * 1024 + col];
                v0 += k0.x; v1 += k0.y; v2 += k1.x; v3 += k1.y;
            }
            *(float2*)&outp[(size_t)r0 * 1024 + col] = make_float2(v0, v1);
            *(float2*)&outp[(size_t)r1 * 1024 + col] = make_float2(v2, v3);
        }
    }
}

// ---------------------------------------------------------------------------
// gemm_up<BNT>: C[4096,N] = (Ah+Al)[4096,1024] @ (Bh+Bl)[N,1024]^T
// CTA 32 x BNT tile; grid (128, N/BNT). cp.async double-buffered, chunk 32.
// Epilogue: tanh on global col < tanhN; fp32 out stride cstride if Cm;
// bf16 hi/lo out at [row*ostride + ocol + gcol] if oh.
// ---------------------------------------------------------------------------
template<int BNT>
__global__ void __launch_bounds__(256)
gemm_up(const bf16* __restrict__ Ah, const bf16* __restrict__ Al,
        const bf16* __restrict__ Bh, const bf16* __restrict__ Bl,
        float* __restrict__ Cm, int cstride, int tanhN,
        bf16* __restrict__ oh, bf16* __restrict__ ol,
        int ostride, int ocol)
{
    constexpr int NI = BNT / 32;              // 2 (64) or 1 (32)
    constexpr int B_BYTES = BNT * 80;
    constexpr int OFF_AL = 2560;
    constexpr int OFF_BH = 5120;
    constexpr int BUF = 5120 + 2 * B_BYTES;

    extern __shared__ __align__(16) char sm[];
    const uint32_t sb = smem_u32(sm);

    const int tid  = threadIdx.x;
    const int lane = tid & 31;
    const int wid  = tid >> 5;
    const int wm   = wid & 1;                 // 2 m16 groups
    const int wn   = wid >> 1;                // 4 col groups of BNT/4
    const int m0 = blockIdx.x * 32;
    const int n0 = blockIdx.y * BNT;

    // loaders: A (32 rows x 4 quarters = 128 slots), B (BNT rows x 4)
    const int arow = (tid & 127) >> 2, aq2 = tid & 3;
    const bf16* pAh = Ah + (size_t)(m0 + arow) * 1024 + aq2 * 8;
    const bf16* pAl = Al + (size_t)(m0 + arow) * 1024 + aq2 * 8;
    const uint32_t stA = (uint32_t)(arow * 80 + aq2 * 16);
    const int brow = (BNT == 64) ? (tid >> 2) : ((tid & 127) >> 2);
    const bf16* pBh = Bh + (size_t)(n0 + brow) * 1024 + aq2 * 8;
    const bf16* pBl = Bl + (size_t)(n0 + brow) * 1024 + aq2 * 8;
    const uint32_t stB = (uint32_t)(brow * 80 + aq2 * 16);
    const bool doA = (tid < 128);
    const bool doB = (BNT == 64) || (tid < 128);

    const uint32_t aLoff = (uint32_t)((lane & 15) * 80 + (lane >> 4) * 16);
    const uint32_t bLoff = (uint32_t)(((lane & 7) + ((lane >> 4) & 1) * 8) * 80
                                      + ((lane >> 3) & 1) * 16);
    const uint32_t bLoff2 = (uint32_t)((lane & 7) * 80 + ((lane >> 3) & 1) * 16);

    float c[NI][4];
#pragma unroll
    for (int j = 0; j < NI; j++)
#pragma unroll
        for (int q = 0; q < 4; q++) c[j][q] = 0.f;

    // prologue
    {
        if (doA) {
            cp_async16(sb + stA, pAh);
            cp_async16(sb + OFF_AL + stA, pAl);
        }
        if (doB) {
            cp_async16(sb + OFF_BH + stB, pBh);
            cp_async16(sb + OFF_BH + B_BYTES + stB, pBl);
        }
        CP_COMMIT();
        CP_WAIT0();
    }
    __syncthreads();

    for (int cidx = 0; cidx < 32; cidx++) {
        const uint32_t bufOff = (uint32_t)((cidx & 1) * BUF);
        const bool more = (cidx + 1 < 32);

        if (more) {
            const int ko = (cidx + 1) * 32;
            uint32_t d = sb + (uint32_t)(((cidx + 1) & 1) * BUF);
            if (doA) {
                cp_async16(d + stA, pAh + ko);
                cp_async16(d + OFF_AL + stA, pAl + ko);
            }
            if (doB) {
                cp_async16(d + OFF_BH + stB, pBh + ko);
                cp_async16(d + OFF_BH + B_BYTES + stB, pBl + ko);
            }
            CP_COMMIT();
        }

        const uint32_t aBase = sb + bufOff + (uint32_t)(wm * 16 * 80) + aLoff;
#pragma unroll
        for (int ks = 0; ks < 2; ks++) {
            uint32_t afh[4], afl[4];
            ldsm4(afh, aBase + (uint32_t)(ks * 32));
            ldsm4(afl, aBase + OFF_AL + (uint32_t)(ks * 32));
            if (BNT == 64) {
                uint32_t bfh[4], bfl[4];
                const uint32_t bBase = sb + bufOff + OFF_BH
                                     + (uint32_t)(wn * 16 * 80) + bLoff
                                     + (uint32_t)(ks * 32);
                ldsm4(bfh, bBase);
                ldsm4(bfl, bBase + (uint32_t)B_BYTES);
#pragma unroll
                for (int ni = 0; ni < NI; ni++) {
                    const uint32_t* bhp = &bfh[ni * 2];
                    const uint32_t* blp = &bfl[ni * 2];
                    mma_bf16(c[ni], afh, bhp);
                    mma_bf16(c[ni], afh, blp);
                    mma_bf16(c[ni], afl, bhp);
                }
            } else {
                uint32_t bfh2[2], bfl2[2];
                const uint32_t bBase = sb + bufOff + OFF_BH
                                     + (uint32_t)(wn * 8 * 80) + bLoff2
                                     + (uint32_t)(ks * 32);
                ldsm2(bfh2, bBase);
                ldsm2(bfl2, bBase + (uint32_t)B_BYTES);
                mma_bf16(c[0], afh, bfh2);
                mma_bf16(c[0], afh, bfl2);
                mma_bf16(c[0], afl, bfh2);
            }
        }

        if (more) CP_WAIT0();
        __syncthreads();
    }

    // epilogue
    const int r0 = m0 + wm * 16 + (lane >> 2);
    const int r1 = r0 + 8;
#pragma unroll
    for (int ni = 0; ni < NI; ni++) {
        const int gcol = n0 + wn * (8 * NI) + ni * 8 + (lane & 3) * 2;
        float v0 = c[ni][0], v1 = c[ni][1];
        float v2 = c[ni][2], v3 = c[ni][3];
        if (gcol < tanhN) {
            v0 = tanhf(v0); v1 = tanhf(v1);
            v2 = tanhf(v2); v3 = tanhf(v3);
        }
        if (Cm) {
            *(float2*)&Cm[(size_t)r0 * cstride + gcol] = make_float2(v0, v1);
            *(float2*)&Cm[(size_t)r1 * cstride + gcol] = make_float2(v2, v3);
        }
        if (oh) {
            uint32_t h0, l0, h1, l1;
            split2(v0, v1, h0, l0);
            split2(v2, v3, h1, l1);
            *(uint32_t*)&oh[(size_t)r0 * ostride + ocol + gcol] = h0;
            *(uint32_t*)&ol[(size_t)r0 * ostride + ocol + gcol] = l0;
            *(uint32_t*)&oh[(size_t)r1 * ostride + ocol + gcol] = h1;
            *(uint32_t*)&ol[(size_t)r1 * ostride + ocol + gcol] = l1;
        }
    }
}

// ---------------------------------------------------------------------------
// conv_bf16 / transconv / packT / pack_bigB
// ---------------------------------------------------------------------------
__global__ void __launch_bounds__(256)
conv_bf16(const float4* __restrict__ src, uint2* __restrict__ h,
          uint2* __restrict__ l)
{
    int i = blockIdx.x * 256 + threadIdx.x;
    uint2 hh, ll;
    split4(src[i], hh, ll);
    h[i] = hh; l[i] = ll;
}

__global__ void __launch_bounds__(256)
transconv_kernel(const float* __restrict__ src, bf16* __restrict__ dh,
                 bf16* __restrict__ dl)
{
    __shared__ float tile[32][33];
    int bx = blockIdx.x;
    int by = blockIdx.y;
    int tx = threadIdx.x & 31, ty = threadIdx.x >> 5;
#pragma unroll
    for (int i = 0; i < 4; i++)
        tile[ty + i * 8][tx] = src[(size_t)(by * 32 + ty + i * 8) * 1024 + bx * 32 + tx];
    __syncthreads();
#pragma unroll
    for (int i = 0; i < 4; i++) {
        float v = tile[tx][ty + i * 8];
        bf16 hv = __float2bfloat16_rn(v);
        bf16 lv = __float2bfloat16_rn(v - __bfloat162float(hv));
        size_t di = (size_t)(bx * 32 + ty + i * 8) * 128 + by * 32 + tx;
        dh[di] = hv; dl[di] = lv;
    }
}

__global__ void __launch_bounds__(256)
packT_w1(const float* __restrict__ src, bf16* __restrict__ dh,
         bf16* __restrict__ dl)
{
    int idx = blockIdx.x * 256 + threadIdx.x;
    int cth = idx >> 10, r = idx & 1023;
    float v = src[(size_t)r * 128 + cth];
    bf16 hv = __float2bfloat16_rn(v);
    bf16 lv = __float2bfloat16_rn(v - __bfloat162float(hv));
    dh[idx] = hv; dl[idx] = lv;
}
__global__ void __launch_bounds__(256)
packT_wa(const float* __restrict__ dw1, const float* __restrict__ aw1,
         const float* __restrict__ maw1)
{
    int idx = blockIdx.x * 256 + threadIdx.x;
    int cth = idx >> 10, r = idx & 1023;
    float v = 0.f;
    if (cth < 64)      v = dw1[r * 64 + cth];
    else if (cth < 80) v = aw1[r * 16 + (cth - 64)];
    else if (cth < 96) v = maw1[r * 16 + (cth - 80)];
    bf16 hv = __float2bfloat16_rn(v);
    bf16 lv = __float2bfloat16_rn(v - __bfloat162float(hv));
    g_s.waTh[idx] = hv; g_s.waTl[idx] = lv;
}
__global__ void __launch_bounds__(256)
packT_k(const float* __restrict__ kw1, const float* __restrict__ mkw1)
{
    int idx = blockIdx.x * 256 + threadIdx.x;
    int cth = idx >> 10, r = idx & 1023;
    float v = (cth < 16) ? kw1[r * 16 + cth] : mkw1[r * 16 + (cth - 16)];
    bf16 hv = __float2bfloat16_rn(v);
    bf16 lv = __float2bfloat16_rn(v - __bfloat162float(hv));
    g_s.kTh[idx] = hv; g_s.kTl[idx] = lv;
}

__global__ void __launch_bounds__(256)
pack_bigB(const float* __restrict__ dw2, const float* __restrict__ aw2,
          const float* __restrict__ maw2, const float* __restrict__ kw2,
          const float* __restrict__ mkw2)
{
    int idx = blockIdx.x * 256 + threadIdx.x;
    int n = idx / 160, kq = idx - (idx / 160) * 160;
    int blk = n >> 10, nloc = n & 1023;
    float v = 0.f;
    switch (blk) {
        case 0: if (kq < 64)               v = dw2 [(size_t)kq * 1024 + nloc]; break;
        case 1: if (kq >= 64 && kq < 80)   v = aw2 [(size_t)(kq - 64) * 1024 + nloc]; break;
        case 2: if (kq >= 80 && kq < 96)   v = maw2[(size_t)(kq - 80) * 1024 + nloc]; break;
        case 3: if (kq >= 128 && kq < 144) v = kw2 [(size_t)(kq - 128) * 1024 + nloc]; break;
        default:if (kq >= 144)             v = mkw2[(size_t)(kq - 144) * 1024 + nloc]; break;
    }
    bf16 hv = __float2bfloat16_rn(v);
    bf16 lv = __float2bfloat16_rn(v - __bfloat162float(hv));
    g_s.bigBh[idx] = hv; g_s.bigBl[idx] = lv;
}

// ---------------------------------------------------------------------------
// fused_mix
// ---------------------------------------------------------------------------
#define MIX_SMEM 131072

__global__ void __launch_bounds__(256)
fused_mix(const float* __restrict__ x, const float* __restrict__ w2,
          const float* __restrict__ m_rg, const float* __restrict__ m_wa,
          const float* __restrict__ m_k,  const float* __restrict__ m_v)
{
    extern __shared__ __align__(16) char smraw[];
    float* As = (float*)smraw;
    float* Bs = (float*)(smraw + 65536);

    const int tid = threadIdx.x;
    const int tx = tid & 15;
    const int ty = tid >> 4;
    const int n0 = blockIdx.x * 128;
    const int m0 = blockIdx.y * 128;

#pragma unroll
    for (int i = 0; i < 16; i++) {
        int u = tid + 256 * i;
        int rw = u >> 5, c4 = u & 31;
        float4 v = *(const float4*)&g_s.mixin[(size_t)(m0 + rw) * 128 + c4 * 4];
        As[(c4 * 4 + 0) * 128 + rw] = v.x;
        As[(c4 * 4 + 1) * 128 + rw] = v.y;
        As[(c4 * 4 + 2) * 128 + rw] = v.z;
        As[(c4 * 4 + 3) * 128 + rw] = v.w;
    }
#pragma unroll
    for (int i = 0; i < 16; i++) {
        int u = tid + 256 * i;
        int kr = u >> 5, n4 = u & 31;
        *(float4*)&Bs[kr * 128 + n4 * 4] =
            *(const float4*)&w2[(size_t)kr * 1024 + n0 + n4 * 4];
    }
    __syncthreads();

    for (int f = 0; f < 4; f++) {
        unsigned long long acc[8][4];
#pragma unroll
        for (int i = 0; i < 8; i++)
#pragma unroll
            for (int j = 0; j < 4; j++) acc[i][j] = 0ull;

#pragma unroll
        for (int kq2 = 0; kq2 < 32; kq2++) {
            const int kq = f * 32 + kq2;
            float4 a0 = *(const float4*)&As[kq * 128 + ty * 8];
            float4 a1 = *(const float4*)&As[kq * 128 + ty * 8 + 4];
            ulonglong2 bA = *(const ulonglong2*)&Bs[kq * 128 + tx * 8];
            ulonglong2 bB = *(const ulonglong2*)&Bs[kq * 128 + tx * 8 + 4];
#define RF(rI, aval) { unsigned long long dp = dup2(aval); \
            fma2(acc[rI][0], dp, bA.x); fma2(acc[rI][1], dp, bA.y); \
            fma2(acc[rI][2], dp, bB.x); fma2(acc[rI][3], dp, bB.y); }
            RF(0, a0.x) RF(1, a0.y) RF(2, a0.z) RF(3, a0.w)
            RF(4, a1.x) RF(5, a1.y) RF(6, a1.z) RF(7, a1.w)
#undef RF
        }

        bf16 *oh, *ol; const float* maa;
        switch (f) {
            case 0: oh = g_s.xrgh; ol = g_s.xrgl; maa = m_rg; break;
            case 1: oh = g_s.xwah; ol = g_s.xwal; maa = m_wa; break;
            case 2: oh = g_s.xkh;  ol = g_s.xkl;  maa = m_k;  break;
            default:oh = g_s.xvh;  ol = g_s.xvl;  maa = m_v;  break;
        }
        const int nc = n0 + tx * 8;
        float4 mv0 = *(const float4*)&maa[nc];
        float4 mv1 = *(const float4*)&maa[nc + 4];
#pragma unroll
        for (int rr = 0; rr < 8; rr++) {
            const int m = m0 + ty * 8 + rr;
            const size_t off = (size_t)m * 1024 + nc;
            float4 xv0 = *(const float4*)&x[off];
            float4 xv1 = *(const float4*)&x[off + 4];
            float4 dx0 = *(const float4*)&g_s.xx[off];
            float4 dx1 = *(const float4*)&g_s.xx[off + 4];
            float vals[8];
            { float2 p = unpack2(acc[rr][0]); vals[0] = p.x; vals[1] = p.y; }
            { float2 p = unpack2(acc[rr][1]); vals[2] = p.x; vals[3] = p.y; }
            { float2 p = unpack2(acc[rr][2]); vals[4] = p.x; vals[5] = p.y; }
            { float2 p = unpack2(acc[rr][3]); vals[6] = p.x; vals[7] = p.y; }
            float4 o0, o1;
            o0.x = xv0.x + dx0.x * (mv0.x + vals[0]);
            o0.y = xv0.y + dx0.y * (mv0.y + vals[1]);
            o0.z = xv0.z + dx0.z * (mv0.z + vals[2]);
            o0.w = xv0.w + dx0.w * (mv0.w + vals[3]);
            o1.x = xv1.x + dx1.x * (mv1.x + vals[4]);
            o1.y = xv1.y + dx1.y * (mv1.y + vals[5]);
            o1.z = xv1.z + dx1.z * (mv1.z + vals[6]);
            o1.w = xv1.w + dx1.w * (mv1.w + vals[7]);
            uint2 h0, l0, h1, l1;
            split4(o0, h0, l0);
            split4(o1, h1, l1);
            *(uint4*)&oh[off] = make_uint4(h0.x, h0.y, h1.x, h1.y);
            *(uint4*)&ol[off] = make_uint4(l0.x, l0.y, l1.x, l1.y);
        }
    }
}

// ---------------------------------------------------------------------------
// ew0
// ---------------------------------------------------------------------------
__global__ void __launch_bounds__(256)
ew0_kernel(const float* __restrict__ x, const float* __restrict__ maa_x)
{
    size_t i4  = (size_t)blockIdx.x * 256 + threadIdx.x;
    size_t idx = i4 * 4;
    int c    = (int)(idx & (CC - 1));
    int nrow = (int)(idx >> 10);
    float4 xv = *(const float4*)&x[idx];
    float4 xp = make_float4(0.f, 0.f, 0.f, 0.f);
    if (nrow & (TT - 1))
        xp = *(const float4*)&x[idx - CC];
    float4 mv = *(const float4*)&maa_x[c];
    float4 d, xm;
    d.x = xp.x - xv.x;  xm.x = xv.x + d.x * mv.x;
    d.y = xp.y - xv.y;  xm.y = xv.y + d.y * mv.y;
    d.z = xp.z - xv.z;  xm.z = xv.z + d.z * mv.z;
    d.w = xp.w - xv.w;  xm.w = xv.w + d.w * mv.w;
    *(float4*)&g_s.xx[idx] = d;
    uint2 h, l;
    split4(xm, h, l);
    *(uint2*)&g_s.xmixh[idx] = h;
    *(uint2*)&g_s.xmixl[idx] = l;
}

// ---------------------------------------------------------------------------
// combine
// ---------------------------------------------------------------------------
__global__ void __launch_bounds__(256)
combine_kernel()
{
    int n   = blockIdx.x;
    int tid = threadIdx.x;
    size_t off = (size_t)n * CC + tid * 4;

    float4 kkv = *(float4*)&g_s.kk[off];
    float ss = kkv.x*kkv.x + kkv.y*kkv.y + kkv.z*kkv.z + kkv.w*kkv.w;
#pragma unroll
    for (int o = 8; o; o >>= 1) ss += __shfl_xor_sync(0xffffffffu, ss, o, 16);
    float inv = 1.f / fmaxf(sqrtf(ss), 1e-12f);

    float4 kq = *(float4*)&g_s.k[off];
    float4 aq = *(float4*)&g_s.asig[off];
    float4 mq = *(float4*)&g_s.ma[off];
    float4 wq = *(float4*)&g_s.w[off];
    float4 mk = *(float4*)&g_s.mk2[off];
    float4 kfv, ddv, avv, bvv;
#define CMB(X) { float fac = mq.X + aq.X * (1.f - mq.X); \
    float ee = expf(fminf(wq.X * mk.X, 0.f)); \
    kfv.X = kq.X * fac * ee; \
    ddv.X = expf(wq.X); \
    float kn = kkv.X * inv; \
    avv.X = -kn; bvv.X = kn * aq.X; }
    CMB(x) CMB(y) CMB(z) CMB(w)
#undef CMB
    *(float4*)&g_s.kf[off] = kfv;
    *(float4*)&g_s.dd[off] = ddv;
    *(float4*)&g_s.av[off] = avv;
    *(float4*)&g_s.bv[off] = bvv;
}

// ---------------------------------------------------------------------------
// WKV-7 scan: cp.async 3-deep pipeline
// ---------------------------------------------------------------------------
__global__ void __launch_bounds__(256)
wkv_kernel()
{
    const int blk = blockIdx.x;
    const int b = blk >> 4;
    const int h = blk & 15;
    const int tid = threadIdx.x;
    const int i  = tid >> 2;
    const int jq = tid & 3;

    __shared__ __align__(16) float sb[4][6][64];
    const size_t rowbase = ((size_t)b * TT) * CC + h * NN;

    const float* gsrc = 0;
    uint32_t sdst[4];
    if (tid < 96) {
        int larr = tid >> 4, lq = tid & 15;
        const float* srcs[6] = { g_s.r, g_s.dd, g_s.kf, g_s.av, g_s.bv, g_s.v };
        gsrc = srcs[larr] + rowbase + lq * 4;
#pragma unroll
        for (int q = 0; q < 4; q++) sdst[q] = smem_u32(&sb[q][larr][lq * 4]);
    }

#pragma unroll
    for (int pre = 0; pre < 3; pre++) {
        if (tid < 96) cp_async16(sdst[pre], gsrc + (size_t)pre * CC);
        CP_COMMIT();
    }

    unsigned long long S2[8];
#pragma unroll
    for (int u = 0; u < 8; u++) S2[u] = 0ull;

    float* yout = g_s.y + rowbase + i;

    for (int t = 0; t < TT; t++) {
        CP_WAIT2();
        __syncthreads();
        const int p = t & 3;

        const ulonglong2* r2p = (const ulonglong2*)(sb[p][0] + jq * 16);
        const ulonglong2* d2p = (const ulonglong2*)(sb[p][1] + jq * 16);
        const ulonglong2* k2p = (const ulonglong2*)(sb[p][2] + jq * 16);
        const ulonglong2* a2p = (const ulonglong2*)(sb[p][3] + jq * 16);
        const ulonglong2* b2p = (const ulonglong2*)(sb[p][4] + jq * 16);
        const float vi = sb[p][5][i];

        ulonglong2 Rv[4], Dv[4], Kv[4], Av[4], Bv[4];
#pragma unroll
        for (int u = 0; u < 4; u++) {
            Rv[u] = r2p[u]; Dv[u] = d2p[u]; Kv[u] = k2p[u];
            Av[u] = a2p[u]; Bv[u] = b2p[u];
        }

        if (tid < 96 && t + 3 < TT)
            cp_async16(sdst[(t + 3) & 3], gsrc + (size_t)(t + 3) * CC);
        CP_COMMIT();

        unsigned long long sa0 = 0ull, sa1 = 0ull, pp0 = 0ull, pp1 = 0ull;
        unsigned long long br0 = 0ull, br1 = 0ull, kr0 = 0ull, kr1 = 0ull;
#pragma unroll
        for (int u = 0; u < 4; u++) {
            unsigned long long drx = mul2(Dv[u].x, Rv[u].x);
            unsigned long long dry = mul2(Dv[u].y, Rv[u].y);
            fma2(sa0, S2[2*u],   Av[u].x);
            fma2(sa1, S2[2*u+1], Av[u].y);
            fma2(pp0, S2[2*u],   drx);
            fma2(pp1, S2[2*u+1], dry);
            fma2(br0, Bv[u].x, Rv[u].x);
            fma2(br1, Bv[u].y, Rv[u].y);
            fma2(kr0, Kv[u].x, Rv[u].x);
            fma2(kr1, Kv[u].y, Rv[u].y);
        }
        float sa = hadd4(sa0, sa1);
        float pp = hadd4(pp0, pp1);
        float br = hadd4(br0, br1);
        float kr = hadd4(kr0, kr1);
        sa += __shfl_xor_sync(0xffffffffu, sa, 1, 4);
        pp += __shfl_xor_sync(0xffffffffu, pp, 1, 4);
        br += __shfl_xor_sync(0xffffffffu, br, 1, 4);
        kr += __shfl_xor_sync(0xffffffffu, kr, 1, 4);
        sa += __shfl_xor_sync(0xffffffffu, sa, 2, 4);
        pp += __shfl_xor_sync(0xffffffffu, pp, 2, 4);
        br += __shfl_xor_sync(0xffffffffu, br, 2, 4);
        kr += __shfl_xor_sync(0xffffffffu, kr, 2, 4);

        if (jq == 0) yout[(size_t)t * CC] = pp + sa * br + vi * kr;

        const unsigned long long sa2 = dup2(sa);
        const unsigned long long v2  = dup2(vi);
#pragma unroll
        for (int u = 0; u < 4; u++) {
            S2[2*u]   = fma2g(S2[2*u],   Dv[u].x,
                              fma2g(sa2, Bv[u].x, mul2(v2, Kv[u].x)));
            S2[2*u+1] = fma2g(S2[2*u+1], Dv[u].y,
                              fma2g(sa2, Bv[u].y, mul2(v2, Kv[u].y)));
        }
    }
}

// ---------------------------------------------------------------------------
// post: GroupNorm + bonus + gate -> z (bf16 hi/lo)
// ---------------------------------------------------------------------------
__global__ void __launch_bounds__(256)
post_kernel(const float* __restrict__ faaaa,
            const float* __restrict__ lnw, const float* __restrict__ lnb)
{
    int n   = blockIdx.x;
    int tid = threadIdx.x;
    int c   = tid * 4;
    size_t off = (size_t)n * CC + c;

    float4 yv = *(float4*)&g_s.y [off];
    float4 rv = *(float4*)&g_s.r [off];
    float4 kv = *(float4*)&g_s.kf[off];
    float4 vv = *(float4*)&g_s.v [off];
    float4 gv = *(float4*)&g_s.g [off];
    float4 fv = *(const float4*)&faaaa[c];

    float s  = yv.x + yv.y + yv.z + yv.w;
    float s2 = yv.x*yv.x + yv.y*yv.y + yv.z*yv.z + yv.w*yv.w;
    float dk = rv.x*kv.x*fv.x + rv.y*kv.y*fv.y + rv.z*kv.z*fv.z + rv.w*kv.w*fv.w;
#pragma unroll
    for (int o = 8; o; o >>= 1) {
        s  += __shfl_xor_sync(0xffffffffu, s,  o, 16);
        s2 += __shfl_xor_sync(0xffffffffu, s2, o, 16);
        dk += __shfl_xor_sync(0xffffffffu, dk, o, 16);
    }
    float mean = s  * (1.f / 64.f);
    float var  = s2 * (1.f / 64.f) - mean * mean;
    float rs   = rsqrtf(var + 64e-5f);

    float4 lw = *(const float4*)&lnw[c];
    float4 lb = *(const float4*)&lnb[c];
    float4 z;
    z.x = (((yv.x - mean) * rs) * lw.x + lb.x + dk * vv.x) * gv.x;
    z.y = (((yv.y - mean) * rs) * lw.y + lb.y + dk * vv.y) * gv.y;
    z.z = (((yv.z - mean) * rs) * lw.z + lb.z + dk * vv.z) * gv.z;
    z.w = (((yv.w - mean) * rs) * lw.w + lb.w + dk * vv.w) * gv.w;
    uint2 h, l;
    split4(z, h, l);
    *(uint2*)&g_s.zh[off] = h;
    *(uint2*)&g_s.zl[off] = l;
}

// ---------------------------------------------------------------------------
// Host orchestration
// ---------------------------------------------------------------------------
static void gmma(const bf16* Ah, const bf16* Al, const bf16* Bh,
                 const bf16* Bl, float* Cp, int K)
{
    dim3 grid(8, MM / 128);
    gemm_mma2<<<grid, 256, MMA_SMEM>>>(Ah, Al, Bh, Bl, Cp, K);
}
static void convw(const float* src, bf16* h, bf16* l, int elems)
{
    conv_bf16<<<elems / 1024, 256>>>((const float4*)src, (uint2*)h, (uint2*)l);
}

#define UP64_SMEM 30720
#define UP32_SMEM 20480

extern "C" void kernel_launch(void* const* d_in, const int* in_sizes, int n_in,
                              void* d_out, int out_size)
{
    const float* x       = (const float*)d_in[0];
    const float* maa_x   = (const float*)d_in[1];
    const float* maa_rg  = (const float*)d_in[2];
    const float* maa_wa  = (const float*)d_in[3];
    const float* maa_k   = (const float*)d_in[4];
    const float* maa_v   = (const float*)d_in[5];
    const float* maa_w1  = (const float*)d_in[6];
    const float* maa_w2  = (const float*)d_in[7];
    const float* tdecay  = (const float*)d_in[8];
    const float* dw1     = (const float*)d_in[9];
    const float* dw2     = (const float*)d_in[10];
    const float* faaaa   = (const float*)d_in[11];
    const float* taaaaa  = (const float*)d_in[12];
    const float* aw1     = (const float*)d_in[13];
    const float* aw2     = (const float*)d_in[14];
    const float* kw1     = (const float*)d_in[15];
    const float* kw2     = (const float*)d_in[16];
    const float* gw1     = (const float*)d_in[17];
    const float* gw2     = (const float*)d_in[18];
    const float* maw1    = (const float*)d_in[19];
    const float* maw2    = (const float*)d_in[20];
    const float* tmisca  = (const float*)d_in[21];
    const float* mkw1    = (const float*)d_in[22];
    const float* mkw2    = (const float*)d_in[23];
    const float* tmisck  = (const float*)d_in[24];
    const float* wr      = (const float*)d_in[25];
    const float* wk      = (const float*)d_in[26];
    const float* wv      = (const float*)d_in[27];
    const float* wo      = (const float*)d_in[28];
    const float* lnw     = (const float*)d_in[29];
    const float* lnb     = (const float*)d_in[30];
    float* out = (float*)d_out;
    (void)in_sizes; (void)n_in; (void)out_size;

    Scratch* S = nullptr;
    cudaGetSymbolAddress((void**)&S, g_s);
    cudaFuncSetAttribute(gemm_mma2, cudaFuncAttributeMaxDynamicSharedMemorySize,
                         MMA_SMEM);
    cudaFuncSetAttribute(gemm_down, cudaFuncAttributeMaxDynamicSharedMemorySize,
                         MMA_SMEM);
    cudaFuncSetAttribute(fused_mix, cudaFuncAttributeMaxDynamicSharedMemorySize,
                         MIX_SMEM);
    cudaFuncSetAttribute(gemm_up<64>,
                         cudaFuncAttributeMaxDynamicSharedMemorySize, UP64_SMEM);
    cudaFuncSetAttribute(gemm_up<32>,
                         cudaFuncAttributeMaxDynamicSharedMemorySize, UP32_SMEM);

    convw(wr, S->wrh, S->wrl, CC * CC);                                  // 1
    ew0_kernel<<<(MM * CC / 4) / 256, 256>>>(x, maa_x);                  // 2
    packT_w1<<<512, 256>>>(maa_w1, S->mw1Th, S->mw1Tl);                  // 3
    gemm_up<64><<<dim3(128, 2), 256, UP64_SMEM>>>(S->xmixh, S->xmixl,    // 4
        S->mw1Th, S->mw1Tl, S->mixin, 128, 128, 0, 0, 0, 0);
    fused_mix<<<dim3(8, 32), 256, MIX_SMEM>>>(x, maa_w2,                 // 5
        maa_rg, maa_wa, maa_k, maa_v);
    gmma(S->xrgh, S->xrgl, S->wrh, S->wrl, S->r, 1024);                  // 6
    convw(wk, S->wkh, S->wkl, CC * CC);                                  // 7
    gmma(S->xkh, S->xkl, S->wkh, S->wkl, S->k, 1024);                    // 8
    convw(wv, S->wvh, S->wvl, CC * CC);                                  // 9
    gmma(S->xvh, S->xvl, S->wvh, S->wvl, S->v, 1024);                    // 10

    // gate
    packT_w1<<<512, 256>>>(gw1, S->gw1Th, S->gw1Tl);
    gemm_up<64><<<dim3(128, 2), 256, UP64_SMEM>>>(S->xrgh, S->xrgl,
        S->gw1Th, S->gw1Tl, 0, 0, 128, S->g1h, S->g1l, 128, 0);
    transconv_kernel<<<dim3(32, 4), 256>>>(gw2, S->gw2Th, S->gw2Tl);
    gmma(S->g1h, S->g1l, S->gw2Th, S->gw2Tl, S->g, 128);

    // LoRA up-projections into loraA (stride 160)
    packT_wa<<<512, 256>>>(dw1, aw1, maw1);
    gemm_up<64><<<dim3(128, 2), 256, UP64_SMEM>>>(S->xwah, S->xwal,
        S->waTh, S->waTl, 0, 0, 64, S->loraAh, S->loraAl, 160, 0);
    packT_k<<<128, 256>>>(kw1, mkw1);
    gemm_up<32><<<dim3(128, 1), 256, UP32_SMEM>>>(S->xkh, S->xkl,
        S->kTh, S->kTl, 0, 0, 16, S->loraAh, S->loraAl, 160, 128);

    // fused block-diagonal down-projection -> w, asig, ma, kk, mk2
    pack_bigB<<<(5120 * 160) / 256, 256>>>(dw2, aw2, maw2, kw2, mkw2);
    gemm_down<<<dim3(40, 32), 256, MMA_SMEM>>>(tdecay, taaaaa, tmisca, tmisck);

    // combine + scan + post + output
    combine_kernel<<<MM, 256>>>();
    wkv_kernel<<<BB * HH, 256>>>();
    post_kernel<<<MM, 256>>>(faaaa, lnw, lnb);
    convw(wo, S->woh, S->wol, CC * CC);
    gmma(S->zh, S->zl, S->woh, S->wol, out, 1024);
}

// round 11
// speedup vs baseline: 2.4268x; 1.0187x over previous
#include <cuda_runtime.h>
#include <cuda_bf16.h>
#include <math.h>
#include <stdint.h>
#include <string.h>

#define BB 4
#define TT 1024
#define CC 1024
#define HH 16
#define NN 64
#define MM (BB*TT)   // 4096 rows

typedef __nv_bfloat16 bf16;

// ---------------------------------------------------------------------------
// Scratch (static device memory)
// ---------------------------------------------------------------------------
struct Scratch {
    float xx   [MM*CC];
    float mixin[MM*128];
    float r    [MM*CC];
    float k    [MM*CC];
    float v    [MM*CC];
    float g    [MM*CC];
    float w    [MM*CC];
    float kk   [MM*CC];
    float asig [MM*CC];
    float ma   [MM*CC];
    float mk2  [MM*CC];
    float kf   [MM*CC];
    float dd   [MM*CC];
    float av   [MM*CC];
    float bv   [MM*CC];
    float y    [MM*CC];
    // bf16 hi/lo activations
    bf16 xmixh[MM*CC], xmixl[MM*CC];
    bf16 xrgh[MM*CC], xrgl[MM*CC];
    bf16 xwah[MM*CC], xwal[MM*CC];
    bf16 xkh [MM*CC], xkl [MM*CC];
    bf16 xvh [MM*CC], xvl [MM*CC];
    bf16 zh  [MM*CC], zl  [MM*CC];
    bf16 g1h [MM*128], g1l [MM*128];
    bf16 loraAh[MM*160], loraAl[MM*160];
    // bf16 hi/lo weights
    bf16 wrh[CC*CC], wrl[CC*CC];
    bf16 wkh[CC*CC], wkl[CC*CC];
    bf16 wvh[CC*CC], wvl[CC*CC];
    bf16 woh[CC*CC], wol[CC*CC];
    bf16 gw2Th[CC*128], gw2Tl[CC*128];
    bf16 mw1Th[128*1024], mw1Tl[128*1024];
    bf16 gw1Th[128*1024], gw1Tl[128*1024];
    bf16 waTh [128*1024], waTl [128*1024];
    bf16 kTh  [64*1024],  kTl  [64*1024];
    bf16 bigBh[5120*160], bigBl[5120*160];
};
__device__ Scratch g_s;

// ---------------------------------------------------------------------------
// Packed f32x2 helpers
// ---------------------------------------------------------------------------
__device__ __forceinline__ unsigned long long dup2(float x) {
    unsigned long long r;
    asm("mov.b64 %0, {%1, %1};" : "=l"(r) : "f"(x));
    return r;
}
__device__ __forceinline__ void fma2(unsigned long long& acc,
                                     unsigned long long a,
                                     unsigned long long b) {
    asm("fma.rn.f32x2 %0, %1, %2, %0;" : "+l"(acc) : "l"(a), "l"(b));
}
__device__ __forceinline__ unsigned long long fma2g(unsigned long long a,
                                                    unsigned long long b,
                                                    unsigned long long c) {
    unsigned long long d;
    asm("fma.rn.f32x2 %0, %1, %2, %3;" : "=l"(d) : "l"(a), "l"(b), "l"(c));
    return d;
}
__device__ __forceinline__ unsigned long long mul2(unsigned long long a,
                                                   unsigned long long b) {
    unsigned long long d;
    asm("mul.rn.f32x2 %0, %1, %2;" : "=l"(d) : "l"(a), "l"(b));
    return d;
}
__device__ __forceinline__ float2 unpack2(unsigned long long v) {
    float2 f;
    asm("mov.b64 {%0, %1}, %2;" : "=f"(f.x), "=f"(f.y) : "l"(v));
    return f;
}
__device__ __forceinline__ float hadd4(unsigned long long a,
                                       unsigned long long b) {
    float2 f = unpack2(a), g = unpack2(b);
    return (f.x + f.y) + (g.x + g.y);
}
__device__ __forceinline__ uint32_t smem_u32(const void* p) {
    uint32_t a;
    asm("{ .reg .u64 t; cvta.to.shared.u64 t, %1; cvt.u32.u64 %0, t; }"
        : "=r"(a) : "l"(p));
    return a;
}

// cp.async helpers
__device__ __forceinline__ void cp_async16(uint32_t saddr, const void* gptr) {
    asm volatile("cp.async.cg.shared.global [%0], [%1], 16;"
        :: "r"(saddr), "l"(gptr) : "memory");
}
#define CP_COMMIT() asm volatile("cp.async.commit_group;" ::: "memory")
#define CP_WAIT0()  asm volatile("cp.async.wait_group 0;" ::: "memory")
#define CP_WAIT2()  asm volatile("cp.async.wait_group 2;" ::: "memory")

// hi/lo splits
__device__ __forceinline__ void split4(float4 f, uint2& h, uint2& l) {
    __nv_bfloat162 h01 = __floats2bfloat162_rn(f.x, f.y);
    __nv_bfloat162 h23 = __floats2bfloat162_rn(f.z, f.w);
    float lx = f.x - __bfloat162float(h01.x);
    float ly = f.y - __bfloat162float(h01.y);
    float lz = f.z - __bfloat162float(h23.x);
    float lw = f.w - __bfloat162float(h23.y);
    __nv_bfloat162 l01 = __floats2bfloat162_rn(lx, ly);
    __nv_bfloat162 l23 = __floats2bfloat162_rn(lz, lw);
    memcpy(&h.x, &h01, 4); memcpy(&h.y, &h23, 4);
    memcpy(&l.x, &l01, 4); memcpy(&l.y, &l23, 4);
}
__device__ __forceinline__ void split2(float a, float b,
                                       uint32_t& h, uint32_t& l) {
    __nv_bfloat162 hh = __floats2bfloat162_rn(a, b);
    float la = a - __bfloat162float(hh.x);
    float lb = b - __bfloat162float(hh.y);
    __nv_bfloat162 ll = __floats2bfloat162_rn(la, lb);
    memcpy(&h, &hh, 4); memcpy(&l, &ll, 4);
}

// ---------------------------------------------------------------------------
// mma.sync / ldmatrix helpers
// ---------------------------------------------------------------------------
__device__ __forceinline__ void ldsm4(uint32_t* r, uint32_t addr) {
    asm volatile("ldmatrix.sync.aligned.m8n8.x4.shared.b16 {%0,%1,%2,%3}, [%4];"
        : "=r"(r[0]), "=r"(r[1]), "=r"(r[2]), "=r"(r[3]) : "r"(addr));
}
__device__ __forceinline__ void mma_bf16(float* c, const uint32_t* a,
                                         const uint32_t* b) {
    asm volatile("mma.sync.aligned.m16n8k16.row.col.f32.bf16.bf16.f32 "
        "{%0,%1,%2,%3}, {%4,%5,%6,%7}, {%8,%9}, {%0,%1,%2,%3};"
        : "+f"(c[0]), "+f"(c[1]), "+f"(c[2]), "+f"(c[3])
        : "r"(a[0]), "r"(a[1]), "r"(a[2]), "r"(a[3]), "r"(b[0]), "r"(b[1]));
}

// ---------------------------------------------------------------------------
// gemm_mma2: C[M,1024] = (Ah+Al)[M,K] @ (Bh+Bl)[1024,K]^T, fp32 accum.
// ---------------------------------------------------------------------------
#define MMA_SMEM 81920

__global__ void __launch_bounds__(256, 2)
gemm_mma2(const bf16* __restrict__ Ah, const bf16* __restrict__ Al,
          const bf16* __restrict__ Bh, const bf16* __restrict__ Bl,
          float* __restrict__ Cm, int K)
{
    extern __shared__ __align__(16) char sm[];
    const uint32_t sb = smem_u32(sm);

    const int tid  = threadIdx.x;
    const int lane = tid & 31;
    const int wid  = tid >> 5;
    const int wm   = wid & 1;
    const int wn   = wid >> 1;
    const int n0 = blockIdx.x * 128;
    const int m0 = blockIdx.y * 128;

    const int row = tid >> 1, half = tid & 1;
    const bf16* pAh = Ah + (size_t)(m0 + row) * K + half * 16;
    const bf16* pAl = Al + (size_t)(m0 + row) * K + half * 16;
    const bf16* pBh = Bh + (size_t)(n0 + row) * K + half * 16;
    const bf16* pBl = Bl + (size_t)(n0 + row) * K + half * 16;
    const uint32_t st = (uint32_t)(row * 80 + half * 32);

    const uint32_t aLoff = (uint32_t)((lane & 15) * 80 + (lane >> 4) * 16);
    const uint32_t bLoff = (uint32_t)(((lane & 7) + ((lane >> 4) & 1) * 8) * 80
                                      + ((lane >> 3) & 1) * 16);

    float c[4][4][4];
#pragma unroll
    for (int i = 0; i < 4; i++)
#pragma unroll
        for (int j = 0; j < 4; j++)
#pragma unroll
            for (int q = 0; q < 4; q++) c[i][j][q] = 0.f;

    const int chunks = K >> 5;

    {
        uint32_t d = sb + st;
        cp_async16(d,             pAh); cp_async16(d + 16,         pAh + 8);
        cp_async16(d + 10240,     pAl); cp_async16(d + 10240 + 16, pAl + 8);
        cp_async16(d + 20480,     pBh); cp_async16(d + 20480 + 16, pBh + 8);
        cp_async16(d + 30720,     pBl); cp_async16(d + 30720 + 16, pBl + 8);
        CP_COMMIT();
        CP_WAIT0();
    }
    __syncthreads();

    for (int cidx = 0; cidx < chunks; cidx++) {
        const uint32_t bufOff = (uint32_t)((cidx & 1) * 40960);
        const bool more = (cidx + 1 < chunks);

        if (more) {
            const int ko = (cidx + 1) * 32;
            uint32_t d = sb + (uint32_t)(((cidx + 1) & 1) * 40960) + st;
            cp_async16(d,             pAh + ko); cp_async16(d + 16,         pAh + ko + 8);
            cp_async16(d + 10240,     pAl + ko); cp_async16(d + 10240 + 16, pAl + ko + 8);
            cp_async16(d + 20480,     pBh + ko); cp_async16(d + 20480 + 16, pBh + ko + 8);
            cp_async16(d + 30720,     pBl + ko); cp_async16(d + 30720 + 16, pBl + ko + 8);
            CP_COMMIT();
        }

        const uint32_t aBase = sb + bufOff + (uint32_t)(wm * 64 * 80) + aLoff;
        const uint32_t bBase = sb + bufOff + 20480u + (uint32_t)(wn * 32 * 80) + bLoff;
#pragma unroll
        for (int ks = 0; ks < 2; ks++) {
            uint32_t afh[4][4], afl[4][4];
#pragma unroll
            for (int mi = 0; mi < 4; mi++) {
                ldsm4(afh[mi], aBase + 0u     + (uint32_t)(mi * 1280 + ks * 32));
                ldsm4(afl[mi], aBase + 10240u + (uint32_t)(mi * 1280 + ks * 32));
            }
            uint32_t bfh[2][4], bfl[2][4];
#pragma unroll
            for (int np = 0; np < 2; np++) {
                ldsm4(bfh[np], bBase + 0u     + (uint32_t)(np * 1280 + ks * 32));
                ldsm4(bfl[np], bBase + 10240u + (uint32_t)(np * 1280 + ks * 32));
            }
#pragma unroll
            for (int mi = 0; mi < 4; mi++) {
#pragma unroll
                for (int ni = 0; ni < 4; ni++) {
                    const uint32_t* bh = &bfh[ni >> 1][(ni & 1) * 2];
                    const uint32_t* bl = &bfl[ni >> 1][(ni & 1) * 2];
                    mma_bf16(c[mi][ni], afh[mi], bh);
                    mma_bf16(c[mi][ni], afh[mi], bl);
                    mma_bf16(c[mi][ni], afl[mi], bh);
                }
            }
        }

        if (more) CP_WAIT0();
        __syncthreads();
    }

    const int erow = m0 + wm * 64 + (lane >> 2);
    const int ecol = n0 + wn * 32 + (lane & 3) * 2;
#pragma unroll
    for (int mi = 0; mi < 4; mi++) {
#pragma unroll
        for (int ni = 0; ni < 4; ni++) {
            size_t base0 = (size_t)(erow + mi * 16)     * 1024 + ecol + ni * 8;
            size_t base1 = (size_t)(erow + mi * 16 + 8) * 1024 + ecol + ni * 8;
            *(float2*)&Cm[base0] = make_float2(c[mi][ni][0], c[mi][ni][1]);
            *(float2*)&Cm[base1] = make_float2(c[mi][ni][2], c[mi][ni][3]);
        }
    }
}

// ---------------------------------------------------------------------------
// gemm_down: fused LoRA down-projections (block-diagonal).
// ---------------------------------------------------------------------------
__global__ void __launch_bounds__(256, 2)
gemm_down(const float* __restrict__ tdecay, const float* __restrict__ taaaaa,
          const float* __restrict__ tmisca, const float* __restrict__ tmisck)
{
    extern __shared__ __align__(16) char sm[];
    const uint32_t sb = smem_u32(sm);

    const int tid  = threadIdx.x;
    const int lane = tid & 31;
    const int wid  = tid >> 5;
    const int wm   = wid & 1;
    const int wn   = wid >> 1;
    const int n0 = blockIdx.x * 128;
    const int m0 = blockIdx.y * 128;

    const int row = tid >> 1, half = tid & 1;
    const bf16* pAh = g_s.loraAh + (size_t)(m0 + row) * 160 + half * 16;
    const bf16* pAl = g_s.loraAl + (size_t)(m0 + row) * 160 + half * 16;
    const bf16* pBh = g_s.bigBh  + (size_t)(n0 + row) * 160 + half * 16;
    const bf16* pBl = g_s.bigBl  + (size_t)(n0 + row) * 160 + half * 16;
    const uint32_t st = (uint32_t)(row * 80 + half * 32);

    const uint32_t aLoff = (uint32_t)((lane & 15) * 80 + (lane >> 4) * 16);
    const uint32_t bLoff = (uint32_t)(((lane & 7) + ((lane >> 4) & 1) * 8) * 80
                                      + ((lane >> 3) & 1) * 16);

    float c[4][4][4];
#pragma unroll
    for (int i = 0; i < 4; i++)
#pragma unroll
        for (int j = 0; j < 4; j++)
#pragma unroll
            for (int q = 0; q < 4; q++) c[i][j][q] = 0.f;

    {
        uint32_t d = sb + st;
        cp_async16(d,             pAh); cp_async16(d + 16,         pAh + 8);
        cp_async16(d + 10240,     pAl); cp_async16(d + 10240 + 16, pAl + 8);
        cp_async16(d + 20480,     pBh); cp_async16(d + 20480 + 16, pBh + 8);
        cp_async16(d + 30720,     pBl); cp_async16(d + 30720 + 16, pBl + 8);
        CP_COMMIT();
        CP_WAIT0();
    }
    __syncthreads();

    for (int cidx = 0; cidx < 5; cidx++) {
        const uint32_t bufOff = (uint32_t)((cidx & 1) * 40960);
        const bool more = (cidx + 1 < 5);

        if (more) {
            const int ko = (cidx + 1) * 32;
            uint32_t d = sb + (uint32_t)(((cidx + 1) & 1) * 40960) + st;
            cp_async16(d,             pAh + ko); cp_async16(d + 16,         pAh + ko + 8);
            cp_async16(d + 10240,     pAl + ko); cp_async16(d + 10240 + 16, pAl + ko + 8);
            cp_async16(d + 20480,     pBh + ko); cp_async16(d + 20480 + 16, pBh + ko + 8);
            cp_async16(d + 30720,     pBl + ko); cp_async16(d + 30720 + 16, pBl + ko + 8);
            CP_COMMIT();
        }

        const uint32_t aBase = sb + bufOff + (uint32_t)(wm * 64 * 80) + aLoff;
        const uint32_t bBase = sb + bufOff + 20480u + (uint32_t)(wn * 32 * 80) + bLoff;
#pragma unroll
        for (int ks = 0; ks < 2; ks++) {
            uint32_t afh[4][4], afl[4][4];
#pragma unroll
            for (int mi = 0; mi < 4; mi++) {
                ldsm4(afh[mi], aBase + 0u     + (uint32_t)(mi * 1280 + ks * 32));
                ldsm4(afl[mi], aBase + 10240u + (uint32_t)(mi * 1280 + ks * 32));
            }
            uint32_t bfh[2][4], bfl[2][4];
#pragma unroll
            for (int np = 0; np < 2; np++) {
                ldsm4(bfh[np], bBase + 0u     + (uint32_t)(np * 1280 + ks * 32));
                ldsm4(bfl[np], bBase + 10240u + (uint32_t)(np * 1280 + ks * 32));
            }
#pragma unroll
            for (int mi = 0; mi < 4; mi++) {
#pragma unroll
                for (int ni = 0; ni < 4; ni++) {
                    const uint32_t* bh = &bfh[ni >> 1][(ni & 1) * 2];
                    const uint32_t* bl = &bfl[ni >> 1][(ni & 1) * 2];
                    mma_bf16(c[mi][ni], afh[mi], bh);
                    mma_bf16(c[mi][ni], afh[mi], bl);
                    mma_bf16(c[mi][ni], afl[mi], bh);
                }
            }
        }

        if (more) CP_WAIT0();
        __syncthreads();
    }

    const int blk = n0 >> 10;
    float* outp; const float* ev; int mode;
    switch (blk) {
        case 0:  outp = g_s.w;    ev = tdecay; mode = 4; break;
        case 1:  outp = g_s.asig; ev = taaaaa; mode = 3; break;
        case 2:  outp = g_s.ma;   ev = tmisca; mode = 3; break;
        case 3:  outp = g_s.kk;   ev = 0;      mode = 5; break;
        default: outp = g_s.mk2;  ev = tmisck; mode = 3; break;
    }
    const int erow = m0 + wm * 64 + (lane >> 2);
    const int ecol = (n0 & 1023) + wn * 32 + (lane & 3) * 2;
#pragma unroll
    for (int mi = 0; mi < 4; mi++) {
#pragma unroll
        for (int ni = 0; ni < 4; ni++) {
            const int col = ecol + ni * 8;
            const int r0 = erow + mi * 16, r1 = r0 + 8;
            float v0 = c[mi][ni][0], v1 = c[mi][ni][1];
            float v2 = c[mi][ni][2], v3 = c[mi][ni][3];
            if (mode == 4) {
                float e0 = ev[col], e1 = ev[col + 1];
                v0 = -log1pf(expf(-(e0 + v0))) - 0.5f;
                v1 = -log1pf(expf(-(e1 + v1))) - 0.5f;
                v2 = -log1pf(expf(-(e0 + v2))) - 0.5f;
                v3 = -log1pf(expf(-(e1 + v3))) - 0.5f;
            } else if (mode == 3) {
                float e0 = ev[col], e1 = ev[col + 1];
                v0 = 1.f / (1.f + expf(-(e0 + v0)));
                v1 = 1.f / (1.f + expf(-(e1 + v1)));
                v2 = 1.f / (1.f + expf(-(e0 + v2)));
                v3 = 1.f / (1.f + expf(-(e1 + v3)));
            } else {
                float2 k0 = *(const float2*)&g_s.k[(size_t)r0 * 1024 + col];
                float2 k1 = *(const float2*)&g_s.k[(size_t)r1 * 1024 + col];
                v0 += k0.x; v1 += k0.y; v2 += k1.x; v3 += k1.y;
            }
            *(float2*)&outp[(size_t)r0 * 1024 + col] = make_float2(v0, v1);
            *(float2*)&outp[(size_t)r1 * 1024 + col] = make_float2(v2, v3);
        }
    }
}

// ---------------------------------------------------------------------------
// up-projection core (CTA 32x64, cp.async dbl-buffered, chunk 32)
// ---------------------------------------------------------------------------
#define UP64_SMEM 30720

__device__ __forceinline__ void up64_body(
    const bf16* __restrict__ Ah, const bf16* __restrict__ Al,
    const bf16* __restrict__ Bh, const bf16* __restrict__ Bl,
    int m0, int n0, int tanhN, int maxcol,
    float* __restrict__ Cm, int cstride,
    bf16* __restrict__ oh, bf16* __restrict__ ol, int ostride, int ocol,
    char* sm)
{
    constexpr int B_BYTES = 64 * 80;          // 5120
    constexpr int OFF_AL = 2560;
    constexpr int OFF_BH = 5120;
    constexpr int BUF = 5120 + 2 * B_BYTES;   // 15360

    const uint32_t sb = smem_u32(sm);
    const int tid  = threadIdx.x;
    const int lane = tid & 31;
    const int wid  = tid >> 5;
    const int wm   = wid & 1;
    const int wn   = wid >> 1;

    const int arow = (tid & 127) >> 2, aq2 = tid & 3;
    const bf16* pAh = Ah + (size_t)(m0 + arow) * 1024 + aq2 * 8;
    const bf16* pAl = Al + (size_t)(m0 + arow) * 1024 + aq2 * 8;
    const uint32_t stA = (uint32_t)(arow * 80 + aq2 * 16);
    const int brow = tid >> 2;
    const bf16* pBh = Bh + (size_t)(n0 + brow) * 1024 + aq2 * 8;
    const bf16* pBl = Bl + (size_t)(n0 + brow) * 1024 + aq2 * 8;
    const uint32_t stB = (uint32_t)(brow * 80 + aq2 * 16);
    const bool doA = (tid < 128);

    const uint32_t aLoff = (uint32_t)((lane & 15) * 80 + (lane >> 4) * 16);
    const uint32_t bLoff = (uint32_t)(((lane & 7) + ((lane >> 4) & 1) * 8) * 80
                                      + ((lane >> 3) & 1) * 16);

    float c[2][4];
#pragma unroll
    for (int j = 0; j < 2; j++)
#pragma unroll
        for (int q = 0; q < 4; q++) c[j][q] = 0.f;

    {
        if (doA) {
            cp_async16(sb + stA, pAh);
            cp_async16(sb + OFF_AL + stA, pAl);
        }
        cp_async16(sb + OFF_BH + stB, pBh);
        cp_async16(sb + OFF_BH + B_BYTES + stB, pBl);
        CP_COMMIT();
        CP_WAIT0();
    }
    __syncthreads();

    for (int cidx = 0; cidx < 32; cidx++) {
        const uint32_t bufOff = (uint32_t)((cidx & 1) * BUF);
        const bool more = (cidx + 1 < 32);

        if (more) {
            const int ko = (cidx + 1) * 32;
            uint32_t d = sb + (uint32_t)(((cidx + 1) & 1) * BUF);
            if (doA) {
                cp_async16(d + stA, pAh + ko);
                cp_async16(d + OFF_AL + stA, pAl + ko);
            }
            cp_async16(d + OFF_BH + stB, pBh + ko);
            cp_async16(d + OFF_BH + B_BYTES + stB, pBl + ko);
            CP_COMMIT();
        }

        const uint32_t aBase = sb + bufOff + (uint32_t)(wm * 16 * 80) + aLoff;
#pragma unroll
        for (int ks = 0; ks < 2; ks++) {
            uint32_t afh[4], afl[4];
            ldsm4(afh, aBase + (uint32_t)(ks * 32));
            ldsm4(afl, aBase + OFF_AL + (uint32_t)(ks * 32));
            uint32_t bfh[4], bfl[4];
            const uint32_t bBase = sb + bufOff + OFF_BH
                                 + (uint32_t)(wn * 16 * 80) + bLoff
                                 + (uint32_t)(ks * 32);
            ldsm4(bfh, bBase);
            ldsm4(bfl, bBase + (uint32_t)B_BYTES);
#pragma unroll
            for (int ni = 0; ni < 2; ni++) {
                const uint32_t* bhp = &bfh[ni * 2];
                const uint32_t* blp = &bfl[ni * 2];
                mma_bf16(c[ni], afh, bhp);
                mma_bf16(c[ni], afh, blp);
                mma_bf16(c[ni], afl, bhp);
            }
        }

        if (more) CP_WAIT0();
        __syncthreads();
    }

    const int r0 = m0 + wm * 16 + (lane >> 2);
    const int r1 = r0 + 8;
#pragma unroll
    for (int ni = 0; ni < 2; ni++) {
        const int gcol = n0 + wn * 16 + ni * 8 + (lane & 3) * 2;
        float v0 = c[ni][0], v1 = c[ni][1];
        float v2 = c[ni][2], v3 = c[ni][3];
        if (gcol < tanhN) {
            v0 = tanhf(v0); v1 = tanhf(v1);
            v2 = tanhf(v2); v3 = tanhf(v3);
        }
        if (gcol < maxcol) {
            if (Cm) {
                *(float2*)&Cm[(size_t)r0 * cstride + gcol] = make_float2(v0, v1);
                *(float2*)&Cm[(size_t)r1 * cstride + gcol] = make_float2(v2, v3);
            }
            if (oh) {
                uint32_t h0, l0, h1, l1;
                split2(v0, v1, h0, l0);
                split2(v2, v3, h1, l1);
                *(uint32_t*)&oh[(size_t)r0 * ostride + ocol + gcol] = h0;
                *(uint32_t*)&ol[(size_t)r0 * ostride + ocol + gcol] = l0;
                *(uint32_t*)&oh[(size_t)r1 * ostride + ocol + gcol] = h1;
                *(uint32_t*)&ol[(size_t)r1 * ostride + ocol + gcol] = l1;
            }
        }
    }
}

// mixin up-projection (standalone; needed before fused_mix)
__global__ void __launch_bounds__(256)
gemm_up_mix()
{
    extern __shared__ __align__(16) char sm[];
    up64_body(g_s.xmixh, g_s.xmixl, g_s.mw1Th, g_s.mw1Tl,
              blockIdx.x * 32, blockIdx.y * 64, 128, 128,
              g_s.mixin, 128, 0, 0, 0, 0, sm);
}

// batched post-mix up-projections: y 0-1 gate1, 2-3 lora_wa, 4 lora_k
__global__ void __launch_bounds__(256)
gemm_up_batch()
{
    extern __shared__ __align__(16) char sm[];
    const int y = blockIdx.y;
    const int m0 = blockIdx.x * 32;
    if (y < 2) {
        up64_body(g_s.xrgh, g_s.xrgl, g_s.gw1Th, g_s.gw1Tl,
                  m0, y * 64, 128, 128,
                  0, 0, g_s.g1h, g_s.g1l, 128, 0, sm);
    } else if (y < 4) {
        up64_body(g_s.xwah, g_s.xwal, g_s.waTh, g_s.waTl,
                  m0, (y - 2) * 64, 64, 128,
                  0, 0, g_s.loraAh, g_s.loraAl, 160, 0, sm);
    } else {
        up64_body(g_s.xkh, g_s.xkl, g_s.kTh, g_s.kTl,
                  m0, 0, 16, 32,
                  0, 0, g_s.loraAh, g_s.loraAl, 160, 128, sm);
    }
}

// ---------------------------------------------------------------------------
// conv4: 4 weight matrices fp32 -> bf16 hi/lo in one launch
// ---------------------------------------------------------------------------
__global__ void __launch_bounds__(256)
conv4(const float* __restrict__ w0, const float* __restrict__ w1,
      const float* __restrict__ w2, const float* __restrict__ w3)
{
    const int wq = blockIdx.x >> 10;
    const int i  = (blockIdx.x & 1023) * 256 + threadIdx.x;  // float4 idx
    const float* src; bf16 *dh, *dl;
    switch (wq) {
        case 0:  src = w0; dh = g_s.wrh; dl = g_s.wrl; break;
        case 1:  src = w1; dh = g_s.wkh; dl = g_s.wkl; break;
        case 2:  src = w2; dh = g_s.wvh; dl = g_s.wvl; break;
        default: src = w3; dh = g_s.woh; dl = g_s.wol; break;
    }
    uint2 hh, ll;
    split4(((const float4*)src)[i], hh, ll);
    ((uint2*)dh)[i] = hh;
    ((uint2*)dl)[i] = ll;
}

// ---------------------------------------------------------------------------
// transconv / packT / pack_bigB
// ---------------------------------------------------------------------------
__global__ void __launch_bounds__(256)
transconv_kernel(const float* __restrict__ src, bf16* __restrict__ dh,
                 bf16* __restrict__ dl)
{
    __shared__ float tile[32][33];
    int bx = blockIdx.x;
    int by = blockIdx.y;
    int tx = threadIdx.x & 31, ty = threadIdx.x >> 5;
#pragma unroll
    for (int i = 0; i < 4; i++)
        tile[ty + i * 8][tx] = src[(size_t)(by * 32 + ty + i * 8) * 1024 + bx * 32 + tx];
    __syncthreads();
#pragma unroll
    for (int i = 0; i < 4; i++) {
        float v = tile[tx][ty + i * 8];
        bf16 hv = __float2bfloat16_rn(v);
        bf16 lv = __float2bfloat16_rn(v - __bfloat162float(hv));
        size_t di = (size_t)(bx * 32 + ty + i * 8) * 128 + by * 32 + tx;
        dh[di] = hv; dl[di] = lv;
    }
}

__global__ void __launch_bounds__(256)
packT_w1(const float* __restrict__ src, bf16* __restrict__ dh,
         bf16* __restrict__ dl)
{
    int idx = blockIdx.x * 256 + threadIdx.x;
    int cth = idx >> 10, r = idx & 1023;
    float v = src[(size_t)r * 128 + cth];
    bf16 hv = __float2bfloat16_rn(v);
    bf16 lv = __float2bfloat16_rn(v - __bfloat162float(hv));
    dh[idx] = hv; dl[idx] = lv;
}
__global__ void __launch_bounds__(256)
packT_wa(const float* __restrict__ dw1, const float* __restrict__ aw1,
         const float* __restrict__ maw1)
{
    int idx = blockIdx.x * 256 + threadIdx.x;
    int cth = idx >> 10, r = idx & 1023;
    float v = 0.f;
    if (cth < 64)      v = dw1[r * 64 + cth];
    else if (cth < 80) v = aw1[r * 16 + (cth - 64)];
    else if (cth < 96) v = maw1[r * 16 + (cth - 80)];
    bf16 hv = __float2bfloat16_rn(v);
    bf16 lv = __float2bfloat16_rn(v - __bfloat162float(hv));
    g_s.waTh[idx] = hv; g_s.waTl[idx] = lv;
}
__global__ void __launch_bounds__(256)
packT_k(const float* __restrict__ kw1, const float* __restrict__ mkw1)
{
    int idx = blockIdx.x * 256 + threadIdx.x;   // 64*1024
    int cth = idx >> 10, r = idx & 1023;
    float v = 0.f;
    if (cth < 16)      v = kw1[r * 16 + cth];
    else if (cth < 32) v = mkw1[r * 16 + (cth - 16)];
    bf16 hv = __float2bfloat16_rn(v);
    bf16 lv = __float2bfloat16_rn(v - __bfloat162float(hv));
    g_s.kTh[idx] = hv; g_s.kTl[idx] = lv;
}

__global__ void __launch_bounds__(256)
pack_bigB(const float* __restrict__ dw2, const float* __restrict__ aw2,
          const float* __restrict__ maw2, const float* __restrict__ kw2,
          const float* __restrict__ mkw2)
{
    int idx = blockIdx.x * 256 + threadIdx.x;
    int n = idx / 160, kq = idx - (idx / 160) * 160;
    int blk = n >> 10, nloc = n & 1023;
    float v = 0.f;
    switch (blk) {
        case 0: if (kq < 64)               v = dw2 [(size_t)kq * 1024 + nloc]; break;
        case 1: if (kq >= 64 && kq < 80)   v = aw2 [(size_t)(kq - 64) * 1024 + nloc]; break;
        case 2: if (kq >= 80 && kq < 96)   v = maw2[(size_t)(kq - 80) * 1024 + nloc]; break;
        case 3: if (kq >= 128 && kq < 144) v = kw2 [(size_t)(kq - 128) * 1024 + nloc]; break;
        default:if (kq >= 144)             v = mkw2[(size_t)(kq - 144) * 1024 + nloc]; break;
    }
    bf16 hv = __float2bfloat16_rn(v);
    bf16 lv = __float2bfloat16_rn(v - __bfloat162float(hv));
    g_s.bigBh[idx] = hv; g_s.bigBl[idx] = lv;
}

// ---------------------------------------------------------------------------
// fused_mix
// ---------------------------------------------------------------------------
#define MIX_SMEM 131072

__global__ void __launch_bounds__(256)
fused_mix(const float* __restrict__ x, const float* __restrict__ w2,
          const float* __restrict__ m_rg, const float* __restrict__ m_wa,
          const float* __restrict__ m_k,  const float* __restrict__ m_v)
{
    extern __shared__ __align__(16) char smraw[];
    float* As = (float*)smraw;
    float* Bs = (float*)(smraw + 65536);

    const int tid = threadIdx.x;
    const int tx = tid & 15;
    const int ty = tid >> 4;
    const int n0 = blockIdx.x * 128;
    const int m0 = blockIdx.y * 128;

#pragma unroll
    for (int i = 0; i < 16; i++) {
        int u = tid + 256 * i;
        int rw = u >> 5, c4 = u & 31;
        float4 v = *(const float4*)&g_s.mixin[(size_t)(m0 + rw) * 128 + c4 * 4];
        As[(c4 * 4 + 0) * 128 + rw] = v.x;
        As[(c4 * 4 + 1) * 128 + rw] = v.y;
        As[(c4 * 4 + 2) * 128 + rw] = v.z;
        As[(c4 * 4 + 3) * 128 + rw] = v.w;
    }
#pragma unroll
    for (int i = 0; i < 16; i++) {
        int u = tid + 256 * i;
        int kr = u >> 5, n4 = u & 31;
        *(float4*)&Bs[kr * 128 + n4 * 4] =
            *(const float4*)&w2[(size_t)kr * 1024 + n0 + n4 * 4];
    }
    __syncthreads();

    for (int f = 0; f < 4; f++) {
        unsigned long long acc[8][4];
#pragma unroll
        for (int i = 0; i < 8; i++)
#pragma unroll
            for (int j = 0; j < 4; j++) acc[i][j] = 0ull;

#pragma unroll
        for (int kq2 = 0; kq2 < 32; kq2++) {
            const int kq = f * 32 + kq2;
            float4 a0 = *(const float4*)&As[kq * 128 + ty * 8];
            float4 a1 = *(const float4*)&As[kq * 128 + ty * 8 + 4];
            ulonglong2 bA = *(const ulonglong2*)&Bs[kq * 128 + tx * 8];
            ulonglong2 bB = *(const ulonglong2*)&Bs[kq * 128 + tx * 8 + 4];
#define RF(rI, aval) { unsigned long long dp = dup2(aval); \
            fma2(acc[rI][0], dp, bA.x); fma2(acc[rI][1], dp, bA.y); \
            fma2(acc[rI][2], dp, bB.x); fma2(acc[rI][3], dp, bB.y); }
            RF(0, a0.x) RF(1, a0.y) RF(2, a0.z) RF(3, a0.w)
            RF(4, a1.x) RF(5, a1.y) RF(6, a1.z) RF(7, a1.w)
#undef RF
        }

        bf16 *oh, *ol; const float* maa;
        switch (f) {
            case 0: oh = g_s.xrgh; ol = g_s.xrgl; maa = m_rg; break;
            case 1: oh = g_s.xwah; ol = g_s.xwal; maa = m_wa; break;
            case 2: oh = g_s.xkh;  ol = g_s.xkl;  maa = m_k;  break;
            default:oh = g_s.xvh;  ol = g_s.xvl;  maa = m_v;  break;
        }
        const int nc = n0 + tx * 8;
        float4 mv0 = *(const float4*)&maa[nc];
        float4 mv1 = *(const float4*)&maa[nc + 4];
#pragma unroll
        for (int rr = 0; rr < 8; rr++) {
            const int m = m0 + ty * 8 + rr;
            const size_t off = (size_t)m * 1024 + nc;
            float4 xv0 = *(const float4*)&x[off];
            float4 xv1 = *(const float4*)&x[off + 4];
            float4 dx0 = *(const float4*)&g_s.xx[off];
            float4 dx1 = *(const float4*)&g_s.xx[off + 4];
            float vals[8];
            { float2 p = unpack2(acc[rr][0]); vals[0] = p.x; vals[1] = p.y; }
            { float2 p = unpack2(acc[rr][1]); vals[2] = p.x; vals[3] = p.y; }
            { float2 p = unpack2(acc[rr][2]); vals[4] = p.x; vals[5] = p.y; }
            { float2 p = unpack2(acc[rr][3]); vals[6] = p.x; vals[7] = p.y; }
            float4 o0, o1;
            o0.x = xv0.x + dx0.x * (mv0.x + vals[0]);
            o0.y = xv0.y + dx0.y * (mv0.y + vals[1]);
            o0.z = xv0.z + dx0.z * (mv0.z + vals[2]);
            o0.w = xv0.w + dx0.w * (mv0.w + vals[3]);
            o1.x = xv1.x + dx1.x * (mv1.x + vals[4]);
            o1.y = xv1.y + dx1.y * (mv1.y + vals[5]);
            o1.z = xv1.z + dx1.z * (mv1.z + vals[6]);
            o1.w = xv1.w + dx1.w * (mv1.w + vals[7]);
            uint2 h0, l0, h1, l1;
            split4(o0, h0, l0);
            split4(o1, h1, l1);
            *(uint4*)&oh[off] = make_uint4(h0.x, h0.y, h1.x, h1.y);
            *(uint4*)&ol[off] = make_uint4(l0.x, l0.y, l1.x, l1.y);
        }
    }
}

// ---------------------------------------------------------------------------
// ew0
// ---------------------------------------------------------------------------
__global__ void __launch_bounds__(256)
ew0_kernel(const float* __restrict__ x, const float* __restrict__ maa_x)
{
    size_t i4  = (size_t)blockIdx.x * 256 + threadIdx.x;
    size_t idx = i4 * 4;
    int c    = (int)(idx & (CC - 1));
    int nrow = (int)(idx >> 10);
    float4 xv = *(const float4*)&x[idx];
    float4 xp = make_float4(0.f, 0.f, 0.f, 0.f);
    if (nrow & (TT - 1))
        xp = *(const float4*)&x[idx - CC];
    float4 mv = *(const float4*)&maa_x[c];
    float4 d, xm;
    d.x = xp.x - xv.x;  xm.x = xv.x + d.x * mv.x;
    d.y = xp.y - xv.y;  xm.y = xv.y + d.y * mv.y;
    d.z = xp.z - xv.z;  xm.z = xv.z + d.z * mv.z;
    d.w = xp.w - xv.w;  xm.w = xv.w + d.w * mv.w;
    *(float4*)&g_s.xx[idx] = d;
    uint2 h, l;
    split4(xm, h, l);
    *(uint2*)&g_s.xmixh[idx] = h;
    *(uint2*)&g_s.xmixl[idx] = l;
}

// ---------------------------------------------------------------------------
// combine
// ---------------------------------------------------------------------------
__global__ void __launch_bounds__(256)
combine_kernel()
{
    int n   = blockIdx.x;
    int tid = threadIdx.x;
    size_t off = (size_t)n * CC + tid * 4;

    float4 kkv = *(float4*)&g_s.kk[off];
    float ss = kkv.x*kkv.x + kkv.y*kkv.y + kkv.z*kkv.z + kkv.w*kkv.w;
#pragma unroll
    for (int o = 8; o; o >>= 1) ss += __shfl_xor_sync(0xffffffffu, ss, o, 16);
    float inv = 1.f / fmaxf(sqrtf(ss), 1e-12f);

    float4 kq = *(float4*)&g_s.k[off];
    float4 aq = *(float4*)&g_s.asig[off];
    float4 mq = *(float4*)&g_s.ma[off];
    float4 wq = *(float4*)&g_s.w[off];
    float4 mk = *(float4*)&g_s.mk2[off];
    float4 kfv, ddv, avv, bvv;
#define CMB(X) { float fac = mq.X + aq.X * (1.f - mq.X); \
    float ee = expf(fminf(wq.X * mk.X, 0.f)); \
    kfv.X = kq.X * fac * ee; \
    ddv.X = expf(wq.X); \
    float kn = kkv.X * inv; \
    avv.X = -kn; bvv.X = kn * aq.X; }
    CMB(x) CMB(y) CMB(z) CMB(w)
#undef CMB
    *(float4*)&g_s.kf[off] = kfv;
    *(float4*)&g_s.dd[off] = ddv;
    *(float4*)&g_s.av[off] = avv;
    *(float4*)&g_s.bv[off] = bvv;
}

// ---------------------------------------------------------------------------
// WKV-7 scan: cp.async 3-deep pipeline
// ---------------------------------------------------------------------------
__global__ void __launch_bounds__(256)
wkv_kernel()
{
    const int blk = blockIdx.x;
    const int b = blk >> 4;
    const int h = blk & 15;
    const int tid = threadIdx.x;
    const int i  = tid >> 2;
    const int jq = tid & 3;

    __shared__ __align__(16) float sb[4][6][64];
    const size_t rowbase = ((size_t)b * TT) * CC + h * NN;

    const float* gsrc = 0;
    uint32_t sdst[4];
    if (tid < 96) {
        int larr = tid >> 4, lq = tid & 15;
        const float* srcs[6] = { g_s.r, g_s.dd, g_s.kf, g_s.av, g_s.bv, g_s.v };
        gsrc = srcs[larr] + rowbase + lq * 4;
#pragma unroll
        for (int q = 0; q < 4; q++) sdst[q] = smem_u32(&sb[q][larr][lq * 4]);
    }

#pragma unroll
    for (int pre = 0; pre < 3; pre++) {
        if (tid < 96) cp_async16(sdst[pre], gsrc + (size_t)pre * CC);
        CP_COMMIT();
    }

    unsigned long long S2[8];
#pragma unroll
    for (int u = 0; u < 8; u++) S2[u] = 0ull;

    float* yout = g_s.y + rowbase + i;

    for (int t = 0; t < TT; t++) {
        CP_WAIT2();
        __syncthreads();
        const int p = t & 3;

        const ulonglong2* r2p = (const ulonglong2*)(sb[p][0] + jq * 16);
        const ulonglong2* d2p = (const ulonglong2*)(sb[p][1] + jq * 16);
        const ulonglong2* k2p = (const ulonglong2*)(sb[p][2] + jq * 16);
        const ulonglong2* a2p = (const ulonglong2*)(sb[p][3] + jq * 16);
        const ulonglong2* b2p = (const ulonglong2*)(sb[p][4] + jq * 16);
        const float vi = sb[p][5][i];

        ulonglong2 Rv[4], Dv[4], Kv[4], Av[4], Bv[4];
#pragma unroll
        for (int u = 0; u < 4; u++) {
            Rv[u] = r2p[u]; Dv[u] = d2p[u]; Kv[u] = k2p[u];
            Av[u] = a2p[u]; Bv[u] = b2p[u];
        }

        if (tid < 96 && t + 3 < TT)
            cp_async16(sdst[(t + 3) & 3], gsrc + (size_t)(t + 3) * CC);
        CP_COMMIT();

        unsigned long long sa0 = 0ull, sa1 = 0ull, pp0 = 0ull, pp1 = 0ull;
        unsigned long long br0 = 0ull, br1 = 0ull, kr0 = 0ull, kr1 = 0ull;
#pragma unroll
        for (int u = 0; u < 4; u++) {
            unsigned long long drx = mul2(Dv[u].x, Rv[u].x);
            unsigned long long dry = mul2(Dv[u].y, Rv[u].y);
            fma2(sa0, S2[2*u],   Av[u].x);
            fma2(sa1, S2[2*u+1], Av[u].y);
            fma2(pp0, S2[2*u],   drx);
            fma2(pp1, S2[2*u+1], dry);
            fma2(br0, Bv[u].x, Rv[u].x);
            fma2(br1, Bv[u].y, Rv[u].y);
            fma2(kr0, Kv[u].x, Rv[u].x);
            fma2(kr1, Kv[u].y, Rv[u].y);
        }
        float sa = hadd4(sa0, sa1);
        float pp = hadd4(pp0, pp1);
        float br = hadd4(br0, br1);
        float kr = hadd4(kr0, kr1);
        sa += __shfl_xor_sync(0xffffffffu, sa, 1, 4);
        pp += __shfl_xor_sync(0xffffffffu, pp, 1, 4);
        br += __shfl_xor_sync(0xffffffffu, br, 1, 4);
        kr += __shfl_xor_sync(0xffffffffu, kr, 1, 4);
        sa += __shfl_xor_sync(0xffffffffu, sa, 2, 4);
        pp += __shfl_xor_sync(0xffffffffu, pp, 2, 4);
        br += __shfl_xor_sync(0xffffffffu, br, 2, 4);
        kr += __shfl_xor_sync(0xffffffffu, kr, 2, 4);

        if (jq == 0) yout[(size_t)t * CC] = pp + sa * br + vi * kr;

        const unsigned long long sa2 = dup2(sa);
        const unsigned long long v2  = dup2(vi);
#pragma unroll
        for (int u = 0; u < 4; u++) {
            S2[2*u]   = fma2g(S2[2*u],   Dv[u].x,
                              fma2g(sa2, Bv[u].x, mul2(v2, Kv[u].x)));
            S2[2*u+1] = fma2g(S2[2*u+1], Dv[u].y,
                              fma2g(sa2, Bv[u].y, mul2(v2, Kv[u].y)));
        }
    }
}

// ---------------------------------------------------------------------------
// post: GroupNorm + bonus + gate -> z (bf16 hi/lo)
// ---------------------------------------------------------------------------
__global__ void __launch_bounds__(256)
post_kernel(const float* __restrict__ faaaa,
            const float* __restrict__ lnw, const float* __restrict__ lnb)
{
    int n   = blockIdx.x;
    int tid = threadIdx.x;
    int c   = tid * 4;
    size_t off = (size_t)n * CC + c;

    float4 yv = *(float4*)&g_s.y [off];
    float4 rv = *(float4*)&g_s.r [off];
    float4 kv = *(float4*)&g_s.kf[off];
    float4 vv = *(float4*)&g_s.v [off];
    float4 gv = *(float4*)&g_s.g [off];
    float4 fv = *(const float4*)&faaaa[c];

    float s  = yv.x + yv.y + yv.z + yv.w;
    float s2 = yv.x*yv.x + yv.y*yv.y + yv.z*yv.z + yv.w*yv.w;
    float dk = rv.x*kv.x*fv.x + rv.y*kv.y*fv.y + rv.z*kv.z*fv.z + rv.w*kv.w*fv.w;
#pragma unroll
    for (int o = 8; o; o >>= 1) {
        s  += __shfl_xor_sync(0xffffffffu, s,  o, 16);
        s2 += __shfl_xor_sync(0xffffffffu, s2, o, 16);
        dk += __shfl_xor_sync(0xffffffffu, dk, o, 16);
    }
    float mean = s  * (1.f / 64.f);
    float var  = s2 * (1.f / 64.f) - mean * mean;
    float rs   = rsqrtf(var + 64e-5f);

    float4 lw = *(const float4*)&lnw[c];
    float4 lb = *(const float4*)&lnb[c];
    float4 z;
    z.x = (((yv.x - mean) * rs) * lw.x + lb.x + dk * vv.x) * gv.x;
    z.y = (((yv.y - mean) * rs) * lw.y + lb.y + dk * vv.y) * gv.y;
    z.z = (((yv.z - mean) * rs) * lw.z + lb.z + dk * vv.z) * gv.z;
    z.w = (((yv.w - mean) * rs) * lw.w + lb.w + dk * vv.w) * gv.w;
    uint2 h, l;
    split4(z, h, l);
    *(uint2*)&g_s.zh[off] = h;
    *(uint2*)&g_s.zl[off] = l;
}

// ---------------------------------------------------------------------------
// Host orchestration
// ---------------------------------------------------------------------------
static void gmma(const bf16* Ah, const bf16* Al, const bf16* Bh,
                 const bf16* Bl, float* Cp, int K)
{
    dim3 grid(8, MM / 128);
    gemm_mma2<<<grid, 256, MMA_SMEM>>>(Ah, Al, Bh, Bl, Cp, K);
}

extern "C" void kernel_launch(void* const* d_in, const int* in_sizes, int n_in,
                              void* d_out, int out_size)
{
    const float* x       = (const float*)d_in[0];
    const float* maa_x   = (const float*)d_in[1];
    const float* maa_rg  = (const float*)d_in[2];
    const float* maa_wa  = (const float*)d_in[3];
    const float* maa_k   = (const float*)d_in[4];
    const float* maa_v   = (const float*)d_in[5];
    const float* maa_w1  = (const float*)d_in[6];
    const float* maa_w2  = (const float*)d_in[7];
    const float* tdecay  = (const float*)d_in[8];
    const float* dw1     = (const float*)d_in[9];
    const float* dw2     = (const float*)d_in[10];
    const float* faaaa   = (const float*)d_in[11];
    const float* taaaaa  = (const float*)d_in[12];
    const float* aw1     = (const float*)d_in[13];
    const float* aw2     = (const float*)d_in[14];
    const float* kw1     = (const float*)d_in[15];
    const float* kw2     = (const float*)d_in[16];
    const float* gw1     = (const float*)d_in[17];
    const float* gw2     = (const float*)d_in[18];
    const float* maw1    = (const float*)d_in[19];
    const float* maw2    = (const float*)d_in[20];
    const float* tmisca  = (const float*)d_in[21];
    const float* mkw1    = (const float*)d_in[22];
    const float* mkw2    = (const float*)d_in[23];
    const float* tmisck  = (const float*)d_in[24];
    const float* wr      = (const float*)d_in[25];
    const float* wk      = (const float*)d_in[26];
    const float* wv      = (const float*)d_in[27];
    const float* wo      = (const float*)d_in[28];
    const float* lnw     = (const float*)d_in[29];
    const float* lnb     = (const float*)d_in[30];
    float* out = (float*)d_out;
    (void)in_sizes; (void)n_in; (void)out_size;

    Scratch* S = nullptr;
    cudaGetSymbolAddress((void**)&S, g_s);
    cudaFuncSetAttribute(gemm_mma2, cudaFuncAttributeMaxDynamicSharedMemorySize,
                         MMA_SMEM);
    cudaFuncSetAttribute(gemm_down, cudaFuncAttributeMaxDynamicSharedMemorySize,
                         MMA_SMEM);
    cudaFuncSetAttribute(fused_mix, cudaFuncAttributeMaxDynamicSharedMemorySize,
                         MIX_SMEM);
    cudaFuncSetAttribute(gemm_up_mix,
                         cudaFuncAttributeMaxDynamicSharedMemorySize, UP64_SMEM);
    cudaFuncSetAttribute(gemm_up_batch,
                         cudaFuncAttributeMaxDynamicSharedMemorySize, UP64_SMEM);

    // 0-3: arranged so ncu's capture slot (4th launch) hits fused_mix
    ew0_kernel<<<(MM * CC / 4) / 256, 256>>>(x, maa_x);                  // 0
    packT_w1<<<512, 256>>>(maa_w1, S->mw1Th, S->mw1Tl);                  // 1
    gemm_up_mix<<<dim3(128, 2), 256, UP64_SMEM>>>();                     // 2
    fused_mix<<<dim3(8, 32), 256, MIX_SMEM>>>(x, maa_w2,                 // 3
        maa_rg, maa_wa, maa_k, maa_v);

    // weight conversions / packs
    conv4<<<4096, 256>>>(wr, wk, wv, wo);
    packT_w1<<<512, 256>>>(gw1, S->gw1Th, S->gw1Tl);
    packT_wa<<<512, 256>>>(dw1, aw1, maw1);
    packT_k<<<256, 256>>>(kw1, mkw1);
    transconv_kernel<<<dim3(32, 4), 256>>>(gw2, S->gw2Th, S->gw2Tl);
    pack_bigB<<<(5120 * 160) / 256, 256>>>(dw2, aw2, maw2, kw2, mkw2);

    // big projections
    gmma(S->xrgh, S->xrgl, S->wrh, S->wrl, S->r, 1024);
    gmma(S->xkh,  S->xkl,  S->wkh, S->wkl, S->k, 1024);
    gmma(S->xvh,  S->xvl,  S->wvh, S->wvl, S->v, 1024);

    // batched up-projections (gate1 + lora_wa + lora_k)
    gemm_up_batch<<<dim3(128, 5), 256, UP64_SMEM>>>();

    // gate down-projection
    gmma(S->g1h, S->g1l, S->gw2Th, S->gw2Tl, S->g, 128);

    // fused block-diagonal LoRA down-projection
    gemm_down<<<dim3(40, 32), 256, MMA_SMEM>>>(tdecay, taaaaa, tmisca, tmisck);

    // combine + scan + post + output
    combine_kernel<<<MM, 256>>>();
    wkv_kernel<<<BB * HH, 256>>>();
    post_kernel<<<MM, 256>>>(faaaa, lnw, lnb);
    gmma(S->zh, S->zl, S->woh, S->wol, out, 1024);
}

// round 13
// speedup vs baseline: 2.4308x; 1.0017x over previous
#include <cuda_runtime.h>
#include <cuda_bf16.h>
#include <math.h>
#include <stdint.h>
#include <string.h>

#define BB 4
#define TT 1024
#define CC 1024
#define HH 16
#define NN 64
#define MM (BB*TT)   // 4096 rows

typedef __nv_bfloat16 bf16;

// ---------------------------------------------------------------------------
// Scratch (static device memory)
// ---------------------------------------------------------------------------
struct Scratch {
    float xx   [MM*CC];
    float r    [MM*CC];
    float k    [MM*CC];
    float v    [MM*CC];
    float g    [MM*CC];
    float w    [MM*CC];
    float kk   [MM*CC];
    float asig [MM*CC];
    float ma   [MM*CC];
    float mk2  [MM*CC];
    float kf   [MM*CC];
    float dd   [MM*CC];
    float av   [MM*CC];
    float bv   [MM*CC];
    float y    [MM*CC];
    // bf16 hi/lo activations
    bf16 xmixh[MM*CC], xmixl[MM*CC];
    bf16 mixinh[MM*128], mixinl[MM*128];
    bf16 xrgh[MM*CC], xrgl[MM*CC];
    bf16 xwah[MM*CC], xwal[MM*CC];
    bf16 xkh [MM*CC], xkl [MM*CC];
    bf16 xvh [MM*CC], xvl [MM*CC];
    bf16 zh  [MM*CC], zl  [MM*CC];
    bf16 g1h [MM*128], g1l [MM*128];
    bf16 loraAh[MM*160], loraAl[MM*160];
    // bf16 hi/lo weights
    bf16 wrh[CC*CC], wrl[CC*CC];
    bf16 wkh[CC*CC], wkl[CC*CC];
    bf16 wvh[CC*CC], wvl[CC*CC];
    bf16 woh[CC*CC], wol[CC*CC];
    bf16 gw2Th[CC*128], gw2Tl[CC*128];
    bf16 mw1Th[128*1024], mw1Tl[128*1024];
    bf16 w2Th[4096*32],  w2Tl[4096*32];
    bf16 gw1Th[128*1024], gw1Tl[128*1024];
    bf16 waTh [128*1024], waTl [128*1024];
    bf16 kTh  [64*1024],  kTl  [64*1024];
    bf16 bigBh[5120*160], bigBl[5120*160];
};
__device__ Scratch g_s;

// ---------------------------------------------------------------------------
// Packed f32x2 helpers
// ---------------------------------------------------------------------------
__device__ __forceinline__ unsigned long long dup2(float x) {
    unsigned long long r;
    asm("mov.b64 %0, {%1, %1};" : "=l"(r) : "f"(x));
    return r;
}
__device__ __forceinline__ void fma2(unsigned long long& acc,
                                     unsigned long long a,
                                     unsigned long long b) {
    asm("fma.rn.f32x2 %0, %1, %2, %0;" : "+l"(acc) : "l"(a), "l"(b));
}
__device__ __forceinline__ unsigned long long fma2g(unsigned long long a,
                                                    unsigned long long b,
                                                    unsigned long long c) {
    unsigned long long d;
    asm("fma.rn.f32x2 %0, %1, %2, %3;" : "=l"(d) : "l"(a), "l"(b), "l"(c));
    return d;
}
__device__ __forceinline__ unsigned long long mul2(unsigned long long a,
                                                   unsigned long long b) {
    unsigned long long d;
    asm("mul.rn.f32x2 %0, %1, %2;" : "=l"(d) : "l"(a), "l"(b));
    return d;
}
__device__ __forceinline__ float2 unpack2(unsigned long long v) {
    float2 f;
    asm("mov.b64 {%0, %1}, %2;" : "=f"(f.x), "=f"(f.y) : "l"(v));
    return f;
}
__device__ __forceinline__ float hadd4(unsigned long long a,
                                       unsigned long long b) {
    float2 f = unpack2(a), g = unpack2(b);
    return (f.x + f.y) + (g.x + g.y);
}
__device__ __forceinline__ uint32_t smem_u32(const void* p) {
    uint32_t a;
    asm("{ .reg .u64 t; cvta.to.shared.u64 t, %1; cvt.u32.u64 %0, t; }"
        : "=r"(a) : "l"(p));
    return a;
}

// cp.async helpers
__device__ __forceinline__ void cp_async16(uint32_t saddr, const void* gptr) {
    asm volatile("cp.async.cg.shared.global [%0], [%1], 16;"
        :: "r"(saddr), "l"(gptr) : "memory");
}
#define CP_COMMIT() asm volatile("cp.async.commit_group;" ::: "memory")
#define CP_WAIT0()  asm volatile("cp.async.wait_group 0;" ::: "memory")
#define CP_WAIT2()  asm volatile("cp.async.wait_group 2;" ::: "memory")

// hi/lo splits
__device__ __forceinline__ void split4(float4 f, uint2& h, uint2& l) {
    __nv_bfloat162 h01 = __floats2bfloat162_rn(f.x, f.y);
    __nv_bfloat162 h23 = __floats2bfloat162_rn(f.z, f.w);
    float lx = f.x - __bfloat162float(h01.x);
    float ly = f.y - __bfloat162float(h01.y);
    float lz = f.z - __bfloat162float(h23.x);
    float lw = f.w - __bfloat162float(h23.y);
    __nv_bfloat162 l01 = __floats2bfloat162_rn(lx, ly);
    __nv_bfloat162 l23 = __floats2bfloat162_rn(lz, lw);
    memcpy(&h.x, &h01, 4); memcpy(&h.y, &h23, 4);
    memcpy(&l.x, &l01, 4); memcpy(&l.y, &l23, 4);
}
__device__ __forceinline__ void split2(float a, float b,
                                       uint32_t& h, uint32_t& l) {
    __nv_bfloat162 hh = __floats2bfloat162_rn(a, b);
    float la = a - __bfloat162float(hh.x);
    float lb = b - __bfloat162float(hh.y);
    __nv_bfloat162 ll = __floats2bfloat162_rn(la, lb);
    memcpy(&h, &hh, 4); memcpy(&l, &ll, 4);
}
__device__ __forceinline__ void splitf(float v, bf16& h, bf16& l) {
    h = __float2bfloat16_rn(v);
    l = __float2bfloat16_rn(v - __bfloat162float(h));
}

// ---------------------------------------------------------------------------
// mma.sync / ldmatrix helpers
// ---------------------------------------------------------------------------
__device__ __forceinline__ void ldsm4(uint32_t* r, uint32_t addr) {
    asm volatile("ldmatrix.sync.aligned.m8n8.x4.shared.b16 {%0,%1,%2,%3}, [%4];"
        : "=r"(r[0]), "=r"(r[1]), "=r"(r[2]), "=r"(r[3]) : "r"(addr));
}
__device__ __forceinline__ void mma_bf16(float* c, const uint32_t* a,
                                         const uint32_t* b) {
    asm volatile("mma.sync.aligned.m16n8k16.row.col.f32.bf16.bf16.f32 "
        "{%0,%1,%2,%3}, {%4,%5,%6,%7}, {%8,%9}, {%0,%1,%2,%3};"
        : "+f"(c[0]), "+f"(c[1]), "+f"(c[2]), "+f"(c[3])
        : "r"(a[0]), "r"(a[1]), "r"(a[2]), "r"(a[3]), "r"(b[0]), "r"(b[1]));
}

// ---------------------------------------------------------------------------
// gemm_mma2: C[M,1024] = (Ah+Al)[M,K] @ (Bh+Bl)[1024,K]^T, fp32 accum.
// ---------------------------------------------------------------------------
#define MMA_SMEM 81920

__global__ void __launch_bounds__(256, 2)
gemm_mma2(const bf16* __restrict__ Ah, const bf16* __restrict__ Al,
          const bf16* __restrict__ Bh, const bf16* __restrict__ Bl,
          float* __restrict__ Cm, int K)
{
    extern __shared__ __align__(16) char sm[];
    const uint32_t sb = smem_u32(sm);

    const int tid  = threadIdx.x;
    const int lane = tid & 31;
    const int wid  = tid >> 5;
    const int wm   = wid & 1;
    const int wn   = wid >> 1;
    const int n0 = blockIdx.x * 128;
    const int m0 = blockIdx.y * 128;

    const int row = tid >> 1, half = tid & 1;
    const bf16* pAh = Ah + (size_t)(m0 + row) * K + half * 16;
    const bf16* pAl = Al + (size_t)(m0 + row) * K + half * 16;
    const bf16* pBh = Bh + (size_t)(n0 + row) * K + half * 16;
    const bf16* pBl = Bl + (size_t)(n0 + row) * K + half * 16;
    const uint32_t st = (uint32_t)(row * 80 + half * 32);

    const uint32_t aLoff = (uint32_t)((lane & 15) * 80 + (lane >> 4) * 16);
    const uint32_t bLoff = (uint32_t)(((lane & 7) + ((lane >> 4) & 1) * 8) * 80
                                      + ((lane >> 3) & 1) * 16);

    float c[4][4][4];
#pragma unroll
    for (int i = 0; i < 4; i++)
#pragma unroll
        for (int j = 0; j < 4; j++)
#pragma unroll
            for (int q = 0; q < 4; q++) c[i][j][q] = 0.f;

    const int chunks = K >> 5;

    {
        uint32_t d = sb + st;
        cp_async16(d,             pAh); cp_async16(d + 16,         pAh + 8);
        cp_async16(d + 10240,     pAl); cp_async16(d + 10240 + 16, pAl + 8);
        cp_async16(d + 20480,     pBh); cp_async16(d + 20480 + 16, pBh + 8);
        cp_async16(d + 30720,     pBl); cp_async16(d + 30720 + 16, pBl + 8);
        CP_COMMIT();
        CP_WAIT0();
    }
    __syncthreads();

    for (int cidx = 0; cidx < chunks; cidx++) {
        const uint32_t bufOff = (uint32_t)((cidx & 1) * 40960);
        const bool more = (cidx + 1 < chunks);

        if (more) {
            const int ko = (cidx + 1) * 32;
            uint32_t d = sb + (uint32_t)(((cidx + 1) & 1) * 40960) + st;
            cp_async16(d,             pAh + ko); cp_async16(d + 16,         pAh + ko + 8);
            cp_async16(d + 10240,     pAl + ko); cp_async16(d + 10240 + 16, pAl + ko + 8);
            cp_async16(d + 20480,     pBh + ko); cp_async16(d + 20480 + 16, pBh + ko + 8);
            cp_async16(d + 30720,     pBl + ko); cp_async16(d + 30720 + 16, pBl + ko + 8);
            CP_COMMIT();
        }

        const uint32_t aBase = sb + bufOff + (uint32_t)(wm * 64 * 80) + aLoff;
        const uint32_t bBase = sb + bufOff + 20480u + (uint32_t)(wn * 32 * 80) + bLoff;
#pragma unroll
        for (int ks = 0; ks < 2; ks++) {
            uint32_t afh[4][4], afl[4][4];
#pragma unroll
            for (int mi = 0; mi < 4; mi++) {
                ldsm4(afh[mi], aBase + 0u     + (uint32_t)(mi * 1280 + ks * 32));
                ldsm4(afl[mi], aBase + 10240u + (uint32_t)(mi * 1280 + ks * 32));
            }
            uint32_t bfh[2][4], bfl[2][4];
#pragma unroll
            for (int np = 0; np < 2; np++) {
                ldsm4(bfh[np], bBase + 0u     + (uint32_t)(np * 1280 + ks * 32));
                ldsm4(bfl[np], bBase + 10240u + (uint32_t)(np * 1280 + ks * 32));
            }
#pragma unroll
            for (int mi = 0; mi < 4; mi++) {
#pragma unroll
                for (int ni = 0; ni < 4; ni++) {
                    const uint32_t* bh = &bfh[ni >> 1][(ni & 1) * 2];
                    const uint32_t* bl = &bfl[ni >> 1][(ni & 1) * 2];
                    mma_bf16(c[mi][ni], afh[mi], bh);
                    mma_bf16(c[mi][ni], afh[mi], bl);
                    mma_bf16(c[mi][ni], afl[mi], bh);
                }
            }
        }

        if (more) CP_WAIT0();
        __syncthreads();
    }

    const int erow = m0 + wm * 64 + (lane >> 2);
    const int ecol = n0 + wn * 32 + (lane & 3) * 2;
#pragma unroll
    for (int mi = 0; mi < 4; mi++) {
#pragma unroll
        for (int ni = 0; ni < 4; ni++) {
            size_t base0 = (size_t)(erow + mi * 16)     * 1024 + ecol + ni * 8;
            size_t base1 = (size_t)(erow + mi * 16 + 8) * 1024 + ecol + ni * 8;
            *(float2*)&Cm[base0] = make_float2(c[mi][ni][0], c[mi][ni][1]);
            *(float2*)&Cm[base1] = make_float2(c[mi][ni][2], c[mi][ni][3]);
        }
    }
}

// ---------------------------------------------------------------------------
// gemm_mix_mma: batched token-mix GEMM + epilogue, HMMA.
// For f = n0>>10:  out_f[m, col] = x + xx*(maa_f[col] + mixin_f @ W2_f)
// A = mixin bf16 hi/lo [4096 x 128] (cols f*32..f*32+32), B = w2T [4096 x 32].
// K = 32 (one chunk). Writes bf16 hi/lo to xrg/xwa/xk/xv.
// ---------------------------------------------------------------------------
#define MIXMMA_SMEM 40960

__global__ void __launch_bounds__(256, 2)
gemm_mix_mma(const float* __restrict__ x,
             const float* __restrict__ m_rg, const float* __restrict__ m_wa,
             const float* __restrict__ m_k,  const float* __restrict__ m_v)
{
    extern __shared__ __align__(16) char sm[];
    const uint32_t sb = smem_u32(sm);

    const int tid  = threadIdx.x;
    const int lane = tid & 31;
    const int wid  = tid >> 5;
    const int wm   = wid & 1;
    const int wn   = wid >> 1;
    const int n0 = blockIdx.x * 128;
    const int m0 = blockIdx.y * 128;
    const int f  = n0 >> 10;
    const int col0 = n0 & 1023;

    const int row = tid >> 1, half = tid & 1;
    {
        const bf16* pAh = g_s.mixinh + (size_t)(m0 + row) * 128 + f * 32 + half * 16;
        const bf16* pAl = g_s.mixinl + (size_t)(m0 + row) * 128 + f * 32 + half * 16;
        const bf16* pBh = g_s.w2Th + (size_t)(n0 + row) * 32 + half * 16;
        const bf16* pBl = g_s.w2Tl + (size_t)(n0 + row) * 32 + half * 16;
        const uint32_t d = sb + (uint32_t)(row * 80 + half * 32);
        cp_async16(d,             pAh); cp_async16(d + 16,         pAh + 8);
        cp_async16(d + 10240,     pAl); cp_async16(d + 10240 + 16, pAl + 8);
        cp_async16(d + 20480,     pBh); cp_async16(d + 20480 + 16, pBh + 8);
        cp_async16(d + 30720,     pBl); cp_async16(d + 30720 + 16, pBl + 8);
        CP_COMMIT();
        CP_WAIT0();
    }
    __syncthreads();

    const uint32_t aLoff = (uint32_t)((lane & 15) * 80 + (lane >> 4) * 16);
    const uint32_t bLoff = (uint32_t)(((lane & 7) + ((lane >> 4) & 1) * 8) * 80
                                      + ((lane >> 3) & 1) * 16);

    float c[4][4][4];
#pragma unroll
    for (int i = 0; i < 4; i++)
#pragma unroll
        for (int j = 0; j < 4; j++)
#pragma unroll
            for (int q = 0; q < 4; q++) c[i][j][q] = 0.f;

    const uint32_t aBase = sb + (uint32_t)(wm * 64 * 80) + aLoff;
    const uint32_t bBase = sb + 20480u + (uint32_t)(wn * 32 * 80) + bLoff;
#pragma unroll
    for (int ks = 0; ks < 2; ks++) {
        uint32_t afh[4][4], afl[4][4];
#pragma unroll
        for (int mi = 0; mi < 4; mi++) {
            ldsm4(afh[mi], aBase + 0u     + (uint32_t)(mi * 1280 + ks * 32));
            ldsm4(afl[mi], aBase + 10240u + (uint32_t)(mi * 1280 + ks * 32));
        }
        uint32_t bfh[2][4], bfl[2][4];
#pragma unroll
        for (int np = 0; np < 2; np++) {
            ldsm4(bfh[np], bBase + 0u     + (uint32_t)(np * 1280 + ks * 32));
            ldsm4(bfl[np], bBase + 10240u + (uint32_t)(np * 1280 + ks * 32));
        }
#pragma unroll
        for (int mi = 0; mi < 4; mi++) {
#pragma unroll
            for (int ni = 0; ni < 4; ni++) {
                const uint32_t* bh = &bfh[ni >> 1][(ni & 1) * 2];
                const uint32_t* bl = &bfl[ni >> 1][(ni & 1) * 2];
                mma_bf16(c[mi][ni], afh[mi], bh);
                mma_bf16(c[mi][ni], afh[mi], bl);
                mma_bf16(c[mi][ni], afl[mi], bh);
            }
        }
    }

    // epilogue
    const float* maa;
    bf16 *oh, *ol;
    switch (f) {
        case 0:  maa = m_rg; oh = g_s.xrgh; ol = g_s.xrgl; break;
        case 1:  maa = m_wa; oh = g_s.xwah; ol = g_s.xwal; break;
        case 2:  maa = m_k;  oh = g_s.xkh;  ol = g_s.xkl;  break;
        default: maa = m_v;  oh = g_s.xvh;  ol = g_s.xvl;  break;
    }
    const int erow = m0 + wm * 64 + (lane >> 2);
    const int ecol = col0 + wn * 32 + (lane & 3) * 2;
#pragma unroll
    for (int mi = 0; mi < 4; mi++) {
#pragma unroll
        for (int ni = 0; ni < 4; ni++) {
            const int col = ecol + ni * 8;
            const int r0 = erow + mi * 16, r1 = r0 + 8;
            const size_t off0 = (size_t)r0 * 1024 + col;
            const size_t off1 = (size_t)r1 * 1024 + col;
            float2 mv  = *(const float2*)&maa[col];
            float2 x0  = *(const float2*)&x[off0];
            float2 x1  = *(const float2*)&x[off1];
            float2 dx0 = *(const float2*)&g_s.xx[off0];
            float2 dx1 = *(const float2*)&g_s.xx[off1];
            float v0 = x0.x + dx0.x * (mv.x + c[mi][ni][0]);
            float v1 = x0.y + dx0.y * (mv.y + c[mi][ni][1]);
            float v2 = x1.x + dx1.x * (mv.x + c[mi][ni][2]);
            float v3 = x1.y + dx1.y * (mv.y + c[mi][ni][3]);
            uint32_t h0, l0, h1, l1;
            split2(v0, v1, h0, l0);
            split2(v2, v3, h1, l1);
            *(uint32_t*)&oh[off0] = h0;
            *(uint32_t*)&ol[off0] = l0;
            *(uint32_t*)&oh[off1] = h1;
            *(uint32_t*)&ol[off1] = l1;
        }
    }
}

// ---------------------------------------------------------------------------
// gemm_down: fused LoRA down-projections (block-diagonal).
// ---------------------------------------------------------------------------
__global__ void __launch_bounds__(256, 2)
gemm_down(const float* __restrict__ tdecay, const float* __restrict__ taaaaa,
          const float* __restrict__ tmisca, const float* __restrict__ tmisck)
{
    extern __shared__ __align__(16) char sm[];
    const uint32_t sb = smem_u32(sm);

    const int tid  = threadIdx.x;
    const int lane = tid & 31;
    const int wid  = tid >> 5;
    const int wm   = wid & 1;
    const int wn   = wid >> 1;
    const int n0 = blockIdx.x * 128;
    const int m0 = blockIdx.y * 128;

    const int row = tid >> 1, half = tid & 1;
    const bf16* pAh = g_s.loraAh + (size_t)(m0 + row) * 160 + half * 16;
    const bf16* pAl = g_s.loraAl + (size_t)(m0 + row) * 160 + half * 16;
    const bf16* pBh = g_s.bigBh  + (size_t)(n0 + row) * 160 + half * 16;
    const bf16* pBl = g_s.bigBl  + (size_t)(n0 + row) * 160 + half * 16;
    const uint32_t st = (uint32_t)(row * 80 + half * 32);

    const uint32_t aLoff = (uint32_t)((lane & 15) * 80 + (lane >> 4) * 16);
    const uint32_t bLoff = (uint32_t)(((lane & 7) + ((lane >> 4) & 1) * 8) * 80
                                      + ((lane >> 3) & 1) * 16);

    float c[4][4][4];
#pragma unroll
    for (int i = 0; i < 4; i++)
#pragma unroll
        for (int j = 0; j < 4; j++)
#pragma unroll
            for (int q = 0; q < 4; q++) c[i][j][q] = 0.f;

    {
        uint32_t d = sb + st;
        cp_async16(d,             pAh); cp_async16(d + 16,         pAh + 8);
        cp_async16(d + 10240,     pAl); cp_async16(d + 10240 + 16, pAl + 8);
        cp_async16(d + 20480,     pBh); cp_async16(d + 20480 + 16, pBh + 8);
        cp_async16(d + 30720,     pBl); cp_async16(d + 30720 + 16, pBl + 8);
        CP_COMMIT();
        CP_WAIT0();
    }
    __syncthreads();

    for (int cidx = 0; cidx < 5; cidx++) {
        const uint32_t bufOff = (uint32_t)((cidx & 1) * 40960);
        const bool more = (cidx + 1 < 5);

        if (more) {
            const int ko = (cidx + 1) * 32;
            uint32_t d = sb + (uint32_t)(((cidx + 1) & 1) * 40960) + st;
            cp_async16(d,             pAh + ko); cp_async16(d + 16,         pAh + ko + 8);
            cp_async16(d + 10240,     pAl + ko); cp_async16(d + 10240 + 16, pAl + ko + 8);
            cp_async16(d + 20480,     pBh + ko); cp_async16(d + 20480 + 16, pBh + ko + 8);
            cp_async16(d + 30720,     pBl + ko); cp_async16(d + 30720 + 16, pBl + ko + 8);
            CP_COMMIT();
        }

        const uint32_t aBase = sb + bufOff + (uint32_t)(wm * 64 * 80) + aLoff;
        const uint32_t bBase = sb + bufOff + 20480u + (uint32_t)(wn * 32 * 80) + bLoff;
#pragma unroll
        for (int ks = 0; ks < 2; ks++) {
            uint32_t afh[4][4], afl[4][4];
#pragma unroll
            for (int mi = 0; mi < 4; mi++) {
                ldsm4(afh[mi], aBase + 0u     + (uint32_t)(mi * 1280 + ks * 32));
                ldsm4(afl[mi], aBase + 10240u + (uint32_t)(mi * 1280 + ks * 32));
            }
            uint32_t bfh[2][4], bfl[2][4];
#pragma unroll
            for (int np = 0; np < 2; np++) {
                ldsm4(bfh[np], bBase + 0u     + (uint32_t)(np * 1280 + ks * 32));
                ldsm4(bfl[np], bBase + 10240u + (uint32_t)(np * 1280 + ks * 32));
            }
#pragma unroll
            for (int mi = 0; mi < 4; mi++) {
#pragma unroll
                for (int ni = 0; ni < 4; ni++) {
                    const uint32_t* bh = &bfh[ni >> 1][(ni & 1) * 2];
                    const uint32_t* bl = &bfl[ni >> 1][(ni & 1) * 2];
                    mma_bf16(c[mi][ni], afh[mi], bh);
                    mma_bf16(c[mi][ni], afh[mi], bl);
                    mma_bf16(c[mi][ni], afl[mi], bh);
                }
            }
        }

        if (more) CP_WAIT0();
        __syncthreads();
    }

    const int blk = n0 >> 10;
    float* outp; const float* ev; int mode;
    switch (blk) {
        case 0:  outp = g_s.w;    ev = tdecay; mode = 4; break;
        case 1:  outp = g_s.asig; ev = taaaaa; mode = 3; break;
        case 2:  outp = g_s.ma;   ev = tmisca; mode = 3; break;
        case 3:  outp = g_s.kk;   ev = 0;      mode = 5; break;
        default: outp = g_s.mk2;  ev = tmisck; mode = 3; break;
    }
    const int erow = m0 + wm * 64 + (lane >> 2);
    const int ecol = (n0 & 1023) + wn * 32 + (lane & 3) * 2;
#pragma unroll
    for (int mi = 0; mi < 4; mi++) {
#pragma unroll
        for (int ni = 0; ni < 4; ni++) {
            const int col = ecol + ni * 8;
            const int r0 = erow + mi * 16, r1 = r0 + 8;
            float v0 = c[mi][ni][0], v1 = c[mi][ni][1];
            float v2 = c[mi][ni][2], v3 = c[mi][ni][3];
            if (mode == 4) {
                float e0 = ev[col], e1 = ev[col + 1];
                v0 = -log1pf(expf(-(e0 + v0))) - 0.5f;
                v1 = -log1pf(expf(-(e1 + v1))) - 0.5f;
                v2 = -log1pf(expf(-(e0 + v2))) - 0.5f;
                v3 = -log1pf(expf(-(e1 + v3))) - 0.5f;
            } else if (mode == 3) {
                float e0 = ev[col], e1 = ev[col + 1];
                v0 = 1.f / (1.f + expf(-(e0 + v0)));
                v1 = 1.f / (1.f + expf(-(e1 + v1)));
                v2 = 1.f / (1.f + expf(-(e0 + v2)));
                v3 = 1.f / (1.f + expf(-(e1 + v3)));
            } else {
                float2 k0 = *(const float2*)&g_s.k[(size_t)r0 * 1024 + col];
                float2 k1 = *(const float2*)&g_s.k[(size_t)r1 * 1024 + col];
                v0 += k0.x; v1 += k0.y; v2 += k1.x; v3 += k1.y;
            }
            *(float2*)&outp[(size_t)r0 * 1024 + col] = make_float2(v0, v1);
            *(float2*)&outp[(size_t)r1 * 1024 + col] = make_float2(v2, v3);
        }
    }
}

// ---------------------------------------------------------------------------
// up-projection core (CTA 32x64, cp.async dbl-buffered, chunk 32)
// ---------------------------------------------------------------------------
#define UP64_SMEM 30720

__device__ __forceinline__ void up64_body(
    const bf16* __restrict__ Ah, const bf16* __restrict__ Al,
    const bf16* __restrict__ Bh, const bf16* __restrict__ Bl,
    int m0, int n0, int tanhN, int maxcol,
    float* __restrict__ Cm, int cstride,
    bf16* __restrict__ oh, bf16* __restrict__ ol, int ostride, int ocol,
    char* sm)
{
    constexpr int B_BYTES = 64 * 80;          // 5120
    constexpr int OFF_AL = 2560;
    constexpr int OFF_BH = 5120;
    constexpr int BUF = 5120 + 2 * B_BYTES;   // 15360

    const uint32_t sb = smem_u32(sm);
    const int tid  = threadIdx.x;
    const int lane = tid & 31;
    const int wid  = tid >> 5;
    const int wm   = wid & 1;
    const int wn   = wid >> 1;

    const int arow = (tid & 127) >> 2, aq2 = tid & 3;
    const bf16* pAh = Ah + (size_t)(m0 + arow) * 1024 + aq2 * 8;
    const bf16* pAl = Al + (size_t)(m0 + arow) * 1024 + aq2 * 8;
    const uint32_t stA = (uint32_t)(arow * 80 + aq2 * 16);
    const int brow = tid >> 2;
    const bf16* pBh = Bh + (size_t)(n0 + brow) * 1024 + aq2 * 8;
    const bf16* pBl = Bl + (size_t)(n0 + brow) * 1024 + aq2 * 8;
    const uint32_t stB = (uint32_t)(brow * 80 + aq2 * 16);
    const bool doA = (tid < 128);

    const uint32_t aLoff = (uint32_t)((lane & 15) * 80 + (lane >> 4) * 16);
    const uint32_t bLoff = (uint32_t)(((lane & 7) + ((lane >> 4) & 1) * 8) * 80
                                      + ((lane >> 3) & 1) * 16);

    float c[2][4];
#pragma unroll
    for (int j = 0; j < 2; j++)
#pragma unroll
        for (int q = 0; q < 4; q++) c[j][q] = 0.f;

    {
        if (doA) {
            cp_async16(sb + stA, pAh);
            cp_async16(sb + OFF_AL + stA, pAl);
        }
        cp_async16(sb + OFF_BH + stB, pBh);
        cp_async16(sb + OFF_BH + B_BYTES + stB, pBl);
        CP_COMMIT();
        CP_WAIT0();
    }
    __syncthreads();

    for (int cidx = 0; cidx < 32; cidx++) {
        const uint32_t bufOff = (uint32_t)((cidx & 1) * BUF);
        const bool more = (cidx + 1 < 32);

        if (more) {
            const int ko = (cidx + 1) * 32;
            uint32_t d = sb + (uint32_t)(((cidx + 1) & 1) * BUF);
            if (doA) {
                cp_async16(d + stA, pAh + ko);
                cp_async16(d + OFF_AL + stA, pAl + ko);
            }
            cp_async16(d + OFF_BH + stB, pBh + ko);
            cp_async16(d + OFF_BH + B_BYTES + stB, pBl + ko);
            CP_COMMIT();
        }

        const uint32_t aBase = sb + bufOff + (uint32_t)(wm * 16 * 80) + aLoff;
#pragma unroll
        for (int ks = 0; ks < 2; ks++) {
            uint32_t afh[4], afl[4];
            ldsm4(afh, aBase + (uint32_t)(ks * 32));
            ldsm4(afl, aBase + OFF_AL + (uint32_t)(ks * 32));
            uint32_t bfh[4], bfl[4];
            const uint32_t bBase = sb + bufOff + OFF_BH
                                 + (uint32_t)(wn * 16 * 80) + bLoff
                                 + (uint32_t)(ks * 32);
            ldsm4(bfh, bBase);
            ldsm4(bfl, bBase + (uint32_t)B_BYTES);
#pragma unroll
            for (int ni = 0; ni < 2; ni++) {
                const uint32_t* bhp = &bfh[ni * 2];
                const uint32_t* blp = &bfl[ni * 2];
                mma_bf16(c[ni], afh, bhp);
                mma_bf16(c[ni], afh, blp);
                mma_bf16(c[ni], afl, bhp);
            }
        }

        if (more) CP_WAIT0();
        __syncthreads();
    }

    const int r0 = m0 + wm * 16 + (lane >> 2);
    const int r1 = r0 + 8;
#pragma unroll
    for (int ni = 0; ni < 2; ni++) {
        const int gcol = n0 + wn * 16 + ni * 8 + (lane & 3) * 2;
        float v0 = c[ni][0], v1 = c[ni][1];
        float v2 = c[ni][2], v3 = c[ni][3];
        if (gcol < tanhN) {
            v0 = tanhf(v0); v1 = tanhf(v1);
            v2 = tanhf(v2); v3 = tanhf(v3);
        }
        if (gcol < maxcol) {
            if (Cm) {
                *(float2*)&Cm[(size_t)r0 * cstride + gcol] = make_float2(v0, v1);
                *(float2*)&Cm[(size_t)r1 * cstride + gcol] = make_float2(v2, v3);
            }
            if (oh) {
                uint32_t h0, l0, h1, l1;
                split2(v0, v1, h0, l0);
                split2(v2, v3, h1, l1);
                *(uint32_t*)&oh[(size_t)r0 * ostride + ocol + gcol] = h0;
                *(uint32_t*)&ol[(size_t)r0 * ostride + ocol + gcol] = l0;
                *(uint32_t*)&oh[(size_t)r1 * ostride + ocol + gcol] = h1;
                *(uint32_t*)&ol[(size_t)r1 * ostride + ocol + gcol] = l1;
            }
        }
    }
}

// mixin up-projection: writes bf16 hi/lo (mixinh/mixinl, stride 128)
__global__ void __launch_bounds__(256)
gemm_up_mix()
{
    extern __shared__ __align__(16) char sm[];
    up64_body(g_s.xmixh, g_s.xmixl, g_s.mw1Th, g_s.mw1Tl,
              blockIdx.x * 32, blockIdx.y * 64, 128, 128,
              0, 0, g_s.mixinh, g_s.mixinl, 128, 0, sm);
}

// batched post-mix up-projections: y 0-1 gate1, 2-3 lora_wa, 4 lora_k
__global__ void __launch_bounds__(256)
gemm_up_batch()
{
    extern __shared__ __align__(16) char sm[];
    const int y = blockIdx.y;
    const int m0 = blockIdx.x * 32;
    if (y < 2) {
        up64_body(g_s.xrgh, g_s.xrgl, g_s.gw1Th, g_s.gw1Tl,
                  m0, y * 64, 128, 128,
                  0, 0, g_s.g1h, g_s.g1l, 128, 0, sm);
    } else if (y < 4) {
        up64_body(g_s.xwah, g_s.xwal, g_s.waTh, g_s.waTl,
                  m0, (y - 2) * 64, 64, 128,
                  0, 0, g_s.loraAh, g_s.loraAl, 160, 0, sm);
    } else {
        up64_body(g_s.xkh, g_s.xkl, g_s.kTh, g_s.kTl,
                  m0, 0, 16, 32,
                  0, 0, g_s.loraAh, g_s.loraAl, 160, 128, sm);
    }
}

// ---------------------------------------------------------------------------
// conv4: 4 weight matrices fp32 -> bf16 hi/lo in one launch
// ---------------------------------------------------------------------------
__global__ void __launch_bounds__(256)
conv4(const float* __restrict__ w0, const float* __restrict__ w1,
      const float* __restrict__ w2, const float* __restrict__ w3)
{
    const int wq = blockIdx.x >> 10;
    const int i  = (blockIdx.x & 1023) * 256 + threadIdx.x;
    const float* src; bf16 *dh, *dl;
    switch (wq) {
        case 0:  src = w0; dh = g_s.wrh; dl = g_s.wrl; break;
        case 1:  src = w1; dh = g_s.wkh; dl = g_s.wkl; break;
        case 2:  src = w2; dh = g_s.wvh; dl = g_s.wvl; break;
        default: src = w3; dh = g_s.woh; dl = g_s.wol; break;
    }
    uint2 hh, ll;
    split4(((const float4*)src)[i], hh, ll);
    ((uint2*)dh)[i] = hh;
    ((uint2*)dl)[i] = ll;
}

// ---------------------------------------------------------------------------
// transconv / packT / pack_bigB / pack_mix
// ---------------------------------------------------------------------------
__global__ void __launch_bounds__(256)
transconv_kernel(const float* __restrict__ src, bf16* __restrict__ dh,
                 bf16* __restrict__ dl)
{
    __shared__ float tile[32][33];
    int bx = blockIdx.x;
    int by = blockIdx.y;
    int tx = threadIdx.x & 31, ty = threadIdx.x >> 5;
#pragma unroll
    for (int i = 0; i < 4; i++)
        tile[ty + i * 8][tx] = src[(size_t)(by * 32 + ty + i * 8) * 1024 + bx * 32 + tx];
    __syncthreads();
#pragma unroll
    for (int i = 0; i < 4; i++) {
        float v = tile[tx][ty + i * 8];
        bf16 hv, lv; splitf(v, hv, lv);
        size_t di = (size_t)(bx * 32 + ty + i * 8) * 128 + by * 32 + tx;
        dh[di] = hv; dl[di] = lv;
    }
}

__global__ void __launch_bounds__(256)
packT_w1(const float* __restrict__ src, bf16* __restrict__ dh,
         bf16* __restrict__ dl)
{
    int idx = blockIdx.x * 256 + threadIdx.x;
    int cth = idx >> 10, r = idx & 1023;
    bf16 hv, lv; splitf(src[(size_t)r * 128 + cth], hv, lv);
    dh[idx] = hv; dl[idx] = lv;
}

// pack_mix: blocks 0-511 = maa_w1 transpose; 512-1023 = W2 block-transpose
__global__ void __launch_bounds__(256)
pack_mix(const float* __restrict__ w1, const float* __restrict__ w2)
{
    const int b = blockIdx.x;
    if (b < 512) {
        int idx = b * 256 + threadIdx.x;          // 128*1024
        int cth = idx >> 10, r = idx & 1023;
        bf16 hv, lv; splitf(w1[(size_t)r * 128 + cth], hv, lv);
        g_s.mw1Th[idx] = hv; g_s.mw1Tl[idx] = lv;
    } else {
        int idx = (b - 512) * 256 + threadIdx.x;  // 4096*32
        int n = idx >> 5, kq = idx & 31;
        int f = n >> 10, nloc = n & 1023;
        bf16 hv, lv;
        splitf(w2[(size_t)(f * 32 + kq) * 1024 + nloc], hv, lv);
        g_s.w2Th[idx] = hv; g_s.w2Tl[idx] = lv;
    }
}

__global__ void __launch_bounds__(256)
packT_wa(const float* __restrict__ dw1, const float* __restrict__ aw1,
         const float* __restrict__ maw1)
{
    int idx = blockIdx.x * 256 + threadIdx.x;
    int cth = idx >> 10, r = idx & 1023;
    float v = 0.f;
    if (cth < 64)      v = dw1[r * 64 + cth];
    else if (cth < 80) v = aw1[r * 16 + (cth - 64)];
    else if (cth < 96) v = maw1[r * 16 + (cth - 80)];
    bf16 hv, lv; splitf(v, hv, lv);
    g_s.waTh[idx] = hv; g_s.waTl[idx] = lv;
}
__global__ void __launch_bounds__(256)
packT_k(const float* __restrict__ kw1, const float* __restrict__ mkw1)
{
    int idx = blockIdx.x * 256 + threadIdx.x;   // 64*1024
    int cth = idx >> 10, r = idx & 1023;
    float v = 0.f;
    if (cth < 16)      v = kw1[r * 16 + cth];
    else if (cth < 32) v = mkw1[r * 16 + (cth - 16)];
    bf16 hv, lv; splitf(v, hv, lv);
    g_s.kTh[idx] = hv; g_s.kTl[idx] = lv;
}

__global__ void __launch_bounds__(256)
pack_bigB(const float* __restrict__ dw2, const float* __restrict__ aw2,
          const float* __restrict__ maw2, const float* __restrict__ kw2,
          const float* __restrict__ mkw2)
{
    int idx = blockIdx.x * 256 + threadIdx.x;
    int n = idx / 160, kq = idx - (idx / 160) * 160;
    int blk = n >> 10, nloc = n & 1023;
    float v = 0.f;
    switch (blk) {
        case 0: if (kq < 64)               v = dw2 [(size_t)kq * 1024 + nloc]; break;
        case 1: if (kq >= 64 && kq < 80)   v = aw2 [(size_t)(kq - 64) * 1024 + nloc]; break;
        case 2: if (kq >= 80 && kq < 96)   v = maw2[(size_t)(kq - 80) * 1024 + nloc]; break;
        case 3: if (kq >= 128 && kq < 144) v = kw2 [(size_t)(kq - 128) * 1024 + nloc]; break;
        default:if (kq >= 144)             v = mkw2[(size_t)(kq - 144) * 1024 + nloc]; break;
    }
    bf16 hv, lv; splitf(v, hv, lv);
    g_s.bigBh[idx] = hv; g_s.bigBl[idx] = lv;
}

// ---------------------------------------------------------------------------
// ew0
// ---------------------------------------------------------------------------
__global__ void __launch_bounds__(256)
ew0_kernel(const float* __restrict__ x, const float* __restrict__ maa_x)
{
    size_t i4  = (size_t)blockIdx.x * 256 + threadIdx.x;
    size_t idx = i4 * 4;
    int c    = (int)(idx & (CC - 1));
    int nrow = (int)(idx >> 10);
    float4 xv = *(const float4*)&x[idx];
    float4 xp = make_float4(0.f, 0.f, 0.f, 0.f);
    if (nrow & (TT - 1))
        xp = *(const float4*)&x[idx - CC];
    float4 mv = *(const float4*)&maa_x[c];
    float4 d, xm;
    d.x = xp.x - xv.x;  xm.x = xv.x + d.x * mv.x;
    d.y = xp.y - xv.y;  xm.y = xv.y + d.y * mv.y;
    d.z = xp.z - xv.z;  xm.z = xv.z + d.z * mv.z;
    d.w = xp.w - xv.w;  xm.w = xv.w + d.w * mv.w;
    *(float4*)&g_s.xx[idx] = d;
    uint2 h, l;
    split4(xm, h, l);
    *(uint2*)&g_s.xmixh[idx] = h;
    *(uint2*)&g_s.xmixl[idx] = l;
}

// ---------------------------------------------------------------------------
// combine
// ---------------------------------------------------------------------------
__global__ void __launch_bounds__(256)
combine_kernel()
{
    int n   = blockIdx.x;
    int tid = threadIdx.x;
    size_t off = (size_t)n * CC + tid * 4;

    float4 kkv = *(float4*)&g_s.kk[off];
    float ss = kkv.x*kkv.x + kkv.y*kkv.y + kkv.z*kkv.z + kkv.w*kkv.w;
#pragma unroll
    for (int o = 8; o; o >>= 1) ss += __shfl_xor_sync(0xffffffffu, ss, o, 16);
    float inv = 1.f / fmaxf(sqrtf(ss), 1e-12f);

    float4 kq = *(float4*)&g_s.k[off];
    float4 aq = *(float4*)&g_s.asig[off];
    float4 mq = *(float4*)&g_s.ma[off];
    float4 wq = *(float4*)&g_s.w[off];
    float4 mk = *(float4*)&g_s.mk2[off];
    float4 kfv, ddv, avv, bvv;
#define CMB(X) { float fac = mq.X + aq.X * (1.f - mq.X); \
    float ee = expf(fminf(wq.X * mk.X, 0.f)); \
    kfv.X = kq.X * fac * ee; \
    ddv.X = expf(wq.X); \
    float kn = kkv.X * inv; \
    avv.X = -kn; bvv.X = kn * aq.X; }
    CMB(x) CMB(y) CMB(z) CMB(w)
#undef CMB
    *(float4*)&g_s.kf[off] = kfv;
    *(float4*)&g_s.dd[off] = ddv;
    *(float4*)&g_s.av[off] = avv;
    *(float4*)&g_s.bv[off] = bvv;
}

// ---------------------------------------------------------------------------
// WKV-7 scan: cp.async 3-deep pipeline
// ---------------------------------------------------------------------------
__global__ void __launch_bounds__(256)
wkv_kernel()
{
    const int blk = blockIdx.x;
    const int b = blk >> 4;
    const int h = blk & 15;
    const int tid = threadIdx.x;
    const int i  = tid >> 2;
    const int jq = tid & 3;

    __shared__ __align__(16) float sb[4][6][64];
    const size_t rowbase = ((size_t)b * TT) * CC + h * NN;

    const float* gsrc = 0;
    uint32_t sdst[4];
    if (tid < 96) {
        int larr = tid >> 4, lq = tid & 15;
        const float* srcs[6] = { g_s.r, g_s.dd, g_s.kf, g_s.av, g_s.bv, g_s.v };
        gsrc = srcs[larr] + rowbase + lq * 4;
#pragma unroll
        for (int q = 0; q < 4; q++) sdst[q] = smem_u32(&sb[q][larr][lq * 4]);
    }

#pragma unroll
    for (int pre = 0; pre < 3; pre++) {
        if (tid < 96) cp_async16(sdst[pre], gsrc + (size_t)pre * CC);
        CP_COMMIT();
    }

    unsigned long long S2[8];
#pragma unroll
    for (int u = 0; u < 8; u++) S2[u] = 0ull;

    float* yout = g_s.y + rowbase + i;

    for (int t = 0; t < TT; t++) {
        CP_WAIT2();
        __syncthreads();
        const int p = t & 3;

        const ulonglong2* r2p = (const ulonglong2*)(sb[p][0] + jq * 16);
        const ulonglong2* d2p = (const ulonglong2*)(sb[p][1] + jq * 16);
        const ulonglong2* k2p = (const ulonglong2*)(sb[p][2] + jq * 16);
        const ulonglong2* a2p = (const ulonglong2*)(sb[p][3] + jq * 16);
        const ulonglong2* b2p = (const ulonglong2*)(sb[p][4] + jq * 16);
        const float vi = sb[p][5][i];

        ulonglong2 Rv[4], Dv[4], Kv[4], Av[4], Bv[4];
#pragma unroll
        for (int u = 0; u < 4; u++) {
            Rv[u] = r2p[u]; Dv[u] = d2p[u]; Kv[u] = k2p[u];
            Av[u] = a2p[u]; Bv[u] = b2p[u];
        }

        if (tid < 96 && t + 3 < TT)
            cp_async16(sdst[(t + 3) & 3], gsrc + (size_t)(t + 3) * CC);
        CP_COMMIT();

        unsigned long long sa0 = 0ull, sa1 = 0ull, pp0 = 0ull, pp1 = 0ull;
        unsigned long long br0 = 0ull, br1 = 0ull, kr0 = 0ull, kr1 = 0ull;
#pragma unroll
        for (int u = 0; u < 4; u++) {
            unsigned long long drx = mul2(Dv[u].x, Rv[u].x);
            unsigned long long dry = mul2(Dv[u].y, Rv[u].y);
            fma2(sa0, S2[2*u],   Av[u].x);
            fma2(sa1, S2[2*u+1], Av[u].y);
            fma2(pp0, S2[2*u],   drx);
            fma2(pp1, S2[2*u+1], dry);
            fma2(br0, Bv[u].x, Rv[u].x);
            fma2(br1, Bv[u].y, Rv[u].y);
            fma2(kr0, Kv[u].x, Rv[u].x);
            fma2(kr1, Kv[u].y, Rv[u].y);
        }
        float sa = hadd4(sa0, sa1);
        float pp = hadd4(pp0, pp1);
        float br = hadd4(br0, br1);
        float kr = hadd4(kr0, kr1);
        sa += __shfl_xor_sync(0xffffffffu, sa, 1, 4);
        pp += __shfl_xor_sync(0xffffffffu, pp, 1, 4);
        br += __shfl_xor_sync(0xffffffffu, br, 1, 4);
        kr += __shfl_xor_sync(0xffffffffu, kr, 1, 4);
        sa += __shfl_xor_sync(0xffffffffu, sa, 2, 4);
        pp += __shfl_xor_sync(0xffffffffu, pp, 2, 4);
        br += __shfl_xor_sync(0xffffffffu, br, 2, 4);
        kr += __shfl_xor_sync(0xffffffffu, kr, 2, 4);

        if (jq == 0) yout[(size_t)t * CC] = pp + sa * br + vi * kr;

        const unsigned long long sa2 = dup2(sa);
        const unsigned long long v2  = dup2(vi);
#pragma unroll
        for (int u = 0; u < 4; u++) {
            S2[2*u]   = fma2g(S2[2*u],   Dv[u].x,
                              fma2g(sa2, Bv[u].x, mul2(v2, Kv[u].x)));
            S2[2*u+1] = fma2g(S2[2*u+1], Dv[u].y,
                              fma2g(sa2, Bv[u].y, mul2(v2, Kv[u].y)));
        }
    }
}

// ---------------------------------------------------------------------------
// post: GroupNorm + bonus + gate -> z (bf16 hi/lo)
// ---------------------------------------------------------------------------
__global__ void __launch_bounds__(256)
post_kernel(const float* __restrict__ faaaa,
            const float* __restrict__ lnw, const float* __restrict__ lnb)
{
    int n   = blockIdx.x;
    int tid = threadIdx.x;
    int c   = tid * 4;
    size_t off = (size_t)n * CC + c;

    float4 yv = *(float4*)&g_s.y [off];
    float4 rv = *(float4*)&g_s.r [off];
    float4 kv = *(float4*)&g_s.kf[off];
    float4 vv = *(float4*)&g_s.v [off];
    float4 gv = *(float4*)&g_s.g [off];
    float4 fv = *(const float4*)&faaaa[c];

    float s  = yv.x + yv.y + yv.z + yv.w;
    float s2 = yv.x*yv.x + yv.y*yv.y + yv.z*yv.z + yv.w*yv.w;
    float dk = rv.x*kv.x*fv.x + rv.y*kv.y*fv.y + rv.z*kv.z*fv.z + rv.w*kv.w*fv.w;
#pragma unroll
    for (int o = 8; o; o >>= 1) {
        s  += __shfl_xor_sync(0xffffffffu, s,  o, 16);
        s2 += __shfl_xor_sync(0xffffffffu, s2, o, 16);
        dk += __shfl_xor_sync(0xffffffffu, dk, o, 16);
    }
    float mean = s  * (1.f / 64.f);
    float var  = s2 * (1.f / 64.f) - mean * mean;
    float rs   = rsqrtf(var + 64e-5f);

    float4 lw = *(const float4*)&lnw[c];
    float4 lb = *(const float4*)&lnb[c];
    float4 z;
    z.x = (((yv.x - mean) * rs) * lw.x + lb.x + dk * vv.x) * gv.x;
    z.y = (((yv.y - mean) * rs) * lw.y + lb.y + dk * vv.y) * gv.y;
    z.z = (((yv.z - mean) * rs) * lw.z + lb.z + dk * vv.z) * gv.z;
    z.w = (((yv.w - mean) * rs) * lw.w + lb.w + dk * vv.w) * gv.w;
    uint2 h, l;
    split4(z, h, l);
    *(uint2*)&g_s.zh[off] = h;
    *(uint2*)&g_s.zl[off] = l;
}

// ---------------------------------------------------------------------------
// Host orchestration
// ---------------------------------------------------------------------------
static void gmma(const bf16* Ah, const bf16* Al, const bf16* Bh,
                 const bf16* Bl, float* Cp, int K)
{
    dim3 grid(8, MM / 128);
    gemm_mma2<<<grid, 256, MMA_SMEM>>>(Ah, Al, Bh, Bl, Cp, K);
}

extern "C" void kernel_launch(void* const* d_in, const int* in_sizes, int n_in,
                              void* d_out, int out_size)
{
    const float* x       = (const float*)d_in[0];
    const float* maa_x   = (const float*)d_in[1];
    const float* maa_rg  = (const float*)d_in[2];
    const float* maa_wa  = (const float*)d_in[3];
    const float* maa_k   = (const float*)d_in[4];
    const float* maa_v   = (const float*)d_in[5];
    const float* maa_w1  = (const float*)d_in[6];
    const float* maa_w2  = (const float*)d_in[7];
    const float* tdecay  = (const float*)d_in[8];
    const float* dw1     = (const float*)d_in[9];
    const float* dw2     = (const float*)d_in[10];
    const float* faaaa   = (const float*)d_in[11];
    const float* taaaaa  = (const float*)d_in[12];
    const float* aw1     = (const float*)d_in[13];
    const float* aw2     = (const float*)d_in[14];
    const float* kw1     = (const float*)d_in[15];
    const float* kw2     = (const float*)d_in[16];
    const float* gw1     = (const float*)d_in[17];
    const float* gw2     = (const float*)d_in[18];
    const float* maw1    = (const float*)d_in[19];
    const float* maw2    = (const float*)d_in[20];
    const float* tmisca  = (const float*)d_in[21];
    const float* mkw1    = (const float*)d_in[22];
    const float* mkw2    = (const float*)d_in[23];
    const float* tmisck  = (const float*)d_in[24];
    const float* wr      = (const float*)d_in[25];
    const float* wk      = (const float*)d_in[26];
    const float* wv      = (const float*)d_in[27];
    const float* wo      = (const float*)d_in[28];
    const float* lnw     = (const float*)d_in[29];
    const float* lnb     = (const float*)d_in[30];
    float* out = (float*)d_out;
    (void)in_sizes; (void)n_in; (void)out_size;

    Scratch* S = nullptr;
    cudaGetSymbolAddress((void**)&S, g_s);
    cudaFuncSetAttribute(gemm_mma2, cudaFuncAttributeMaxDynamicSharedMemorySize,
                         MMA_SMEM);
    cudaFuncSetAttribute(gemm_down, cudaFuncAttributeMaxDynamicSharedMemorySize,
                         MMA_SMEM);
    cudaFuncSetAttribute(gemm_mix_mma,
                         cudaFuncAttributeMaxDynamicSharedMemorySize, MIXMMA_SMEM);
    cudaFuncSetAttribute(gemm_up_mix,
                         cudaFuncAttributeMaxDynamicSharedMemorySize, UP64_SMEM);
    cudaFuncSetAttribute(gemm_up_batch,
                         cudaFuncAttributeMaxDynamicSharedMemorySize, UP64_SMEM);

    // 1-4: ncu captures the 4th launch -> gemm_mix_mma
    ew0_kernel<<<(MM * CC / 4) / 256, 256>>>(x, maa_x);                  // 1
    pack_mix<<<1024, 256>>>(maa_w1, maa_w2);                             // 2
    gemm_up_mix<<<dim3(128, 2), 256, UP64_SMEM>>>();                     // 3
    gemm_mix_mma<<<dim3(32, 32), 256, MIXMMA_SMEM>>>(x,                  // 4
        maa_rg, maa_wa, maa_k, maa_v);

    // weight conversions / packs
    conv4<<<4096, 256>>>(wr, wk, wv, wo);
    packT_w1<<<512, 256>>>(gw1, S->gw1Th, S->gw1Tl);
    packT_wa<<<512, 256>>>(dw1, aw1, maw1);
    packT_k<<<256, 256>>>(kw1, mkw1);
    transconv_kernel<<<dim3(32, 4), 256>>>(gw2, S->gw2Th, S->gw2Tl);
    pack_bigB<<<(5120 * 160) / 256, 256>>>(dw2, aw2, maw2, kw2, mkw2);

    // big projections
    gmma(S->xrgh, S->xrgl, S->wrh, S->wrl, S->r, 1024);
    gmma(S->xkh,  S->xkl,  S->wkh, S->wkl, S->k, 1024);
    gmma(S->xvh,  S->xvl,  S->wvh, S->wvl, S->v, 1024);

    // batched up-projections (gate1 + lora_wa + lora_k)
    gemm_up_batch<<<dim3(128, 5), 256, UP64_SMEM>>>();

    // gate down-projection
    gmma(S->g1h, S->g1l, S->gw2Th, S->gw2Tl, S->g, 128);

    // fused block-diagonal LoRA down-projection
    gemm_down<<<dim3(40, 32), 256, MMA_SMEM>>>(tdecay, taaaaa, tmisca, tmisck);

    // combine + scan + post + output
    combine_kernel<<<MM, 256>>>();
    wkv_kernel<<<BB * HH, 256>>>();
    post_kernel<<<MM, 256>>>(faaaa, lnw, lnb);
    gmma(S->zh, S->zl, S->woh, S->wol, out, 1024);
}